// round 2
// baseline (speedup 1.0000x reference)
#include <cuda_runtime.h>
#include <math.h>
#include <stdint.h>

#define B_  128
#define C_  1024
#define H_  24
#define W_  24
#define N_  576          // H*W
#define NH  8
#define HD  128          // C/NH
#define QH  12
#define QW  12
#define QN  144          // QH*QW

// ---------------- scratch (static device allocations; allowed) ----------------
__device__ float g_xt  [(size_t)B_*N_*C_];     // [B,N,C]   302 MB
__device__ float g_xp  [(size_t)B_*QN*C_];     // [B,qN,C]   75 MB
__device__ float g_q   [(size_t)B_*QN*C_];     // [B,qN,C]   75 MB
__device__ float g_k   [(size_t)B_*N_*C_];     // [B,N,C]   302 MB
__device__ float g_v   [(size_t)B_*N_*C_];     // [B,N,C]   302 MB
__device__ float g_attn[(size_t)B_*NH*QN*N_];  // [BH,qN,N] 340 MB
__device__ float g_relh[(size_t)B_*NH*QN*H_];  // [BH,qN,24]
__device__ float g_relw[(size_t)B_*NH*QN*W_];  // [BH,qN,24]
__device__ float g_o   [(size_t)B_*QN*C_];     // [B,qN,C]   75 MB

// ---------------- 1) transpose x[B,C,N] -> xt[B,N,C] ----------------
__global__ __launch_bounds__(256) void transpose_kernel(const float* __restrict__ x) {
    __shared__ float tile[32][33];
    int b  = blockIdx.z;
    int n0 = blockIdx.x * 32;   // over N (576/32 = 18)
    int c0 = blockIdx.y * 32;   // over C (1024/32 = 32)
    int tx = threadIdx.x, ty = threadIdx.y;  // (32, 8)
    const float* xb = x + (size_t)b * C_ * N_;
    #pragma unroll
    for (int i = 0; i < 4; i++) {
        int c = c0 + ty + i * 8;
        tile[ty + i * 8][tx] = xb[(size_t)c * N_ + n0 + tx];
    }
    __syncthreads();
    float* xt = g_xt + (size_t)b * N_ * C_;
    #pragma unroll
    for (int i = 0; i < 4; i++) {
        int n = n0 + ty + i * 8;
        xt[(size_t)n * C_ + c0 + tx] = tile[tx][ty + i * 8];
    }
}

// ---------------- 2) avg-pool 3x3 s2 pad1 (count_include_pad) -> xp[B,qN,C] ----------------
__global__ __launch_bounds__(256) void pool_kernel(const float* __restrict__ x) {
    __shared__ float sp[16][577];   // [c_local][spatial], padded stride
    int b  = blockIdx.y;
    int c0 = blockIdx.x * 16;
    int tid = threadIdx.x;
    const float* xb = x + (size_t)b * C_ * N_ + (size_t)c0 * N_;
    #pragma unroll
    for (int r = 0; r < 36; r++) {          // 16*576/256 = 36
        int idx = tid + r * 256;
        int p = idx / 576, n = idx - p * 576;
        sp[p][n] = xb[(size_t)p * N_ + n];
    }
    __syncthreads();
    #pragma unroll
    for (int r = 0; r < 9; r++) {           // 144*16/256 = 9
        int idx = tid + r * 256;
        int qn = idx >> 4, cl = idx & 15;
        int qy = qn / 12, qx = qn - qy * 12;
        float s = 0.f;
        #pragma unroll
        for (int dy = -1; dy <= 1; dy++) {
            int y = 2 * qy + dy;
            if ((unsigned)y < 24u) {
                #pragma unroll
                for (int dx = -1; dx <= 1; dx++) {
                    int xx = 2 * qx + dx;
                    if ((unsigned)xx < 24u) s += sp[cl][y * 24 + xx];
                }
            }
        }
        g_xp[((size_t)b * QN + qn) * C_ + c0 + cl] = s * (1.0f / 9.0f);
    }
}

// ---------------- 3) generic GEMM C = A[M,K] @ B[K,N] (+ bias / NCHW scatter) ----------------
// mode 0: C[m,n] row-major.  mode 1: out[b, n, m%QN] with bias (final projection)
__global__ __launch_bounds__(256) void gemm128(const float* __restrict__ A,
                                               const float* __restrict__ Bm,
                                               const float* __restrict__ bias,
                                               float* __restrict__ Cm,
                                               int M, int N, int K, int mode) {
    __shared__ float As[8][128];  // transposed: As[k][m]
    __shared__ float Bs[8][128];
    int tid = threadIdx.x;
    int rowBase = blockIdx.y * 128;
    int colBase = blockIdx.x * 128;
    int aRow = tid >> 1;
    int aK   = (tid & 1) * 4;
    int bK   = tid >> 5;
    int bCol = (tid & 31) * 4;
    const float* Ap = A  + (size_t)(rowBase + aRow) * K + aK;
    const float* Bp = Bm + (size_t)bK * N + colBase + bCol;
    int ty = tid >> 4, tx = tid & 15;
    float acc[8][8];
    #pragma unroll
    for (int i = 0; i < 8; i++)
        #pragma unroll
        for (int j = 0; j < 8; j++) acc[i][j] = 0.f;

    for (int k0 = 0; k0 < K; k0 += 8) {
        float4 a4 = *(const float4*)(Ap + k0);
        float4 b4 = *(const float4*)(Bp + (size_t)k0 * N);
        As[aK + 0][aRow] = a4.x;
        As[aK + 1][aRow] = a4.y;
        As[aK + 2][aRow] = a4.z;
        As[aK + 3][aRow] = a4.w;
        *(float4*)&Bs[bK][bCol] = b4;
        __syncthreads();
        #pragma unroll
        for (int k = 0; k < 8; k++) {
            float ar[8], br[8];
            *(float4*)&ar[0] = *(const float4*)&As[k][ty * 8];
            *(float4*)&ar[4] = *(const float4*)&As[k][ty * 8 + 4];
            *(float4*)&br[0] = *(const float4*)&Bs[k][tx * 8];
            *(float4*)&br[4] = *(const float4*)&Bs[k][tx * 8 + 4];
            #pragma unroll
            for (int i = 0; i < 8; i++)
                #pragma unroll
                for (int j = 0; j < 8; j++)
                    acc[i][j] += ar[i] * br[j];
        }
        __syncthreads();
    }

    if (mode == 0) {
        #pragma unroll
        for (int i = 0; i < 8; i++) {
            int row = rowBase + ty * 8 + i;
            float* cp = Cm + (size_t)row * N + colBase + tx * 8;
            *(float4*)(cp + 0) = make_float4(acc[i][0], acc[i][1], acc[i][2], acc[i][3]);
            *(float4*)(cp + 4) = make_float4(acc[i][4], acc[i][5], acc[i][6], acc[i][7]);
        }
    } else {
        #pragma unroll
        for (int i = 0; i < 8; i++) {
            int row = rowBase + ty * 8 + i;
            int bq = row / QN, qi = row - bq * QN;
            #pragma unroll
            for (int j = 0; j < 8; j++) {
                int col = colBase + tx * 8 + j;
                Cm[((size_t)bq * C_ + col) * QN + qi] = acc[i][j] + bias[col];
            }
        }
    }
}

// ---------------- 4) relative position bias dots ----------------
// rh[bh,i,ky] = dot(q[bh,i,:], rel_pos_h[2*qy-ky+23, :]);  rw analogous
__global__ __launch_bounds__(64) void relpos_kernel(const float* __restrict__ rel_h,
                                                    const float* __restrict__ rel_w) {
    int gid = blockIdx.x;              // bh*QN + i
    int bh = gid / QN, i = gid - bh * QN;
    int b = bh >> 3, h = bh & 7;
    int qy = i / 12, qx = i - qy * 12;
    int t = threadIdx.x;
    const float* qrow = g_q + ((size_t)b * QN + i) * C_ + h * HD;
    if (t < 24) {
        const float* R = rel_h + (size_t)(2 * qy - t + 23) * HD;
        float a0 = 0, a1 = 0, a2 = 0, a3 = 0;
        #pragma unroll
        for (int d = 0; d < HD; d += 4) {
            a0 += qrow[d + 0] * R[d + 0];
            a1 += qrow[d + 1] * R[d + 1];
            a2 += qrow[d + 2] * R[d + 2];
            a3 += qrow[d + 3] * R[d + 3];
        }
        g_relh[(size_t)gid * 24 + t] = (a0 + a1) + (a2 + a3);
    } else if (t >= 32 && t < 56) {
        int kx = t - 32;
        const float* R = rel_w + (size_t)(2 * qx - kx + 23) * HD;
        float a0 = 0, a1 = 0, a2 = 0, a3 = 0;
        #pragma unroll
        for (int d = 0; d < HD; d += 4) {
            a0 += qrow[d + 0] * R[d + 0];
            a1 += qrow[d + 1] * R[d + 1];
            a2 += qrow[d + 2] * R[d + 2];
            a3 += qrow[d + 3] * R[d + 3];
        }
        g_relw[(size_t)gid * 24 + kx] = (a0 + a1) + (a2 + a3);
    }
}

// ---------------- 5) attn logits: scale*q@k^T + rel_h + rel_w ----------------
// per (b,h): [144,128] @ [576,128]^T ; tile 48x64, thread 3x4
__global__ __launch_bounds__(256) void qk_kernel() {
    __shared__ float Qs[64][49];   // [k][row]
    __shared__ float Ks[64][68];   // [k][col]
    int bh = blockIdx.z;
    int b = bh >> 3, h = bh & 7;
    int rowBase = blockIdx.y * 48;
    int colBase = blockIdx.x * 64;
    int tid = threadIdx.x;
    int tx = tid & 15, ty = tid >> 4;
    const float* qbase = g_q + ((size_t)b * QN + rowBase) * C_ + h * HD;
    const float* kbase = g_k + ((size_t)b * N_ + colBase) * C_ + h * HD;
    float acc[3][4] = {{0.f}};

    for (int kc = 0; kc < HD; kc += 64) {
        #pragma unroll
        for (int r = 0; r < 3; r++) {          // 48*64/4/256 = 3
            int f4i = tid + 256 * r;
            int row = f4i >> 4;
            int kk = (f4i & 15) * 4;
            float4 vv = *(const float4*)(qbase + (size_t)row * C_ + kc + kk);
            Qs[kk + 0][row] = vv.x; Qs[kk + 1][row] = vv.y;
            Qs[kk + 2][row] = vv.z; Qs[kk + 3][row] = vv.w;
        }
        #pragma unroll
        for (int r = 0; r < 4; r++) {          // 64*64/4/256 = 4
            int f4i = tid + 256 * r;
            int col = f4i >> 4;
            int kk = (f4i & 15) * 4;
            float4 vv = *(const float4*)(kbase + (size_t)col * C_ + kc + kk);
            Ks[kk + 0][col] = vv.x; Ks[kk + 1][col] = vv.y;
            Ks[kk + 2][col] = vv.z; Ks[kk + 3][col] = vv.w;
        }
        __syncthreads();
        #pragma unroll 8
        for (int kk = 0; kk < 64; kk++) {
            float4 bv = *(const float4*)&Ks[kk][tx * 4];
            float a0 = Qs[kk][ty * 3 + 0];
            float a1 = Qs[kk][ty * 3 + 1];
            float a2 = Qs[kk][ty * 3 + 2];
            acc[0][0] += a0 * bv.x; acc[0][1] += a0 * bv.y; acc[0][2] += a0 * bv.z; acc[0][3] += a0 * bv.w;
            acc[1][0] += a1 * bv.x; acc[1][1] += a1 * bv.y; acc[1][2] += a1 * bv.z; acc[1][3] += a1 * bv.w;
            acc[2][0] += a2 * bv.x; acc[2][1] += a2 * bv.y; acc[2][2] += a2 * bv.z; acc[2][3] += a2 * bv.w;
        }
        __syncthreads();
    }

    const float scale = 0.08838834764831845f;   // 128^-0.5
    #pragma unroll
    for (int m = 0; m < 3; m++) {
        int i = rowBase + ty * 3 + m;
        const float* rh = g_relh + ((size_t)bh * QN + i) * 24;
        const float* rw = g_relw + ((size_t)bh * QN + i) * 24;
        float* sp = g_attn + ((size_t)bh * QN + i) * N_ + colBase + tx * 4;
        #pragma unroll
        for (int j = 0; j < 4; j++) {
            int jj = colBase + tx * 4 + j;
            int ky = jj / 24, kx = jj - ky * 24;
            sp[j] = acc[m][j] * scale + rh[ky] + rw[kx];
        }
    }
}

// ---------------- 6) softmax over last dim (576) ----------------
__global__ __launch_bounds__(192) void softmax_kernel() {
    __shared__ float sm[6], ss[6];
    size_t row = blockIdx.x;
    float* p = g_attn + row * (size_t)N_;
    int t = threadIdx.x;
    float v0 = p[t], v1 = p[t + 192], v2 = p[t + 384];
    float m = fmaxf(v0, fmaxf(v1, v2));
    #pragma unroll
    for (int o = 16; o > 0; o >>= 1) m = fmaxf(m, __shfl_xor_sync(0xffffffffu, m, o));
    if ((t & 31) == 0) sm[t >> 5] = m;
    __syncthreads();
    float mm = fmaxf(fmaxf(fmaxf(sm[0], sm[1]), fmaxf(sm[2], sm[3])), fmaxf(sm[4], sm[5]));
    float e0 = __expf(v0 - mm), e1 = __expf(v1 - mm), e2 = __expf(v2 - mm);
    float s = e0 + e1 + e2;
    #pragma unroll
    for (int o = 16; o > 0; o >>= 1) s += __shfl_xor_sync(0xffffffffu, s, o);
    if ((t & 31) == 0) ss[t >> 5] = s;
    __syncthreads();
    float tot = (ss[0] + ss[1]) + (ss[2] + ss[3]) + (ss[4] + ss[5]);
    float inv = 1.0f / tot;
    p[t] = e0 * inv; p[t + 192] = e1 * inv; p[t + 384] = e2 * inv;
}

// ---------------- 7) out = attn @ v + q  (per b,h: [144,576]@[576,128]) ----------------
__global__ __launch_bounds__(256) void av_kernel() {
    __shared__ float Ps[48][33];
    __shared__ float Vs[32][68];
    int bh = blockIdx.z;
    int b = bh >> 3, h = bh & 7;
    int rowBase = blockIdx.y * 48;
    int colBase = blockIdx.x * 64;
    int tid = threadIdx.x;
    int tx = tid & 15, ty = tid >> 4;
    const float* pbase = g_attn + ((size_t)bh * QN + rowBase) * N_;
    const float* vbase = g_v + (size_t)b * N_ * C_ + h * HD + colBase;
    float acc[3][4] = {{0.f}};

    for (int k0 = 0; k0 < N_; k0 += 32) {
        #pragma unroll
        for (int r = 0; r < 6; r++) {          // 48*32/256 = 6
            int idx = tid + 256 * r;
            int row = idx >> 5, kk = idx & 31;
            Ps[row][kk] = pbase[(size_t)row * N_ + k0 + kk];
        }
        #pragma unroll
        for (int r = 0; r < 2; r++) {          // 32*64/4/256 = 2
            int f4i = tid + 256 * r;
            int vrow = f4i >> 4, col = (f4i & 15) * 4;
            float4 vv = *(const float4*)(vbase + (size_t)(k0 + vrow) * C_ + col);
            *(float4*)&Vs[vrow][col] = vv;
        }
        __syncthreads();
        #pragma unroll 8
        for (int kk = 0; kk < 32; kk++) {
            float4 bv = *(const float4*)&Vs[kk][tx * 4];
            float a0 = Ps[ty * 3 + 0][kk];
            float a1 = Ps[ty * 3 + 1][kk];
            float a2 = Ps[ty * 3 + 2][kk];
            acc[0][0] += a0 * bv.x; acc[0][1] += a0 * bv.y; acc[0][2] += a0 * bv.z; acc[0][3] += a0 * bv.w;
            acc[1][0] += a1 * bv.x; acc[1][1] += a1 * bv.y; acc[1][2] += a1 * bv.z; acc[1][3] += a1 * bv.w;
            acc[2][0] += a2 * bv.x; acc[2][1] += a2 * bv.y; acc[2][2] += a2 * bv.z; acc[2][3] += a2 * bv.w;
        }
        __syncthreads();
    }

    #pragma unroll
    for (int m = 0; m < 3; m++) {
        int i = rowBase + ty * 3 + m;
        size_t off = ((size_t)b * QN + i) * C_ + h * HD + colBase + tx * 4;
        const float* qp = g_q + off;
        float* op = g_o + off;
        #pragma unroll
        for (int j = 0; j < 4; j++) op[j] = acc[m][j] + qp[j];
    }
}

// ---------------- launch ----------------
extern "C" void kernel_launch(void* const* d_in, const int* in_sizes, int n_in,
                              void* d_out, int out_size) {
    const float* x   = (const float*)d_in[0];
    const float* Wq  = (const float*)d_in[1];
    const float* Wk  = (const float*)d_in[2];
    const float* Wv  = (const float*)d_in[3];
    const float* Wp  = (const float*)d_in[4];
    const float* bp  = (const float*)d_in[5];
    const float* rph = (const float*)d_in[6];
    const float* rpw = (const float*)d_in[7];
    float* out = (float*)d_out;

    float *xt, *xp, *q, *k, *v, *o;
    cudaGetSymbolAddress((void**)&xt, g_xt);
    cudaGetSymbolAddress((void**)&xp, g_xp);
    cudaGetSymbolAddress((void**)&q,  g_q);
    cudaGetSymbolAddress((void**)&k,  g_k);
    cudaGetSymbolAddress((void**)&v,  g_v);
    cudaGetSymbolAddress((void**)&o,  g_o);

    transpose_kernel<<<dim3(18, 32, B_), dim3(32, 8)>>>(x);
    pool_kernel<<<dim3(C_ / 16, B_), 256>>>(x);

    gemm128<<<dim3(C_ / 128, (B_ * N_) / 128), 256>>>(xt, Wk, nullptr, k, B_ * N_, C_, C_, 0);
    gemm128<<<dim3(C_ / 128, (B_ * N_) / 128), 256>>>(xt, Wv, nullptr, v, B_ * N_, C_, C_, 0);
    gemm128<<<dim3(C_ / 128, (B_ * QN) / 128), 256>>>(xp, Wq, nullptr, q, B_ * QN, C_, C_, 0);

    relpos_kernel<<<B_ * NH * QN, 64>>>(rph, rpw);
    qk_kernel<<<dim3(N_ / 64, QN / 48, B_ * NH), 256>>>();
    softmax_kernel<<<B_ * NH * QN, 192>>>();
    av_kernel<<<dim3(HD / 64, QN / 48, B_ * NH), 256>>>();

    gemm128<<<dim3(C_ / 128, (B_ * QN) / 128), 256>>>(o, Wp, bp, out, B_ * QN, C_, C_, 1);
}

// round 4
// speedup vs baseline: 1.9464x; 1.9464x over previous
#include <cuda_runtime.h>
#include <cuda_bf16.h>
#include <math.h>
#include <stdint.h>

#define B_  128
#define C_  1024
#define H_  24
#define W_  24
#define N_  576          // H*W
#define NH  8
#define HD  128          // C/NH
#define QH  12
#define QW  12
#define QN  144          // QH*QW
#define K3  3072         // 3*C : split-bf16 expanded K
#define NT  96           // K3/32 k-tiles

// ---------------- scratch ----------------
__device__ float g_xp  [(size_t)B_*QN*C_];     // pooled x [B,qN,C]
__device__ float g_q   [(size_t)B_*QN*C_];
__device__ float g_k   [(size_t)B_*N_*C_];
__device__ float g_v   [(size_t)B_*N_*C_];
__device__ float g_attn[(size_t)B_*NH*QN*N_];
__device__ float g_relh[(size_t)B_*NH*QN*H_];
__device__ float g_relw[(size_t)B_*NH*QN*W_];
__device__ float g_o   [(size_t)B_*QN*C_];
// split-bf16 operands
__device__ __nv_bfloat16 g_ax[(size_t)B_*N_*K3];   // A' for K/V gemm  (x transposed+split)
__device__ __nv_bfloat16 g_aq[(size_t)B_*QN*K3];   // A' for Q gemm    (xp split)
__device__ __nv_bfloat16 g_ao[(size_t)B_*QN*K3];   // A' for out gemm  (o split)
__device__ __nv_bfloat16 g_bwq[(size_t)K3*C_];
__device__ __nv_bfloat16 g_bwk[(size_t)K3*C_];
__device__ __nv_bfloat16 g_bwv[(size_t)K3*C_];
__device__ __nv_bfloat16 g_bwp[(size_t)K3*C_];

// ---------------- helpers ----------------
__device__ __forceinline__ void split2(float v, __nv_bfloat16& hi, __nv_bfloat16& lo) {
    hi = __float2bfloat16(v);
    lo = __float2bfloat16(v - __bfloat162float(hi));
}

#define CP_ASYNC16(dst, src) \
    asm volatile("cp.async.cg.shared.global [%0], [%1], 16;" :: "r"(dst), "l"(src))
#define CP_COMMIT() asm volatile("cp.async.commit_group;")
#define CP_WAIT0()  asm volatile("cp.async.wait_group 0;")

// ---------------- conversion kernels ----------------
// weight W[1024,1024] -> B'[3072,1024] = [Wh ; Wl ; Wh]
__global__ __launch_bounds__(256) void split_w_kernel(const float* __restrict__ W,
                                                      __nv_bfloat16* __restrict__ Bp) {
    int i = blockIdx.x * 256 + threadIdx.x;          // 0..1M-1
    float w = W[i];
    __nv_bfloat16 hi, lo; split2(w, hi, lo);
    Bp[i] = hi;
    Bp[i + C_ * C_] = lo;
    Bp[i + 2 * C_ * C_] = hi;
}

// x[B,C,N] -> A'[B*N, 3072] = [xh | xh | xl] (transposed)
__global__ __launch_bounds__(256) void split_x_kernel(const float* __restrict__ x) {
    __shared__ float tile[32][33];
    int b  = blockIdx.z;
    int n0 = blockIdx.x * 32;
    int c0 = blockIdx.y * 32;
    int tx = threadIdx.x, ty = threadIdx.y;          // (32,8)
    const float* xb = x + (size_t)b * C_ * N_;
    #pragma unroll
    for (int i = 0; i < 4; i++)
        tile[ty + i * 8][tx] = xb[(size_t)(c0 + ty + i * 8) * N_ + n0 + tx];
    __syncthreads();
    #pragma unroll
    for (int i = 0; i < 4; i++) {
        int n = n0 + ty + i * 8;
        float v = tile[tx][ty + i * 8];
        __nv_bfloat16 hi, lo; split2(v, hi, lo);
        size_t base = ((size_t)b * N_ + n) * K3 + c0 + tx;
        g_ax[base] = hi; g_ax[base + C_] = hi; g_ax[base + 2 * C_] = lo;
    }
}

// generic row-major [rows,1024] fp32 -> [rows,3072] split
__global__ __launch_bounds__(256) void split_rows_kernel(const float* __restrict__ in,
                                                         __nv_bfloat16* __restrict__ out) {
    int i = blockIdx.x * 256 + threadIdx.x;
    int row = i >> 10, c = i & 1023;
    float v = in[i];
    __nv_bfloat16 hi, lo; split2(v, hi, lo);
    size_t base = (size_t)row * K3 + c;
    out[base] = hi; out[base + C_] = hi; out[base + 2 * C_] = lo;
}

// ---------------- avg-pool 3x3 s2 pad1 -> xp[B,qN,C] ----------------
__global__ __launch_bounds__(256) void pool_kernel(const float* __restrict__ x) {
    __shared__ float sp[16][577];
    int b  = blockIdx.y;
    int c0 = blockIdx.x * 16;
    int tid = threadIdx.x;
    const float* xb = x + (size_t)b * C_ * N_ + (size_t)c0 * N_;
    #pragma unroll
    for (int r = 0; r < 36; r++) {
        int idx = tid + r * 256;
        int p = idx / 576, n = idx - p * 576;
        sp[p][n] = xb[(size_t)p * N_ + n];
    }
    __syncthreads();
    #pragma unroll
    for (int r = 0; r < 9; r++) {
        int idx = tid + r * 256;
        int qn = idx >> 4, cl = idx & 15;
        int qy = qn / 12, qx = qn - qy * 12;
        float s = 0.f;
        #pragma unroll
        for (int dy = -1; dy <= 1; dy++) {
            int y = 2 * qy + dy;
            if ((unsigned)y < 24u) {
                #pragma unroll
                for (int dx = -1; dx <= 1; dx++) {
                    int xx = 2 * qx + dx;
                    if ((unsigned)xx < 24u) s += sp[cl][y * 24 + xx];
                }
            }
        }
        g_xp[((size_t)b * QN + qn) * C_ + c0 + cl] = s * (1.0f / 9.0f);
    }
}

// ---------------- bf16 tensor-core GEMM: C[M,1024] = A[M,3072] @ B[3072,1024] ----------------
// mode 0: row-major fp32 out.  mode 1: out[bq, col, qi] NCHW scatter + bias.
__global__ __launch_bounds__(256) void gemm_bf16(const __nv_bfloat16* __restrict__ A,
                                                 const __nv_bfloat16* __restrict__ Bm,
                                                 const float* __restrict__ bias,
                                                 float* __restrict__ Cm,
                                                 int mode) {
    __shared__ __nv_bfloat16 As[2][128][40];   // 32 k + 8 pad
    __shared__ __nv_bfloat16 Bs[2][32][136];   // 128 n + 8 pad

    int tid  = threadIdx.x;
    int lane = tid & 31;
    int warp = tid >> 5;
    int wm = warp >> 1;          // 0..3
    int wn = warp & 1;           // 0..1
    int mBase = wm * 32;
    int nBase = wn * 64;
    int rowBase = blockIdx.y * 128;
    int colBase = blockIdx.x * 128;

    float acc[2][8][4];
    #pragma unroll
    for (int i = 0; i < 2; i++)
        #pragma unroll
        for (int j = 0; j < 8; j++)
            #pragma unroll
            for (int r = 0; r < 4; r++) acc[i][j][r] = 0.f;

    // prefetch: tile kt into buffer buf
    auto prefetch = [&](int kt, int buf) {
        #pragma unroll
        for (int c = 0; c < 2; c++) {
            int chunk = c * 256 + tid;               // 0..511
            int row = chunk >> 2, off = (chunk & 3) * 8;
            const __nv_bfloat16* src = A + (size_t)(rowBase + row) * K3 + kt * 32 + off;
            uint32_t dst = (uint32_t)__cvta_generic_to_shared(&As[buf][row][off]);
            CP_ASYNC16(dst, src);
        }
        #pragma unroll
        for (int c = 0; c < 2; c++) {
            int chunk = c * 256 + tid;
            int row = chunk >> 4, col = (chunk & 15) * 8;
            const __nv_bfloat16* src = Bm + (size_t)(kt * 32 + row) * C_ + colBase + col;
            uint32_t dst = (uint32_t)__cvta_generic_to_shared(&Bs[buf][row][col]);
            CP_ASYNC16(dst, src);
        }
        CP_COMMIT();
    };

    prefetch(0, 0);

    for (int kt = 0; kt < NT; kt++) {
        int buf = kt & 1;
        CP_WAIT0();
        __syncthreads();
        if (kt + 1 < NT) prefetch(kt + 1, buf ^ 1);

        #pragma unroll
        for (int kk = 0; kk < 32; kk += 16) {
            uint32_t a[2][4];
            #pragma unroll
            for (int mf = 0; mf < 2; mf++) {
                int row = mBase + mf * 16 + (lane & 7) + ((lane >> 3) & 1) * 8;
                int col = kk + ((lane >> 4) << 3);
                uint32_t addr = (uint32_t)__cvta_generic_to_shared(&As[buf][row][col]);
                asm volatile("ldmatrix.sync.aligned.m8n8.x4.shared.b16 {%0,%1,%2,%3}, [%4];"
                             : "=r"(a[mf][0]), "=r"(a[mf][1]), "=r"(a[mf][2]), "=r"(a[mf][3])
                             : "r"(addr));
            }
            uint32_t bf[4][4];
            #pragma unroll
            for (int nf2 = 0; nf2 < 4; nf2++) {
                int row = kk + (lane & 15);
                int col = nBase + nf2 * 16 + ((lane >> 4) << 3);
                uint32_t addr = (uint32_t)__cvta_generic_to_shared(&Bs[buf][row][col]);
                asm volatile("ldmatrix.sync.aligned.m8n8.x4.trans.shared.b16 {%0,%1,%2,%3}, [%4];"
                             : "=r"(bf[nf2][0]), "=r"(bf[nf2][1]), "=r"(bf[nf2][2]), "=r"(bf[nf2][3])
                             : "r"(addr));
            }
            #pragma unroll
            for (int mf = 0; mf < 2; mf++)
                #pragma unroll
                for (int nf = 0; nf < 8; nf++) {
                    uint32_t b0 = bf[nf >> 1][(nf & 1) * 2 + 0];
                    uint32_t b1 = bf[nf >> 1][(nf & 1) * 2 + 1];
                    asm volatile(
                        "mma.sync.aligned.m16n8k16.row.col.f32.bf16.bf16.f32 "
                        "{%0,%1,%2,%3}, {%4,%5,%6,%7}, {%8,%9}, {%0,%1,%2,%3};"
                        : "+f"(acc[mf][nf][0]), "+f"(acc[mf][nf][1]),
                          "+f"(acc[mf][nf][2]), "+f"(acc[mf][nf][3])
                        : "r"(a[mf][0]), "r"(a[mf][1]), "r"(a[mf][2]), "r"(a[mf][3]),
                          "r"(b0), "r"(b1));
                }
        }
        __syncthreads();
    }

    // epilogue
    int gid = lane >> 2, tig = lane & 3;
    if (mode == 0) {
        #pragma unroll
        for (int mf = 0; mf < 2; mf++)
            #pragma unroll
            for (int nf = 0; nf < 8; nf++) {
                int r0 = rowBase + mBase + mf * 16 + gid;
                int c0 = colBase + nBase + nf * 8 + tig * 2;
                *(float2*)&Cm[(size_t)r0 * C_ + c0] = make_float2(acc[mf][nf][0], acc[mf][nf][1]);
                *(float2*)&Cm[(size_t)(r0 + 8) * C_ + c0] = make_float2(acc[mf][nf][2], acc[mf][nf][3]);
            }
    } else {
        #pragma unroll
        for (int mf = 0; mf < 2; mf++)
            #pragma unroll
            for (int nf = 0; nf < 8; nf++) {
                int c0 = colBase + nBase + nf * 8 + tig * 2;
                float bv0 = bias[c0], bv1 = bias[c0 + 1];
                #pragma unroll
                for (int rr = 0; rr < 2; rr++) {
                    int row = rowBase + mBase + mf * 16 + gid + rr * 8;
                    int bq = row / QN, qi = row - bq * QN;
                    Cm[((size_t)bq * C_ + c0) * QN + qi]     = acc[mf][nf][rr * 2 + 0] + bv0;
                    Cm[((size_t)bq * C_ + c0 + 1) * QN + qi] = acc[mf][nf][rr * 2 + 1] + bv1;
                }
            }
    }
}

// ---------------- relative position bias dots ----------------
__global__ __launch_bounds__(64) void relpos_kernel(const float* __restrict__ rel_h,
                                                    const float* __restrict__ rel_w) {
    int gid = blockIdx.x;
    int bh = gid / QN, i = gid - bh * QN;
    int b = bh >> 3, h = bh & 7;
    int qy = i / 12, qx = i - qy * 12;
    int t = threadIdx.x;
    const float* qrow = g_q + ((size_t)b * QN + i) * C_ + h * HD;
    if (t < 24) {
        const float* R = rel_h + (size_t)(2 * qy - t + 23) * HD;
        float a0 = 0, a1 = 0, a2 = 0, a3 = 0;
        #pragma unroll
        for (int d = 0; d < HD; d += 4) {
            a0 += qrow[d + 0] * R[d + 0];
            a1 += qrow[d + 1] * R[d + 1];
            a2 += qrow[d + 2] * R[d + 2];
            a3 += qrow[d + 3] * R[d + 3];
        }
        g_relh[(size_t)gid * 24 + t] = (a0 + a1) + (a2 + a3);
    } else if (t >= 32 && t < 56) {
        int kx = t - 32;
        const float* R = rel_w + (size_t)(2 * qx - kx + 23) * HD;
        float a0 = 0, a1 = 0, a2 = 0, a3 = 0;
        #pragma unroll
        for (int d = 0; d < HD; d += 4) {
            a0 += qrow[d + 0] * R[d + 0];
            a1 += qrow[d + 1] * R[d + 1];
            a2 += qrow[d + 2] * R[d + 2];
            a3 += qrow[d + 3] * R[d + 3];
        }
        g_relw[(size_t)gid * 24 + kx] = (a0 + a1) + (a2 + a3);
    }
}

// ---------------- attn logits ----------------
__global__ __launch_bounds__(256) void qk_kernel() {
    __shared__ float Qs[64][49];
    __shared__ float Ks[64][68];
    int bh = blockIdx.z;
    int b = bh >> 3, h = bh & 7;
    int rowBase = blockIdx.y * 48;
    int colBase = blockIdx.x * 64;
    int tid = threadIdx.x;
    int tx = tid & 15, ty = tid >> 4;
    const float* qbase = g_q + ((size_t)b * QN + rowBase) * C_ + h * HD;
    const float* kbase = g_k + ((size_t)b * N_ + colBase) * C_ + h * HD;
    float acc[3][4] = {{0.f}};

    for (int kc = 0; kc < HD; kc += 64) {
        #pragma unroll
        for (int r = 0; r < 3; r++) {
            int f4i = tid + 256 * r;
            int row = f4i >> 4;
            int kk = (f4i & 15) * 4;
            float4 vv = *(const float4*)(qbase + (size_t)row * C_ + kc + kk);
            Qs[kk + 0][row] = vv.x; Qs[kk + 1][row] = vv.y;
            Qs[kk + 2][row] = vv.z; Qs[kk + 3][row] = vv.w;
        }
        #pragma unroll
        for (int r = 0; r < 4; r++) {
            int f4i = tid + 256 * r;
            int col = f4i >> 4;
            int kk = (f4i & 15) * 4;
            float4 vv = *(const float4*)(kbase + (size_t)col * C_ + kc + kk);
            Ks[kk + 0][col] = vv.x; Ks[kk + 1][col] = vv.y;
            Ks[kk + 2][col] = vv.z; Ks[kk + 3][col] = vv.w;
        }
        __syncthreads();
        #pragma unroll 8
        for (int kk = 0; kk < 64; kk++) {
            float4 bv = *(const float4*)&Ks[kk][tx * 4];
            float a0 = Qs[kk][ty * 3 + 0];
            float a1 = Qs[kk][ty * 3 + 1];
            float a2 = Qs[kk][ty * 3 + 2];
            acc[0][0] += a0 * bv.x; acc[0][1] += a0 * bv.y; acc[0][2] += a0 * bv.z; acc[0][3] += a0 * bv.w;
            acc[1][0] += a1 * bv.x; acc[1][1] += a1 * bv.y; acc[1][2] += a1 * bv.z; acc[1][3] += a1 * bv.w;
            acc[2][0] += a2 * bv.x; acc[2][1] += a2 * bv.y; acc[2][2] += a2 * bv.z; acc[2][3] += a2 * bv.w;
        }
        __syncthreads();
    }

    const float scale = 0.08838834764831845f;
    #pragma unroll
    for (int m = 0; m < 3; m++) {
        int i = rowBase + ty * 3 + m;
        const float* rh = g_relh + ((size_t)bh * QN + i) * 24;
        const float* rw = g_relw + ((size_t)bh * QN + i) * 24;
        float* sp = g_attn + ((size_t)bh * QN + i) * N_ + colBase + tx * 4;
        #pragma unroll
        for (int j = 0; j < 4; j++) {
            int jj = colBase + tx * 4 + j;
            int ky = jj / 24, kx = jj - ky * 24;
            sp[j] = acc[m][j] * scale + rh[ky] + rw[kx];
        }
    }
}

// ---------------- softmax ----------------
__global__ __launch_bounds__(192) void softmax_kernel() {
    __shared__ float sm[6], ss[6];
    size_t row = blockIdx.x;
    float* p = g_attn + row * (size_t)N_;
    int t = threadIdx.x;
    float v0 = p[t], v1 = p[t + 192], v2 = p[t + 384];
    float m = fmaxf(v0, fmaxf(v1, v2));
    #pragma unroll
    for (int o = 16; o > 0; o >>= 1) m = fmaxf(m, __shfl_xor_sync(0xffffffffu, m, o));
    if ((t & 31) == 0) sm[t >> 5] = m;
    __syncthreads();
    float mm = fmaxf(fmaxf(fmaxf(sm[0], sm[1]), fmaxf(sm[2], sm[3])), fmaxf(sm[4], sm[5]));
    float e0 = __expf(v0 - mm), e1 = __expf(v1 - mm), e2 = __expf(v2 - mm);
    float s = e0 + e1 + e2;
    #pragma unroll
    for (int o = 16; o > 0; o >>= 1) s += __shfl_xor_sync(0xffffffffu, s, o);
    if ((t & 31) == 0) ss[t >> 5] = s;
    __syncthreads();
    float tot = (ss[0] + ss[1]) + (ss[2] + ss[3]) + (ss[4] + ss[5]);
    float inv = 1.0f / tot;
    p[t] = e0 * inv; p[t + 192] = e1 * inv; p[t + 384] = e2 * inv;
}

// ---------------- out = attn @ v + q ----------------
__global__ __launch_bounds__(256) void av_kernel() {
    __shared__ float Ps[48][33];
    __shared__ float Vs[32][68];
    int bh = blockIdx.z;
    int b = bh >> 3, h = bh & 7;
    int rowBase = blockIdx.y * 48;
    int colBase = blockIdx.x * 64;
    int tid = threadIdx.x;
    int tx = tid & 15, ty = tid >> 4;
    const float* pbase = g_attn + ((size_t)bh * QN + rowBase) * N_;
    const float* vbase = g_v + (size_t)b * N_ * C_ + h * HD + colBase;
    float acc[3][4] = {{0.f}};

    for (int k0 = 0; k0 < N_; k0 += 32) {
        #pragma unroll
        for (int r = 0; r < 6; r++) {
            int idx = tid + 256 * r;
            int row = idx >> 5, kk = idx & 31;
            Ps[row][kk] = pbase[(size_t)row * N_ + k0 + kk];
        }
        #pragma unroll
        for (int r = 0; r < 2; r++) {
            int f4i = tid + 256 * r;
            int vrow = f4i >> 4, col = (f4i & 15) * 4;
            float4 vv = *(const float4*)(vbase + (size_t)(k0 + vrow) * C_ + col);
            *(float4*)&Vs[vrow][col] = vv;
        }
        __syncthreads();
        #pragma unroll 8
        for (int kk = 0; kk < 32; kk++) {
            float4 bv = *(const float4*)&Vs[kk][tx * 4];
            float a0 = Ps[ty * 3 + 0][kk];
            float a1 = Ps[ty * 3 + 1][kk];
            float a2 = Ps[ty * 3 + 2][kk];
            acc[0][0] += a0 * bv.x; acc[0][1] += a0 * bv.y; acc[0][2] += a0 * bv.z; acc[0][3] += a0 * bv.w;
            acc[1][0] += a1 * bv.x; acc[1][1] += a1 * bv.y; acc[1][2] += a1 * bv.z; acc[1][3] += a1 * bv.w;
            acc[2][0] += a2 * bv.x; acc[2][1] += a2 * bv.y; acc[2][2] += a2 * bv.z; acc[2][3] += a2 * bv.w;
        }
        __syncthreads();
    }

    #pragma unroll
    for (int m = 0; m < 3; m++) {
        int i = rowBase + ty * 3 + m;
        size_t off = ((size_t)b * QN + i) * C_ + h * HD + colBase + tx * 4;
        const float* qp = g_q + off;
        float* op = g_o + off;
        #pragma unroll
        for (int j = 0; j < 4; j++) op[j] = acc[m][j] + qp[j];
    }
}

// ---------------- launch ----------------
extern "C" void kernel_launch(void* const* d_in, const int* in_sizes, int n_in,
                              void* d_out, int out_size) {
    const float* x   = (const float*)d_in[0];
    const float* Wq  = (const float*)d_in[1];
    const float* Wk  = (const float*)d_in[2];
    const float* Wv  = (const float*)d_in[3];
    const float* Wp  = (const float*)d_in[4];
    const float* bp  = (const float*)d_in[5];
    const float* rph = (const float*)d_in[6];
    const float* rpw = (const float*)d_in[7];
    float* out = (float*)d_out;

    float *xp, *q, *k, *v, *o;
    __nv_bfloat16 *ax, *aq, *ao, *bwq, *bwk, *bwv, *bwp;
    cudaGetSymbolAddress((void**)&xp, g_xp);
    cudaGetSymbolAddress((void**)&q,  g_q);
    cudaGetSymbolAddress((void**)&k,  g_k);
    cudaGetSymbolAddress((void**)&v,  g_v);
    cudaGetSymbolAddress((void**)&o,  g_o);
    cudaGetSymbolAddress((void**)&ax, g_ax);
    cudaGetSymbolAddress((void**)&aq, g_aq);
    cudaGetSymbolAddress((void**)&ao, g_ao);
    cudaGetSymbolAddress((void**)&bwq, g_bwq);
    cudaGetSymbolAddress((void**)&bwk, g_bwk);
    cudaGetSymbolAddress((void**)&bwv, g_bwv);
    cudaGetSymbolAddress((void**)&bwp, g_bwp);

    split_w_kernel<<<4096, 256>>>(Wq, bwq);
    split_w_kernel<<<4096, 256>>>(Wk, bwk);
    split_w_kernel<<<4096, 256>>>(Wv, bwv);
    split_w_kernel<<<4096, 256>>>(Wp, bwp);

    split_x_kernel<<<dim3(18, 32, B_), dim3(32, 8)>>>(x);
    pool_kernel<<<dim3(C_ / 16, B_), 256>>>(x);
    split_rows_kernel<<<(B_ * QN * C_) / 256, 256>>>(xp, aq);

    gemm_bf16<<<dim3(8, (B_ * N_) / 128), 256>>>(ax, bwk, nullptr, k, 0);
    gemm_bf16<<<dim3(8, (B_ * N_) / 128), 256>>>(ax, bwv, nullptr, v, 0);
    gemm_bf16<<<dim3(8, (B_ * QN) / 128), 256>>>(aq, bwq, nullptr, q, 0);

    relpos_kernel<<<B_ * NH * QN, 64>>>(rph, rpw);
    qk_kernel<<<dim3(N_ / 64, QN / 48, B_ * NH), 256>>>();
    softmax_kernel<<<B_ * NH * QN, 192>>>();
    av_kernel<<<dim3(HD / 64, QN / 48, B_ * NH), 256>>>();

    split_rows_kernel<<<(B_ * QN * C_) / 256, 256>>>(o, ao);
    gemm_bf16<<<dim3(8, (B_ * QN) / 128), 256>>>(ao, bwp, bp, out, 1);
}

// round 5
// speedup vs baseline: 2.0571x; 1.0569x over previous
#include <cuda_runtime.h>
#include <cuda_bf16.h>
#include <math.h>
#include <stdint.h>

#define B_  128
#define C_  1024
#define H_  24
#define W_  24
#define N_  576          // H*W
#define NH  8
#define HD  128          // C/NH
#define QH  12
#define QW  12
#define QN  144          // QH*QW
#define KTILES 32        // 1024/32

// ---------------- scratch ----------------
__device__ float g_xp  [(size_t)B_*QN*C_];
__device__ float g_q   [(size_t)B_*QN*C_];
__device__ float g_k   [(size_t)B_*N_*C_];
__device__ float g_v   [(size_t)B_*N_*C_];
__device__ float g_attn[(size_t)B_*NH*QN*N_];
__device__ float g_relh[(size_t)B_*NH*QN*H_];
__device__ float g_relw[(size_t)B_*NH*QN*W_];
__device__ float g_o   [(size_t)B_*QN*C_];
// hi/lo bf16 operands (K=1024 each)
__device__ __nv_bfloat16 g_axh[(size_t)B_*N_*C_];
__device__ __nv_bfloat16 g_axl[(size_t)B_*N_*C_];
__device__ __nv_bfloat16 g_aqh[(size_t)B_*QN*C_];
__device__ __nv_bfloat16 g_aql[(size_t)B_*QN*C_];
__device__ __nv_bfloat16 g_aoh[(size_t)B_*QN*C_];
__device__ __nv_bfloat16 g_aol[(size_t)B_*QN*C_];
__device__ __nv_bfloat16 g_wqh[(size_t)C_*C_];
__device__ __nv_bfloat16 g_wql[(size_t)C_*C_];
__device__ __nv_bfloat16 g_wkh[(size_t)C_*C_];
__device__ __nv_bfloat16 g_wkl[(size_t)C_*C_];
__device__ __nv_bfloat16 g_wvh[(size_t)C_*C_];
__device__ __nv_bfloat16 g_wvl[(size_t)C_*C_];
__device__ __nv_bfloat16 g_wph[(size_t)C_*C_];
__device__ __nv_bfloat16 g_wpl[(size_t)C_*C_];

// ---------------- helpers ----------------
__device__ __forceinline__ void split2(float v, __nv_bfloat16& hi, __nv_bfloat16& lo) {
    hi = __float2bfloat16(v);
    lo = __float2bfloat16(v - __bfloat162float(hi));
}

#define CP_ASYNC16(dst, src) \
    asm volatile("cp.async.cg.shared.global [%0], [%1], 16;" :: "r"(dst), "l"(src))
#define CP_COMMIT() asm volatile("cp.async.commit_group;")
#define CP_WAIT0()  asm volatile("cp.async.wait_group 0;")

#define MMA_BF16(ACC, A, B0, B1)                                              \
    asm volatile(                                                             \
        "mma.sync.aligned.m16n8k16.row.col.f32.bf16.bf16.f32 "                \
        "{%0,%1,%2,%3}, {%4,%5,%6,%7}, {%8,%9}, {%0,%1,%2,%3};"               \
        : "+f"((ACC)[0]), "+f"((ACC)[1]), "+f"((ACC)[2]), "+f"((ACC)[3])      \
        : "r"((A)[0]), "r"((A)[1]), "r"((A)[2]), "r"((A)[3]),                 \
          "r"(B0), "r"(B1))

// ---------------- conversions ----------------
__global__ __launch_bounds__(256) void split_w2_kernel(const float* __restrict__ W,
                                                       __nv_bfloat16* __restrict__ Wh,
                                                       __nv_bfloat16* __restrict__ Wl) {
    int i = blockIdx.x * 256 + threadIdx.x;
    __nv_bfloat16 hi, lo; split2(W[i], hi, lo);
    Wh[i] = hi; Wl[i] = lo;
}

// x[B,C,N] -> transpose + split into axh/axl [B*N, 1024]
__global__ __launch_bounds__(256) void split_x2_kernel(const float* __restrict__ x) {
    __shared__ float tile[32][33];
    int b  = blockIdx.z;
    int n0 = blockIdx.x * 32;
    int c0 = blockIdx.y * 32;
    int tx = threadIdx.x, ty = threadIdx.y;          // (32,8)
    const float* xb = x + (size_t)b * C_ * N_;
    #pragma unroll
    for (int i = 0; i < 4; i++)
        tile[ty + i * 8][tx] = xb[(size_t)(c0 + ty + i * 8) * N_ + n0 + tx];
    __syncthreads();
    #pragma unroll
    for (int i = 0; i < 4; i++) {
        int n = n0 + ty + i * 8;
        __nv_bfloat16 hi, lo; split2(tile[tx][ty + i * 8], hi, lo);
        size_t base = ((size_t)b * N_ + n) * C_ + c0 + tx;
        g_axh[base] = hi; g_axl[base] = lo;
    }
}

__global__ __launch_bounds__(256) void split_rows2_kernel(const float* __restrict__ in,
                                                          __nv_bfloat16* __restrict__ oh,
                                                          __nv_bfloat16* __restrict__ ol) {
    int i = blockIdx.x * 256 + threadIdx.x;
    __nv_bfloat16 hi, lo; split2(in[i], hi, lo);
    oh[i] = hi; ol[i] = lo;
}

// ---------------- avg-pool 3x3 s2 pad1 -> xp[B,qN,C] ----------------
__global__ __launch_bounds__(256) void pool_kernel(const float* __restrict__ x) {
    __shared__ float sp[16][577];
    int b  = blockIdx.y;
    int c0 = blockIdx.x * 16;
    int tid = threadIdx.x;
    const float* xb = x + (size_t)b * C_ * N_ + (size_t)c0 * N_;
    #pragma unroll
    for (int r = 0; r < 36; r++) {
        int idx = tid + r * 256;
        int p = idx / 576, n = idx - p * 576;
        sp[p][n] = xb[(size_t)p * N_ + n];
    }
    __syncthreads();
    #pragma unroll
    for (int r = 0; r < 9; r++) {
        int idx = tid + r * 256;
        int qn = idx >> 4, cl = idx & 15;
        int qy = qn / 12, qx = qn - qy * 12;
        float s = 0.f;
        #pragma unroll
        for (int dy = -1; dy <= 1; dy++) {
            int y = 2 * qy + dy;
            if ((unsigned)y < 24u) {
                #pragma unroll
                for (int dx = -1; dx <= 1; dx++) {
                    int xx = 2 * qx + dx;
                    if ((unsigned)xx < 24u) s += sp[cl][y * 24 + xx];
                }
            }
        }
        g_xp[((size_t)b * QN + qn) * C_ + c0 + cl] = s * (1.0f / 9.0f);
    }
}

// ---------------- split-bf16 tensor-core GEMM ----------------
// C[M,1024] = Ah(Bh+Bl) + Al*Bh  over K=1024.
// Dynamic smem layout (bf16 elements):
//   Ah: 2*128*40      Al: +10240
//   Bh: 2*32*136      Bl: +4352
#define SM_AH   0
#define SM_AL   (2*128*40)
#define SM_BH   (2*(2*128*40))
#define SM_BL   (SM_BH + 2*32*136)
#define SM_ELEMS (SM_BH + 2*(2*32*136))
#define SMEM_BYTES (SM_ELEMS * 2)

__global__ __launch_bounds__(256) void gemm_split(const __nv_bfloat16* __restrict__ Ahg,
                                                  const __nv_bfloat16* __restrict__ Alg,
                                                  const __nv_bfloat16* __restrict__ Bhg,
                                                  const __nv_bfloat16* __restrict__ Blg,
                                                  const float* __restrict__ bias,
                                                  float* __restrict__ Cm,
                                                  int mode) {
    extern __shared__ __nv_bfloat16 sm[];
    __nv_bfloat16* sAh = sm + SM_AH;   // [2][128][40]
    __nv_bfloat16* sAl = sm + SM_AL;
    __nv_bfloat16* sBh = sm + SM_BH;   // [2][32][136]
    __nv_bfloat16* sBl = sm + SM_BL;

    int tid  = threadIdx.x;
    int lane = tid & 31;
    int warp = tid >> 5;
    int wm = warp >> 1;          // 0..3
    int wn = warp & 1;           // 0..1
    int mBase = wm * 32;
    int nBase = wn * 64;
    int rowBase = blockIdx.y * 128;
    int colBase = blockIdx.x * 128;

    float acc[2][8][4];
    #pragma unroll
    for (int i = 0; i < 2; i++)
        #pragma unroll
        for (int j = 0; j < 8; j++)
            #pragma unroll
            for (int r = 0; r < 4; r++) acc[i][j][r] = 0.f;

    auto prefetch = [&](int kt, int buf) {
        #pragma unroll
        for (int c = 0; c < 2; c++) {
            int chunk = c * 256 + tid;                 // 0..511
            int row = chunk >> 2, off = (chunk & 3) * 8;
            size_t goff = (size_t)(rowBase + row) * C_ + kt * 32 + off;
            int soff = buf * (128 * 40) + row * 40 + off;
            CP_ASYNC16((uint32_t)__cvta_generic_to_shared(sAh + soff), Ahg + goff);
            CP_ASYNC16((uint32_t)__cvta_generic_to_shared(sAl + soff), Alg + goff);
        }
        #pragma unroll
        for (int c = 0; c < 2; c++) {
            int chunk = c * 256 + tid;
            int row = chunk >> 4, col = (chunk & 15) * 8;
            size_t goff = (size_t)(kt * 32 + row) * C_ + colBase + col;
            int soff = buf * (32 * 136) + row * 136 + col;
            CP_ASYNC16((uint32_t)__cvta_generic_to_shared(sBh + soff), Bhg + goff);
            CP_ASYNC16((uint32_t)__cvta_generic_to_shared(sBl + soff), Blg + goff);
        }
        CP_COMMIT();
    };

    prefetch(0, 0);

    for (int kt = 0; kt < KTILES; kt++) {
        int buf = kt & 1;
        CP_WAIT0();
        __syncthreads();
        if (kt + 1 < KTILES) prefetch(kt + 1, buf ^ 1);

        #pragma unroll
        for (int kk = 0; kk < 32; kk += 16) {
            uint32_t ah[2][4], al[2][4];
            #pragma unroll
            for (int mf = 0; mf < 2; mf++) {
                int row = mBase + mf * 16 + (lane & 7) + ((lane >> 3) & 1) * 8;
                int col = kk + ((lane >> 4) << 3);
                int soff = buf * (128 * 40) + row * 40 + col;
                uint32_t addrH = (uint32_t)__cvta_generic_to_shared(sAh + soff);
                uint32_t addrL = (uint32_t)__cvta_generic_to_shared(sAl + soff);
                asm volatile("ldmatrix.sync.aligned.m8n8.x4.shared.b16 {%0,%1,%2,%3}, [%4];"
                             : "=r"(ah[mf][0]), "=r"(ah[mf][1]), "=r"(ah[mf][2]), "=r"(ah[mf][3])
                             : "r"(addrH));
                asm volatile("ldmatrix.sync.aligned.m8n8.x4.shared.b16 {%0,%1,%2,%3}, [%4];"
                             : "=r"(al[mf][0]), "=r"(al[mf][1]), "=r"(al[mf][2]), "=r"(al[mf][3])
                             : "r"(addrL));
            }
            uint32_t bh[4][4], bl[4][4];
            #pragma unroll
            for (int nf2 = 0; nf2 < 4; nf2++) {
                int row = kk + (lane & 15);
                int col = nBase + nf2 * 16 + ((lane >> 4) << 3);
                int soff = buf * (32 * 136) + row * 136 + col;
                uint32_t addrH = (uint32_t)__cvta_generic_to_shared(sBh + soff);
                uint32_t addrL = (uint32_t)__cvta_generic_to_shared(sBl + soff);
                asm volatile("ldmatrix.sync.aligned.m8n8.x4.trans.shared.b16 {%0,%1,%2,%3}, [%4];"
                             : "=r"(bh[nf2][0]), "=r"(bh[nf2][1]), "=r"(bh[nf2][2]), "=r"(bh[nf2][3])
                             : "r"(addrH));
                asm volatile("ldmatrix.sync.aligned.m8n8.x4.trans.shared.b16 {%0,%1,%2,%3}, [%4];"
                             : "=r"(bl[nf2][0]), "=r"(bl[nf2][1]), "=r"(bl[nf2][2]), "=r"(bl[nf2][3])
                             : "r"(addrL));
            }
            #pragma unroll
            for (int mf = 0; mf < 2; mf++)
                #pragma unroll
                for (int nf = 0; nf < 8; nf++) {
                    uint32_t bh0 = bh[nf >> 1][(nf & 1) * 2 + 0];
                    uint32_t bh1 = bh[nf >> 1][(nf & 1) * 2 + 1];
                    uint32_t bl0 = bl[nf >> 1][(nf & 1) * 2 + 0];
                    uint32_t bl1 = bl[nf >> 1][(nf & 1) * 2 + 1];
                    MMA_BF16(acc[mf][nf], ah[mf], bh0, bh1);
                    MMA_BF16(acc[mf][nf], ah[mf], bl0, bl1);
                    MMA_BF16(acc[mf][nf], al[mf], bh0, bh1);
                }
        }
        __syncthreads();
    }

    int gid = lane >> 2, tig = lane & 3;
    if (mode == 0) {
        #pragma unroll
        for (int mf = 0; mf < 2; mf++)
            #pragma unroll
            for (int nf = 0; nf < 8; nf++) {
                int r0 = rowBase + mBase + mf * 16 + gid;
                int c0 = colBase + nBase + nf * 8 + tig * 2;
                *(float2*)&Cm[(size_t)r0 * C_ + c0] = make_float2(acc[mf][nf][0], acc[mf][nf][1]);
                *(float2*)&Cm[(size_t)(r0 + 8) * C_ + c0] = make_float2(acc[mf][nf][2], acc[mf][nf][3]);
            }
    } else {
        #pragma unroll
        for (int mf = 0; mf < 2; mf++)
            #pragma unroll
            for (int nf = 0; nf < 8; nf++) {
                int c0 = colBase + nBase + nf * 8 + tig * 2;
                float bv0 = bias[c0], bv1 = bias[c0 + 1];
                #pragma unroll
                for (int rr = 0; rr < 2; rr++) {
                    int row = rowBase + mBase + mf * 16 + gid + rr * 8;
                    int bq = row / QN, qi = row - bq * QN;
                    Cm[((size_t)bq * C_ + c0) * QN + qi]     = acc[mf][nf][rr * 2 + 0] + bv0;
                    Cm[((size_t)bq * C_ + c0 + 1) * QN + qi] = acc[mf][nf][rr * 2 + 1] + bv1;
                }
            }
    }
}

// ---------------- relative position bias dots ----------------
__global__ __launch_bounds__(64) void relpos_kernel(const float* __restrict__ rel_h,
                                                    const float* __restrict__ rel_w) {
    int gid = blockIdx.x;
    int bh = gid / QN, i = gid - bh * QN;
    int b = bh >> 3, h = bh & 7;
    int qy = i / 12, qx = i - qy * 12;
    int t = threadIdx.x;
    const float* qrow = g_q + ((size_t)b * QN + i) * C_ + h * HD;
    if (t < 24) {
        const float* R = rel_h + (size_t)(2 * qy - t + 23) * HD;
        float a0 = 0, a1 = 0, a2 = 0, a3 = 0;
        #pragma unroll
        for (int d = 0; d < HD; d += 4) {
            a0 += qrow[d + 0] * R[d + 0];
            a1 += qrow[d + 1] * R[d + 1];
            a2 += qrow[d + 2] * R[d + 2];
            a3 += qrow[d + 3] * R[d + 3];
        }
        g_relh[(size_t)gid * 24 + t] = (a0 + a1) + (a2 + a3);
    } else if (t >= 32 && t < 56) {
        int kx = t - 32;
        const float* R = rel_w + (size_t)(2 * qx - kx + 23) * HD;
        float a0 = 0, a1 = 0, a2 = 0, a3 = 0;
        #pragma unroll
        for (int d = 0; d < HD; d += 4) {
            a0 += qrow[d + 0] * R[d + 0];
            a1 += qrow[d + 1] * R[d + 1];
            a2 += qrow[d + 2] * R[d + 2];
            a3 += qrow[d + 3] * R[d + 3];
        }
        g_relw[(size_t)gid * 24 + kx] = (a0 + a1) + (a2 + a3);
    }
}

// ---------------- attn logits ----------------
__global__ __launch_bounds__(256) void qk_kernel() {
    __shared__ float Qs[64][49];
    __shared__ float Ks[64][68];
    int bh = blockIdx.z;
    int b = bh >> 3, h = bh & 7;
    int rowBase = blockIdx.y * 48;
    int colBase = blockIdx.x * 64;
    int tid = threadIdx.x;
    int tx = tid & 15, ty = tid >> 4;
    const float* qbase = g_q + ((size_t)b * QN + rowBase) * C_ + h * HD;
    const float* kbase = g_k + ((size_t)b * N_ + colBase) * C_ + h * HD;
    float acc[3][4] = {{0.f}};

    for (int kc = 0; kc < HD; kc += 64) {
        #pragma unroll
        for (int r = 0; r < 3; r++) {
            int f4i = tid + 256 * r;
            int row = f4i >> 4;
            int kk = (f4i & 15) * 4;
            float4 vv = *(const float4*)(qbase + (size_t)row * C_ + kc + kk);
            Qs[kk + 0][row] = vv.x; Qs[kk + 1][row] = vv.y;
            Qs[kk + 2][row] = vv.z; Qs[kk + 3][row] = vv.w;
        }
        #pragma unroll
        for (int r = 0; r < 4; r++) {
            int f4i = tid + 256 * r;
            int col = f4i >> 4;
            int kk = (f4i & 15) * 4;
            float4 vv = *(const float4*)(kbase + (size_t)col * C_ + kc + kk);
            Ks[kk + 0][col] = vv.x; Ks[kk + 1][col] = vv.y;
            Ks[kk + 2][col] = vv.z; Ks[kk + 3][col] = vv.w;
        }
        __syncthreads();
        #pragma unroll 8
        for (int kk = 0; kk < 64; kk++) {
            float4 bv = *(const float4*)&Ks[kk][tx * 4];
            float a0 = Qs[kk][ty * 3 + 0];
            float a1 = Qs[kk][ty * 3 + 1];
            float a2 = Qs[kk][ty * 3 + 2];
            acc[0][0] += a0 * bv.x; acc[0][1] += a0 * bv.y; acc[0][2] += a0 * bv.z; acc[0][3] += a0 * bv.w;
            acc[1][0] += a1 * bv.x; acc[1][1] += a1 * bv.y; acc[1][2] += a1 * bv.z; acc[1][3] += a1 * bv.w;
            acc[2][0] += a2 * bv.x; acc[2][1] += a2 * bv.y; acc[2][2] += a2 * bv.z; acc[2][3] += a2 * bv.w;
        }
        __syncthreads();
    }

    const float scale = 0.08838834764831845f;
    #pragma unroll
    for (int m = 0; m < 3; m++) {
        int i = rowBase + ty * 3 + m;
        const float* rh = g_relh + ((size_t)bh * QN + i) * 24;
        const float* rw = g_relw + ((size_t)bh * QN + i) * 24;
        float* sp = g_attn + ((size_t)bh * QN + i) * N_ + colBase + tx * 4;
        #pragma unroll
        for (int j = 0; j < 4; j++) {
            int jj = colBase + tx * 4 + j;
            int ky = jj / 24, kx = jj - ky * 24;
            sp[j] = acc[m][j] * scale + rh[ky] + rw[kx];
        }
    }
}

// ---------------- softmax ----------------
__global__ __launch_bounds__(192) void softmax_kernel() {
    __shared__ float sm6[6], ss[6];
    size_t row = blockIdx.x;
    float* p = g_attn + row * (size_t)N_;
    int t = threadIdx.x;
    float v0 = p[t], v1 = p[t + 192], v2 = p[t + 384];
    float m = fmaxf(v0, fmaxf(v1, v2));
    #pragma unroll
    for (int o = 16; o > 0; o >>= 1) m = fmaxf(m, __shfl_xor_sync(0xffffffffu, m, o));
    if ((t & 31) == 0) sm6[t >> 5] = m;
    __syncthreads();
    float mm = fmaxf(fmaxf(fmaxf(sm6[0], sm6[1]), fmaxf(sm6[2], sm6[3])), fmaxf(sm6[4], sm6[5]));
    float e0 = __expf(v0 - mm), e1 = __expf(v1 - mm), e2 = __expf(v2 - mm);
    float s = e0 + e1 + e2;
    #pragma unroll
    for (int o = 16; o > 0; o >>= 1) s += __shfl_xor_sync(0xffffffffu, s, o);
    if ((t & 31) == 0) ss[t >> 5] = s;
    __syncthreads();
    float tot = (ss[0] + ss[1]) + (ss[2] + ss[3]) + (ss[4] + ss[5]);
    float inv = 1.0f / tot;
    p[t] = e0 * inv; p[t + 192] = e1 * inv; p[t + 384] = e2 * inv;
}

// ---------------- out = attn @ v + q ----------------
__global__ __launch_bounds__(256) void av_kernel() {
    __shared__ float Ps[48][33];
    __shared__ float Vs[32][68];
    int bh = blockIdx.z;
    int b = bh >> 3, h = bh & 7;
    int rowBase = blockIdx.y * 48;
    int colBase = blockIdx.x * 64;
    int tid = threadIdx.x;
    int tx = tid & 15, ty = tid >> 4;
    const float* pbase = g_attn + ((size_t)bh * QN + rowBase) * N_;
    const float* vbase = g_v + (size_t)b * N_ * C_ + h * HD + colBase;
    float acc[3][4] = {{0.f}};

    for (int k0 = 0; k0 < N_; k0 += 32) {
        #pragma unroll
        for (int r = 0; r < 6; r++) {
            int idx = tid + 256 * r;
            int row = idx >> 5, kk = idx & 31;
            Ps[row][kk] = pbase[(size_t)row * N_ + k0 + kk];
        }
        #pragma unroll
        for (int r = 0; r < 2; r++) {
            int f4i = tid + 256 * r;
            int vrow = f4i >> 4, col = (f4i & 15) * 4;
            float4 vv = *(const float4*)(vbase + (size_t)(k0 + vrow) * C_ + col);
            *(float4*)&Vs[vrow][col] = vv;
        }
        __syncthreads();
        #pragma unroll 8
        for (int kk = 0; kk < 32; kk++) {
            float4 bv = *(const float4*)&Vs[kk][tx * 4];
            float a0 = Ps[ty * 3 + 0][kk];
            float a1 = Ps[ty * 3 + 1][kk];
            float a2 = Ps[ty * 3 + 2][kk];
            acc[0][0] += a0 * bv.x; acc[0][1] += a0 * bv.y; acc[0][2] += a0 * bv.z; acc[0][3] += a0 * bv.w;
            acc[1][0] += a1 * bv.x; acc[1][1] += a1 * bv.y; acc[1][2] += a1 * bv.z; acc[1][3] += a1 * bv.w;
            acc[2][0] += a2 * bv.x; acc[2][1] += a2 * bv.y; acc[2][2] += a2 * bv.z; acc[2][3] += a2 * bv.w;
        }
        __syncthreads();
    }

    #pragma unroll
    for (int m = 0; m < 3; m++) {
        int i = rowBase + ty * 3 + m;
        size_t off = ((size_t)b * QN + i) * C_ + h * HD + colBase + tx * 4;
        const float* qp = g_q + off;
        float* op = g_o + off;
        #pragma unroll
        for (int j = 0; j < 4; j++) op[j] = acc[m][j] + qp[j];
    }
}

// ---------------- launch ----------------
extern "C" void kernel_launch(void* const* d_in, const int* in_sizes, int n_in,
                              void* d_out, int out_size) {
    const float* x   = (const float*)d_in[0];
    const float* Wq  = (const float*)d_in[1];
    const float* Wk  = (const float*)d_in[2];
    const float* Wv  = (const float*)d_in[3];
    const float* Wp  = (const float*)d_in[4];
    const float* bp  = (const float*)d_in[5];
    const float* rph = (const float*)d_in[6];
    const float* rpw = (const float*)d_in[7];
    float* out = (float*)d_out;

    float *xp, *q, *k, *v, *o;
    __nv_bfloat16 *axh, *axl, *aqh, *aql, *aoh, *aol;
    __nv_bfloat16 *wqh, *wql, *wkh, *wkl, *wvh, *wvl, *wph, *wpl;
    cudaGetSymbolAddress((void**)&xp, g_xp);
    cudaGetSymbolAddress((void**)&q,  g_q);
    cudaGetSymbolAddress((void**)&k,  g_k);
    cudaGetSymbolAddress((void**)&v,  g_v);
    cudaGetSymbolAddress((void**)&o,  g_o);
    cudaGetSymbolAddress((void**)&axh, g_axh);
    cudaGetSymbolAddress((void**)&axl, g_axl);
    cudaGetSymbolAddress((void**)&aqh, g_aqh);
    cudaGetSymbolAddress((void**)&aql, g_aql);
    cudaGetSymbolAddress((void**)&aoh, g_aoh);
    cudaGetSymbolAddress((void**)&aol, g_aol);
    cudaGetSymbolAddress((void**)&wqh, g_wqh);
    cudaGetSymbolAddress((void**)&wql, g_wql);
    cudaGetSymbolAddress((void**)&wkh, g_wkh);
    cudaGetSymbolAddress((void**)&wkl, g_wkl);
    cudaGetSymbolAddress((void**)&wvh, g_wvh);
    cudaGetSymbolAddress((void**)&wvl, g_wvl);
    cudaGetSymbolAddress((void**)&wph, g_wph);
    cudaGetSymbolAddress((void**)&wpl, g_wpl);

    cudaFuncSetAttribute(gemm_split, cudaFuncAttributeMaxDynamicSharedMemorySize, SMEM_BYTES);

    split_w2_kernel<<<4096, 256>>>(Wq, wqh, wql);
    split_w2_kernel<<<4096, 256>>>(Wk, wkh, wkl);
    split_w2_kernel<<<4096, 256>>>(Wv, wvh, wvl);
    split_w2_kernel<<<4096, 256>>>(Wp, wph, wpl);

    split_x2_kernel<<<dim3(18, 32, B_), dim3(32, 8)>>>(x);
    pool_kernel<<<dim3(C_ / 16, B_), 256>>>(x);
    split_rows2_kernel<<<(B_ * QN * C_) / 256, 256>>>(xp, aqh, aql);

    gemm_split<<<dim3(8, (B_ * N_) / 128), 256, SMEM_BYTES>>>(axh, axl, wkh, wkl, nullptr, k, 0);
    gemm_split<<<dim3(8, (B_ * N_) / 128), 256, SMEM_BYTES>>>(axh, axl, wvh, wvl, nullptr, v, 0);
    gemm_split<<<dim3(8, (B_ * QN) / 128), 256, SMEM_BYTES>>>(aqh, aql, wqh, wql, nullptr, q, 0);

    relpos_kernel<<<B_ * NH * QN, 64>>>(rph, rpw);
    qk_kernel<<<dim3(N_ / 64, QN / 48, B_ * NH), 256>>>();
    softmax_kernel<<<B_ * NH * QN, 192>>>();
    av_kernel<<<dim3(HD / 64, QN / 48, B_ * NH), 256>>>();

    split_rows2_kernel<<<(B_ * QN * C_) / 256, 256>>>(o, aoh, aol);
    gemm_split<<<dim3(8, (B_ * QN) / 128), 256, SMEM_BYTES>>>(aoh, aol, wph, wpl, bp, out, 1);
}

// round 6
// speedup vs baseline: 2.1648x; 1.0524x over previous
#include <cuda_runtime.h>
#include <cuda_bf16.h>
#include <math.h>
#include <stdint.h>

#define B_  128
#define C_  1024
#define H_  24
#define W_  24
#define N_  576
#define NH  8
#define HD  128
#define QH  12
#define QW  12
#define QN  144
#define BH  (B_*NH)
#define KTILES 32

// ---------------- fp32 scratch ----------------
__device__ float g_xp  [(size_t)B_*QN*C_];
__device__ float g_q   [(size_t)B_*QN*C_];
__device__ float g_attn[(size_t)BH*QN*N_];
__device__ float g_relh[(size_t)BH*QN*H_];
__device__ float g_relw[(size_t)BH*QN*W_];
__device__ float g_o   [(size_t)B_*QN*C_];
// bf16 hi/lo operands
__device__ __nv_bfloat16 g_axh[(size_t)B_*N_*C_];
__device__ __nv_bfloat16 g_axl[(size_t)B_*N_*C_];
__device__ __nv_bfloat16 g_aqh[(size_t)B_*QN*C_];
__device__ __nv_bfloat16 g_aql[(size_t)B_*QN*C_];
__device__ __nv_bfloat16 g_aoh[(size_t)B_*QN*C_];
__device__ __nv_bfloat16 g_aol[(size_t)B_*QN*C_];
__device__ __nv_bfloat16 g_wqh[(size_t)C_*C_];
__device__ __nv_bfloat16 g_wql[(size_t)C_*C_];
__device__ __nv_bfloat16 g_wkh[(size_t)C_*C_];
__device__ __nv_bfloat16 g_wkl[(size_t)C_*C_];
__device__ __nv_bfloat16 g_wvh[(size_t)C_*C_];
__device__ __nv_bfloat16 g_wvl[(size_t)C_*C_];
__device__ __nv_bfloat16 g_wph[(size_t)C_*C_];
__device__ __nv_bfloat16 g_wpl[(size_t)C_*C_];
// head-major bf16 hi/lo tensors
__device__ __nv_bfloat16 g_qh[(size_t)BH*QN*HD];
__device__ __nv_bfloat16 g_ql[(size_t)BH*QN*HD];
__device__ __nv_bfloat16 g_kh[(size_t)BH*N_*HD];
__device__ __nv_bfloat16 g_kl[(size_t)BH*N_*HD];
__device__ __nv_bfloat16 g_vh[(size_t)BH*N_*HD];
__device__ __nv_bfloat16 g_vl[(size_t)BH*N_*HD];
__device__ __nv_bfloat16 g_ph[(size_t)BH*QN*N_];
__device__ __nv_bfloat16 g_pl[(size_t)BH*QN*N_];

// ---------------- helpers ----------------
__device__ __forceinline__ void split2(float v, __nv_bfloat16& hi, __nv_bfloat16& lo) {
    hi = __float2bfloat16(v);
    lo = __float2bfloat16(v - __bfloat162float(hi));
}

#define CP_ASYNC16(dst, src) \
    asm volatile("cp.async.cg.shared.global [%0], [%1], 16;" :: "r"(dst), "l"(src))
#define CP_COMMIT() asm volatile("cp.async.commit_group;")
#define CP_WAIT0()  asm volatile("cp.async.wait_group 0;")

#define MMA_BF16(ACC, A, B0, B1)                                              \
    asm volatile(                                                             \
        "mma.sync.aligned.m16n8k16.row.col.f32.bf16.bf16.f32 "                \
        "{%0,%1,%2,%3}, {%4,%5,%6,%7}, {%8,%9}, {%0,%1,%2,%3};"               \
        : "+f"((ACC)[0]), "+f"((ACC)[1]), "+f"((ACC)[2]), "+f"((ACC)[3])      \
        : "r"((A)[0]), "r"((A)[1]), "r"((A)[2]), "r"((A)[3]),                 \
          "r"(B0), "r"(B1))

#define LDSM_X4(R, ADDR)                                                      \
    asm volatile("ldmatrix.sync.aligned.m8n8.x4.shared.b16 {%0,%1,%2,%3}, [%4];" \
                 : "=r"((R)[0]), "=r"((R)[1]), "=r"((R)[2]), "=r"((R)[3]) : "r"(ADDR))
#define LDSM_X4T(R, ADDR)                                                     \
    asm volatile("ldmatrix.sync.aligned.m8n8.x4.trans.shared.b16 {%0,%1,%2,%3}, [%4];" \
                 : "=r"((R)[0]), "=r"((R)[1]), "=r"((R)[2]), "=r"((R)[3]) : "r"(ADDR))

// ---------------- conversions ----------------
__global__ __launch_bounds__(256) void split_w2_kernel(const float* __restrict__ W,
                                                       __nv_bfloat16* __restrict__ Wh,
                                                       __nv_bfloat16* __restrict__ Wl) {
    int i = blockIdx.x * 256 + threadIdx.x;
    __nv_bfloat16 hi, lo; split2(W[i], hi, lo);
    Wh[i] = hi; Wl[i] = lo;
}

__global__ __launch_bounds__(256) void split_x2_kernel(const float* __restrict__ x) {
    __shared__ float tile[32][33];
    int b  = blockIdx.z;
    int n0 = blockIdx.x * 32;
    int c0 = blockIdx.y * 32;
    int tx = threadIdx.x, ty = threadIdx.y;
    const float* xb = x + (size_t)b * C_ * N_;
    #pragma unroll
    for (int i = 0; i < 4; i++)
        tile[ty + i * 8][tx] = xb[(size_t)(c0 + ty + i * 8) * N_ + n0 + tx];
    __syncthreads();
    #pragma unroll
    for (int i = 0; i < 4; i++) {
        int n = n0 + ty + i * 8;
        __nv_bfloat16 hi, lo; split2(tile[tx][ty + i * 8], hi, lo);
        size_t base = ((size_t)b * N_ + n) * C_ + c0 + tx;
        g_axh[base] = hi; g_axl[base] = lo;
    }
}

__global__ __launch_bounds__(256) void split_rows2_kernel(const float* __restrict__ in,
                                                          __nv_bfloat16* __restrict__ oh,
                                                          __nv_bfloat16* __restrict__ ol) {
    int i = blockIdx.x * 256 + threadIdx.x;
    __nv_bfloat16 hi, lo; split2(in[i], hi, lo);
    oh[i] = hi; ol[i] = lo;
}

// ---------------- avg-pool 3x3 s2 pad1 -> xp[B,qN,C] ----------------
__global__ __launch_bounds__(256) void pool_kernel(const float* __restrict__ x) {
    __shared__ float sp[16][577];
    int b  = blockIdx.y;
    int c0 = blockIdx.x * 16;
    int tid = threadIdx.x;
    const float* xb = x + (size_t)b * C_ * N_ + (size_t)c0 * N_;
    #pragma unroll
    for (int r = 0; r < 36; r++) {
        int idx = tid + r * 256;
        int p = idx / 576, n = idx - p * 576;
        sp[p][n] = xb[(size_t)p * N_ + n];
    }
    __syncthreads();
    #pragma unroll
    for (int r = 0; r < 9; r++) {
        int idx = tid + r * 256;
        int qn = idx >> 4, cl = idx & 15;
        int qy = qn / 12, qx = qn - qy * 12;
        float s = 0.f;
        #pragma unroll
        for (int dy = -1; dy <= 1; dy++) {
            int y = 2 * qy + dy;
            if ((unsigned)y < 24u) {
                #pragma unroll
                for (int dx = -1; dx <= 1; dx++) {
                    int xx = 2 * qx + dx;
                    if ((unsigned)xx < 24u) s += sp[cl][y * 24 + xx];
                }
            }
        }
        g_xp[((size_t)b * QN + qn) * C_ + c0 + cl] = s * (1.0f / 9.0f);
    }
}

// ---------------- split-bf16 projection GEMM (512 thr, 16 warps 4x4) ----------------
// C[M,1024] = Ah(Bh+Bl) + Al*Bh.
// mode 1: fp32 NCHW scatter + bias.   mode 2: bf16 hi/lo head-major.   mode 3: mode2 + fp32 row-major.
#define SM_AH   0
#define SM_AL   (2*128*40)
#define SM_BH   (2*(2*128*40))
#define SM_BL   (SM_BH + 2*32*136)
#define SM_ELEMS (SM_BH + 2*(2*32*136))
#define SMEM_BYTES (SM_ELEMS * 2)

__global__ __launch_bounds__(512) void gemm_split(const __nv_bfloat16* __restrict__ Ahg,
                                                  const __nv_bfloat16* __restrict__ Alg,
                                                  const __nv_bfloat16* __restrict__ Bhg,
                                                  const __nv_bfloat16* __restrict__ Blg,
                                                  const float* __restrict__ bias,
                                                  float* __restrict__ Cm,
                                                  __nv_bfloat16* __restrict__ Dh,
                                                  __nv_bfloat16* __restrict__ Dl,
                                                  int rpb, int mode) {
    extern __shared__ __nv_bfloat16 sm[];
    __nv_bfloat16* sAh = sm + SM_AH;
    __nv_bfloat16* sAl = sm + SM_AL;
    __nv_bfloat16* sBh = sm + SM_BH;
    __nv_bfloat16* sBl = sm + SM_BL;

    int tid  = threadIdx.x;
    int lane = tid & 31;
    int warp = tid >> 5;
    int wm = warp >> 2;          // 0..3
    int wn = warp & 3;           // 0..3
    int mBase = wm * 32;
    int nBase = wn * 32;
    int rowBase = blockIdx.y * 128;
    int colBase = blockIdx.x * 128;

    float acc[2][4][4];
    #pragma unroll
    for (int i = 0; i < 2; i++)
        #pragma unroll
        for (int j = 0; j < 4; j++)
            #pragma unroll
            for (int r = 0; r < 4; r++) acc[i][j][r] = 0.f;

    auto prefetch = [&](int kt, int buf) {
        {
            int row = tid >> 2, off = (tid & 3) * 8;
            size_t goff = (size_t)(rowBase + row) * C_ + kt * 32 + off;
            int soff = buf * (128 * 40) + row * 40 + off;
            CP_ASYNC16((uint32_t)__cvta_generic_to_shared(sAh + soff), Ahg + goff);
            CP_ASYNC16((uint32_t)__cvta_generic_to_shared(sAl + soff), Alg + goff);
        }
        {
            int row = tid >> 4, col = (tid & 15) * 8;
            size_t goff = (size_t)(kt * 32 + row) * C_ + colBase + col;
            int soff = buf * (32 * 136) + row * 136 + col;
            CP_ASYNC16((uint32_t)__cvta_generic_to_shared(sBh + soff), Bhg + goff);
            CP_ASYNC16((uint32_t)__cvta_generic_to_shared(sBl + soff), Blg + goff);
        }
        CP_COMMIT();
    };

    prefetch(0, 0);

    for (int kt = 0; kt < KTILES; kt++) {
        int buf = kt & 1;
        CP_WAIT0();
        __syncthreads();
        if (kt + 1 < KTILES) prefetch(kt + 1, buf ^ 1);

        #pragma unroll
        for (int kk = 0; kk < 32; kk += 16) {
            uint32_t ah[2][4], al[2][4];
            #pragma unroll
            for (int mf = 0; mf < 2; mf++) {
                int row = mBase + mf * 16 + (lane & 7) + ((lane >> 3) & 1) * 8;
                int col = kk + ((lane >> 4) << 3);
                int soff = buf * (128 * 40) + row * 40 + col;
                LDSM_X4(ah[mf], (uint32_t)__cvta_generic_to_shared(sAh + soff));
                LDSM_X4(al[mf], (uint32_t)__cvta_generic_to_shared(sAl + soff));
            }
            uint32_t bhf[2][4], blf[2][4];
            #pragma unroll
            for (int g = 0; g < 2; g++) {
                int row = kk + (lane & 15);
                int col = nBase + g * 16 + ((lane >> 4) << 3);
                int soff = buf * (32 * 136) + row * 136 + col;
                LDSM_X4T(bhf[g], (uint32_t)__cvta_generic_to_shared(sBh + soff));
                LDSM_X4T(blf[g], (uint32_t)__cvta_generic_to_shared(sBl + soff));
            }
            #pragma unroll
            for (int mf = 0; mf < 2; mf++)
                #pragma unroll
                for (int nf = 0; nf < 4; nf++) {
                    uint32_t bh0 = bhf[nf >> 1][(nf & 1) * 2 + 0];
                    uint32_t bh1 = bhf[nf >> 1][(nf & 1) * 2 + 1];
                    uint32_t bl0 = blf[nf >> 1][(nf & 1) * 2 + 0];
                    uint32_t bl1 = blf[nf >> 1][(nf & 1) * 2 + 1];
                    MMA_BF16(acc[mf][nf], ah[mf], bh0, bh1);
                    MMA_BF16(acc[mf][nf], ah[mf], bl0, bl1);
                    MMA_BF16(acc[mf][nf], al[mf], bh0, bh1);
                }
        }
        __syncthreads();
    }

    int gid = lane >> 2, tig = lane & 3;
    #pragma unroll
    for (int mf = 0; mf < 2; mf++)
        #pragma unroll
        for (int nf = 0; nf < 4; nf++) {
            int c0 = colBase + nBase + nf * 8 + tig * 2;
            #pragma unroll
            for (int rr = 0; rr < 2; rr++) {
                int row = rowBase + mBase + mf * 16 + gid + rr * 8;
                float v0 = acc[mf][nf][rr * 2 + 0];
                float v1 = acc[mf][nf][rr * 2 + 1];
                if (mode == 1) {
                    int bq = row / QN, qi = row - bq * QN;
                    Cm[((size_t)bq * C_ + c0) * QN + qi]     = v0 + bias[c0];
                    Cm[((size_t)bq * C_ + c0 + 1) * QN + qi] = v1 + bias[c0 + 1];
                } else {
                    int b = row / rpb, n = row - b * rpb;
                    int h = c0 >> 7, d = c0 & 127;
                    size_t di = (((size_t)b * NH + h) * rpb + n) * HD + d;
                    __nv_bfloat162 th, tl;
                    split2(v0, th.x, tl.x);
                    split2(v1, th.y, tl.y);
                    *(__nv_bfloat162*)(Dh + di) = th;
                    *(__nv_bfloat162*)(Dl + di) = tl;
                    if (mode == 3)
                        *(float2*)&Cm[(size_t)row * C_ + c0] = make_float2(v0, v1);
                }
            }
        }
}

// ---------------- relative position bias dots ----------------
__global__ __launch_bounds__(64) void relpos_kernel(const float* __restrict__ rel_h,
                                                    const float* __restrict__ rel_w) {
    int gid = blockIdx.x;
    int bh = gid / QN, i = gid - bh * QN;
    int b = bh >> 3, h = bh & 7;
    int qy = i / 12, qx = i - qy * 12;
    int t = threadIdx.x;
    const float* qrow = g_q + ((size_t)b * QN + i) * C_ + h * HD;
    if (t < 24) {
        const float* R = rel_h + (size_t)(2 * qy - t + 23) * HD;
        float a0 = 0, a1 = 0, a2 = 0, a3 = 0;
        #pragma unroll
        for (int d = 0; d < HD; d += 4) {
            a0 += qrow[d + 0] * R[d + 0];
            a1 += qrow[d + 1] * R[d + 1];
            a2 += qrow[d + 2] * R[d + 2];
            a3 += qrow[d + 3] * R[d + 3];
        }
        g_relh[(size_t)gid * 24 + t] = (a0 + a1) + (a2 + a3);
    } else if (t >= 32 && t < 56) {
        int kx = t - 32;
        const float* R = rel_w + (size_t)(2 * qx - kx + 23) * HD;
        float a0 = 0, a1 = 0, a2 = 0, a3 = 0;
        #pragma unroll
        for (int d = 0; d < HD; d += 4) {
            a0 += qrow[d + 0] * R[d + 0];
            a1 += qrow[d + 1] * R[d + 1];
            a2 += qrow[d + 2] * R[d + 2];
            a3 += qrow[d + 3] * R[d + 3];
        }
        g_relw[(size_t)gid * 24 + kx] = (a0 + a1) + (a2 + a3);
    }
}

// ---------------- QK^T mma: logits = scale*Q@K^T + relh + relw ----------------
// 192 thr / 6 warps (3m x 2n). Block tile 48x96, K=128 resident.
#define QK_SQH 0
#define QK_SQL (48*136)
#define QK_SKH (2*48*136)
#define QK_SKL (2*48*136 + 96*136)
#define QK_ELEMS (2*48*136 + 2*96*136)
#define QK_SMEM (QK_ELEMS*2)

__global__ __launch_bounds__(192) void qk_mma() {
    extern __shared__ __nv_bfloat16 smq[];
    __nv_bfloat16* sQh = smq + QK_SQH;
    __nv_bfloat16* sQl = smq + QK_SQL;
    __nv_bfloat16* sKh = smq + QK_SKH;
    __nv_bfloat16* sKl = smq + QK_SKL;

    int bh = blockIdx.z;
    int rowBase = blockIdx.y * 48;
    int colBase = blockIdx.x * 96;
    int tid = threadIdx.x, lane = tid & 31, warp = tid >> 5;
    int wm = warp >> 1, wn = warp & 1;

    // load Q tile (48x128) and K tile (96x128), hi+lo
    #pragma unroll
    for (int r = 0; r < 4; r++) {
        int chunk = tid + 192 * r;             // 768 chunks
        int row = chunk >> 4, off = (chunk & 15) * 8;
        size_t goff = ((size_t)bh * QN + rowBase + row) * HD + off;
        int soff = row * 136 + off;
        CP_ASYNC16((uint32_t)__cvta_generic_to_shared(sQh + soff), g_qh + goff);
        CP_ASYNC16((uint32_t)__cvta_generic_to_shared(sQl + soff), g_ql + goff);
    }
    #pragma unroll
    for (int r = 0; r < 8; r++) {
        int chunk = tid + 192 * r;             // 1536 chunks
        int row = chunk >> 4, off = (chunk & 15) * 8;
        size_t goff = ((size_t)bh * N_ + colBase + row) * HD + off;
        int soff = row * 136 + off;
        CP_ASYNC16((uint32_t)__cvta_generic_to_shared(sKh + soff), g_kh + goff);
        CP_ASYNC16((uint32_t)__cvta_generic_to_shared(sKl + soff), g_kl + goff);
    }
    CP_COMMIT(); CP_WAIT0();
    __syncthreads();

    float acc[6][4];
    #pragma unroll
    for (int j = 0; j < 6; j++)
        #pragma unroll
        for (int r = 0; r < 4; r++) acc[j][r] = 0.f;

    #pragma unroll
    for (int kk = 0; kk < 128; kk += 16) {
        uint32_t ah[4], al[4];
        {
            int row = wm * 16 + (lane & 7) + ((lane >> 3) & 1) * 8;
            int col = kk + ((lane >> 4) << 3);
            LDSM_X4(ah, (uint32_t)__cvta_generic_to_shared(sQh + row * 136 + col));
            LDSM_X4(al, (uint32_t)__cvta_generic_to_shared(sQl + row * 136 + col));
        }
        uint32_t bhf[3][4], blf[3][4];
        #pragma unroll
        for (int g = 0; g < 3; g++) {
            int n = wn * 48 + g * 16 + (lane & 7) + ((lane >> 4) & 1) * 8;
            int kc = kk + ((lane >> 3) & 1) * 8;
            LDSM_X4(bhf[g], (uint32_t)__cvta_generic_to_shared(sKh + n * 136 + kc));
            LDSM_X4(blf[g], (uint32_t)__cvta_generic_to_shared(sKl + n * 136 + kc));
        }
        #pragma unroll
        for (int nf = 0; nf < 6; nf++) {
            uint32_t bh0 = bhf[nf >> 1][(nf & 1) * 2 + 0];
            uint32_t bh1 = bhf[nf >> 1][(nf & 1) * 2 + 1];
            uint32_t bl0 = blf[nf >> 1][(nf & 1) * 2 + 0];
            uint32_t bl1 = blf[nf >> 1][(nf & 1) * 2 + 1];
            MMA_BF16(acc[nf], ah, bh0, bh1);
            MMA_BF16(acc[nf], ah, bl0, bl1);
            MMA_BF16(acc[nf], al, bh0, bh1);
        }
    }

    const float scale = 0.08838834764831845f;
    int gid = lane >> 2, tig = lane & 3;
    #pragma unroll
    for (int nf = 0; nf < 6; nf++) {
        int jj0 = colBase + wn * 48 + nf * 8 + tig * 2;
        #pragma unroll
        for (int rr = 0; rr < 2; rr++) {
            int i = rowBase + wm * 16 + gid + rr * 8;
            const float* rh = g_relh + ((size_t)bh * QN + i) * 24;
            const float* rw = g_relw + ((size_t)bh * QN + i) * 24;
            float* sp = g_attn + ((size_t)bh * QN + i) * N_;
            #pragma unroll
            for (int cc = 0; cc < 2; cc++) {
                int jj = jj0 + cc;
                int ky = jj / 24, kx = jj - ky * 24;
                sp[jj] = acc[nf][rr * 2 + cc] * scale + rh[ky] + rw[kx];
            }
        }
    }
}

// ---------------- softmax + fused bf16 hi/lo split ----------------
__global__ __launch_bounds__(192) void softmax_kernel() {
    __shared__ float sm6[6], ss[6];
    size_t row = blockIdx.x;
    const float* p = g_attn + row * (size_t)N_;
    __nv_bfloat16* ph = g_ph + row * (size_t)N_;
    __nv_bfloat16* pl = g_pl + row * (size_t)N_;
    int t = threadIdx.x;
    float v0 = p[t], v1 = p[t + 192], v2 = p[t + 384];
    float m = fmaxf(v0, fmaxf(v1, v2));
    #pragma unroll
    for (int o = 16; o > 0; o >>= 1) m = fmaxf(m, __shfl_xor_sync(0xffffffffu, m, o));
    if ((t & 31) == 0) sm6[t >> 5] = m;
    __syncthreads();
    float mm = fmaxf(fmaxf(fmaxf(sm6[0], sm6[1]), fmaxf(sm6[2], sm6[3])), fmaxf(sm6[4], sm6[5]));
    float e0 = __expf(v0 - mm), e1 = __expf(v1 - mm), e2 = __expf(v2 - mm);
    float s = e0 + e1 + e2;
    #pragma unroll
    for (int o = 16; o > 0; o >>= 1) s += __shfl_xor_sync(0xffffffffu, s, o);
    if ((t & 31) == 0) ss[t >> 5] = s;
    __syncthreads();
    float tot = (ss[0] + ss[1]) + (ss[2] + ss[3]) + (ss[4] + ss[5]);
    float inv = 1.0f / tot;
    __nv_bfloat16 hi, lo;
    split2(e0 * inv, hi, lo); ph[t] = hi;       pl[t] = lo;
    split2(e1 * inv, hi, lo); ph[t + 192] = hi; pl[t + 192] = lo;
    split2(e2 * inv, hi, lo); ph[t + 384] = hi; pl[t + 384] = lo;
}

// ---------------- AV mma: o = P@V + q ----------------
// 192 thr / 6 warps (3m x 2n). Block tile 48x128, K=576 in 9 chunks of 64 (double-buffered).
#define AV_SPH 0
#define AV_SPL (2*48*72)
#define AV_SVH (2*(2*48*72))
#define AV_SVL (AV_SVH + 2*64*136)
#define AV_ELEMS (AV_SVH + 2*(2*64*136))
#define AV_SMEM (AV_ELEMS*2)

__global__ __launch_bounds__(192) void av_mma() {
    extern __shared__ __nv_bfloat16 sma[];
    __nv_bfloat16* sPh = sma + AV_SPH;   // [2][48][72]
    __nv_bfloat16* sPl = sma + AV_SPL;
    __nv_bfloat16* sVh = sma + AV_SVH;   // [2][64][136]
    __nv_bfloat16* sVl = sma + AV_SVL;

    int bh = blockIdx.z;
    int b = bh >> 3, h = bh & 7;
    int rowBase = blockIdx.y * 48;
    int tid = threadIdx.x, lane = tid & 31, warp = tid >> 5;
    int wm = warp >> 1, wn = warp & 1;
    int nBase = wn * 64;

    float acc[8][4];
    #pragma unroll
    for (int j = 0; j < 8; j++)
        #pragma unroll
        for (int r = 0; r < 4; r++) acc[j][r] = 0.f;

    auto prefetch = [&](int c, int buf) {
        int k0 = c * 64;
        #pragma unroll
        for (int r = 0; r < 2; r++) {
            int chunk = tid + 192 * r;                 // 384 chunks (48x64/8)
            int row = chunk >> 3, off = (chunk & 7) * 8;
            size_t goff = ((size_t)bh * QN + rowBase + row) * N_ + k0 + off;
            int soff = buf * (48 * 72) + row * 72 + off;
            CP_ASYNC16((uint32_t)__cvta_generic_to_shared(sPh + soff), g_ph + goff);
            CP_ASYNC16((uint32_t)__cvta_generic_to_shared(sPl + soff), g_pl + goff);
        }
        #pragma unroll
        for (int r = 0; r < 6; r++) {
            int idx = tid + 192 * r;                   // 1024 chunks (64x128/8)
            if (idx < 1024) {
                int row = idx >> 4, off = (idx & 15) * 8;
                size_t goff = ((size_t)bh * N_ + k0 + row) * HD + off;
                int soff = buf * (64 * 136) + row * 136 + off;
                CP_ASYNC16((uint32_t)__cvta_generic_to_shared(sVh + soff), g_vh + goff);
                CP_ASYNC16((uint32_t)__cvta_generic_to_shared(sVl + soff), g_vl + goff);
            }
        }
        CP_COMMIT();
    };

    prefetch(0, 0);

    for (int c = 0; c < 9; c++) {
        int buf = c & 1;
        CP_WAIT0();
        __syncthreads();
        if (c + 1 < 9) prefetch(c + 1, buf ^ 1);

        #pragma unroll
        for (int kk = 0; kk < 64; kk += 16) {
            uint32_t ah[4], al[4];
            {
                int row = wm * 16 + (lane & 7) + ((lane >> 3) & 1) * 8;
                int col = kk + ((lane >> 4) << 3);
                int soff = buf * (48 * 72) + row * 72 + col;
                LDSM_X4(ah, (uint32_t)__cvta_generic_to_shared(sPh + soff));
                LDSM_X4(al, (uint32_t)__cvta_generic_to_shared(sPl + soff));
            }
            uint32_t bhf[4][4], blf[4][4];
            #pragma unroll
            for (int g = 0; g < 4; g++) {
                int row = kk + (lane & 15);
                int col = nBase + g * 16 + ((lane >> 4) << 3);
                int soff = buf * (64 * 136) + row * 136 + col;
                LDSM_X4T(bhf[g], (uint32_t)__cvta_generic_to_shared(sVh + soff));
                LDSM_X4T(blf[g], (uint32_t)__cvta_generic_to_shared(sVl + soff));
            }
            #pragma unroll
            for (int nf = 0; nf < 8; nf++) {
                uint32_t bh0 = bhf[nf >> 1][(nf & 1) * 2 + 0];
                uint32_t bh1 = bhf[nf >> 1][(nf & 1) * 2 + 1];
                uint32_t bl0 = blf[nf >> 1][(nf & 1) * 2 + 0];
                uint32_t bl1 = blf[nf >> 1][(nf & 1) * 2 + 1];
                MMA_BF16(acc[nf], ah, bh0, bh1);
                MMA_BF16(acc[nf], ah, bl0, bl1);
                MMA_BF16(acc[nf], al, bh0, bh1);
            }
        }
        __syncthreads();
    }

    int gid = lane >> 2, tig = lane & 3;
    #pragma unroll
    for (int nf = 0; nf < 8; nf++) {
        int d = nBase + nf * 8 + tig * 2;
        #pragma unroll
        for (int rr = 0; rr < 2; rr++) {
            int i = rowBase + wm * 16 + gid + rr * 8;
            size_t off = ((size_t)b * QN + i) * C_ + h * HD + d;
            float2 qv = *(const float2*)(g_q + off);
            *(float2*)(g_o + off) = make_float2(acc[nf][rr * 2 + 0] + qv.x,
                                                acc[nf][rr * 2 + 1] + qv.y);
        }
    }
}

// ---------------- launch ----------------
extern "C" void kernel_launch(void* const* d_in, const int* in_sizes, int n_in,
                              void* d_out, int out_size) {
    const float* x   = (const float*)d_in[0];
    const float* Wq  = (const float*)d_in[1];
    const float* Wk  = (const float*)d_in[2];
    const float* Wv  = (const float*)d_in[3];
    const float* Wp  = (const float*)d_in[4];
    const float* bp  = (const float*)d_in[5];
    const float* rph = (const float*)d_in[6];
    const float* rpw = (const float*)d_in[7];
    float* out = (float*)d_out;

    float *xp, *q, *o;
    __nv_bfloat16 *axh, *axl, *aqh, *aql, *aoh, *aol;
    __nv_bfloat16 *wqh, *wql, *wkh, *wkl, *wvh, *wvl, *wph, *wpl;
    __nv_bfloat16 *qh, *ql, *kh, *kl, *vh, *vl;
    cudaGetSymbolAddress((void**)&xp, g_xp);
    cudaGetSymbolAddress((void**)&q,  g_q);
    cudaGetSymbolAddress((void**)&o,  g_o);
    cudaGetSymbolAddress((void**)&axh, g_axh);
    cudaGetSymbolAddress((void**)&axl, g_axl);
    cudaGetSymbolAddress((void**)&aqh, g_aqh);
    cudaGetSymbolAddress((void**)&aql, g_aql);
    cudaGetSymbolAddress((void**)&aoh, g_aoh);
    cudaGetSymbolAddress((void**)&aol, g_aol);
    cudaGetSymbolAddress((void**)&wqh, g_wqh);
    cudaGetSymbolAddress((void**)&wql, g_wql);
    cudaGetSymbolAddress((void**)&wkh, g_wkh);
    cudaGetSymbolAddress((void**)&wkl, g_wkl);
    cudaGetSymbolAddress((void**)&wvh, g_wvh);
    cudaGetSymbolAddress((void**)&wvl, g_wvl);
    cudaGetSymbolAddress((void**)&wph, g_wph);
    cudaGetSymbolAddress((void**)&wpl, g_wpl);
    cudaGetSymbolAddress((void**)&qh, g_qh);
    cudaGetSymbolAddress((void**)&ql, g_ql);
    cudaGetSymbolAddress((void**)&kh, g_kh);
    cudaGetSymbolAddress((void**)&kl, g_kl);
    cudaGetSymbolAddress((void**)&vh, g_vh);
    cudaGetSymbolAddress((void**)&vl, g_vl);

    cudaFuncSetAttribute(gemm_split, cudaFuncAttributeMaxDynamicSharedMemorySize, SMEM_BYTES);
    cudaFuncSetAttribute(qk_mma, cudaFuncAttributeMaxDynamicSharedMemorySize, QK_SMEM);
    cudaFuncSetAttribute(av_mma, cudaFuncAttributeMaxDynamicSharedMemorySize, AV_SMEM);

    split_w2_kernel<<<4096, 256>>>(Wq, wqh, wql);
    split_w2_kernel<<<4096, 256>>>(Wk, wkh, wkl);
    split_w2_kernel<<<4096, 256>>>(Wv, wvh, wvl);
    split_w2_kernel<<<4096, 256>>>(Wp, wph, wpl);

    split_x2_kernel<<<dim3(18, 32, B_), dim3(32, 8)>>>(x);
    pool_kernel<<<dim3(C_ / 16, B_), 256>>>(x);
    split_rows2_kernel<<<(B_ * QN * C_) / 256, 256>>>(xp, aqh, aql);

    gemm_split<<<dim3(8, (B_ * N_) / 128), 512, SMEM_BYTES>>>(axh, axl, wkh, wkl, nullptr, nullptr, kh, kl, N_, 2);
    gemm_split<<<dim3(8, (B_ * N_) / 128), 512, SMEM_BYTES>>>(axh, axl, wvh, wvl, nullptr, nullptr, vh, vl, N_, 2);
    gemm_split<<<dim3(8, (B_ * QN) / 128), 512, SMEM_BYTES>>>(aqh, aql, wqh, wql, nullptr, q, qh, ql, QN, 3);

    relpos_kernel<<<BH * QN, 64>>>(rph, rpw);
    qk_mma<<<dim3(6, 3, BH), 192, QK_SMEM>>>();
    softmax_kernel<<<BH * QN, 192>>>();
    av_mma<<<dim3(1, 3, BH), 192, AV_SMEM>>>();

    split_rows2_kernel<<<(B_ * QN * C_) / 256, 256>>>(o, aoh, aol);
    gemm_split<<<dim3(8, (B_ * QN) / 128), 512, SMEM_BYTES>>>(aoh, aol, wph, wpl, bp, out, nullptr, nullptr, QN, 1);
}

// round 8
// speedup vs baseline: 2.4982x; 1.1540x over previous
#include <cuda.h>
#include <cuda_runtime.h>
#include <cuda_bf16.h>
#include <math.h>
#include <stdint.h>

#define B_  128
#define C_  1024
#define H_  24
#define W_  24
#define N_  576
#define NH  8
#define HD  128
#define QH  12
#define QW  12
#define QN  144
#define BH  (B_*NH)

// ---------------- fp32 scratch ----------------
__device__ float g_xp  [(size_t)B_*QN*C_];
__device__ float g_q   [(size_t)B_*QN*C_];
__device__ float g_attn[(size_t)BH*QN*N_];
__device__ float g_relh[(size_t)BH*QN*H_];
__device__ float g_relw[(size_t)BH*QN*W_];
__device__ float g_o   [(size_t)B_*QN*C_];
// bf16 hi/lo A operands
__device__ __nv_bfloat16 g_axh[(size_t)B_*N_*C_];
__device__ __nv_bfloat16 g_axl[(size_t)B_*N_*C_];
__device__ __nv_bfloat16 g_aqh[(size_t)B_*QN*C_];
__device__ __nv_bfloat16 g_aql[(size_t)B_*QN*C_];
__device__ __nv_bfloat16 g_aoh[(size_t)B_*QN*C_];
__device__ __nv_bfloat16 g_aol[(size_t)B_*QN*C_];
// TRANSPOSED weights [N,K] hi/lo
__device__ __nv_bfloat16 g_wqh[(size_t)C_*C_];
__device__ __nv_bfloat16 g_wql[(size_t)C_*C_];
__device__ __nv_bfloat16 g_wkh[(size_t)C_*C_];
__device__ __nv_bfloat16 g_wkl[(size_t)C_*C_];
__device__ __nv_bfloat16 g_wvh[(size_t)C_*C_];
__device__ __nv_bfloat16 g_wvl[(size_t)C_*C_];
__device__ __nv_bfloat16 g_wph[(size_t)C_*C_];
__device__ __nv_bfloat16 g_wpl[(size_t)C_*C_];
// head-major bf16 hi/lo tensors
__device__ __nv_bfloat16 g_qh[(size_t)BH*QN*HD];
__device__ __nv_bfloat16 g_ql[(size_t)BH*QN*HD];
__device__ __nv_bfloat16 g_kh[(size_t)BH*N_*HD];
__device__ __nv_bfloat16 g_kl[(size_t)BH*N_*HD];
__device__ __nv_bfloat16 g_vh[(size_t)BH*N_*HD];
__device__ __nv_bfloat16 g_vl[(size_t)BH*N_*HD];
__device__ __nv_bfloat16 g_ph[(size_t)BH*QN*N_];
__device__ __nv_bfloat16 g_pl[(size_t)BH*QN*N_];

// ---------------- helpers ----------------
__device__ __forceinline__ void split2(float v, __nv_bfloat16& hi, __nv_bfloat16& lo) {
    hi = __float2bfloat16(v);
    lo = __float2bfloat16(v - __bfloat162float(hi));
}
__device__ __forceinline__ uint32_t smem_u32(const void* p) {
    return (uint32_t)__cvta_generic_to_shared(p);
}
__device__ __forceinline__ uint32_t swz(uint32_t o) {      // SW128, 128B rows
    return o ^ ((o >> 3) & 0x70);
}

#define MMA_BF16(ACC, A, B0, B1)                                              \
    asm volatile(                                                             \
        "mma.sync.aligned.m16n8k16.row.col.f32.bf16.bf16.f32 "                \
        "{%0,%1,%2,%3}, {%4,%5,%6,%7}, {%8,%9}, {%0,%1,%2,%3};"               \
        : "+f"((ACC)[0]), "+f"((ACC)[1]), "+f"((ACC)[2]), "+f"((ACC)[3])      \
        : "r"((A)[0]), "r"((A)[1]), "r"((A)[2]), "r"((A)[3]),                 \
          "r"(B0), "r"(B1))

#define LDSM_X4(R, ADDR)                                                      \
    asm volatile("ldmatrix.sync.aligned.m8n8.x4.shared.b16 {%0,%1,%2,%3}, [%4];" \
                 : "=r"((R)[0]), "=r"((R)[1]), "=r"((R)[2]), "=r"((R)[3]) : "r"(ADDR))
#define LDSM_X4T(R, ADDR)                                                     \
    asm volatile("ldmatrix.sync.aligned.m8n8.x4.trans.shared.b16 {%0,%1,%2,%3}, [%4];" \
                 : "=r"((R)[0]), "=r"((R)[1]), "=r"((R)[2]), "=r"((R)[3]) : "r"(ADDR))

#define MBAR_INIT(mb, cnt) \
    asm volatile("mbarrier.init.shared.b64 [%0], %1;" :: "r"(mb), "r"((uint32_t)(cnt)) : "memory")
#define MBAR_EXPECT_TX(mb, bytes) \
    asm volatile("mbarrier.arrive.expect_tx.shared.b64 _, [%0], %1;" :: "r"(mb), "r"((uint32_t)(bytes)) : "memory")
#define MBAR_ARRIVE(mb) \
    asm volatile("mbarrier.arrive.shared.b64 _, [%0];" :: "r"(mb) : "memory")
#define MBAR_WAIT(mb, ph) do {                                                    \
    asm volatile("{\n\t.reg .pred P1;\n\t"                                        \
        "WAIT_LOOP_%=:\n\t"                                                       \
        "mbarrier.try_wait.parity.acquire.cta.shared::cta.b64 P1, [%0], %1, 0x989680;\n\t" \
        "@P1 bra.uni WAIT_DONE_%=;\n\t"                                           \
        "bra.uni WAIT_LOOP_%=;\n\t"                                               \
        "WAIT_DONE_%=:\n\t}"                                                      \
        :: "r"(mb), "r"((uint32_t)(ph)) : "memory");                              \
} while(0)

#define TMA_LOAD_2D(sa, map, cx, cy, mb)                                          \
    asm volatile("cp.async.bulk.tensor.2d.shared::cta.global.tile.mbarrier::complete_tx::bytes " \
        "[%0], [%1, {%2, %3}], [%4];"                                             \
        :: "r"(sa), "l"(map), "r"((int32_t)(cx)), "r"((int32_t)(cy)), "r"(mb) : "memory")

// ---------------- conversions ----------------
__global__ __launch_bounds__(256) void split_wT_kernel(const float* __restrict__ W,
                                                       __nv_bfloat16* __restrict__ WhT,
                                                       __nv_bfloat16* __restrict__ WlT) {
    __shared__ float t[32][33];
    int k0 = blockIdx.x * 32, n0 = blockIdx.y * 32;
    int tx = threadIdx.x, ty = threadIdx.y;
    #pragma unroll
    for (int i = 0; i < 4; i++)
        t[ty + i * 8][tx] = W[(size_t)(k0 + ty + i * 8) * C_ + n0 + tx];
    __syncthreads();
    #pragma unroll
    for (int i = 0; i < 4; i++) {
        __nv_bfloat16 hi, lo; split2(t[tx][ty + i * 8], hi, lo);
        size_t idx = (size_t)(n0 + ty + i * 8) * C_ + k0 + tx;
        WhT[idx] = hi; WlT[idx] = lo;
    }
}

__global__ __launch_bounds__(256) void split_x2_kernel(const float* __restrict__ x) {
    __shared__ float tile[32][33];
    int b  = blockIdx.z;
    int n0 = blockIdx.x * 32;
    int c0 = blockIdx.y * 32;
    int tx = threadIdx.x, ty = threadIdx.y;
    const float* xb = x + (size_t)b * C_ * N_;
    #pragma unroll
    for (int i = 0; i < 4; i++)
        tile[ty + i * 8][tx] = xb[(size_t)(c0 + ty + i * 8) * N_ + n0 + tx];
    __syncthreads();
    #pragma unroll
    for (int i = 0; i < 4; i++) {
        int n = n0 + ty + i * 8;
        __nv_bfloat16 hi, lo; split2(tile[tx][ty + i * 8], hi, lo);
        size_t base = ((size_t)b * N_ + n) * C_ + c0 + tx;
        g_axh[base] = hi; g_axl[base] = lo;
    }
}

__global__ __launch_bounds__(256) void split_rows2_kernel(const float* __restrict__ in,
                                                          __nv_bfloat16* __restrict__ oh,
                                                          __nv_bfloat16* __restrict__ ol) {
    int i = blockIdx.x * 256 + threadIdx.x;
    __nv_bfloat16 hi, lo; split2(in[i], hi, lo);
    oh[i] = hi; ol[i] = lo;
}

// ---------------- avg-pool 3x3 s2 pad1 ----------------
__global__ __launch_bounds__(256) void pool_kernel(const float* __restrict__ x) {
    __shared__ float sp[16][577];
    int b  = blockIdx.y;
    int c0 = blockIdx.x * 16;
    int tid = threadIdx.x;
    const float* xb = x + (size_t)b * C_ * N_ + (size_t)c0 * N_;
    #pragma unroll
    for (int r = 0; r < 36; r++) {
        int idx = tid + r * 256;
        int p = idx / 576, n = idx - p * 576;
        sp[p][n] = xb[(size_t)p * N_ + n];
    }
    __syncthreads();
    #pragma unroll
    for (int r = 0; r < 9; r++) {
        int idx = tid + r * 256;
        int qn = idx >> 4, cl = idx & 15;
        int qy = qn / 12, qx = qn - qy * 12;
        float s = 0.f;
        #pragma unroll
        for (int dy = -1; dy <= 1; dy++) {
            int y = 2 * qy + dy;
            if ((unsigned)y < 24u) {
                #pragma unroll
                for (int dx = -1; dx <= 1; dx++) {
                    int xx = 2 * qx + dx;
                    if ((unsigned)xx < 24u) s += sp[cl][y * 24 + xx];
                }
            }
        }
        g_xp[((size_t)b * QN + qn) * C_ + c0 + cl] = s * (1.0f / 9.0f);
    }
}

// ---------------- TMA + mma.sync projection GEMM ----------------
// C[M,1024] = Ah(Bh+Bl) + Al*Bh; 128x128 tile, 512 thr (16 warps 4x4, 32x32 warp tile),
// 16 stages of K=64, TMA double buffer. B = transposed weights [N,K].
// mode 1: fp32 NCHW scatter + bias.  mode 2: bf16 hi/lo head-major.  mode 3: mode2 + fp32 row-major.
#define GT_TILE  16384                   // 128 rows x 128B
#define GT_BUF   (4*GT_TILE)             // Ah Al Bh Bl
#define GT_SMEM  (2*GT_BUF + 2048)
#define NSTAGE   16

__global__ __launch_bounds__(512) void gemm_tma(
    const __grid_constant__ CUtensorMap tmAh,
    const __grid_constant__ CUtensorMap tmAl,
    const __grid_constant__ CUtensorMap tmBh,
    const __grid_constant__ CUtensorMap tmBl,
    const float* __restrict__ bias,
    float* __restrict__ Cm,
    __nv_bfloat16* __restrict__ Dh,
    __nv_bfloat16* __restrict__ Dl,
    int rpb, int mode)
{
    extern __shared__ char smem[];
    uint32_t sraw = smem_u32(smem);
    uint32_t fullb[2]  = {sraw, sraw + 8};
    uint32_t emptyb[2] = {sraw + 16, sraw + 24};
    uint32_t tiles = (sraw + 64 + 1023) & ~1023u;

    int tid = threadIdx.x, lane = tid & 31, warp = tid >> 5;
    int wm = warp >> 2, wn = warp & 3;
    int rowBase = blockIdx.y * 128;
    int colBase = blockIdx.x * 128;

    if (tid == 0) {
        MBAR_INIT(fullb[0], 1);  MBAR_INIT(fullb[1], 1);
        MBAR_INIT(emptyb[0], 512); MBAR_INIT(emptyb[1], 512);
    }
    __syncthreads();

    float acc[2][4][4];
    #pragma unroll
    for (int i = 0; i < 2; i++)
        #pragma unroll
        for (int j = 0; j < 4; j++)
            #pragma unroll
            for (int r = 0; r < 4; r++) acc[i][j][r] = 0.f;

    int phF[2] = {0, 0};
    int phE[2] = {1, 1};

    if (tid == 0) {
        MBAR_WAIT(emptyb[0], phE[0]); phE[0] ^= 1;
        uint32_t base = tiles;
        MBAR_EXPECT_TX(fullb[0], GT_BUF);
        TMA_LOAD_2D(base,               &tmAh, 0, rowBase, fullb[0]);
        TMA_LOAD_2D(base + GT_TILE,     &tmAl, 0, rowBase, fullb[0]);
        TMA_LOAD_2D(base + 2 * GT_TILE, &tmBh, 0, colBase, fullb[0]);
        TMA_LOAD_2D(base + 3 * GT_TILE, &tmBl, 0, colBase, fullb[0]);
    }

    for (int s = 0; s < NSTAGE; s++) {
        int buf = s & 1;
        if (tid == 0 && s + 1 < NSTAGE) {
            int nb = buf ^ 1;
            MBAR_WAIT(emptyb[nb], phE[nb]); phE[nb] ^= 1;
            uint32_t base = tiles + nb * GT_BUF;
            MBAR_EXPECT_TX(fullb[nb], GT_BUF);
            int k0 = (s + 1) * 64;
            TMA_LOAD_2D(base,               &tmAh, k0, rowBase, fullb[nb]);
            TMA_LOAD_2D(base + GT_TILE,     &tmAl, k0, rowBase, fullb[nb]);
            TMA_LOAD_2D(base + 2 * GT_TILE, &tmBh, k0, colBase, fullb[nb]);
            TMA_LOAD_2D(base + 3 * GT_TILE, &tmBl, k0, colBase, fullb[nb]);
        }
        MBAR_WAIT(fullb[buf], phF[buf]); phF[buf] ^= 1;

        uint32_t aH = tiles + buf * GT_BUF;
        uint32_t aL = aH + GT_TILE;
        uint32_t bH = aH + 2 * GT_TILE;
        uint32_t bL = aH + 3 * GT_TILE;

        #pragma unroll
        for (int kk = 0; kk < 64; kk += 16) {
            uint32_t ah[2][4], al[2][4];
            #pragma unroll
            for (int mf = 0; mf < 2; mf++) {
                int row = wm * 32 + mf * 16 + (lane & 7) + ((lane >> 3) & 1) * 8;
                int ce  = kk + ((lane >> 4) << 3);
                uint32_t off = swz((uint32_t)(row * 128 + ce * 2));
                LDSM_X4(ah[mf], aH + off);
                LDSM_X4(al[mf], aL + off);
            }
            uint32_t bhf[2][4], blf[2][4];
            #pragma unroll
            for (int g = 0; g < 2; g++) {
                int n  = wn * 32 + g * 16 + (lane & 7) + ((lane >> 4) & 1) * 8;
                int kc = kk + ((lane >> 3) & 1) * 8;
                uint32_t off = swz((uint32_t)(n * 128 + kc * 2));
                LDSM_X4(bhf[g], bH + off);
                LDSM_X4(blf[g], bL + off);
            }
            #pragma unroll
            for (int mf = 0; mf < 2; mf++)
                #pragma unroll
                for (int nf = 0; nf < 4; nf++) {
                    uint32_t b0 = bhf[nf >> 1][(nf & 1) * 2 + 0];
                    uint32_t b1 = bhf[nf >> 1][(nf & 1) * 2 + 1];
                    uint32_t c0 = blf[nf >> 1][(nf & 1) * 2 + 0];
                    uint32_t c1 = blf[nf >> 1][(nf & 1) * 2 + 1];
                    MMA_BF16(acc[mf][nf], ah[mf], b0, b1);
                    MMA_BF16(acc[mf][nf], ah[mf], c0, c1);
                    MMA_BF16(acc[mf][nf], al[mf], b0, b1);
                }
        }
        MBAR_ARRIVE(emptyb[buf]);
    }

    int gid = lane >> 2, tig = lane & 3;
    #pragma unroll
    for (int mf = 0; mf < 2; mf++)
        #pragma unroll
        for (int nf = 0; nf < 4; nf++) {
            int c0 = colBase + wn * 32 + nf * 8 + tig * 2;
            #pragma unroll
            for (int rr = 0; rr < 2; rr++) {
                int row = rowBase + wm * 32 + mf * 16 + gid + rr * 8;
                float v0 = acc[mf][nf][rr * 2 + 0];
                float v1 = acc[mf][nf][rr * 2 + 1];
                if (mode == 1) {
                    int bq = row / QN, qi = row - bq * QN;
                    Cm[((size_t)bq * C_ + c0) * QN + qi]     = v0 + bias[c0];
                    Cm[((size_t)bq * C_ + c0 + 1) * QN + qi] = v1 + bias[c0 + 1];
                } else {
                    int b = row / rpb, n = row - b * rpb;
                    int h = c0 >> 7, d = c0 & 127;
                    size_t di = (((size_t)b * NH + h) * rpb + n) * HD + d;
                    __nv_bfloat162 th, tl;
                    split2(v0, th.x, tl.x);
                    split2(v1, th.y, tl.y);
                    *(__nv_bfloat162*)(Dh + di) = th;
                    *(__nv_bfloat162*)(Dl + di) = tl;
                    if (mode == 3)
                        *(float2*)&Cm[(size_t)row * C_ + c0] = make_float2(v0, v1);
                }
            }
        }
}

// ---------------- relative position bias dots ----------------
__global__ __launch_bounds__(64) void relpos_kernel(const float* __restrict__ rel_h,
                                                    const float* __restrict__ rel_w) {
    int gid = blockIdx.x;
    int bh = gid / QN, i = gid - bh * QN;
    int b = bh >> 3, h = bh & 7;
    int qy = i / 12, qx = i - qy * 12;
    int t = threadIdx.x;
    const float* qrow = g_q + ((size_t)b * QN + i) * C_ + h * HD;
    if (t < 24) {
        const float* R = rel_h + (size_t)(2 * qy - t + 23) * HD;
        float a0 = 0, a1 = 0, a2 = 0, a3 = 0;
        #pragma unroll
        for (int d = 0; d < HD; d += 4) {
            a0 += qrow[d + 0] * R[d + 0];
            a1 += qrow[d + 1] * R[d + 1];
            a2 += qrow[d + 2] * R[d + 2];
            a3 += qrow[d + 3] * R[d + 3];
        }
        g_relh[(size_t)gid * 24 + t] = (a0 + a1) + (a2 + a3);
    } else if (t >= 32 && t < 56) {
        int kx = t - 32;
        const float* R = rel_w + (size_t)(2 * qx - kx + 23) * HD;
        float a0 = 0, a1 = 0, a2 = 0, a3 = 0;
        #pragma unroll
        for (int d = 0; d < HD; d += 4) {
            a0 += qrow[d + 0] * R[d + 0];
            a1 += qrow[d + 1] * R[d + 1];
            a2 += qrow[d + 2] * R[d + 2];
            a3 += qrow[d + 3] * R[d + 3];
        }
        g_relw[(size_t)gid * 24 + kx] = (a0 + a1) + (a2 + a3);
    }
}

// ---------------- QK^T mma (TMA loads, K=128 resident) ----------------
// tiles: Q 2x(48x64) hi/lo, K 2x(96x64) hi/lo. 192 thr / 6 warps (3m x 2n).
#define QK_QH  0
#define QK_QL  12288
#define QK_KH  24576
#define QK_KL  49152
#define QK_BYTES 73728
#define QK_SMEM  (QK_BYTES + 2048)

__global__ __launch_bounds__(192) void qk_mma(
    const __grid_constant__ CUtensorMap tmQh,
    const __grid_constant__ CUtensorMap tmQl,
    const __grid_constant__ CUtensorMap tmKh,
    const __grid_constant__ CUtensorMap tmKl)
{
    extern __shared__ char smem[];
    uint32_t sraw = smem_u32(smem);
    uint32_t fullb = sraw;
    uint32_t tiles = (sraw + 64 + 1023) & ~1023u;

    int bh = blockIdx.z;
    int rowBase = blockIdx.y * 48;
    int colBase = blockIdx.x * 96;
    int tid = threadIdx.x, lane = tid & 31, warp = tid >> 5;
    int wm = warp >> 1, wn = warp & 1;

    if (tid == 0) MBAR_INIT(fullb, 1);
    __syncthreads();
    if (tid == 0) {
        MBAR_EXPECT_TX(fullb, QK_BYTES);
        int qy = bh * QN + rowBase;
        int ky = bh * N_ + colBase;
        TMA_LOAD_2D(tiles + QK_QH,        &tmQh, 0,  qy, fullb);
        TMA_LOAD_2D(tiles + QK_QH + 6144, &tmQh, 64, qy, fullb);
        TMA_LOAD_2D(tiles + QK_QL,        &tmQl, 0,  qy, fullb);
        TMA_LOAD_2D(tiles + QK_QL + 6144, &tmQl, 64, qy, fullb);
        TMA_LOAD_2D(tiles + QK_KH,         &tmKh, 0,  ky, fullb);
        TMA_LOAD_2D(tiles + QK_KH + 12288, &tmKh, 64, ky, fullb);
        TMA_LOAD_2D(tiles + QK_KL,         &tmKl, 0,  ky, fullb);
        TMA_LOAD_2D(tiles + QK_KL + 12288, &tmKl, 64, ky, fullb);
    }
    MBAR_WAIT(fullb, 0);

    float acc[6][4];
    #pragma unroll
    for (int j = 0; j < 6; j++)
        #pragma unroll
        for (int r = 0; r < 4; r++) acc[j][r] = 0.f;

    #pragma unroll
    for (int kk = 0; kk < 128; kk += 16) {
        uint32_t ah[4], al[4];
        {
            int row = wm * 16 + (lane & 7) + ((lane >> 3) & 1) * 8;
            int ce  = kk + ((lane >> 4) << 3);
            uint32_t off = (uint32_t)((ce >> 6) * 6144) + swz((uint32_t)(row * 128 + (ce & 63) * 2));
            LDSM_X4(ah, tiles + QK_QH + off);
            LDSM_X4(al, tiles + QK_QL + off);
        }
        uint32_t bhf[3][4], blf[3][4];
        #pragma unroll
        for (int g = 0; g < 3; g++) {
            int n  = wn * 48 + g * 16 + (lane & 7) + ((lane >> 4) & 1) * 8;
            int kc = kk + ((lane >> 3) & 1) * 8;
            uint32_t off = (uint32_t)((kc >> 6) * 12288) + swz((uint32_t)(n * 128 + (kc & 63) * 2));
            LDSM_X4(bhf[g], tiles + QK_KH + off);
            LDSM_X4(blf[g], tiles + QK_KL + off);
        }
        #pragma unroll
        for (int nf = 0; nf < 6; nf++) {
            uint32_t b0 = bhf[nf >> 1][(nf & 1) * 2 + 0];
            uint32_t b1 = bhf[nf >> 1][(nf & 1) * 2 + 1];
            uint32_t c0 = blf[nf >> 1][(nf & 1) * 2 + 0];
            uint32_t c1 = blf[nf >> 1][(nf & 1) * 2 + 1];
            MMA_BF16(acc[nf], ah, b0, b1);
            MMA_BF16(acc[nf], ah, c0, c1);
            MMA_BF16(acc[nf], al, b0, b1);
        }
    }

    const float scale = 0.08838834764831845f;
    int gid = lane >> 2, tig = lane & 3;
    #pragma unroll
    for (int nf = 0; nf < 6; nf++) {
        int jj0 = colBase + wn * 48 + nf * 8 + tig * 2;
        #pragma unroll
        for (int rr = 0; rr < 2; rr++) {
            int i = rowBase + wm * 16 + gid + rr * 8;
            const float* rh = g_relh + ((size_t)bh * QN + i) * 24;
            const float* rw = g_relw + ((size_t)bh * QN + i) * 24;
            float* sp = g_attn + ((size_t)bh * QN + i) * N_;
            #pragma unroll
            for (int cc = 0; cc < 2; cc++) {
                int jj = jj0 + cc;
                int ky = jj / 24, kx = jj - ky * 24;
                sp[jj] = acc[nf][rr * 2 + cc] * scale + rh[ky] + rw[kx];
            }
        }
    }
}

// ---------------- softmax + fused hi/lo split ----------------
__global__ __launch_bounds__(192) void softmax_kernel() {
    __shared__ float sm6[6], ss[6];
    size_t row = blockIdx.x;
    const float* p = g_attn + row * (size_t)N_;
    __nv_bfloat16* ph = g_ph + row * (size_t)N_;
    __nv_bfloat16* pl = g_pl + row * (size_t)N_;
    int t = threadIdx.x;
    float v0 = p[t], v1 = p[t + 192], v2 = p[t + 384];
    float m = fmaxf(v0, fmaxf(v1, v2));
    #pragma unroll
    for (int o = 16; o > 0; o >>= 1) m = fmaxf(m, __shfl_xor_sync(0xffffffffu, m, o));
    if ((t & 31) == 0) sm6[t >> 5] = m;
    __syncthreads();
    float mm = fmaxf(fmaxf(fmaxf(sm6[0], sm6[1]), fmaxf(sm6[2], sm6[3])), fmaxf(sm6[4], sm6[5]));
    float e0 = __expf(v0 - mm), e1 = __expf(v1 - mm), e2 = __expf(v2 - mm);
    float s = e0 + e1 + e2;
    #pragma unroll
    for (int o = 16; o > 0; o >>= 1) s += __shfl_xor_sync(0xffffffffu, s, o);
    if ((t & 31) == 0) ss[t >> 5] = s;
    __syncthreads();
    float tot = (ss[0] + ss[1]) + (ss[2] + ss[3]) + (ss[4] + ss[5]);
    float inv = 1.0f / tot;
    __nv_bfloat16 hi, lo;
    split2(e0 * inv, hi, lo); ph[t] = hi;       pl[t] = lo;
    split2(e1 * inv, hi, lo); ph[t + 192] = hi; pl[t + 192] = lo;
    split2(e2 * inv, hi, lo); ph[t + 384] = hi; pl[t + 384] = lo;
}

// ---------------- AV mma (TMA pipelined, 9 stages of K=64) ----------------
// per buffer: P 48x64 hi/lo (6144B each), V 2x(64x64) hi/lo (16384B each)
#define AV_PH   0
#define AV_PL   6144
#define AV_VH   12288
#define AV_VL   28672
#define AV_BUF  45056
#define AV_SMEM (2*AV_BUF + 2048)

__global__ __launch_bounds__(192) void av_mma(
    const __grid_constant__ CUtensorMap tmPh,
    const __grid_constant__ CUtensorMap tmPl,
    const __grid_constant__ CUtensorMap tmVh,
    const __grid_constant__ CUtensorMap tmVl)
{
    extern __shared__ char smem[];
    uint32_t sraw = smem_u32(smem);
    uint32_t fullb[2]  = {sraw, sraw + 8};
    uint32_t emptyb[2] = {sraw + 16, sraw + 24};
    uint32_t tiles = (sraw + 64 + 1023) & ~1023u;

    int bh = blockIdx.z;
    int b = bh >> 3, h = bh & 7;
    int rowBase = blockIdx.y * 48;
    int tid = threadIdx.x, lane = tid & 31, warp = tid >> 5;
    int wm = warp >> 1, wn = warp & 1;
    int nBase = wn * 64;

    if (tid == 0) {
        MBAR_INIT(fullb[0], 1);  MBAR_INIT(fullb[1], 1);
        MBAR_INIT(emptyb[0], 192); MBAR_INIT(emptyb[1], 192);
    }
    __syncthreads();

    float acc[8][4];
    #pragma unroll
    for (int j = 0; j < 8; j++)
        #pragma unroll
        for (int r = 0; r < 4; r++) acc[j][r] = 0.f;

    int phF[2] = {0, 0};
    int phE[2] = {1, 1};

    auto issue = [&](int s, int buf) {
        uint32_t base = tiles + buf * AV_BUF;
        MBAR_EXPECT_TX(fullb[buf], AV_BUF);
        int k0 = s * 64;
        int py = bh * QN + rowBase;
        int vy = bh * N_ + k0;
        TMA_LOAD_2D(base + AV_PH, &tmPh, k0, py, fullb[buf]);
        TMA_LOAD_2D(base + AV_PL, &tmPl, k0, py, fullb[buf]);
        TMA_LOAD_2D(base + AV_VH,        &tmVh, 0,  vy, fullb[buf]);
        TMA_LOAD_2D(base + AV_VH + 8192, &tmVh, 64, vy, fullb[buf]);
        TMA_LOAD_2D(base + AV_VL,        &tmVl, 0,  vy, fullb[buf]);
        TMA_LOAD_2D(base + AV_VL + 8192, &tmVl, 64, vy, fullb[buf]);
    };

    if (tid == 0) {
        MBAR_WAIT(emptyb[0], phE[0]); phE[0] ^= 1;
        issue(0, 0);
    }

    for (int s = 0; s < 9; s++) {
        int buf = s & 1;
        if (tid == 0 && s + 1 < 9) {
            int nb = buf ^ 1;
            MBAR_WAIT(emptyb[nb], phE[nb]); phE[nb] ^= 1;
            issue(s + 1, nb);
        }
        MBAR_WAIT(fullb[buf], phF[buf]); phF[buf] ^= 1;
        uint32_t base = tiles + buf * AV_BUF;

        #pragma unroll
        for (int kk = 0; kk < 64; kk += 16) {
            uint32_t ah[4], al[4];
            {
                int row = wm * 16 + (lane & 7) + ((lane >> 3) & 1) * 8;
                int ce  = kk + ((lane >> 4) << 3);
                uint32_t off = swz((uint32_t)(row * 128 + ce * 2));
                LDSM_X4(ah, base + AV_PH + off);
                LDSM_X4(al, base + AV_PL + off);
            }
            uint32_t bhf[4][4], blf[4][4];
            #pragma unroll
            for (int g = 0; g < 4; g++) {
                int vrow = kk + (lane & 15);
                int d    = nBase + g * 16 + ((lane >> 4) << 3);
                uint32_t off = (uint32_t)((d >> 6) * 8192) + swz((uint32_t)(vrow * 128 + (d & 63) * 2));
                LDSM_X4T(bhf[g], base + AV_VH + off);
                LDSM_X4T(blf[g], base + AV_VL + off);
            }
            #pragma unroll
            for (int nf = 0; nf < 8; nf++) {
                uint32_t b0 = bhf[nf >> 1][(nf & 1) * 2 + 0];
                uint32_t b1 = bhf[nf >> 1][(nf & 1) * 2 + 1];
                uint32_t c0 = blf[nf >> 1][(nf & 1) * 2 + 0];
                uint32_t c1 = blf[nf >> 1][(nf & 1) * 2 + 1];
                MMA_BF16(acc[nf], ah, b0, b1);
                MMA_BF16(acc[nf], ah, c0, c1);
                MMA_BF16(acc[nf], al, b0, b1);
            }
        }
        MBAR_ARRIVE(emptyb[buf]);
    }

    int gid = lane >> 2, tig = lane & 3;
    #pragma unroll
    for (int nf = 0; nf < 8; nf++) {
        int d = nBase + nf * 8 + tig * 2;
        #pragma unroll
        for (int rr = 0; rr < 2; rr++) {
            int i = rowBase + wm * 16 + gid + rr * 8;
            size_t off = ((size_t)b * QN + i) * C_ + h * HD + d;
            float2 qv = *(const float2*)(g_q + off);
            *(float2*)(g_o + off) = make_float2(acc[nf][rr * 2 + 0] + qv.x,
                                                acc[nf][rr * 2 + 1] + qv.y);
        }
    }
}

// ---------------- host: tensormap builder ----------------
typedef CUresult (*EncodeTiledFn)(CUtensorMap*, CUtensorMapDataType, cuuint32_t, void*,
                                  const cuuint64_t*, const cuuint64_t*, const cuuint32_t*,
                                  const cuuint32_t*, CUtensorMapInterleave, CUtensorMapSwizzle,
                                  CUtensorMapL2promotion, CUtensorMapFloatOOBfill);

static void make_map(EncodeTiledFn enc, CUtensorMap* m, void* ptr,
                     uint64_t dim0, uint64_t rows, uint32_t box0, uint32_t box1) {
    cuuint64_t dims[2]    = {(cuuint64_t)dim0, (cuuint64_t)rows};
    cuuint64_t strides[1] = {(cuuint64_t)dim0 * 2};
    cuuint32_t box[2]     = {box0, box1};
    cuuint32_t es[2]      = {1, 1};
    enc(m, CU_TENSOR_MAP_DATA_TYPE_BFLOAT16, 2, ptr, dims, strides, box, es,
        CU_TENSOR_MAP_INTERLEAVE_NONE, CU_TENSOR_MAP_SWIZZLE_128B,
        CU_TENSOR_MAP_L2_PROMOTION_L2_128B, CU_TENSOR_MAP_FLOAT_OOB_FILL_NONE);
}

// ---------------- launch ----------------
extern "C" void kernel_launch(void* const* d_in, const int* in_sizes, int n_in,
                              void* d_out, int out_size) {
    const float* x   = (const float*)d_in[0];
    const float* Wq  = (const float*)d_in[1];
    const float* Wk  = (const float*)d_in[2];
    const float* Wv  = (const float*)d_in[3];
    const float* Wp  = (const float*)d_in[4];
    const float* bp  = (const float*)d_in[5];
    const float* rph = (const float*)d_in[6];
    const float* rpw = (const float*)d_in[7];
    float* out = (float*)d_out;

    float *xp, *q, *o;
    __nv_bfloat16 *axh, *axl, *aqh, *aql, *aoh, *aol;
    __nv_bfloat16 *wqh, *wql, *wkh, *wkl, *wvh, *wvl, *wph, *wpl;
    __nv_bfloat16 *qh, *ql, *kh, *kl, *vh, *vl, *ph, *pl;
    cudaGetSymbolAddress((void**)&xp, g_xp);
    cudaGetSymbolAddress((void**)&q,  g_q);
    cudaGetSymbolAddress((void**)&o,  g_o);
    cudaGetSymbolAddress((void**)&axh, g_axh);
    cudaGetSymbolAddress((void**)&axl, g_axl);
    cudaGetSymbolAddress((void**)&aqh, g_aqh);
    cudaGetSymbolAddress((void**)&aql, g_aql);
    cudaGetSymbolAddress((void**)&aoh, g_aoh);
    cudaGetSymbolAddress((void**)&aol, g_aol);
    cudaGetSymbolAddress((void**)&wqh, g_wqh);
    cudaGetSymbolAddress((void**)&wql, g_wql);
    cudaGetSymbolAddress((void**)&wkh, g_wkh);
    cudaGetSymbolAddress((void**)&wkl, g_wkl);
    cudaGetSymbolAddress((void**)&wvh, g_wvh);
    cudaGetSymbolAddress((void**)&wvl, g_wvl);
    cudaGetSymbolAddress((void**)&wph, g_wph);
    cudaGetSymbolAddress((void**)&wpl, g_wpl);
    cudaGetSymbolAddress((void**)&qh, g_qh);
    cudaGetSymbolAddress((void**)&ql, g_ql);
    cudaGetSymbolAddress((void**)&kh, g_kh);
    cudaGetSymbolAddress((void**)&kl, g_kl);
    cudaGetSymbolAddress((void**)&vh, g_vh);
    cudaGetSymbolAddress((void**)&vl, g_vl);
    cudaGetSymbolAddress((void**)&ph, g_ph);
    cudaGetSymbolAddress((void**)&pl, g_pl);

    EncodeTiledFn enc = nullptr;
    {
        void* fn = nullptr;
        cudaDriverEntryPointQueryResult st;
        cudaGetDriverEntryPoint("cuTensorMapEncodeTiled", &fn, cudaEnableDefault, &st);
        enc = (EncodeTiledFn)fn;
    }
    CUtensorMap mAxh, mAxl, mAqh, mAql, mAoh, mAol;
    CUtensorMap mWqh, mWql, mWkh, mWkl, mWvh, mWvl, mWph, mWpl;
    CUtensorMap mQh, mQl, mKh, mKl, mVh, mVl, mPh, mPl;
    make_map(enc, &mAxh, axh, C_, (uint64_t)B_ * N_, 64, 128);
    make_map(enc, &mAxl, axl, C_, (uint64_t)B_ * N_, 64, 128);
    make_map(enc, &mAqh, aqh, C_, (uint64_t)B_ * QN, 64, 128);
    make_map(enc, &mAql, aql, C_, (uint64_t)B_ * QN, 64, 128);
    make_map(enc, &mAoh, aoh, C_, (uint64_t)B_ * QN, 64, 128);
    make_map(enc, &mAol, aol, C_, (uint64_t)B_ * QN, 64, 128);
    make_map(enc, &mWqh, wqh, C_, C_, 64, 128);
    make_map(enc, &mWql, wql, C_, C_, 64, 128);
    make_map(enc, &mWkh, wkh, C_, C_, 64, 128);
    make_map(enc, &mWkl, wkl, C_, C_, 64, 128);
    make_map(enc, &mWvh, wvh, C_, C_, 64, 128);
    make_map(enc, &mWvl, wvl, C_, C_, 64, 128);
    make_map(enc, &mWph, wph, C_, C_, 64, 128);
    make_map(enc, &mWpl, wpl, C_, C_, 64, 128);
    make_map(enc, &mQh, qh, HD, (uint64_t)BH * QN, 64, 48);
    make_map(enc, &mQl, ql, HD, (uint64_t)BH * QN, 64, 48);
    make_map(enc, &mKh, kh, HD, (uint64_t)BH * N_, 64, 96);
    make_map(enc, &mKl, kl, HD, (uint64_t)BH * N_, 64, 96);
    make_map(enc, &mVh, vh, HD, (uint64_t)BH * N_, 64, 64);
    make_map(enc, &mVl, vl, HD, (uint64_t)BH * N_, 64, 64);
    make_map(enc, &mPh, ph, N_, (uint64_t)BH * QN, 64, 48);
    make_map(enc, &mPl, pl, N_, (uint64_t)BH * QN, 64, 48);

    cudaFuncSetAttribute(gemm_tma, cudaFuncAttributeMaxDynamicSharedMemorySize, GT_SMEM);
    cudaFuncSetAttribute(qk_mma, cudaFuncAttributeMaxDynamicSharedMemorySize, QK_SMEM);
    cudaFuncSetAttribute(av_mma, cudaFuncAttributeMaxDynamicSharedMemorySize, AV_SMEM);

    split_wT_kernel<<<dim3(32, 32), dim3(32, 8)>>>(Wq, wqh, wql);
    split_wT_kernel<<<dim3(32, 32), dim3(32, 8)>>>(Wk, wkh, wkl);
    split_wT_kernel<<<dim3(32, 32), dim3(32, 8)>>>(Wv, wvh, wvl);
    split_wT_kernel<<<dim3(32, 32), dim3(32, 8)>>>(Wp, wph, wpl);

    split_x2_kernel<<<dim3(18, 32, B_), dim3(32, 8)>>>(x);
    pool_kernel<<<dim3(C_ / 16, B_), 256>>>(x);
    split_rows2_kernel<<<(B_ * QN * C_) / 256, 256>>>(xp, aqh, aql);

    gemm_tma<<<dim3(8, (B_ * N_) / 128), 512, GT_SMEM>>>(mAxh, mAxl, mWkh, mWkl, nullptr, nullptr, kh, kl, N_, 2);
    gemm_tma<<<dim3(8, (B_ * N_) / 128), 512, GT_SMEM>>>(mAxh, mAxl, mWvh, mWvl, nullptr, nullptr, vh, vl, N_, 2);
    gemm_tma<<<dim3(8, (B_ * QN) / 128), 512, GT_SMEM>>>(mAqh, mAql, mWqh, mWql, nullptr, q, qh, ql, QN, 3);

    relpos_kernel<<<BH * QN, 64>>>(rph, rpw);
    qk_mma<<<dim3(6, 3, BH), 192, QK_SMEM>>>(mQh, mQl, mKh, mKl);
    softmax_kernel<<<BH * QN, 192>>>();
    av_mma<<<dim3(1, 3, BH), 192, AV_SMEM>>>(mPh, mPl, mVh, mVl);

    split_rows2_kernel<<<(B_ * QN * C_) / 256, 256>>>(o, aoh, aol);
    gemm_tma<<<dim3(8, (B_ * QN) / 128), 512, GT_SMEM>>>(mAoh, mAol, mWph, mWpl, bp, out, nullptr, nullptr, QN, 1);
}

// round 9
// speedup vs baseline: 2.5015x; 1.0013x over previous
#include <cuda.h>
#include <cuda_runtime.h>
#include <cuda_bf16.h>
#include <math.h>
#include <stdint.h>

#define B_  128
#define C_  1024
#define H_  24
#define W_  24
#define N_  576
#define NH  8
#define HD  128
#define QH  12
#define QW  12
#define QN  144
#define BH  (B_*NH)

// ---------------- fp32 scratch ----------------
__device__ float g_xp  [(size_t)B_*QN*C_];
__device__ float g_q   [(size_t)B_*QN*C_];
__device__ float g_attn[(size_t)BH*QN*N_];
__device__ float g_relh[(size_t)BH*QN*H_];
__device__ float g_relw[(size_t)BH*QN*W_];
__device__ float g_o   [(size_t)B_*QN*C_];
// bf16 hi/lo A operands
__device__ __nv_bfloat16 g_axh[(size_t)B_*N_*C_];
__device__ __nv_bfloat16 g_axl[(size_t)B_*N_*C_];
__device__ __nv_bfloat16 g_aqh[(size_t)B_*QN*C_];
__device__ __nv_bfloat16 g_aql[(size_t)B_*QN*C_];
__device__ __nv_bfloat16 g_aoh[(size_t)B_*QN*C_];
__device__ __nv_bfloat16 g_aol[(size_t)B_*QN*C_];
// TRANSPOSED weights [N,K] hi/lo
__device__ __nv_bfloat16 g_wqh[(size_t)C_*C_];
__device__ __nv_bfloat16 g_wql[(size_t)C_*C_];
__device__ __nv_bfloat16 g_wkh[(size_t)C_*C_];
__device__ __nv_bfloat16 g_wkl[(size_t)C_*C_];
__device__ __nv_bfloat16 g_wvh[(size_t)C_*C_];
__device__ __nv_bfloat16 g_wvl[(size_t)C_*C_];
__device__ __nv_bfloat16 g_wph[(size_t)C_*C_];
__device__ __nv_bfloat16 g_wpl[(size_t)C_*C_];
// head-major bf16 hi/lo tensors
__device__ __nv_bfloat16 g_qh[(size_t)BH*QN*HD];
__device__ __nv_bfloat16 g_ql[(size_t)BH*QN*HD];
__device__ __nv_bfloat16 g_kh[(size_t)BH*N_*HD];
__device__ __nv_bfloat16 g_kl[(size_t)BH*N_*HD];
__device__ __nv_bfloat16 g_vh[(size_t)BH*N_*HD];
__device__ __nv_bfloat16 g_vl[(size_t)BH*N_*HD];
__device__ __nv_bfloat16 g_ph[(size_t)BH*QN*N_];
__device__ __nv_bfloat16 g_pl[(size_t)BH*QN*N_];

// ---------------- helpers ----------------
__device__ __forceinline__ void split2(float v, __nv_bfloat16& hi, __nv_bfloat16& lo) {
    hi = __float2bfloat16(v);
    lo = __float2bfloat16(v - __bfloat162float(hi));
}
__device__ __forceinline__ uint32_t smem_u32(const void* p) {
    return (uint32_t)__cvta_generic_to_shared(p);
}
__device__ __forceinline__ uint32_t swz(uint32_t o) {      // SW128, 128B rows
    return o ^ ((o >> 3) & 0x70);
}

#define MMA_BF16(ACC, A, B0, B1)                                              \
    asm volatile(                                                             \
        "mma.sync.aligned.m16n8k16.row.col.f32.bf16.bf16.f32 "                \
        "{%0,%1,%2,%3}, {%4,%5,%6,%7}, {%8,%9}, {%0,%1,%2,%3};"               \
        : "+f"((ACC)[0]), "+f"((ACC)[1]), "+f"((ACC)[2]), "+f"((ACC)[3])      \
        : "r"((A)[0]), "r"((A)[1]), "r"((A)[2]), "r"((A)[3]),                 \
          "r"(B0), "r"(B1))

#define LDSM_X4(R, ADDR)                                                      \
    asm volatile("ldmatrix.sync.aligned.m8n8.x4.shared.b16 {%0,%1,%2,%3}, [%4];" \
                 : "=r"((R)[0]), "=r"((R)[1]), "=r"((R)[2]), "=r"((R)[3]) : "r"(ADDR))
#define LDSM_X4T(R, ADDR)                                                     \
    asm volatile("ldmatrix.sync.aligned.m8n8.x4.trans.shared.b16 {%0,%1,%2,%3}, [%4];" \
                 : "=r"((R)[0]), "=r"((R)[1]), "=r"((R)[2]), "=r"((R)[3]) : "r"(ADDR))

#define MBAR_INIT(mb, cnt) \
    asm volatile("mbarrier.init.shared.b64 [%0], %1;" :: "r"(mb), "r"((uint32_t)(cnt)) : "memory")
#define MBAR_EXPECT_TX(mb, bytes) \
    asm volatile("mbarrier.arrive.expect_tx.shared.b64 _, [%0], %1;" :: "r"(mb), "r"((uint32_t)(bytes)) : "memory")
#define MBAR_ARRIVE(mb) \
    asm volatile("mbarrier.arrive.shared.b64 _, [%0];" :: "r"(mb) : "memory")
#define MBAR_WAIT(mb, ph) do {                                                    \
    asm volatile("{\n\t.reg .pred P1;\n\t"                                        \
        "WAIT_LOOP_%=:\n\t"                                                       \
        "mbarrier.try_wait.parity.acquire.cta.shared::cta.b64 P1, [%0], %1, 0x989680;\n\t" \
        "@P1 bra.uni WAIT_DONE_%=;\n\t"                                           \
        "bra.uni WAIT_LOOP_%=;\n\t"                                               \
        "WAIT_DONE_%=:\n\t}"                                                      \
        :: "r"(mb), "r"((uint32_t)(ph)) : "memory");                              \
} while(0)

#define TMA_LOAD_2D(sa, map, cx, cy, mb)                                          \
    asm volatile("cp.async.bulk.tensor.2d.shared::cta.global.tile.mbarrier::complete_tx::bytes " \
        "[%0], [%1, {%2, %3}], [%4];"                                             \
        :: "r"(sa), "l"(map), "r"((int32_t)(cx)), "r"((int32_t)(cy)), "r"(mb) : "memory")

// ---------------- conversions ----------------
__global__ __launch_bounds__(256) void split_wT_kernel(const float* __restrict__ W,
                                                       __nv_bfloat16* __restrict__ WhT,
                                                       __nv_bfloat16* __restrict__ WlT) {
    __shared__ float t[32][33];
    int k0 = blockIdx.x * 32, n0 = blockIdx.y * 32;
    int tx = threadIdx.x, ty = threadIdx.y;
    #pragma unroll
    for (int i = 0; i < 4; i++)
        t[ty + i * 8][tx] = W[(size_t)(k0 + ty + i * 8) * C_ + n0 + tx];
    __syncthreads();
    #pragma unroll
    for (int i = 0; i < 4; i++) {
        __nv_bfloat16 hi, lo; split2(t[tx][ty + i * 8], hi, lo);
        size_t idx = (size_t)(n0 + ty + i * 8) * C_ + k0 + tx;
        WhT[idx] = hi; WlT[idx] = lo;
    }
}

__global__ __launch_bounds__(256) void split_x2_kernel(const float* __restrict__ x) {
    __shared__ float tile[32][33];
    int b  = blockIdx.z;
    int n0 = blockIdx.x * 32;
    int c0 = blockIdx.y * 32;
    int tx = threadIdx.x, ty = threadIdx.y;
    const float* xb = x + (size_t)b * C_ * N_;
    #pragma unroll
    for (int i = 0; i < 4; i++)
        tile[ty + i * 8][tx] = xb[(size_t)(c0 + ty + i * 8) * N_ + n0 + tx];
    __syncthreads();
    #pragma unroll
    for (int i = 0; i < 4; i++) {
        int n = n0 + ty + i * 8;
        __nv_bfloat16 hi, lo; split2(tile[tx][ty + i * 8], hi, lo);
        size_t base = ((size_t)b * N_ + n) * C_ + c0 + tx;
        g_axh[base] = hi; g_axl[base] = lo;
    }
}

__global__ __launch_bounds__(256) void split_rows2_kernel(const float* __restrict__ in,
                                                          __nv_bfloat16* __restrict__ oh,
                                                          __nv_bfloat16* __restrict__ ol) {
    int i = blockIdx.x * 256 + threadIdx.x;
    __nv_bfloat16 hi, lo; split2(in[i], hi, lo);
    oh[i] = hi; ol[i] = lo;
}

// ---------------- avg-pool 3x3 s2 pad1 ----------------
__global__ __launch_bounds__(256) void pool_kernel(const float* __restrict__ x) {
    __shared__ float sp[16][577];
    int b  = blockIdx.y;
    int c0 = blockIdx.x * 16;
    int tid = threadIdx.x;
    const float* xb = x + (size_t)b * C_ * N_ + (size_t)c0 * N_;
    #pragma unroll
    for (int r = 0; r < 36; r++) {
        int idx = tid + r * 256;
        int p = idx / 576, n = idx - p * 576;
        sp[p][n] = xb[(size_t)p * N_ + n];
    }
    __syncthreads();
    #pragma unroll
    for (int r = 0; r < 9; r++) {
        int idx = tid + r * 256;
        int qn = idx >> 4, cl = idx & 15;
        int qy = qn / 12, qx = qn - qy * 12;
        float s = 0.f;
        #pragma unroll
        for (int dy = -1; dy <= 1; dy++) {
            int y = 2 * qy + dy;
            if ((unsigned)y < 24u) {
                #pragma unroll
                for (int dx = -1; dx <= 1; dx++) {
                    int xx = 2 * qx + dx;
                    if ((unsigned)xx < 24u) s += sp[cl][y * 24 + xx];
                }
            }
        }
        g_xp[((size_t)b * QN + qn) * C_ + c0 + cl] = s * (1.0f / 9.0f);
    }
}

// ---------------- TMA + mma.sync projection GEMM (3-stage, frag-pipelined) ----------------
// C[M,1024] = Ah(Bh+Bl) + Al*Bh; 128x128 tile, 512 thr (16 warps 4x4, 32x32 warp tile),
// 16 k-stages of 64, TMA triple buffer, manual ldmatrix/MMA double-buffer.
// mode 1: fp32 NCHW scatter + bias.  mode 2: bf16 hi/lo head-major.  mode 3: mode2 + fp32 row-major.
#define GT_TILE  16384                   // 128 rows x 128B
#define GT_BUF   (4*GT_TILE)             // Ah Al Bh Bl = 64KB
#define GT_SMEM  (3*GT_BUF + 1024)
#define NSTAGE   16

__global__ __launch_bounds__(512) void gemm_tma(
    const __grid_constant__ CUtensorMap tmAh,
    const __grid_constant__ CUtensorMap tmAl,
    const __grid_constant__ CUtensorMap tmBh,
    const __grid_constant__ CUtensorMap tmBl,
    const float* __restrict__ bias,
    float* __restrict__ Cm,
    __nv_bfloat16* __restrict__ Dh,
    __nv_bfloat16* __restrict__ Dl,
    int rpb, int mode)
{
    extern __shared__ char smem[];
    uint32_t sraw = smem_u32(smem);
    uint32_t fullb[3]  = {sraw, sraw + 8, sraw + 16};
    uint32_t emptyb[3] = {sraw + 24, sraw + 32, sraw + 40};
    uint32_t tiles = (sraw + 64 + 1023) & ~1023u;

    int tid = threadIdx.x, lane = tid & 31, warp = tid >> 5;
    int wm = warp >> 2, wn = warp & 3;
    int rowBase = blockIdx.y * 128;
    int colBase = blockIdx.x * 128;

    if (tid == 0) {
        MBAR_INIT(fullb[0], 1);  MBAR_INIT(fullb[1], 1);  MBAR_INIT(fullb[2], 1);
        MBAR_INIT(emptyb[0], 512); MBAR_INIT(emptyb[1], 512); MBAR_INIT(emptyb[2], 512);
    }
    __syncthreads();

    float acc[2][4][4];
    #pragma unroll
    for (int i = 0; i < 2; i++)
        #pragma unroll
        for (int j = 0; j < 4; j++)
            #pragma unroll
            for (int r = 0; r < 4; r++) acc[i][j][r] = 0.f;

    int phF[3] = {0, 0, 0};
    int phE[3] = {0, 0, 0};

    auto issue = [&](int s, int slot) {
        uint32_t base = tiles + slot * GT_BUF;
        MBAR_EXPECT_TX(fullb[slot], GT_BUF);
        int k0 = s * 64;
        TMA_LOAD_2D(base,               &tmAh, k0, rowBase, fullb[slot]);
        TMA_LOAD_2D(base + GT_TILE,     &tmAl, k0, rowBase, fullb[slot]);
        TMA_LOAD_2D(base + 2 * GT_TILE, &tmBh, k0, colBase, fullb[slot]);
        TMA_LOAD_2D(base + 3 * GT_TILE, &tmBl, k0, colBase, fullb[slot]);
    };

    if (tid == 0) { issue(0, 0); issue(1, 1); issue(2, 2); }

    // fragment double buffers
    uint32_t ah[2][2][4], al[2][2][4], bhf[2][2][4], blf[2][2][4];

    // per-thread precomputed addressing pieces
    int arow0 = wm * 32 + (lane & 7) + ((lane >> 3) & 1) * 8;     // + mf*16
    int acol8 = (lane >> 4) << 3;                                  // + kk
    int brow0 = wn * 32 + (lane & 7) + ((lane >> 4) & 1) * 8;     // + g*16
    int bcol8 = (lane >> 3) & 1 ? 8 : 0;                           // + kk

    for (int s = 0; s < NSTAGE; s++) {
        int slot = s % 3;
        MBAR_WAIT(fullb[slot], phF[slot]); phF[slot] ^= 1;

        uint32_t aH = tiles + slot * GT_BUF;
        uint32_t aL = aH + GT_TILE;
        uint32_t bH = aH + 2 * GT_TILE;
        uint32_t bL = aH + 3 * GT_TILE;

        // load kk=0 fragments into buffer 0
        {
            #pragma unroll
            for (int mf = 0; mf < 2; mf++) {
                uint32_t off = swz((uint32_t)((arow0 + mf * 16) * 128 + acol8 * 2));
                LDSM_X4(ah[0][mf], aH + off);
                LDSM_X4(al[0][mf], aL + off);
            }
            #pragma unroll
            for (int g = 0; g < 2; g++) {
                uint32_t off = swz((uint32_t)((brow0 + g * 16) * 128 + bcol8 * 2));
                LDSM_X4(bhf[0][g], bH + off);
                LDSM_X4(blf[0][g], bL + off);
            }
        }

        #pragma unroll
        for (int kki = 0; kki < 4; kki++) {
            int pb = kki & 1;
            if (kki < 3) {
                int nb = pb ^ 1;
                int kk = (kki + 1) * 16;
                #pragma unroll
                for (int mf = 0; mf < 2; mf++) {
                    uint32_t off = swz((uint32_t)((arow0 + mf * 16) * 128 + (kk + acol8) * 2));
                    LDSM_X4(ah[nb][mf], aH + off);
                    LDSM_X4(al[nb][mf], aL + off);
                }
                #pragma unroll
                for (int g = 0; g < 2; g++) {
                    uint32_t off = swz((uint32_t)((brow0 + g * 16) * 128 + (kk + bcol8) * 2));
                    LDSM_X4(bhf[nb][g], bH + off);
                    LDSM_X4(blf[nb][g], bL + off);
                }
            }
            #pragma unroll
            for (int mf = 0; mf < 2; mf++)
                #pragma unroll
                for (int nf = 0; nf < 4; nf++) {
                    uint32_t b0 = bhf[pb][nf >> 1][(nf & 1) * 2 + 0];
                    uint32_t b1 = bhf[pb][nf >> 1][(nf & 1) * 2 + 1];
                    uint32_t c0 = blf[pb][nf >> 1][(nf & 1) * 2 + 0];
                    uint32_t c1 = blf[pb][nf >> 1][(nf & 1) * 2 + 1];
                    MMA_BF16(acc[mf][nf], ah[pb][mf], b0, b1);
                    MMA_BF16(acc[mf][nf], ah[pb][mf], c0, c1);
                    MMA_BF16(acc[mf][nf], al[pb][mf], b0, b1);
                }
        }
        MBAR_ARRIVE(emptyb[slot]);
        if (tid == 0 && s + 3 < NSTAGE) {
            MBAR_WAIT(emptyb[slot], phE[slot]); phE[slot] ^= 1;
            issue(s + 3, slot);
        }
    }

    int gid = lane >> 2, tig = lane & 3;
    #pragma unroll
    for (int mf = 0; mf < 2; mf++)
        #pragma unroll
        for (int nf = 0; nf < 4; nf++) {
            int c0 = colBase + wn * 32 + nf * 8 + tig * 2;
            #pragma unroll
            for (int rr = 0; rr < 2; rr++) {
                int row = rowBase + wm * 32 + mf * 16 + gid + rr * 8;
                float v0 = acc[mf][nf][rr * 2 + 0];
                float v1 = acc[mf][nf][rr * 2 + 1];
                if (mode == 1) {
                    int bq = row / QN, qi = row - bq * QN;
                    Cm[((size_t)bq * C_ + c0) * QN + qi]     = v0 + bias[c0];
                    Cm[((size_t)bq * C_ + c0 + 1) * QN + qi] = v1 + bias[c0 + 1];
                } else {
                    int b = row / rpb, n = row - b * rpb;
                    int h = c0 >> 7, d = c0 & 127;
                    size_t di = (((size_t)b * NH + h) * rpb + n) * HD + d;
                    __nv_bfloat162 th, tl;
                    split2(v0, th.x, tl.x);
                    split2(v1, th.y, tl.y);
                    *(__nv_bfloat162*)(Dh + di) = th;
                    *(__nv_bfloat162*)(Dl + di) = tl;
                    if (mode == 3)
                        *(float2*)&Cm[(size_t)row * C_ + c0] = make_float2(v0, v1);
                }
            }
        }
}

// ---------------- relative position bias dots ----------------
__global__ __launch_bounds__(64) void relpos_kernel(const float* __restrict__ rel_h,
                                                    const float* __restrict__ rel_w) {
    int gid = blockIdx.x;
    int bh = gid / QN, i = gid - bh * QN;
    int b = bh >> 3, h = bh & 7;
    int qy = i / 12, qx = i - qy * 12;
    int t = threadIdx.x;
    const float* qrow = g_q + ((size_t)b * QN + i) * C_ + h * HD;
    if (t < 24) {
        const float* R = rel_h + (size_t)(2 * qy - t + 23) * HD;
        float a0 = 0, a1 = 0, a2 = 0, a3 = 0;
        #pragma unroll
        for (int d = 0; d < HD; d += 4) {
            a0 += qrow[d + 0] * R[d + 0];
            a1 += qrow[d + 1] * R[d + 1];
            a2 += qrow[d + 2] * R[d + 2];
            a3 += qrow[d + 3] * R[d + 3];
        }
        g_relh[(size_t)gid * 24 + t] = (a0 + a1) + (a2 + a3);
    } else if (t >= 32 && t < 56) {
        int kx = t - 32;
        const float* R = rel_w + (size_t)(2 * qx - kx + 23) * HD;
        float a0 = 0, a1 = 0, a2 = 0, a3 = 0;
        #pragma unroll
        for (int d = 0; d < HD; d += 4) {
            a0 += qrow[d + 0] * R[d + 0];
            a1 += qrow[d + 1] * R[d + 1];
            a2 += qrow[d + 2] * R[d + 2];
            a3 += qrow[d + 3] * R[d + 3];
        }
        g_relw[(size_t)gid * 24 + kx] = (a0 + a1) + (a2 + a3);
    }
}

// ---------------- QK^T mma (TMA loads, K=128 resident) ----------------
#define QK_QH  0
#define QK_QL  12288
#define QK_KH  24576
#define QK_KL  49152
#define QK_BYTES 73728
#define QK_SMEM  (QK_BYTES + 2048)

__global__ __launch_bounds__(192) void qk_mma(
    const __grid_constant__ CUtensorMap tmQh,
    const __grid_constant__ CUtensorMap tmQl,
    const __grid_constant__ CUtensorMap tmKh,
    const __grid_constant__ CUtensorMap tmKl)
{
    extern __shared__ char smem[];
    uint32_t sraw = smem_u32(smem);
    uint32_t fullb = sraw;
    uint32_t tiles = (sraw + 64 + 1023) & ~1023u;

    int bh = blockIdx.z;
    int rowBase = blockIdx.y * 48;
    int colBase = blockIdx.x * 96;
    int tid = threadIdx.x, lane = tid & 31, warp = tid >> 5;
    int wm = warp >> 1, wn = warp & 1;

    if (tid == 0) MBAR_INIT(fullb, 1);
    __syncthreads();
    if (tid == 0) {
        MBAR_EXPECT_TX(fullb, QK_BYTES);
        int qy = bh * QN + rowBase;
        int ky = bh * N_ + colBase;
        TMA_LOAD_2D(tiles + QK_QH,        &tmQh, 0,  qy, fullb);
        TMA_LOAD_2D(tiles + QK_QH + 6144, &tmQh, 64, qy, fullb);
        TMA_LOAD_2D(tiles + QK_QL,        &tmQl, 0,  qy, fullb);
        TMA_LOAD_2D(tiles + QK_QL + 6144, &tmQl, 64, qy, fullb);
        TMA_LOAD_2D(tiles + QK_KH,         &tmKh, 0,  ky, fullb);
        TMA_LOAD_2D(tiles + QK_KH + 12288, &tmKh, 64, ky, fullb);
        TMA_LOAD_2D(tiles + QK_KL,         &tmKl, 0,  ky, fullb);
        TMA_LOAD_2D(tiles + QK_KL + 12288, &tmKl, 64, ky, fullb);
    }
    MBAR_WAIT(fullb, 0);

    float acc[6][4];
    #pragma unroll
    for (int j = 0; j < 6; j++)
        #pragma unroll
        for (int r = 0; r < 4; r++) acc[j][r] = 0.f;

    #pragma unroll
    for (int kk = 0; kk < 128; kk += 16) {
        uint32_t ah[4], al[4];
        {
            int row = wm * 16 + (lane & 7) + ((lane >> 3) & 1) * 8;
            int ce  = kk + ((lane >> 4) << 3);
            uint32_t off = (uint32_t)((ce >> 6) * 6144) + swz((uint32_t)(row * 128 + (ce & 63) * 2));
            LDSM_X4(ah, tiles + QK_QH + off);
            LDSM_X4(al, tiles + QK_QL + off);
        }
        uint32_t bhf[3][4], blf[3][4];
        #pragma unroll
        for (int g = 0; g < 3; g++) {
            int n  = wn * 48 + g * 16 + (lane & 7) + ((lane >> 4) & 1) * 8;
            int kc = kk + ((lane >> 3) & 1) * 8;
            uint32_t off = (uint32_t)((kc >> 6) * 12288) + swz((uint32_t)(n * 128 + (kc & 63) * 2));
            LDSM_X4(bhf[g], tiles + QK_KH + off);
            LDSM_X4(blf[g], tiles + QK_KL + off);
        }
        #pragma unroll
        for (int nf = 0; nf < 6; nf++) {
            uint32_t b0 = bhf[nf >> 1][(nf & 1) * 2 + 0];
            uint32_t b1 = bhf[nf >> 1][(nf & 1) * 2 + 1];
            uint32_t c0 = blf[nf >> 1][(nf & 1) * 2 + 0];
            uint32_t c1 = blf[nf >> 1][(nf & 1) * 2 + 1];
            MMA_BF16(acc[nf], ah, b0, b1);
            MMA_BF16(acc[nf], ah, c0, c1);
            MMA_BF16(acc[nf], al, b0, b1);
        }
    }

    const float scale = 0.08838834764831845f;
    int gid = lane >> 2, tig = lane & 3;
    #pragma unroll
    for (int nf = 0; nf < 6; nf++) {
        int jj0 = colBase + wn * 48 + nf * 8 + tig * 2;
        #pragma unroll
        for (int rr = 0; rr < 2; rr++) {
            int i = rowBase + wm * 16 + gid + rr * 8;
            const float* rh = g_relh + ((size_t)bh * QN + i) * 24;
            const float* rw = g_relw + ((size_t)bh * QN + i) * 24;
            float* sp = g_attn + ((size_t)bh * QN + i) * N_;
            #pragma unroll
            for (int cc = 0; cc < 2; cc++) {
                int jj = jj0 + cc;
                int ky = jj / 24, kx = jj - ky * 24;
                sp[jj] = acc[nf][rr * 2 + cc] * scale + rh[ky] + rw[kx];
            }
        }
    }
}

// ---------------- softmax + fused hi/lo split ----------------
__global__ __launch_bounds__(192) void softmax_kernel() {
    __shared__ float sm6[6], ss[6];
    size_t row = blockIdx.x;
    const float* p = g_attn + row * (size_t)N_;
    __nv_bfloat16* ph = g_ph + row * (size_t)N_;
    __nv_bfloat16* pl = g_pl + row * (size_t)N_;
    int t = threadIdx.x;
    float v0 = p[t], v1 = p[t + 192], v2 = p[t + 384];
    float m = fmaxf(v0, fmaxf(v1, v2));
    #pragma unroll
    for (int o = 16; o > 0; o >>= 1) m = fmaxf(m, __shfl_xor_sync(0xffffffffu, m, o));
    if ((t & 31) == 0) sm6[t >> 5] = m;
    __syncthreads();
    float mm = fmaxf(fmaxf(fmaxf(sm6[0], sm6[1]), fmaxf(sm6[2], sm6[3])), fmaxf(sm6[4], sm6[5]));
    float e0 = __expf(v0 - mm), e1 = __expf(v1 - mm), e2 = __expf(v2 - mm);
    float s = e0 + e1 + e2;
    #pragma unroll
    for (int o = 16; o > 0; o >>= 1) s += __shfl_xor_sync(0xffffffffu, s, o);
    if ((t & 31) == 0) ss[t >> 5] = s;
    __syncthreads();
    float tot = (ss[0] + ss[1]) + (ss[2] + ss[3]) + (ss[4] + ss[5]);
    float inv = 1.0f / tot;
    __nv_bfloat16 hi, lo;
    split2(e0 * inv, hi, lo); ph[t] = hi;       pl[t] = lo;
    split2(e1 * inv, hi, lo); ph[t + 192] = hi; pl[t + 192] = lo;
    split2(e2 * inv, hi, lo); ph[t + 384] = hi; pl[t + 384] = lo;
}

// ---------------- AV mma (TMA pipelined, 9 stages of K=64) ----------------
#define AV_PH   0
#define AV_PL   6144
#define AV_VH   12288
#define AV_VL   28672
#define AV_BUF  45056
#define AV_SMEM (2*AV_BUF + 2048)

__global__ __launch_bounds__(192) void av_mma(
    const __grid_constant__ CUtensorMap tmPh,
    const __grid_constant__ CUtensorMap tmPl,
    const __grid_constant__ CUtensorMap tmVh,
    const __grid_constant__ CUtensorMap tmVl)
{
    extern __shared__ char smem[];
    uint32_t sraw = smem_u32(smem);
    uint32_t fullb[2]  = {sraw, sraw + 8};
    uint32_t emptyb[2] = {sraw + 16, sraw + 24};
    uint32_t tiles = (sraw + 64 + 1023) & ~1023u;

    int bh = blockIdx.z;
    int b = bh >> 3, h = bh & 7;
    int rowBase = blockIdx.y * 48;
    int tid = threadIdx.x, lane = tid & 31, warp = tid >> 5;
    int wm = warp >> 1, wn = warp & 1;
    int nBase = wn * 64;

    if (tid == 0) {
        MBAR_INIT(fullb[0], 1);  MBAR_INIT(fullb[1], 1);
        MBAR_INIT(emptyb[0], 192); MBAR_INIT(emptyb[1], 192);
    }
    __syncthreads();

    float acc[8][4];
    #pragma unroll
    for (int j = 0; j < 8; j++)
        #pragma unroll
        for (int r = 0; r < 4; r++) acc[j][r] = 0.f;

    int phF[2] = {0, 0};
    int phE[2] = {1, 1};

    auto issue = [&](int s, int buf) {
        uint32_t base = tiles + buf * AV_BUF;
        MBAR_EXPECT_TX(fullb[buf], AV_BUF);
        int k0 = s * 64;
        int py = bh * QN + rowBase;
        int vy = bh * N_ + k0;
        TMA_LOAD_2D(base + AV_PH, &tmPh, k0, py, fullb[buf]);
        TMA_LOAD_2D(base + AV_PL, &tmPl, k0, py, fullb[buf]);
        TMA_LOAD_2D(base + AV_VH,        &tmVh, 0,  vy, fullb[buf]);
        TMA_LOAD_2D(base + AV_VH + 8192, &tmVh, 64, vy, fullb[buf]);
        TMA_LOAD_2D(base + AV_VL,        &tmVl, 0,  vy, fullb[buf]);
        TMA_LOAD_2D(base + AV_VL + 8192, &tmVl, 64, vy, fullb[buf]);
    };

    if (tid == 0) {
        MBAR_WAIT(emptyb[0], phE[0]); phE[0] ^= 1;
        issue(0, 0);
    }

    for (int s = 0; s < 9; s++) {
        int buf = s & 1;
        if (tid == 0 && s + 1 < 9) {
            int nb = buf ^ 1;
            MBAR_WAIT(emptyb[nb], phE[nb]); phE[nb] ^= 1;
            issue(s + 1, nb);
        }
        MBAR_WAIT(fullb[buf], phF[buf]); phF[buf] ^= 1;
        uint32_t base = tiles + buf * AV_BUF;

        #pragma unroll
        for (int kk = 0; kk < 64; kk += 16) {
            uint32_t ah[4], al[4];
            {
                int row = wm * 16 + (lane & 7) + ((lane >> 3) & 1) * 8;
                int ce  = kk + ((lane >> 4) << 3);
                uint32_t off = swz((uint32_t)(row * 128 + ce * 2));
                LDSM_X4(ah, base + AV_PH + off);
                LDSM_X4(al, base + AV_PL + off);
            }
            uint32_t bhf[4][4], blf[4][4];
            #pragma unroll
            for (int g = 0; g < 4; g++) {
                int vrow = kk + (lane & 15);
                int d    = nBase + g * 16 + ((lane >> 4) << 3);
                uint32_t off = (uint32_t)((d >> 6) * 8192) + swz((uint32_t)(vrow * 128 + (d & 63) * 2));
                LDSM_X4T(bhf[g], base + AV_VH + off);
                LDSM_X4T(blf[g], base + AV_VL + off);
            }
            #pragma unroll
            for (int nf = 0; nf < 8; nf++) {
                uint32_t b0 = bhf[nf >> 1][(nf & 1) * 2 + 0];
                uint32_t b1 = bhf[nf >> 1][(nf & 1) * 2 + 1];
                uint32_t c0 = blf[nf >> 1][(nf & 1) * 2 + 0];
                uint32_t c1 = blf[nf >> 1][(nf & 1) * 2 + 1];
                MMA_BF16(acc[nf], ah, b0, b1);
                MMA_BF16(acc[nf], ah, c0, c1);
                MMA_BF16(acc[nf], al, b0, b1);
            }
        }
        MBAR_ARRIVE(emptyb[buf]);
    }

    int gid = lane >> 2, tig = lane & 3;
    #pragma unroll
    for (int nf = 0; nf < 8; nf++) {
        int d = nBase + nf * 8 + tig * 2;
        #pragma unroll
        for (int rr = 0; rr < 2; rr++) {
            int i = rowBase + wm * 16 + gid + rr * 8;
            size_t off = ((size_t)b * QN + i) * C_ + h * HD + d;
            float2 qv = *(const float2*)(g_q + off);
            *(float2*)(g_o + off) = make_float2(acc[nf][rr * 2 + 0] + qv.x,
                                                acc[nf][rr * 2 + 1] + qv.y);
        }
    }
}

// ---------------- host: tensormap builder ----------------
typedef CUresult (*EncodeTiledFn)(CUtensorMap*, CUtensorMapDataType, cuuint32_t, void*,
                                  const cuuint64_t*, const cuuint64_t*, const cuuint32_t*,
                                  const cuuint32_t*, CUtensorMapInterleave, CUtensorMapSwizzle,
                                  CUtensorMapL2promotion, CUtensorMapFloatOOBfill);

static void make_map(EncodeTiledFn enc, CUtensorMap* m, void* ptr,
                     uint64_t dim0, uint64_t rows, uint32_t box0, uint32_t box1) {
    cuuint64_t dims[2]    = {(cuuint64_t)dim0, (cuuint64_t)rows};
    cuuint64_t strides[1] = {(cuuint64_t)dim0 * 2};
    cuuint32_t box[2]     = {box0, box1};
    cuuint32_t es[2]      = {1, 1};
    enc(m, CU_TENSOR_MAP_DATA_TYPE_BFLOAT16, 2, ptr, dims, strides, box, es,
        CU_TENSOR_MAP_INTERLEAVE_NONE, CU_TENSOR_MAP_SWIZZLE_128B,
        CU_TENSOR_MAP_L2_PROMOTION_L2_128B, CU_TENSOR_MAP_FLOAT_OOB_FILL_NONE);
}

// ---------------- launch ----------------
extern "C" void kernel_launch(void* const* d_in, const int* in_sizes, int n_in,
                              void* d_out, int out_size) {
    const float* x   = (const float*)d_in[0];
    const float* Wq  = (const float*)d_in[1];
    const float* Wk  = (const float*)d_in[2];
    const float* Wv  = (const float*)d_in[3];
    const float* Wp  = (const float*)d_in[4];
    const float* bp  = (const float*)d_in[5];
    const float* rph = (const float*)d_in[6];
    const float* rpw = (const float*)d_in[7];
    float* out = (float*)d_out;

    float *xp, *q, *o;
    __nv_bfloat16 *axh, *axl, *aqh, *aql, *aoh, *aol;
    __nv_bfloat16 *wqh, *wql, *wkh, *wkl, *wvh, *wvl, *wph, *wpl;
    __nv_bfloat16 *qh, *ql, *kh, *kl, *vh, *vl, *ph, *pl;
    cudaGetSymbolAddress((void**)&xp, g_xp);
    cudaGetSymbolAddress((void**)&q,  g_q);
    cudaGetSymbolAddress((void**)&o,  g_o);
    cudaGetSymbolAddress((void**)&axh, g_axh);
    cudaGetSymbolAddress((void**)&axl, g_axl);
    cudaGetSymbolAddress((void**)&aqh, g_aqh);
    cudaGetSymbolAddress((void**)&aql, g_aql);
    cudaGetSymbolAddress((void**)&aoh, g_aoh);
    cudaGetSymbolAddress((void**)&aol, g_aol);
    cudaGetSymbolAddress((void**)&wqh, g_wqh);
    cudaGetSymbolAddress((void**)&wql, g_wql);
    cudaGetSymbolAddress((void**)&wkh, g_wkh);
    cudaGetSymbolAddress((void**)&wkl, g_wkl);
    cudaGetSymbolAddress((void**)&wvh, g_wvh);
    cudaGetSymbolAddress((void**)&wvl, g_wvl);
    cudaGetSymbolAddress((void**)&wph, g_wph);
    cudaGetSymbolAddress((void**)&wpl, g_wpl);
    cudaGetSymbolAddress((void**)&qh, g_qh);
    cudaGetSymbolAddress((void**)&ql, g_ql);
    cudaGetSymbolAddress((void**)&kh, g_kh);
    cudaGetSymbolAddress((void**)&kl, g_kl);
    cudaGetSymbolAddress((void**)&vh, g_vh);
    cudaGetSymbolAddress((void**)&vl, g_vl);
    cudaGetSymbolAddress((void**)&ph, g_ph);
    cudaGetSymbolAddress((void**)&pl, g_pl);

    EncodeTiledFn enc = nullptr;
    {
        void* fn = nullptr;
        cudaDriverEntryPointQueryResult st;
        cudaGetDriverEntryPoint("cuTensorMapEncodeTiled", &fn, cudaEnableDefault, &st);
        enc = (EncodeTiledFn)fn;
    }
    CUtensorMap mAxh, mAxl, mAqh, mAql, mAoh, mAol;
    CUtensorMap mWqh, mWql, mWkh, mWkl, mWvh, mWvl, mWph, mWpl;
    CUtensorMap mQh, mQl, mKh, mKl, mVh, mVl, mPh, mPl;
    make_map(enc, &mAxh, axh, C_, (uint64_t)B_ * N_, 64, 128);
    make_map(enc, &mAxl, axl, C_, (uint64_t)B_ * N_, 64, 128);
    make_map(enc, &mAqh, aqh, C_, (uint64_t)B_ * QN, 64, 128);
    make_map(enc, &mAql, aql, C_, (uint64_t)B_ * QN, 64, 128);
    make_map(enc, &mAoh, aoh, C_, (uint64_t)B_ * QN, 64, 128);
    make_map(enc, &mAol, aol, C_, (uint64_t)B_ * QN, 64, 128);
    make_map(enc, &mWqh, wqh, C_, C_, 64, 128);
    make_map(enc, &mWql, wql, C_, C_, 64, 128);
    make_map(enc, &mWkh, wkh, C_, C_, 64, 128);
    make_map(enc, &mWkl, wkl, C_, C_, 64, 128);
    make_map(enc, &mWvh, wvh, C_, C_, 64, 128);
    make_map(enc, &mWvl, wvl, C_, C_, 64, 128);
    make_map(enc, &mWph, wph, C_, C_, 64, 128);
    make_map(enc, &mWpl, wpl, C_, C_, 64, 128);
    make_map(enc, &mQh, qh, HD, (uint64_t)BH * QN, 64, 48);
    make_map(enc, &mQl, ql, HD, (uint64_t)BH * QN, 64, 48);
    make_map(enc, &mKh, kh, HD, (uint64_t)BH * N_, 64, 96);
    make_map(enc, &mKl, kl, HD, (uint64_t)BH * N_, 64, 96);
    make_map(enc, &mVh, vh, HD, (uint64_t)BH * N_, 64, 64);
    make_map(enc, &mVl, vl, HD, (uint64_t)BH * N_, 64, 64);
    make_map(enc, &mPh, ph, N_, (uint64_t)BH * QN, 64, 48);
    make_map(enc, &mPl, pl, N_, (uint64_t)BH * QN, 64, 48);

    cudaFuncSetAttribute(gemm_tma, cudaFuncAttributeMaxDynamicSharedMemorySize, GT_SMEM);
    cudaFuncSetAttribute(qk_mma, cudaFuncAttributeMaxDynamicSharedMemorySize, QK_SMEM);
    cudaFuncSetAttribute(av_mma, cudaFuncAttributeMaxDynamicSharedMemorySize, AV_SMEM);

    split_wT_kernel<<<dim3(32, 32), dim3(32, 8)>>>(Wq, wqh, wql);
    split_wT_kernel<<<dim3(32, 32), dim3(32, 8)>>>(Wk, wkh, wkl);
    split_wT_kernel<<<dim3(32, 32), dim3(32, 8)>>>(Wv, wvh, wvl);
    split_wT_kernel<<<dim3(32, 32), dim3(32, 8)>>>(Wp, wph, wpl);

    split_x2_kernel<<<dim3(18, 32, B_), dim3(32, 8)>>>(x);
    pool_kernel<<<dim3(C_ / 16, B_), 256>>>(x);
    split_rows2_kernel<<<(B_ * QN * C_) / 256, 256>>>(xp, aqh, aql);

    gemm_tma<<<dim3(8, (B_ * N_) / 128), 512, GT_SMEM>>>(mAxh, mAxl, mWkh, mWkl, nullptr, nullptr, kh, kl, N_, 2);
    gemm_tma<<<dim3(8, (B_ * N_) / 128), 512, GT_SMEM>>>(mAxh, mAxl, mWvh, mWvl, nullptr, nullptr, vh, vl, N_, 2);
    gemm_tma<<<dim3(8, (B_ * QN) / 128), 512, GT_SMEM>>>(mAqh, mAql, mWqh, mWql, nullptr, q, qh, ql, QN, 3);

    relpos_kernel<<<BH * QN, 64>>>(rph, rpw);
    qk_mma<<<dim3(6, 3, BH), 192, QK_SMEM>>>(mQh, mQl, mKh, mKl);
    softmax_kernel<<<BH * QN, 192>>>();
    av_mma<<<dim3(1, 3, BH), 192, AV_SMEM>>>(mPh, mPl, mVh, mVl);

    split_rows2_kernel<<<(B_ * QN * C_) / 256, 256>>>(o, aoh, aol);
    gemm_tma<<<dim3(8, (B_ * QN) / 128), 512, GT_SMEM>>>(mAoh, mAol, mWph, mWpl, bp, out, nullptr, nullptr, QN, 1);
}

// round 10
// speedup vs baseline: 2.5545x; 1.0212x over previous
#include <cuda.h>
#include <cuda_runtime.h>
#include <cuda_bf16.h>
#include <math.h>
#include <stdint.h>

#define B_  128
#define C_  1024
#define H_  24
#define W_  24
#define N_  576
#define NH  8
#define HD  128
#define QH  12
#define QW  12
#define QN  144
#define BH  (B_*NH)

// ---------------- fp32 scratch ----------------
__device__ float g_xp  [(size_t)B_*QN*C_];
__device__ float g_q   [(size_t)B_*QN*C_];
__device__ float g_relh[(size_t)BH*QN*H_];
__device__ float g_relw[(size_t)BH*QN*W_];
// bf16 hi/lo A operands
__device__ __nv_bfloat16 g_axh[(size_t)B_*N_*C_];
__device__ __nv_bfloat16 g_axl[(size_t)B_*N_*C_];
__device__ __nv_bfloat16 g_aqh[(size_t)B_*QN*C_];
__device__ __nv_bfloat16 g_aql[(size_t)B_*QN*C_];
__device__ __nv_bfloat16 g_aoh[(size_t)B_*QN*C_];
__device__ __nv_bfloat16 g_aol[(size_t)B_*QN*C_];
// TRANSPOSED weights [N,K] hi/lo
__device__ __nv_bfloat16 g_wqh[(size_t)C_*C_];
__device__ __nv_bfloat16 g_wql[(size_t)C_*C_];
__device__ __nv_bfloat16 g_wkh[(size_t)C_*C_];
__device__ __nv_bfloat16 g_wkl[(size_t)C_*C_];
__device__ __nv_bfloat16 g_wvh[(size_t)C_*C_];
__device__ __nv_bfloat16 g_wvl[(size_t)C_*C_];
__device__ __nv_bfloat16 g_wph[(size_t)C_*C_];
__device__ __nv_bfloat16 g_wpl[(size_t)C_*C_];
// head-major bf16 hi/lo tensors
__device__ __nv_bfloat16 g_qh[(size_t)BH*QN*HD];
__device__ __nv_bfloat16 g_ql[(size_t)BH*QN*HD];
__device__ __nv_bfloat16 g_kh[(size_t)BH*N_*HD];
__device__ __nv_bfloat16 g_kl[(size_t)BH*N_*HD];
__device__ __nv_bfloat16 g_vh[(size_t)BH*N_*HD];
__device__ __nv_bfloat16 g_vl[(size_t)BH*N_*HD];
__device__ __nv_bfloat16 g_ph[(size_t)BH*QN*N_];
__device__ __nv_bfloat16 g_pl[(size_t)BH*QN*N_];

// ---------------- helpers ----------------
__device__ __forceinline__ void split2(float v, __nv_bfloat16& hi, __nv_bfloat16& lo) {
    hi = __float2bfloat16(v);
    lo = __float2bfloat16(v - __bfloat162float(hi));
}
__device__ __forceinline__ uint32_t smem_u32(const void* p) {
    return (uint32_t)__cvta_generic_to_shared(p);
}
__device__ __forceinline__ uint32_t swz(uint32_t o) {      // SW128, 128B rows
    return o ^ ((o >> 3) & 0x70);
}

#define MMA_BF16(ACC, A, B0, B1)                                              \
    asm volatile(                                                             \
        "mma.sync.aligned.m16n8k16.row.col.f32.bf16.bf16.f32 "                \
        "{%0,%1,%2,%3}, {%4,%5,%6,%7}, {%8,%9}, {%0,%1,%2,%3};"               \
        : "+f"((ACC)[0]), "+f"((ACC)[1]), "+f"((ACC)[2]), "+f"((ACC)[3])      \
        : "r"((A)[0]), "r"((A)[1]), "r"((A)[2]), "r"((A)[3]),                 \
          "r"(B0), "r"(B1))

#define LDSM_X4(R, ADDR)                                                      \
    asm volatile("ldmatrix.sync.aligned.m8n8.x4.shared.b16 {%0,%1,%2,%3}, [%4];" \
                 : "=r"((R)[0]), "=r"((R)[1]), "=r"((R)[2]), "=r"((R)[3]) : "r"(ADDR))
#define LDSM_X4T(R, ADDR)                                                     \
    asm volatile("ldmatrix.sync.aligned.m8n8.x4.trans.shared.b16 {%0,%1,%2,%3}, [%4];" \
                 : "=r"((R)[0]), "=r"((R)[1]), "=r"((R)[2]), "=r"((R)[3]) : "r"(ADDR))

#define MBAR_INIT(mb, cnt) \
    asm volatile("mbarrier.init.shared.b64 [%0], %1;" :: "r"(mb), "r"((uint32_t)(cnt)) : "memory")
#define MBAR_EXPECT_TX(mb, bytes) \
    asm volatile("mbarrier.arrive.expect_tx.shared.b64 _, [%0], %1;" :: "r"(mb), "r"((uint32_t)(bytes)) : "memory")
#define MBAR_ARRIVE(mb) \
    asm volatile("mbarrier.arrive.shared.b64 _, [%0];" :: "r"(mb) : "memory")
#define MBAR_WAIT(mb, ph) do {                                                    \
    asm volatile("{\n\t.reg .pred P1;\n\t"                                        \
        "WAIT_LOOP_%=:\n\t"                                                       \
        "mbarrier.try_wait.parity.acquire.cta.shared::cta.b64 P1, [%0], %1, 0x989680;\n\t" \
        "@P1 bra.uni WAIT_DONE_%=;\n\t"                                           \
        "bra.uni WAIT_LOOP_%=;\n\t"                                               \
        "WAIT_DONE_%=:\n\t}"                                                      \
        :: "r"(mb), "r"((uint32_t)(ph)) : "memory");                              \
} while(0)

#define TMA_LOAD_2D(sa, map, cx, cy, mb)                                          \
    asm volatile("cp.async.bulk.tensor.2d.shared::cta.global.tile.mbarrier::complete_tx::bytes " \
        "[%0], [%1, {%2, %3}], [%4];"                                             \
        :: "r"(sa), "l"(map), "r"((int32_t)(cx)), "r"((int32_t)(cy)), "r"(mb) : "memory")

// ---------------- conversions ----------------
__global__ __launch_bounds__(256) void split_wT_kernel(const float* __restrict__ W,
                                                       __nv_bfloat16* __restrict__ WhT,
                                                       __nv_bfloat16* __restrict__ WlT) {
    __shared__ float t[32][33];
    int k0 = blockIdx.x * 32, n0 = blockIdx.y * 32;
    int tx = threadIdx.x, ty = threadIdx.y;
    #pragma unroll
    for (int i = 0; i < 4; i++)
        t[ty + i * 8][tx] = W[(size_t)(k0 + ty + i * 8) * C_ + n0 + tx];
    __syncthreads();
    #pragma unroll
    for (int i = 0; i < 4; i++) {
        __nv_bfloat16 hi, lo; split2(t[tx][ty + i * 8], hi, lo);
        size_t idx = (size_t)(n0 + ty + i * 8) * C_ + k0 + tx;
        WhT[idx] = hi; WlT[idx] = lo;
    }
}

__global__ __launch_bounds__(256) void split_x2_kernel(const float* __restrict__ x) {
    __shared__ float tile[32][33];
    int b  = blockIdx.z;
    int n0 = blockIdx.x * 32;
    int c0 = blockIdx.y * 32;
    int tx = threadIdx.x, ty = threadIdx.y;
    const float* xb = x + (size_t)b * C_ * N_;
    #pragma unroll
    for (int i = 0; i < 4; i++)
        tile[ty + i * 8][tx] = xb[(size_t)(c0 + ty + i * 8) * N_ + n0 + tx];
    __syncthreads();
    #pragma unroll
    for (int i = 0; i < 4; i++) {
        int n = n0 + ty + i * 8;
        __nv_bfloat16 hi, lo; split2(tile[tx][ty + i * 8], hi, lo);
        size_t base = ((size_t)b * N_ + n) * C_ + c0 + tx;
        g_axh[base] = hi; g_axl[base] = lo;
    }
}

__global__ __launch_bounds__(256) void split_rows2_kernel(const float* __restrict__ in,
                                                          __nv_bfloat16* __restrict__ oh,
                                                          __nv_bfloat16* __restrict__ ol) {
    int i = blockIdx.x * 256 + threadIdx.x;
    __nv_bfloat16 hi, lo; split2(in[i], hi, lo);
    oh[i] = hi; ol[i] = lo;
}

// ---------------- avg-pool 3x3 s2 pad1 ----------------
__global__ __launch_bounds__(256) void pool_kernel(const float* __restrict__ x) {
    __shared__ float sp[16][577];
    int b  = blockIdx.y;
    int c0 = blockIdx.x * 16;
    int tid = threadIdx.x;
    const float* xb = x + (size_t)b * C_ * N_ + (size_t)c0 * N_;
    #pragma unroll
    for (int r = 0; r < 36; r++) {
        int idx = tid + r * 256;
        int p = idx / 576, n = idx - p * 576;
        sp[p][n] = xb[(size_t)p * N_ + n];
    }
    __syncthreads();
    #pragma unroll
    for (int r = 0; r < 9; r++) {
        int idx = tid + r * 256;
        int qn = idx >> 4, cl = idx & 15;
        int qy = qn / 12, qx = qn - qy * 12;
        float s = 0.f;
        #pragma unroll
        for (int dy = -1; dy <= 1; dy++) {
            int y = 2 * qy + dy;
            if ((unsigned)y < 24u) {
                #pragma unroll
                for (int dx = -1; dx <= 1; dx++) {
                    int xx = 2 * qx + dx;
                    if ((unsigned)xx < 24u) s += sp[cl][y * 24 + xx];
                }
            }
        }
        g_xp[((size_t)b * QN + qn) * C_ + c0 + cl] = s * (1.0f / 9.0f);
    }
}

// ---------------- TMA + mma.sync projection GEMM (from R8, unchanged core) ----------------
#define GT_TILE  16384
#define GT_BUF   (4*GT_TILE)
#define GT_SMEM  (3*GT_BUF + 1024)
#define NSTAGE   16

__global__ __launch_bounds__(512) void gemm_tma(
    const __grid_constant__ CUtensorMap tmAh,
    const __grid_constant__ CUtensorMap tmAl,
    const __grid_constant__ CUtensorMap tmBh,
    const __grid_constant__ CUtensorMap tmBl,
    const float* __restrict__ bias,
    float* __restrict__ Cm,
    __nv_bfloat16* __restrict__ Dh,
    __nv_bfloat16* __restrict__ Dl,
    int rpb, int mode)
{
    extern __shared__ char smem[];
    uint32_t sraw = smem_u32(smem);
    uint32_t fullb[3]  = {sraw, sraw + 8, sraw + 16};
    uint32_t emptyb[3] = {sraw + 24, sraw + 32, sraw + 40};
    uint32_t tiles = (sraw + 64 + 1023) & ~1023u;

    int tid = threadIdx.x, lane = tid & 31, warp = tid >> 5;
    int wm = warp >> 2, wn = warp & 3;
    int rowBase = blockIdx.y * 128;
    int colBase = blockIdx.x * 128;

    if (tid == 0) {
        MBAR_INIT(fullb[0], 1);  MBAR_INIT(fullb[1], 1);  MBAR_INIT(fullb[2], 1);
        MBAR_INIT(emptyb[0], 512); MBAR_INIT(emptyb[1], 512); MBAR_INIT(emptyb[2], 512);
    }
    __syncthreads();

    float acc[2][4][4];
    #pragma unroll
    for (int i = 0; i < 2; i++)
        #pragma unroll
        for (int j = 0; j < 4; j++)
            #pragma unroll
            for (int r = 0; r < 4; r++) acc[i][j][r] = 0.f;

    int phF[3] = {0, 0, 0};
    int phE[3] = {0, 0, 0};

    auto issue = [&](int s, int slot) {
        uint32_t base = tiles + slot * GT_BUF;
        MBAR_EXPECT_TX(fullb[slot], GT_BUF);
        int k0 = s * 64;
        TMA_LOAD_2D(base,               &tmAh, k0, rowBase, fullb[slot]);
        TMA_LOAD_2D(base + GT_TILE,     &tmAl, k0, rowBase, fullb[slot]);
        TMA_LOAD_2D(base + 2 * GT_TILE, &tmBh, k0, colBase, fullb[slot]);
        TMA_LOAD_2D(base + 3 * GT_TILE, &tmBl, k0, colBase, fullb[slot]);
    };

    if (tid == 0) { issue(0, 0); issue(1, 1); issue(2, 2); }

    uint32_t ah[2][2][4], al[2][2][4], bhf[2][2][4], blf[2][2][4];

    int arow0 = wm * 32 + (lane & 7) + ((lane >> 3) & 1) * 8;
    int acol8 = (lane >> 4) << 3;
    int brow0 = wn * 32 + (lane & 7) + ((lane >> 4) & 1) * 8;
    int bcol8 = (lane >> 3) & 1 ? 8 : 0;

    for (int s = 0; s < NSTAGE; s++) {
        int slot = s % 3;
        MBAR_WAIT(fullb[slot], phF[slot]); phF[slot] ^= 1;

        uint32_t aH = tiles + slot * GT_BUF;
        uint32_t aL = aH + GT_TILE;
        uint32_t bH = aH + 2 * GT_TILE;
        uint32_t bL = aH + 3 * GT_TILE;

        {
            #pragma unroll
            for (int mf = 0; mf < 2; mf++) {
                uint32_t off = swz((uint32_t)((arow0 + mf * 16) * 128 + acol8 * 2));
                LDSM_X4(ah[0][mf], aH + off);
                LDSM_X4(al[0][mf], aL + off);
            }
            #pragma unroll
            for (int g = 0; g < 2; g++) {
                uint32_t off = swz((uint32_t)((brow0 + g * 16) * 128 + bcol8 * 2));
                LDSM_X4(bhf[0][g], bH + off);
                LDSM_X4(blf[0][g], bL + off);
            }
        }

        #pragma unroll
        for (int kki = 0; kki < 4; kki++) {
            int pb = kki & 1;
            if (kki < 3) {
                int nb = pb ^ 1;
                int kk = (kki + 1) * 16;
                #pragma unroll
                for (int mf = 0; mf < 2; mf++) {
                    uint32_t off = swz((uint32_t)((arow0 + mf * 16) * 128 + (kk + acol8) * 2));
                    LDSM_X4(ah[nb][mf], aH + off);
                    LDSM_X4(al[nb][mf], aL + off);
                }
                #pragma unroll
                for (int g = 0; g < 2; g++) {
                    uint32_t off = swz((uint32_t)((brow0 + g * 16) * 128 + (kk + bcol8) * 2));
                    LDSM_X4(bhf[nb][g], bH + off);
                    LDSM_X4(blf[nb][g], bL + off);
                }
            }
            #pragma unroll
            for (int mf = 0; mf < 2; mf++)
                #pragma unroll
                for (int nf = 0; nf < 4; nf++) {
                    uint32_t b0 = bhf[pb][nf >> 1][(nf & 1) * 2 + 0];
                    uint32_t b1 = bhf[pb][nf >> 1][(nf & 1) * 2 + 1];
                    uint32_t c0 = blf[pb][nf >> 1][(nf & 1) * 2 + 0];
                    uint32_t c1 = blf[pb][nf >> 1][(nf & 1) * 2 + 1];
                    MMA_BF16(acc[mf][nf], ah[pb][mf], b0, b1);
                    MMA_BF16(acc[mf][nf], ah[pb][mf], c0, c1);
                    MMA_BF16(acc[mf][nf], al[pb][mf], b0, b1);
                }
        }
        MBAR_ARRIVE(emptyb[slot]);
        if (tid == 0 && s + 3 < NSTAGE) {
            MBAR_WAIT(emptyb[slot], phE[slot]); phE[slot] ^= 1;
            issue(s + 3, slot);
        }
    }

    int gid = lane >> 2, tig = lane & 3;
    #pragma unroll
    for (int mf = 0; mf < 2; mf++)
        #pragma unroll
        for (int nf = 0; nf < 4; nf++) {
            int c0 = colBase + wn * 32 + nf * 8 + tig * 2;
            #pragma unroll
            for (int rr = 0; rr < 2; rr++) {
                int row = rowBase + wm * 32 + mf * 16 + gid + rr * 8;
                float v0 = acc[mf][nf][rr * 2 + 0];
                float v1 = acc[mf][nf][rr * 2 + 1];
                if (mode == 1) {
                    int bq = row / QN, qi = row - bq * QN;
                    Cm[((size_t)bq * C_ + c0) * QN + qi]     = v0 + bias[c0];
                    Cm[((size_t)bq * C_ + c0 + 1) * QN + qi] = v1 + bias[c0 + 1];
                } else {
                    int b = row / rpb, n = row - b * rpb;
                    int h = c0 >> 7, d = c0 & 127;
                    size_t di = (((size_t)b * NH + h) * rpb + n) * HD + d;
                    __nv_bfloat162 th, tl;
                    split2(v0, th.x, tl.x);
                    split2(v1, th.y, tl.y);
                    *(__nv_bfloat162*)(Dh + di) = th;
                    *(__nv_bfloat162*)(Dl + di) = tl;
                    if (mode == 3)
                        *(float2*)&Cm[(size_t)row * C_ + c0] = make_float2(v0, v1);
                }
            }
        }
}

// ---------------- relative position bias dots ----------------
__global__ __launch_bounds__(64) void relpos_kernel(const float* __restrict__ rel_h,
                                                    const float* __restrict__ rel_w) {
    int gid = blockIdx.x;
    int bh = gid / QN, i = gid - bh * QN;
    int b = bh >> 3, h = bh & 7;
    int qy = i / 12, qx = i - qy * 12;
    int t = threadIdx.x;
    const float* qrow = g_q + ((size_t)b * QN + i) * C_ + h * HD;
    if (t < 24) {
        const float* R = rel_h + (size_t)(2 * qy - t + 23) * HD;
        float a0 = 0, a1 = 0, a2 = 0, a3 = 0;
        #pragma unroll
        for (int d = 0; d < HD; d += 4) {
            a0 += qrow[d + 0] * R[d + 0];
            a1 += qrow[d + 1] * R[d + 1];
            a2 += qrow[d + 2] * R[d + 2];
            a3 += qrow[d + 3] * R[d + 3];
        }
        g_relh[(size_t)gid * 24 + t] = (a0 + a1) + (a2 + a3);
    } else if (t >= 32 && t < 56) {
        int kx = t - 32;
        const float* R = rel_w + (size_t)(2 * qx - kx + 23) * HD;
        float a0 = 0, a1 = 0, a2 = 0, a3 = 0;
        #pragma unroll
        for (int d = 0; d < HD; d += 4) {
            a0 += qrow[d + 0] * R[d + 0];
            a1 += qrow[d + 1] * R[d + 1];
            a2 += qrow[d + 2] * R[d + 2];
            a3 += qrow[d + 3] * R[d + 3];
        }
        g_relw[(size_t)gid * 24 + kx] = (a0 + a1) + (a2 + a3);
    }
}

// ---------------- FUSED QK^T + bias + softmax + P-split ----------------
// One CTA: 48 q-rows x ALL 576 keys for one bh. 576 thr / 18 warps (3m x 6n).
// Q resident (48x128 hi/lo); K staged in 6 chunks of 96 keys, double-buffered TMA.
// Warp (wm,wn): rows wm*16..+15; per chunk c, cols c*96 + wn*16..+15.
#define QKF_QH   0
#define QKF_QL   12288
#define QKF_K0   24576
#define QKF_KBUF 49152                 // KH 24576 + KL 24576
#define QKF_REL  (24576 + 2*49152)     // 122880: relh 4608, relw 4608
#define QKF_RED  (QKF_REL + 9216)      // smax 1152, ssum 1152
#define QKF_SMEM (QKF_RED + 2304 + 1088)

__global__ __launch_bounds__(576) void qk_fused(
    const __grid_constant__ CUtensorMap tmQh,
    const __grid_constant__ CUtensorMap tmQl,
    const __grid_constant__ CUtensorMap tmKh,
    const __grid_constant__ CUtensorMap tmKl)
{
    extern __shared__ char smem[];
    uint32_t sraw = smem_u32(smem);
    uint32_t fullb[2]  = {sraw, sraw + 8};
    uint32_t emptyb[2] = {sraw + 16, sraw + 24};
    uint32_t tiles = (sraw + 64 + 1023) & ~1023u;
    char* tilesp = smem + (tiles - sraw);
    float* srelh = (float*)(tilesp + QKF_REL);
    float* srelw = srelh + 48 * 24;
    float* smax  = (float*)(tilesp + QKF_RED);      // [48][6]
    float* ssum  = smax + 48 * 6;

    int bh = blockIdx.z;
    int rowBase = blockIdx.y * 48;
    int tid = threadIdx.x, lane = tid & 31, warp = tid >> 5;
    int wm = warp / 6, wn = warp % 6;
    int gid = lane >> 2, tig = lane & 3;

    if (tid == 0) {
        MBAR_INIT(fullb[0], 1);  MBAR_INIT(fullb[1], 1);
        MBAR_INIT(emptyb[0], 576); MBAR_INIT(emptyb[1], 576);
    }
    __syncthreads();

    // rel bias to smem
    for (int idx = tid; idx < 48 * 24; idx += 576) {
        size_t gidx = ((size_t)bh * QN + rowBase + idx / 24) * 24 + (idx % 24);
        srelh[idx] = g_relh[gidx];
        srelw[idx] = g_relw[gidx];
    }

    int phF[2] = {0, 0}, phE[2] = {0, 0};
    auto issue = [&](int c, int buf) {
        uint32_t kb = tiles + QKF_K0 + buf * QKF_KBUF;
        MBAR_EXPECT_TX(fullb[buf], (c == 0) ? (24576u + QKF_KBUF) : (uint32_t)QKF_KBUF);
        int ky0 = bh * N_ + c * 96;
        if (c == 0) {
            int qy = bh * QN + rowBase;
            TMA_LOAD_2D(tiles + QKF_QH,        &tmQh, 0,  qy, fullb[0]);
            TMA_LOAD_2D(tiles + QKF_QH + 6144, &tmQh, 64, qy, fullb[0]);
            TMA_LOAD_2D(tiles + QKF_QL,        &tmQl, 0,  qy, fullb[0]);
            TMA_LOAD_2D(tiles + QKF_QL + 6144, &tmQl, 64, qy, fullb[0]);
        }
        TMA_LOAD_2D(kb,                 &tmKh, 0,  ky0, fullb[buf]);
        TMA_LOAD_2D(kb + 12288,         &tmKh, 64, ky0, fullb[buf]);
        TMA_LOAD_2D(kb + 24576,         &tmKl, 0,  ky0, fullb[buf]);
        TMA_LOAD_2D(kb + 24576 + 12288, &tmKl, 64, ky0, fullb[buf]);
    };
    if (tid == 0) { issue(0, 0); issue(1, 1); }

    float acc[12][4];
    #pragma unroll
    for (int j = 0; j < 12; j++)
        #pragma unroll
        for (int r = 0; r < 4; r++) acc[j][r] = 0.f;

    int arow = wm * 16 + (lane & 7) + ((lane >> 3) & 1) * 8;
    int acol8 = (lane >> 4) << 3;
    int brow = wn * 16 + (lane & 7) + ((lane >> 4) & 1) * 8;
    int bcol8 = ((lane >> 3) & 1) * 8;

    for (int c = 0; c < 6; c++) {
        int buf = c & 1;
        MBAR_WAIT(fullb[buf], phF[buf]); phF[buf] ^= 1;
        uint32_t kB = tiles + QKF_K0 + buf * QKF_KBUF;

        #pragma unroll
        for (int kk = 0; kk < 128; kk += 16) {
            uint32_t a_h[4], a_l[4];
            {
                int ce = kk + acol8;
                uint32_t off = (uint32_t)((ce >> 6) * 6144) + swz((uint32_t)(arow * 128 + (ce & 63) * 2));
                LDSM_X4(a_h, tiles + QKF_QH + off);
                LDSM_X4(a_l, tiles + QKF_QL + off);
            }
            uint32_t b_h[4], b_l[4];
            {
                int kc = kk + bcol8;
                uint32_t off = (uint32_t)((kc >> 6) * 12288) + swz((uint32_t)(brow * 128 + (kc & 63) * 2));
                LDSM_X4(b_h, kB + off);
                LDSM_X4(b_l, kB + 24576 + off);
            }
            #pragma unroll
            for (int j = 0; j < 2; j++) {
                float* A = acc[c * 2 + j];
                MMA_BF16(A, a_h, b_h[j * 2], b_h[j * 2 + 1]);
                MMA_BF16(A, a_h, b_l[j * 2], b_l[j * 2 + 1]);
                MMA_BF16(A, a_l, b_h[j * 2], b_h[j * 2 + 1]);
            }
        }
        MBAR_ARRIVE(emptyb[buf]);
        if (tid == 0 && c + 2 < 6) {
            MBAR_WAIT(emptyb[buf], phE[buf]); phE[buf] ^= 1;
            issue(c + 2, buf);
        }
    }
    __syncthreads();   // srel visible; reduction arrays ready

    // bias + scale, row max
    const float scale = 0.08838834764831845f;
    int il0 = wm * 16 + gid;          // local row (rr=0), +8 for rr=1
    float mrow[2] = {-1e30f, -1e30f};
    #pragma unroll
    for (int nf = 0; nf < 12; nf++) {
        int colb = (nf >> 1) * 96 + wn * 16 + (nf & 1) * 8 + tig * 2;
        #pragma unroll
        for (int rr = 0; rr < 2; rr++) {
            int il = il0 + rr * 8;
            #pragma unroll
            for (int cc = 0; cc < 2; cc++) {
                int col = colb + cc;
                int ky = col / 24, kx = col - ky * 24;
                float v = acc[nf][rr * 2 + cc] * scale + srelh[il * 24 + ky] + srelw[il * 24 + kx];
                acc[nf][rr * 2 + cc] = v;
                mrow[rr] = fmaxf(mrow[rr], v);
            }
        }
    }
    #pragma unroll
    for (int o = 1; o <= 2; o <<= 1) {
        mrow[0] = fmaxf(mrow[0], __shfl_xor_sync(0xffffffffu, mrow[0], o));
        mrow[1] = fmaxf(mrow[1], __shfl_xor_sync(0xffffffffu, mrow[1], o));
    }
    if (tig == 0) {
        smax[(il0) * 6 + wn] = mrow[0];
        smax[(il0 + 8) * 6 + wn] = mrow[1];
    }
    __syncthreads();
    float M[2];
    #pragma unroll
    for (int rr = 0; rr < 2; rr++) {
        const float* r = smax + (il0 + rr * 8) * 6;
        M[rr] = fmaxf(fmaxf(fmaxf(r[0], r[1]), fmaxf(r[2], r[3])), fmaxf(r[4], r[5]));
    }
    float srow[2] = {0.f, 0.f};
    #pragma unroll
    for (int nf = 0; nf < 12; nf++)
        #pragma unroll
        for (int rr = 0; rr < 2; rr++)
            #pragma unroll
            for (int cc = 0; cc < 2; cc++) {
                float e = __expf(acc[nf][rr * 2 + cc] - M[rr]);
                acc[nf][rr * 2 + cc] = e;
                srow[rr] += e;
            }
    #pragma unroll
    for (int o = 1; o <= 2; o <<= 1) {
        srow[0] += __shfl_xor_sync(0xffffffffu, srow[0], o);
        srow[1] += __shfl_xor_sync(0xffffffffu, srow[1], o);
    }
    if (tig == 0) {
        ssum[(il0) * 6 + wn] = srow[0];
        ssum[(il0 + 8) * 6 + wn] = srow[1];
    }
    __syncthreads();
    float inv[2];
    #pragma unroll
    for (int rr = 0; rr < 2; rr++) {
        const float* r = ssum + (il0 + rr * 8) * 6;
        inv[rr] = 1.0f / ((r[0] + r[1]) + (r[2] + r[3]) + (r[4] + r[5]));
    }
    // write P hi/lo
    #pragma unroll
    for (int nf = 0; nf < 12; nf++) {
        int colb = (nf >> 1) * 96 + wn * 16 + (nf & 1) * 8 + tig * 2;
        #pragma unroll
        for (int rr = 0; rr < 2; rr++) {
            size_t off = ((size_t)bh * QN + rowBase + il0 + rr * 8) * N_ + colb;
            __nv_bfloat162 th, tl;
            split2(acc[nf][rr * 2 + 0] * inv[rr], th.x, tl.x);
            split2(acc[nf][rr * 2 + 1] * inv[rr], th.y, tl.y);
            *(__nv_bfloat162*)(g_ph + off) = th;
            *(__nv_bfloat162*)(g_pl + off) = tl;
        }
    }
}

// ---------------- AV mma (TMA pipelined); epilogue writes aoh/aol split ----------------
#define AV_PH   0
#define AV_PL   6144
#define AV_VH   12288
#define AV_VL   28672
#define AV_BUF  45056
#define AV_SMEM (2*AV_BUF + 2048)

__global__ __launch_bounds__(192) void av_mma(
    const __grid_constant__ CUtensorMap tmPh,
    const __grid_constant__ CUtensorMap tmPl,
    const __grid_constant__ CUtensorMap tmVh,
    const __grid_constant__ CUtensorMap tmVl)
{
    extern __shared__ char smem[];
    uint32_t sraw = smem_u32(smem);
    uint32_t fullb[2]  = {sraw, sraw + 8};
    uint32_t emptyb[2] = {sraw + 16, sraw + 24};
    uint32_t tiles = (sraw + 64 + 1023) & ~1023u;

    int bh = blockIdx.z;
    int b = bh >> 3, h = bh & 7;
    int rowBase = blockIdx.y * 48;
    int tid = threadIdx.x, lane = tid & 31, warp = tid >> 5;
    int wm = warp >> 1, wn = warp & 1;
    int nBase = wn * 64;

    if (tid == 0) {
        MBAR_INIT(fullb[0], 1);  MBAR_INIT(fullb[1], 1);
        MBAR_INIT(emptyb[0], 192); MBAR_INIT(emptyb[1], 192);
    }
    __syncthreads();

    float acc[8][4];
    #pragma unroll
    for (int j = 0; j < 8; j++)
        #pragma unroll
        for (int r = 0; r < 4; r++) acc[j][r] = 0.f;

    int phF[2] = {0, 0};
    int phE[2] = {1, 1};

    auto issue = [&](int s, int buf) {
        uint32_t base = tiles + buf * AV_BUF;
        MBAR_EXPECT_TX(fullb[buf], AV_BUF);
        int k0 = s * 64;
        int py = bh * QN + rowBase;
        int vy = bh * N_ + k0;
        TMA_LOAD_2D(base + AV_PH, &tmPh, k0, py, fullb[buf]);
        TMA_LOAD_2D(base + AV_PL, &tmPl, k0, py, fullb[buf]);
        TMA_LOAD_2D(base + AV_VH,        &tmVh, 0,  vy, fullb[buf]);
        TMA_LOAD_2D(base + AV_VH + 8192, &tmVh, 64, vy, fullb[buf]);
        TMA_LOAD_2D(base + AV_VL,        &tmVl, 0,  vy, fullb[buf]);
        TMA_LOAD_2D(base + AV_VL + 8192, &tmVl, 64, vy, fullb[buf]);
    };

    if (tid == 0) {
        MBAR_WAIT(emptyb[0], phE[0]); phE[0] ^= 1;
        issue(0, 0);
    }

    for (int s = 0; s < 9; s++) {
        int buf = s & 1;
        if (tid == 0 && s + 1 < 9) {
            int nb = buf ^ 1;
            MBAR_WAIT(emptyb[nb], phE[nb]); phE[nb] ^= 1;
            issue(s + 1, nb);
        }
        MBAR_WAIT(fullb[buf], phF[buf]); phF[buf] ^= 1;
        uint32_t base = tiles + buf * AV_BUF;

        #pragma unroll
        for (int kk = 0; kk < 64; kk += 16) {
            uint32_t ah[4], al[4];
            {
                int row = wm * 16 + (lane & 7) + ((lane >> 3) & 1) * 8;
                int ce  = kk + ((lane >> 4) << 3);
                uint32_t off = swz((uint32_t)(row * 128 + ce * 2));
                LDSM_X4(ah, base + AV_PH + off);
                LDSM_X4(al, base + AV_PL + off);
            }
            uint32_t bhf[4][4], blf[4][4];
            #pragma unroll
            for (int g = 0; g < 4; g++) {
                int vrow = kk + (lane & 15);
                int d    = nBase + g * 16 + ((lane >> 4) << 3);
                uint32_t off = (uint32_t)((d >> 6) * 8192) + swz((uint32_t)(vrow * 128 + (d & 63) * 2));
                LDSM_X4T(bhf[g], base + AV_VH + off);
                LDSM_X4T(blf[g], base + AV_VL + off);
            }
            #pragma unroll
            for (int nf = 0; nf < 8; nf++) {
                uint32_t b0 = bhf[nf >> 1][(nf & 1) * 2 + 0];
                uint32_t b1 = bhf[nf >> 1][(nf & 1) * 2 + 1];
                uint32_t c0 = blf[nf >> 1][(nf & 1) * 2 + 0];
                uint32_t c1 = blf[nf >> 1][(nf & 1) * 2 + 1];
                MMA_BF16(acc[nf], ah, b0, b1);
                MMA_BF16(acc[nf], ah, c0, c1);
                MMA_BF16(acc[nf], al, b0, b1);
            }
        }
        MBAR_ARRIVE(emptyb[buf]);
    }

    int gid = lane >> 2, tig = lane & 3;
    #pragma unroll
    for (int nf = 0; nf < 8; nf++) {
        int d = nBase + nf * 8 + tig * 2;
        #pragma unroll
        for (int rr = 0; rr < 2; rr++) {
            int i = rowBase + wm * 16 + gid + rr * 8;
            size_t off = ((size_t)b * QN + i) * C_ + h * HD + d;
            float2 qv = *(const float2*)(g_q + off);
            float v0 = acc[nf][rr * 2 + 0] + qv.x;
            float v1 = acc[nf][rr * 2 + 1] + qv.y;
            __nv_bfloat162 th, tl;
            split2(v0, th.x, tl.x);
            split2(v1, th.y, tl.y);
            *(__nv_bfloat162*)(g_aoh + off) = th;
            *(__nv_bfloat162*)(g_aol + off) = tl;
        }
    }
}

// ---------------- host: tensormap builder ----------------
typedef CUresult (*EncodeTiledFn)(CUtensorMap*, CUtensorMapDataType, cuuint32_t, void*,
                                  const cuuint64_t*, const cuuint64_t*, const cuuint32_t*,
                                  const cuuint32_t*, CUtensorMapInterleave, CUtensorMapSwizzle,
                                  CUtensorMapL2promotion, CUtensorMapFloatOOBfill);

static void make_map(EncodeTiledFn enc, CUtensorMap* m, void* ptr,
                     uint64_t dim0, uint64_t rows, uint32_t box0, uint32_t box1) {
    cuuint64_t dims[2]    = {(cuuint64_t)dim0, (cuuint64_t)rows};
    cuuint64_t strides[1] = {(cuuint64_t)dim0 * 2};
    cuuint32_t box[2]     = {box0, box1};
    cuuint32_t es[2]      = {1, 1};
    enc(m, CU_TENSOR_MAP_DATA_TYPE_BFLOAT16, 2, ptr, dims, strides, box, es,
        CU_TENSOR_MAP_INTERLEAVE_NONE, CU_TENSOR_MAP_SWIZZLE_128B,
        CU_TENSOR_MAP_L2_PROMOTION_L2_128B, CU_TENSOR_MAP_FLOAT_OOB_FILL_NONE);
}

// ---------------- launch ----------------
extern "C" void kernel_launch(void* const* d_in, const int* in_sizes, int n_in,
                              void* d_out, int out_size) {
    const float* x   = (const float*)d_in[0];
    const float* Wq  = (const float*)d_in[1];
    const float* Wk  = (const float*)d_in[2];
    const float* Wv  = (const float*)d_in[3];
    const float* Wp  = (const float*)d_in[4];
    const float* bp  = (const float*)d_in[5];
    const float* rph = (const float*)d_in[6];
    const float* rpw = (const float*)d_in[7];
    float* out = (float*)d_out;

    float *xp, *q;
    __nv_bfloat16 *axh, *axl, *aqh, *aql, *aoh, *aol;
    __nv_bfloat16 *wqh, *wql, *wkh, *wkl, *wvh, *wvl, *wph, *wpl;
    __nv_bfloat16 *qh, *ql, *kh, *kl, *vh, *vl, *ph, *pl;
    cudaGetSymbolAddress((void**)&xp, g_xp);
    cudaGetSymbolAddress((void**)&q,  g_q);
    cudaGetSymbolAddress((void**)&axh, g_axh);
    cudaGetSymbolAddress((void**)&axl, g_axl);
    cudaGetSymbolAddress((void**)&aqh, g_aqh);
    cudaGetSymbolAddress((void**)&aql, g_aql);
    cudaGetSymbolAddress((void**)&aoh, g_aoh);
    cudaGetSymbolAddress((void**)&aol, g_aol);
    cudaGetSymbolAddress((void**)&wqh, g_wqh);
    cudaGetSymbolAddress((void**)&wql, g_wql);
    cudaGetSymbolAddress((void**)&wkh, g_wkh);
    cudaGetSymbolAddress((void**)&wkl, g_wkl);
    cudaGetSymbolAddress((void**)&wvh, g_wvh);
    cudaGetSymbolAddress((void**)&wvl, g_wvl);
    cudaGetSymbolAddress((void**)&wph, g_wph);
    cudaGetSymbolAddress((void**)&wpl, g_wpl);
    cudaGetSymbolAddress((void**)&qh, g_qh);
    cudaGetSymbolAddress((void**)&ql, g_ql);
    cudaGetSymbolAddress((void**)&kh, g_kh);
    cudaGetSymbolAddress((void**)&kl, g_kl);
    cudaGetSymbolAddress((void**)&vh, g_vh);
    cudaGetSymbolAddress((void**)&vl, g_vl);
    cudaGetSymbolAddress((void**)&ph, g_ph);
    cudaGetSymbolAddress((void**)&pl, g_pl);

    EncodeTiledFn enc = nullptr;
    {
        void* fn = nullptr;
        cudaDriverEntryPointQueryResult st;
        cudaGetDriverEntryPoint("cuTensorMapEncodeTiled", &fn, cudaEnableDefault, &st);
        enc = (EncodeTiledFn)fn;
    }
    CUtensorMap mAxh, mAxl, mAqh, mAql, mAoh, mAol;
    CUtensorMap mWqh, mWql, mWkh, mWkl, mWvh, mWvl, mWph, mWpl;
    CUtensorMap mQh, mQl, mKh, mKl, mVh, mVl, mPh, mPl;
    make_map(enc, &mAxh, axh, C_, (uint64_t)B_ * N_, 64, 128);
    make_map(enc, &mAxl, axl, C_, (uint64_t)B_ * N_, 64, 128);
    make_map(enc, &mAqh, aqh, C_, (uint64_t)B_ * QN, 64, 128);
    make_map(enc, &mAql, aql, C_, (uint64_t)B_ * QN, 64, 128);
    make_map(enc, &mAoh, aoh, C_, (uint64_t)B_ * QN, 64, 128);
    make_map(enc, &mAol, aol, C_, (uint64_t)B_ * QN, 64, 128);
    make_map(enc, &mWqh, wqh, C_, C_, 64, 128);
    make_map(enc, &mWql, wql, C_, C_, 64, 128);
    make_map(enc, &mWkh, wkh, C_, C_, 64, 128);
    make_map(enc, &mWkl, wkl, C_, C_, 64, 128);
    make_map(enc, &mWvh, wvh, C_, C_, 64, 128);
    make_map(enc, &mWvl, wvl, C_, C_, 64, 128);
    make_map(enc, &mWph, wph, C_, C_, 64, 128);
    make_map(enc, &mWpl, wpl, C_, C_, 64, 128);
    make_map(enc, &mQh, qh, HD, (uint64_t)BH * QN, 64, 48);
    make_map(enc, &mQl, ql, HD, (uint64_t)BH * QN, 64, 48);
    make_map(enc, &mKh, kh, HD, (uint64_t)BH * N_, 64, 96);
    make_map(enc, &mKl, kl, HD, (uint64_t)BH * N_, 64, 96);
    make_map(enc, &mVh, vh, HD, (uint64_t)BH * N_, 64, 64);
    make_map(enc, &mVl, vl, HD, (uint64_t)BH * N_, 64, 64);
    make_map(enc, &mPh, ph, N_, (uint64_t)BH * QN, 64, 48);
    make_map(enc, &mPl, pl, N_, (uint64_t)BH * QN, 64, 48);

    cudaFuncSetAttribute(gemm_tma, cudaFuncAttributeMaxDynamicSharedMemorySize, GT_SMEM);
    cudaFuncSetAttribute(qk_fused, cudaFuncAttributeMaxDynamicSharedMemorySize, QKF_SMEM);
    cudaFuncSetAttribute(av_mma, cudaFuncAttributeMaxDynamicSharedMemorySize, AV_SMEM);

    // launch order chosen so ncu (-s 5 -c 1) profiles the K-projection GEMM (6th launch)
    split_x2_kernel<<<dim3(18, 32, B_), dim3(32, 8)>>>(x);
    split_wT_kernel<<<dim3(32, 32), dim3(32, 8)>>>(Wk, wkh, wkl);
    split_wT_kernel<<<dim3(32, 32), dim3(32, 8)>>>(Wv, wvh, wvl);
    split_wT_kernel<<<dim3(32, 32), dim3(32, 8)>>>(Wq, wqh, wql);
    split_wT_kernel<<<dim3(32, 32), dim3(32, 8)>>>(Wp, wph, wpl);

    gemm_tma<<<dim3(8, (B_ * N_) / 128), 512, GT_SMEM>>>(mAxh, mAxl, mWkh, mWkl, nullptr, nullptr, kh, kl, N_, 2);
    gemm_tma<<<dim3(8, (B_ * N_) / 128), 512, GT_SMEM>>>(mAxh, mAxl, mWvh, mWvl, nullptr, nullptr, vh, vl, N_, 2);

    pool_kernel<<<dim3(C_ / 16, B_), 256>>>(x);
    split_rows2_kernel<<<(B_ * QN * C_) / 256, 256>>>(xp, aqh, aql);
    gemm_tma<<<dim3(8, (B_ * QN) / 128), 512, GT_SMEM>>>(mAqh, mAql, mWqh, mWql, nullptr, q, qh, ql, QN, 3);

    relpos_kernel<<<BH * QN, 64>>>(rph, rpw);
    qk_fused<<<dim3(1, 3, BH), 576, QKF_SMEM>>>(mQh, mQl, mKh, mKl);
    av_mma<<<dim3(1, 3, BH), 192, AV_SMEM>>>(mPh, mPl, mVh, mVl);

    gemm_tma<<<dim3(8, (B_ * QN) / 128), 512, GT_SMEM>>>(mAoh, mAol, mWph, mWpl, bp, out, nullptr, nullptr, QN, 1);
}

// round 11
// speedup vs baseline: 2.6785x; 1.0485x over previous
#include <cuda.h>
#include <cuda_runtime.h>
#include <cuda_bf16.h>
#include <cuda_fp16.h>
#include <math.h>
#include <stdint.h>

#define B_  128
#define C_  1024
#define H_  24
#define W_  24
#define N_  576
#define NH  8
#define HD  128
#define QH  12
#define QW  12
#define QN  144
#define BH  (B_*NH)

// ---------------- fp32 scratch ----------------
__device__ float g_q   [(size_t)B_*QN*C_];
__device__ float g_relh[(size_t)BH*QN*H_];
__device__ float g_relw[(size_t)BH*QN*W_];
// bf16 hi/lo A operands
__device__ __nv_bfloat16 g_axh[(size_t)B_*N_*C_];
__device__ __nv_bfloat16 g_axl[(size_t)B_*N_*C_];
__device__ __nv_bfloat16 g_aqh[(size_t)B_*QN*C_];
__device__ __nv_bfloat16 g_aql[(size_t)B_*QN*C_];
__device__ __nv_bfloat16 g_aoh[(size_t)B_*QN*C_];
__device__ __nv_bfloat16 g_aol[(size_t)B_*QN*C_];
// fp16 hi/lo x operands (for the fp16 2-term V GEMM probe)
__device__ __half g_axh2[(size_t)B_*N_*C_];
__device__ __half g_axl2[(size_t)B_*N_*C_];
// TRANSPOSED weights [N,K]
__device__ __nv_bfloat16 g_wqh[(size_t)C_*C_];
__device__ __nv_bfloat16 g_wql[(size_t)C_*C_];
__device__ __nv_bfloat16 g_wkh[(size_t)C_*C_];
__device__ __nv_bfloat16 g_wkl[(size_t)C_*C_];
__device__ __half        g_wv2[(size_t)C_*C_];    // single fp16
__device__ __nv_bfloat16 g_wph[(size_t)C_*C_];
__device__ __nv_bfloat16 g_wpl[(size_t)C_*C_];
// head-major bf16 hi/lo tensors
__device__ __nv_bfloat16 g_qh[(size_t)BH*QN*HD];
__device__ __nv_bfloat16 g_ql[(size_t)BH*QN*HD];
__device__ __nv_bfloat16 g_kh[(size_t)BH*N_*HD];
__device__ __nv_bfloat16 g_kl[(size_t)BH*N_*HD];
__device__ __nv_bfloat16 g_vh[(size_t)BH*N_*HD];
__device__ __nv_bfloat16 g_vl[(size_t)BH*N_*HD];
__device__ __nv_bfloat16 g_ph[(size_t)BH*QN*N_];
__device__ __nv_bfloat16 g_pl[(size_t)BH*QN*N_];

// ---------------- helpers ----------------
__device__ __forceinline__ void split2(float v, __nv_bfloat16& hi, __nv_bfloat16& lo) {
    hi = __float2bfloat16(v);
    lo = __float2bfloat16(v - __bfloat162float(hi));
}
__device__ __forceinline__ void split2h(float v, __half& hi, __half& lo) {
    hi = __float2half(v);
    lo = __float2half(v - __half2float(hi));
}
__device__ __forceinline__ uint32_t smem_u32(const void* p) {
    return (uint32_t)__cvta_generic_to_shared(p);
}
__device__ __forceinline__ uint32_t swz(uint32_t o) {      // SW128, 128B rows
    return o ^ ((o >> 3) & 0x70);
}

#define MMA_BF16(ACC, A, B0, B1)                                              \
    asm volatile(                                                             \
        "mma.sync.aligned.m16n8k16.row.col.f32.bf16.bf16.f32 "                \
        "{%0,%1,%2,%3}, {%4,%5,%6,%7}, {%8,%9}, {%0,%1,%2,%3};"               \
        : "+f"((ACC)[0]), "+f"((ACC)[1]), "+f"((ACC)[2]), "+f"((ACC)[3])      \
        : "r"((A)[0]), "r"((A)[1]), "r"((A)[2]), "r"((A)[3]),                 \
          "r"(B0), "r"(B1))

#define MMA_F16(ACC, A, B0, B1)                                               \
    asm volatile(                                                             \
        "mma.sync.aligned.m16n8k16.row.col.f32.f16.f16.f32 "                  \
        "{%0,%1,%2,%3}, {%4,%5,%6,%7}, {%8,%9}, {%0,%1,%2,%3};"               \
        : "+f"((ACC)[0]), "+f"((ACC)[1]), "+f"((ACC)[2]), "+f"((ACC)[3])      \
        : "r"((A)[0]), "r"((A)[1]), "r"((A)[2]), "r"((A)[3]),                 \
          "r"(B0), "r"(B1))

#define LDSM_X4(R, ADDR)                                                      \
    asm volatile("ldmatrix.sync.aligned.m8n8.x4.shared.b16 {%0,%1,%2,%3}, [%4];" \
                 : "=r"((R)[0]), "=r"((R)[1]), "=r"((R)[2]), "=r"((R)[3]) : "r"(ADDR))
#define LDSM_X4T(R, ADDR)                                                     \
    asm volatile("ldmatrix.sync.aligned.m8n8.x4.trans.shared.b16 {%0,%1,%2,%3}, [%4];" \
                 : "=r"((R)[0]), "=r"((R)[1]), "=r"((R)[2]), "=r"((R)[3]) : "r"(ADDR))

#define MBAR_INIT(mb, cnt) \
    asm volatile("mbarrier.init.shared.b64 [%0], %1;" :: "r"(mb), "r"((uint32_t)(cnt)) : "memory")
#define MBAR_EXPECT_TX(mb, bytes) \
    asm volatile("mbarrier.arrive.expect_tx.shared.b64 _, [%0], %1;" :: "r"(mb), "r"((uint32_t)(bytes)) : "memory")
#define MBAR_ARRIVE(mb) \
    asm volatile("mbarrier.arrive.shared.b64 _, [%0];" :: "r"(mb) : "memory")
#define MBAR_WAIT(mb, ph) do {                                                    \
    asm volatile("{\n\t.reg .pred P1;\n\t"                                        \
        "WAIT_LOOP_%=:\n\t"                                                       \
        "mbarrier.try_wait.parity.acquire.cta.shared::cta.b64 P1, [%0], %1, 0x989680;\n\t" \
        "@P1 bra.uni WAIT_DONE_%=;\n\t"                                           \
        "bra.uni WAIT_LOOP_%=;\n\t"                                               \
        "WAIT_DONE_%=:\n\t}"                                                      \
        :: "r"(mb), "r"((uint32_t)(ph)) : "memory");                              \
} while(0)

#define TMA_LOAD_2D(sa, map, cx, cy, mb)                                          \
    asm volatile("cp.async.bulk.tensor.2d.shared::cta.global.tile.mbarrier::complete_tx::bytes " \
        "[%0], [%1, {%2, %3}], [%4];"                                             \
        :: "r"(sa), "l"(map), "r"((int32_t)(cx)), "r"((int32_t)(cy)), "r"(mb) : "memory")

// ---------------- conversions ----------------
__global__ __launch_bounds__(256) void split_wT_kernel(const float* __restrict__ W,
                                                       __nv_bfloat16* __restrict__ WhT,
                                                       __nv_bfloat16* __restrict__ WlT) {
    __shared__ float t[32][33];
    int k0 = blockIdx.x * 32, n0 = blockIdx.y * 32;
    int tx = threadIdx.x, ty = threadIdx.y;
    #pragma unroll
    for (int i = 0; i < 4; i++)
        t[ty + i * 8][tx] = W[(size_t)(k0 + ty + i * 8) * C_ + n0 + tx];
    __syncthreads();
    #pragma unroll
    for (int i = 0; i < 4; i++) {
        __nv_bfloat16 hi, lo; split2(t[tx][ty + i * 8], hi, lo);
        size_t idx = (size_t)(n0 + ty + i * 8) * C_ + k0 + tx;
        WhT[idx] = hi; WlT[idx] = lo;
    }
}

// W -> single fp16, transposed [N,K]
__global__ __launch_bounds__(256) void split_wT_f16_kernel(const float* __restrict__ W,
                                                           __half* __restrict__ WT) {
    __shared__ float t[32][33];
    int k0 = blockIdx.x * 32, n0 = blockIdx.y * 32;
    int tx = threadIdx.x, ty = threadIdx.y;
    #pragma unroll
    for (int i = 0; i < 4; i++)
        t[ty + i * 8][tx] = W[(size_t)(k0 + ty + i * 8) * C_ + n0 + tx];
    __syncthreads();
    #pragma unroll
    for (int i = 0; i < 4; i++)
        WT[(size_t)(n0 + ty + i * 8) * C_ + k0 + tx] = __float2half(t[tx][ty + i * 8]);
}

// x[B,C,N] -> transposed: bf16 hi/lo AND fp16 hi/lo
__global__ __launch_bounds__(256) void split_x2_kernel(const float* __restrict__ x) {
    __shared__ float tile[32][33];
    int b  = blockIdx.z;
    int n0 = blockIdx.x * 32;
    int c0 = blockIdx.y * 32;
    int tx = threadIdx.x, ty = threadIdx.y;
    const float* xb = x + (size_t)b * C_ * N_;
    #pragma unroll
    for (int i = 0; i < 4; i++)
        tile[ty + i * 8][tx] = xb[(size_t)(c0 + ty + i * 8) * N_ + n0 + tx];
    __syncthreads();
    #pragma unroll
    for (int i = 0; i < 4; i++) {
        int n = n0 + ty + i * 8;
        float v = tile[tx][ty + i * 8];
        size_t base = ((size_t)b * N_ + n) * C_ + c0 + tx;
        __nv_bfloat16 hi, lo; split2(v, hi, lo);
        g_axh[base] = hi; g_axl[base] = lo;
        __half h2, l2; split2h(v, h2, l2);
        g_axh2[base] = h2; g_axl2[base] = l2;
    }
}

// ---------------- avg-pool 3x3 s2 pad1 -> aqh/aql (bf16 split fused) ----------------
__global__ __launch_bounds__(256) void pool_kernel(const float* __restrict__ x) {
    __shared__ float sp[16][577];
    int b  = blockIdx.y;
    int c0 = blockIdx.x * 16;
    int tid = threadIdx.x;
    const float* xb = x + (size_t)b * C_ * N_ + (size_t)c0 * N_;
    #pragma unroll
    for (int r = 0; r < 36; r++) {
        int idx = tid + r * 256;
        int p = idx / 576, n = idx - p * 576;
        sp[p][n] = xb[(size_t)p * N_ + n];
    }
    __syncthreads();
    #pragma unroll
    for (int r = 0; r < 9; r++) {
        int idx = tid + r * 256;
        int qn = idx >> 4, cl = idx & 15;
        int qy = qn / 12, qx = qn - qy * 12;
        float s = 0.f;
        #pragma unroll
        for (int dy = -1; dy <= 1; dy++) {
            int y = 2 * qy + dy;
            if ((unsigned)y < 24u) {
                #pragma unroll
                for (int dx = -1; dx <= 1; dx++) {
                    int xx = 2 * qx + dx;
                    if ((unsigned)xx < 24u) s += sp[cl][y * 24 + xx];
                }
            }
        }
        __nv_bfloat16 hi, lo; split2(s * (1.0f / 9.0f), hi, lo);
        size_t o = ((size_t)b * QN + qn) * C_ + c0 + cl;
        g_aqh[o] = hi; g_aql[o] = lo;
    }
}

// ---------------- TMA + mma.sync bf16 3-term GEMM (proven R8 core) ----------------
#define GT_TILE  16384
#define GT_BUF   (4*GT_TILE)
#define GT_SMEM  (3*GT_BUF + 1024)
#define NSTAGE   16

__global__ __launch_bounds__(512) void gemm_tma(
    const __grid_constant__ CUtensorMap tmAh,
    const __grid_constant__ CUtensorMap tmAl,
    const __grid_constant__ CUtensorMap tmBh,
    const __grid_constant__ CUtensorMap tmBl,
    const float* __restrict__ bias,
    float* __restrict__ Cm,
    __nv_bfloat16* __restrict__ Dh,
    __nv_bfloat16* __restrict__ Dl,
    int rpb, int mode)
{
    extern __shared__ char smem[];
    uint32_t sraw = smem_u32(smem);
    uint32_t fullb[3]  = {sraw, sraw + 8, sraw + 16};
    uint32_t emptyb[3] = {sraw + 24, sraw + 32, sraw + 40};
    uint32_t tiles = (sraw + 64 + 1023) & ~1023u;

    int tid = threadIdx.x, lane = tid & 31, warp = tid >> 5;
    int wm = warp >> 2, wn = warp & 3;
    int rowBase = blockIdx.y * 128;
    int colBase = blockIdx.x * 128;

    if (tid == 0) {
        MBAR_INIT(fullb[0], 1);  MBAR_INIT(fullb[1], 1);  MBAR_INIT(fullb[2], 1);
        MBAR_INIT(emptyb[0], 512); MBAR_INIT(emptyb[1], 512); MBAR_INIT(emptyb[2], 512);
    }
    __syncthreads();

    float acc[2][4][4];
    #pragma unroll
    for (int i = 0; i < 2; i++)
        #pragma unroll
        for (int j = 0; j < 4; j++)
            #pragma unroll
            for (int r = 0; r < 4; r++) acc[i][j][r] = 0.f;

    int phF[3] = {0, 0, 0};
    int phE[3] = {0, 0, 0};

    auto issue = [&](int s, int slot) {
        uint32_t base = tiles + slot * GT_BUF;
        MBAR_EXPECT_TX(fullb[slot], GT_BUF);
        int k0 = s * 64;
        TMA_LOAD_2D(base,               &tmAh, k0, rowBase, fullb[slot]);
        TMA_LOAD_2D(base + GT_TILE,     &tmAl, k0, rowBase, fullb[slot]);
        TMA_LOAD_2D(base + 2 * GT_TILE, &tmBh, k0, colBase, fullb[slot]);
        TMA_LOAD_2D(base + 3 * GT_TILE, &tmBl, k0, colBase, fullb[slot]);
    };

    if (tid == 0) { issue(0, 0); issue(1, 1); issue(2, 2); }

    uint32_t ah[2][2][4], al[2][2][4], bhf[2][2][4], blf[2][2][4];

    int arow0 = wm * 32 + (lane & 7) + ((lane >> 3) & 1) * 8;
    int acol8 = (lane >> 4) << 3;
    int brow0 = wn * 32 + (lane & 7) + ((lane >> 4) & 1) * 8;
    int bcol8 = (lane >> 3) & 1 ? 8 : 0;

    for (int s = 0; s < NSTAGE; s++) {
        int slot = s % 3;
        MBAR_WAIT(fullb[slot], phF[slot]); phF[slot] ^= 1;

        uint32_t aH = tiles + slot * GT_BUF;
        uint32_t aL = aH + GT_TILE;
        uint32_t bH = aH + 2 * GT_TILE;
        uint32_t bL = aH + 3 * GT_TILE;

        {
            #pragma unroll
            for (int mf = 0; mf < 2; mf++) {
                uint32_t off = swz((uint32_t)((arow0 + mf * 16) * 128 + acol8 * 2));
                LDSM_X4(ah[0][mf], aH + off);
                LDSM_X4(al[0][mf], aL + off);
            }
            #pragma unroll
            for (int g = 0; g < 2; g++) {
                uint32_t off = swz((uint32_t)((brow0 + g * 16) * 128 + bcol8 * 2));
                LDSM_X4(bhf[0][g], bH + off);
                LDSM_X4(blf[0][g], bL + off);
            }
        }

        #pragma unroll
        for (int kki = 0; kki < 4; kki++) {
            int pb = kki & 1;
            if (kki < 3) {
                int nb = pb ^ 1;
                int kk = (kki + 1) * 16;
                #pragma unroll
                for (int mf = 0; mf < 2; mf++) {
                    uint32_t off = swz((uint32_t)((arow0 + mf * 16) * 128 + (kk + acol8) * 2));
                    LDSM_X4(ah[nb][mf], aH + off);
                    LDSM_X4(al[nb][mf], aL + off);
                }
                #pragma unroll
                for (int g = 0; g < 2; g++) {
                    uint32_t off = swz((uint32_t)((brow0 + g * 16) * 128 + (kk + bcol8) * 2));
                    LDSM_X4(bhf[nb][g], bH + off);
                    LDSM_X4(blf[nb][g], bL + off);
                }
            }
            #pragma unroll
            for (int mf = 0; mf < 2; mf++)
                #pragma unroll
                for (int nf = 0; nf < 4; nf++) {
                    uint32_t b0 = bhf[pb][nf >> 1][(nf & 1) * 2 + 0];
                    uint32_t b1 = bhf[pb][nf >> 1][(nf & 1) * 2 + 1];
                    uint32_t c0 = blf[pb][nf >> 1][(nf & 1) * 2 + 0];
                    uint32_t c1 = blf[pb][nf >> 1][(nf & 1) * 2 + 1];
                    MMA_BF16(acc[mf][nf], ah[pb][mf], b0, b1);
                    MMA_BF16(acc[mf][nf], ah[pb][mf], c0, c1);
                    MMA_BF16(acc[mf][nf], al[pb][mf], b0, b1);
                }
        }
        MBAR_ARRIVE(emptyb[slot]);
        if (tid == 0 && s + 3 < NSTAGE) {
            MBAR_WAIT(emptyb[slot], phE[slot]); phE[slot] ^= 1;
            issue(s + 3, slot);
        }
    }

    int gid = lane >> 2, tig = lane & 3;
    #pragma unroll
    for (int mf = 0; mf < 2; mf++)
        #pragma unroll
        for (int nf = 0; nf < 4; nf++) {
            int c0 = colBase + wn * 32 + nf * 8 + tig * 2;
            #pragma unroll
            for (int rr = 0; rr < 2; rr++) {
                int row = rowBase + wm * 32 + mf * 16 + gid + rr * 8;
                float v0 = acc[mf][nf][rr * 2 + 0];
                float v1 = acc[mf][nf][rr * 2 + 1];
                if (mode == 1) {
                    int bq = row / QN, qi = row - bq * QN;
                    Cm[((size_t)bq * C_ + c0) * QN + qi]     = v0 + bias[c0];
                    Cm[((size_t)bq * C_ + c0 + 1) * QN + qi] = v1 + bias[c0 + 1];
                } else {
                    int b = row / rpb, n = row - b * rpb;
                    int h = c0 >> 7, d = c0 & 127;
                    size_t di = (((size_t)b * NH + h) * rpb + n) * HD + d;
                    __nv_bfloat162 th, tl;
                    split2(v0, th.x, tl.x);
                    split2(v1, th.y, tl.y);
                    *(__nv_bfloat162*)(Dh + di) = th;
                    *(__nv_bfloat162*)(Dl + di) = tl;
                    if (mode == 3)
                        *(float2*)&Cm[(size_t)row * C_ + c0] = make_float2(v0, v1);
                }
            }
        }
}

// ---------------- fp16 2-term GEMM: C = (Ah+Al)·B,  A fp16 hi/lo, B single fp16 ----------------
#define G2_TILE  16384
#define G2_BUF   (3*G2_TILE)
#define G2_SMEM  (3*G2_BUF + 1024)

__global__ __launch_bounds__(512) void gemm_f16(
    const __grid_constant__ CUtensorMap tmAh,
    const __grid_constant__ CUtensorMap tmAl,
    const __grid_constant__ CUtensorMap tmB,
    __nv_bfloat16* __restrict__ Dh,
    __nv_bfloat16* __restrict__ Dl,
    int rpb)
{
    extern __shared__ char smem[];
    uint32_t sraw = smem_u32(smem);
    uint32_t fullb[3]  = {sraw, sraw + 8, sraw + 16};
    uint32_t emptyb[3] = {sraw + 24, sraw + 32, sraw + 40};
    uint32_t tiles = (sraw + 64 + 1023) & ~1023u;

    int tid = threadIdx.x, lane = tid & 31, warp = tid >> 5;
    int wm = warp >> 2, wn = warp & 3;
    int rowBase = blockIdx.y * 128;
    int colBase = blockIdx.x * 128;

    if (tid == 0) {
        MBAR_INIT(fullb[0], 1);  MBAR_INIT(fullb[1], 1);  MBAR_INIT(fullb[2], 1);
        MBAR_INIT(emptyb[0], 512); MBAR_INIT(emptyb[1], 512); MBAR_INIT(emptyb[2], 512);
    }
    __syncthreads();

    float acc[2][4][4];
    #pragma unroll
    for (int i = 0; i < 2; i++)
        #pragma unroll
        for (int j = 0; j < 4; j++)
            #pragma unroll
            for (int r = 0; r < 4; r++) acc[i][j][r] = 0.f;

    int phF[3] = {0, 0, 0};
    int phE[3] = {0, 0, 0};

    auto issue = [&](int s, int slot) {
        uint32_t base = tiles + slot * G2_BUF;
        MBAR_EXPECT_TX(fullb[slot], G2_BUF);
        int k0 = s * 64;
        TMA_LOAD_2D(base,               &tmAh, k0, rowBase, fullb[slot]);
        TMA_LOAD_2D(base + G2_TILE,     &tmAl, k0, rowBase, fullb[slot]);
        TMA_LOAD_2D(base + 2 * G2_TILE, &tmB,  k0, colBase, fullb[slot]);
    };

    if (tid == 0) { issue(0, 0); issue(1, 1); issue(2, 2); }

    uint32_t ah[2][2][4], al[2][2][4], bf[2][2][4];

    int arow0 = wm * 32 + (lane & 7) + ((lane >> 3) & 1) * 8;
    int acol8 = (lane >> 4) << 3;
    int brow0 = wn * 32 + (lane & 7) + ((lane >> 4) & 1) * 8;
    int bcol8 = (lane >> 3) & 1 ? 8 : 0;

    for (int s = 0; s < NSTAGE; s++) {
        int slot = s % 3;
        MBAR_WAIT(fullb[slot], phF[slot]); phF[slot] ^= 1;

        uint32_t aH = tiles + slot * G2_BUF;
        uint32_t aL = aH + G2_TILE;
        uint32_t bB = aH + 2 * G2_TILE;

        {
            #pragma unroll
            for (int mf = 0; mf < 2; mf++) {
                uint32_t off = swz((uint32_t)((arow0 + mf * 16) * 128 + acol8 * 2));
                LDSM_X4(ah[0][mf], aH + off);
                LDSM_X4(al[0][mf], aL + off);
            }
            #pragma unroll
            for (int g = 0; g < 2; g++) {
                uint32_t off = swz((uint32_t)((brow0 + g * 16) * 128 + bcol8 * 2));
                LDSM_X4(bf[0][g], bB + off);
            }
        }

        #pragma unroll
        for (int kki = 0; kki < 4; kki++) {
            int pb = kki & 1;
            if (kki < 3) {
                int nb = pb ^ 1;
                int kk = (kki + 1) * 16;
                #pragma unroll
                for (int mf = 0; mf < 2; mf++) {
                    uint32_t off = swz((uint32_t)((arow0 + mf * 16) * 128 + (kk + acol8) * 2));
                    LDSM_X4(ah[nb][mf], aH + off);
                    LDSM_X4(al[nb][mf], aL + off);
                }
                #pragma unroll
                for (int g = 0; g < 2; g++) {
                    uint32_t off = swz((uint32_t)((brow0 + g * 16) * 128 + (kk + bcol8) * 2));
                    LDSM_X4(bf[nb][g], bB + off);
                }
            }
            #pragma unroll
            for (int mf = 0; mf < 2; mf++)
                #pragma unroll
                for (int nf = 0; nf < 4; nf++) {
                    uint32_t b0 = bf[pb][nf >> 1][(nf & 1) * 2 + 0];
                    uint32_t b1 = bf[pb][nf >> 1][(nf & 1) * 2 + 1];
                    MMA_F16(acc[mf][nf], ah[pb][mf], b0, b1);
                    MMA_F16(acc[mf][nf], al[pb][mf], b0, b1);
                }
        }
        MBAR_ARRIVE(emptyb[slot]);
        if (tid == 0 && s + 3 < NSTAGE) {
            MBAR_WAIT(emptyb[slot], phE[slot]); phE[slot] ^= 1;
            issue(s + 3, slot);
        }
    }

    int gid = lane >> 2, tig = lane & 3;
    #pragma unroll
    for (int mf = 0; mf < 2; mf++)
        #pragma unroll
        for (int nf = 0; nf < 4; nf++) {
            int c0 = colBase + wn * 32 + nf * 8 + tig * 2;
            #pragma unroll
            for (int rr = 0; rr < 2; rr++) {
                int row = rowBase + wm * 32 + mf * 16 + gid + rr * 8;
                float v0 = acc[mf][nf][rr * 2 + 0];
                float v1 = acc[mf][nf][rr * 2 + 1];
                int b = row / rpb, n = row - b * rpb;
                int h = c0 >> 7, d = c0 & 127;
                size_t di = (((size_t)b * NH + h) * rpb + n) * HD + d;
                __nv_bfloat162 th, tl;
                split2(v0, th.x, tl.x);
                split2(v1, th.y, tl.y);
                *(__nv_bfloat162*)(Dh + di) = th;
                *(__nv_bfloat162*)(Dl + di) = tl;
            }
        }
}

// ---------------- relative position bias dots ----------------
__global__ __launch_bounds__(64) void relpos_kernel(const float* __restrict__ rel_h,
                                                    const float* __restrict__ rel_w) {
    int gid = blockIdx.x;
    int bh = gid / QN, i = gid - bh * QN;
    int b = bh >> 3, h = bh & 7;
    int qy = i / 12, qx = i - qy * 12;
    int t = threadIdx.x;
    const float* qrow = g_q + ((size_t)b * QN + i) * C_ + h * HD;
    if (t < 24) {
        const float* R = rel_h + (size_t)(2 * qy - t + 23) * HD;
        float a0 = 0, a1 = 0, a2 = 0, a3 = 0;
        #pragma unroll
        for (int d = 0; d < HD; d += 4) {
            a0 += qrow[d + 0] * R[d + 0];
            a1 += qrow[d + 1] * R[d + 1];
            a2 += qrow[d + 2] * R[d + 2];
            a3 += qrow[d + 3] * R[d + 3];
        }
        g_relh[(size_t)gid * 24 + t] = (a0 + a1) + (a2 + a3);
    } else if (t >= 32 && t < 56) {
        int kx = t - 32;
        const float* R = rel_w + (size_t)(2 * qx - kx + 23) * HD;
        float a0 = 0, a1 = 0, a2 = 0, a3 = 0;
        #pragma unroll
        for (int d = 0; d < HD; d += 4) {
            a0 += qrow[d + 0] * R[d + 0];
            a1 += qrow[d + 1] * R[d + 1];
            a2 += qrow[d + 2] * R[d + 2];
            a3 += qrow[d + 3] * R[d + 3];
        }
        g_relw[(size_t)gid * 24 + kx] = (a0 + a1) + (a2 + a3);
    }
}

// ---------------- FUSED QK^T + bias + softmax + P-split (R9, unchanged) ----------------
#define QKF_QH   0
#define QKF_QL   12288
#define QKF_K0   24576
#define QKF_KBUF 49152
#define QKF_REL  (24576 + 2*49152)
#define QKF_RED  (QKF_REL + 9216)
#define QKF_SMEM (QKF_RED + 2304 + 1088)

__global__ __launch_bounds__(576) void qk_fused(
    const __grid_constant__ CUtensorMap tmQh,
    const __grid_constant__ CUtensorMap tmQl,
    const __grid_constant__ CUtensorMap tmKh,
    const __grid_constant__ CUtensorMap tmKl)
{
    extern __shared__ char smem[];
    uint32_t sraw = smem_u32(smem);
    uint32_t fullb[2]  = {sraw, sraw + 8};
    uint32_t emptyb[2] = {sraw + 16, sraw + 24};
    uint32_t tiles = (sraw + 64 + 1023) & ~1023u;
    char* tilesp = smem + (tiles - sraw);
    float* srelh = (float*)(tilesp + QKF_REL);
    float* srelw = srelh + 48 * 24;
    float* smax  = (float*)(tilesp + QKF_RED);
    float* ssum  = smax + 48 * 6;

    int bh = blockIdx.z;
    int rowBase = blockIdx.y * 48;
    int tid = threadIdx.x, lane = tid & 31, warp = tid >> 5;
    int wm = warp / 6, wn = warp % 6;
    int gid = lane >> 2, tig = lane & 3;

    if (tid == 0) {
        MBAR_INIT(fullb[0], 1);  MBAR_INIT(fullb[1], 1);
        MBAR_INIT(emptyb[0], 576); MBAR_INIT(emptyb[1], 576);
    }
    __syncthreads();

    for (int idx = tid; idx < 48 * 24; idx += 576) {
        size_t gidx = ((size_t)bh * QN + rowBase + idx / 24) * 24 + (idx % 24);
        srelh[idx] = g_relh[gidx];
        srelw[idx] = g_relw[gidx];
    }

    int phF[2] = {0, 0}, phE[2] = {0, 0};
    auto issue = [&](int c, int buf) {
        uint32_t kb = tiles + QKF_K0 + buf * QKF_KBUF;
        MBAR_EXPECT_TX(fullb[buf], (c == 0) ? (24576u + QKF_KBUF) : (uint32_t)QKF_KBUF);
        int ky0 = bh * N_ + c * 96;
        if (c == 0) {
            int qy = bh * QN + rowBase;
            TMA_LOAD_2D(tiles + QKF_QH,        &tmQh, 0,  qy, fullb[0]);
            TMA_LOAD_2D(tiles + QKF_QH + 6144, &tmQh, 64, qy, fullb[0]);
            TMA_LOAD_2D(tiles + QKF_QL,        &tmQl, 0,  qy, fullb[0]);
            TMA_LOAD_2D(tiles + QKF_QL + 6144, &tmQl, 64, qy, fullb[0]);
        }
        TMA_LOAD_2D(kb,                 &tmKh, 0,  ky0, fullb[buf]);
        TMA_LOAD_2D(kb + 12288,         &tmKh, 64, ky0, fullb[buf]);
        TMA_LOAD_2D(kb + 24576,         &tmKl, 0,  ky0, fullb[buf]);
        TMA_LOAD_2D(kb + 24576 + 12288, &tmKl, 64, ky0, fullb[buf]);
    };
    if (tid == 0) { issue(0, 0); issue(1, 1); }

    float acc[12][4];
    #pragma unroll
    for (int j = 0; j < 12; j++)
        #pragma unroll
        for (int r = 0; r < 4; r++) acc[j][r] = 0.f;

    int arow = wm * 16 + (lane & 7) + ((lane >> 3) & 1) * 8;
    int acol8 = (lane >> 4) << 3;
    int brow = wn * 16 + (lane & 7) + ((lane >> 4) & 1) * 8;
    int bcol8 = ((lane >> 3) & 1) * 8;

    for (int c = 0; c < 6; c++) {
        int buf = c & 1;
        MBAR_WAIT(fullb[buf], phF[buf]); phF[buf] ^= 1;
        uint32_t kB = tiles + QKF_K0 + buf * QKF_KBUF;

        #pragma unroll
        for (int kk = 0; kk < 128; kk += 16) {
            uint32_t a_h[4], a_l[4];
            {
                int ce = kk + acol8;
                uint32_t off = (uint32_t)((ce >> 6) * 6144) + swz((uint32_t)(arow * 128 + (ce & 63) * 2));
                LDSM_X4(a_h, tiles + QKF_QH + off);
                LDSM_X4(a_l, tiles + QKF_QL + off);
            }
            uint32_t b_h[4], b_l[4];
            {
                int kc = kk + bcol8;
                uint32_t off = (uint32_t)((kc >> 6) * 12288) + swz((uint32_t)(brow * 128 + (kc & 63) * 2));
                LDSM_X4(b_h, kB + off);
                LDSM_X4(b_l, kB + 24576 + off);
            }
            #pragma unroll
            for (int j = 0; j < 2; j++) {
                float* A = acc[c * 2 + j];
                MMA_BF16(A, a_h, b_h[j * 2], b_h[j * 2 + 1]);
                MMA_BF16(A, a_h, b_l[j * 2], b_l[j * 2 + 1]);
                MMA_BF16(A, a_l, b_h[j * 2], b_h[j * 2 + 1]);
            }
        }
        MBAR_ARRIVE(emptyb[buf]);
        if (tid == 0 && c + 2 < 6) {
            MBAR_WAIT(emptyb[buf], phE[buf]); phE[buf] ^= 1;
            issue(c + 2, buf);
        }
    }
    __syncthreads();

    const float scale = 0.08838834764831845f;
    int il0 = wm * 16 + gid;
    float mrow[2] = {-1e30f, -1e30f};
    #pragma unroll
    for (int nf = 0; nf < 12; nf++) {
        int colb = (nf >> 1) * 96 + wn * 16 + (nf & 1) * 8 + tig * 2;
        #pragma unroll
        for (int rr = 0; rr < 2; rr++) {
            int il = il0 + rr * 8;
            #pragma unroll
            for (int cc = 0; cc < 2; cc++) {
                int col = colb + cc;
                int ky = col / 24, kx = col - ky * 24;
                float v = acc[nf][rr * 2 + cc] * scale + srelh[il * 24 + ky] + srelw[il * 24 + kx];
                acc[nf][rr * 2 + cc] = v;
                mrow[rr] = fmaxf(mrow[rr], v);
            }
        }
    }
    #pragma unroll
    for (int o = 1; o <= 2; o <<= 1) {
        mrow[0] = fmaxf(mrow[0], __shfl_xor_sync(0xffffffffu, mrow[0], o));
        mrow[1] = fmaxf(mrow[1], __shfl_xor_sync(0xffffffffu, mrow[1], o));
    }
    if (tig == 0) {
        smax[(il0) * 6 + wn] = mrow[0];
        smax[(il0 + 8) * 6 + wn] = mrow[1];
    }
    __syncthreads();
    float M[2];
    #pragma unroll
    for (int rr = 0; rr < 2; rr++) {
        const float* r = smax + (il0 + rr * 8) * 6;
        M[rr] = fmaxf(fmaxf(fmaxf(r[0], r[1]), fmaxf(r[2], r[3])), fmaxf(r[4], r[5]));
    }
    float srow[2] = {0.f, 0.f};
    #pragma unroll
    for (int nf = 0; nf < 12; nf++)
        #pragma unroll
        for (int rr = 0; rr < 2; rr++)
            #pragma unroll
            for (int cc = 0; cc < 2; cc++) {
                float e = __expf(acc[nf][rr * 2 + cc] - M[rr]);
                acc[nf][rr * 2 + cc] = e;
                srow[rr] += e;
            }
    #pragma unroll
    for (int o = 1; o <= 2; o <<= 1) {
        srow[0] += __shfl_xor_sync(0xffffffffu, srow[0], o);
        srow[1] += __shfl_xor_sync(0xffffffffu, srow[1], o);
    }
    if (tig == 0) {
        ssum[(il0) * 6 + wn] = srow[0];
        ssum[(il0 + 8) * 6 + wn] = srow[1];
    }
    __syncthreads();
    float inv[2];
    #pragma unroll
    for (int rr = 0; rr < 2; rr++) {
        const float* r = ssum + (il0 + rr * 8) * 6;
        inv[rr] = 1.0f / ((r[0] + r[1]) + (r[2] + r[3]) + (r[4] + r[5]));
    }
    #pragma unroll
    for (int nf = 0; nf < 12; nf++) {
        int colb = (nf >> 1) * 96 + wn * 16 + (nf & 1) * 8 + tig * 2;
        #pragma unroll
        for (int rr = 0; rr < 2; rr++) {
            size_t off = ((size_t)bh * QN + rowBase + il0 + rr * 8) * N_ + colb;
            __nv_bfloat162 th, tl;
            split2(acc[nf][rr * 2 + 0] * inv[rr], th.x, tl.x);
            split2(acc[nf][rr * 2 + 1] * inv[rr], th.y, tl.y);
            *(__nv_bfloat162*)(g_ph + off) = th;
            *(__nv_bfloat162*)(g_pl + off) = tl;
        }
    }
}

// ---------------- AV mma (R9, unchanged) ----------------
#define AV_PH   0
#define AV_PL   6144
#define AV_VH   12288
#define AV_VL   28672
#define AV_BUF  45056
#define AV_SMEM (2*AV_BUF + 2048)

__global__ __launch_bounds__(192) void av_mma(
    const __grid_constant__ CUtensorMap tmPh,
    const __grid_constant__ CUtensorMap tmPl,
    const __grid_constant__ CUtensorMap tmVh,
    const __grid_constant__ CUtensorMap tmVl)
{
    extern __shared__ char smem[];
    uint32_t sraw = smem_u32(smem);
    uint32_t fullb[2]  = {sraw, sraw + 8};
    uint32_t emptyb[2] = {sraw + 16, sraw + 24};
    uint32_t tiles = (sraw + 64 + 1023) & ~1023u;

    int bh = blockIdx.z;
    int b = bh >> 3, h = bh & 7;
    int rowBase = blockIdx.y * 48;
    int tid = threadIdx.x, lane = tid & 31, warp = tid >> 5;
    int wm = warp >> 1, wn = warp & 1;
    int nBase = wn * 64;

    if (tid == 0) {
        MBAR_INIT(fullb[0], 1);  MBAR_INIT(fullb[1], 1);
        MBAR_INIT(emptyb[0], 192); MBAR_INIT(emptyb[1], 192);
    }
    __syncthreads();

    float acc[8][4];
    #pragma unroll
    for (int j = 0; j < 8; j++)
        #pragma unroll
        for (int r = 0; r < 4; r++) acc[j][r] = 0.f;

    int phF[2] = {0, 0};
    int phE[2] = {1, 1};

    auto issue = [&](int s, int buf) {
        uint32_t base = tiles + buf * AV_BUF;
        MBAR_EXPECT_TX(fullb[buf], AV_BUF);
        int k0 = s * 64;
        int py = bh * QN + rowBase;
        int vy = bh * N_ + k0;
        TMA_LOAD_2D(base + AV_PH, &tmPh, k0, py, fullb[buf]);
        TMA_LOAD_2D(base + AV_PL, &tmPl, k0, py, fullb[buf]);
        TMA_LOAD_2D(base + AV_VH,        &tmVh, 0,  vy, fullb[buf]);
        TMA_LOAD_2D(base + AV_VH + 8192, &tmVh, 64, vy, fullb[buf]);
        TMA_LOAD_2D(base + AV_VL,        &tmVl, 0,  vy, fullb[buf]);
        TMA_LOAD_2D(base + AV_VL + 8192, &tmVl, 64, vy, fullb[buf]);
    };

    if (tid == 0) {
        MBAR_WAIT(emptyb[0], phE[0]); phE[0] ^= 1;
        issue(0, 0);
    }

    for (int s = 0; s < 9; s++) {
        int buf = s & 1;
        if (tid == 0 && s + 1 < 9) {
            int nb = buf ^ 1;
            MBAR_WAIT(emptyb[nb], phE[nb]); phE[nb] ^= 1;
            issue(s + 1, nb);
        }
        MBAR_WAIT(fullb[buf], phF[buf]); phF[buf] ^= 1;
        uint32_t base = tiles + buf * AV_BUF;

        #pragma unroll
        for (int kk = 0; kk < 64; kk += 16) {
            uint32_t ah[4], al[4];
            {
                int row = wm * 16 + (lane & 7) + ((lane >> 3) & 1) * 8;
                int ce  = kk + ((lane >> 4) << 3);
                uint32_t off = swz((uint32_t)(row * 128 + ce * 2));
                LDSM_X4(ah, base + AV_PH + off);
                LDSM_X4(al, base + AV_PL + off);
            }
            uint32_t bhf[4][4], blf[4][4];
            #pragma unroll
            for (int g = 0; g < 4; g++) {
                int vrow = kk + (lane & 15);
                int d    = nBase + g * 16 + ((lane >> 4) << 3);
                uint32_t off = (uint32_t)((d >> 6) * 8192) + swz((uint32_t)(vrow * 128 + (d & 63) * 2));
                LDSM_X4T(bhf[g], base + AV_VH + off);
                LDSM_X4T(blf[g], base + AV_VL + off);
            }
            #pragma unroll
            for (int nf = 0; nf < 8; nf++) {
                uint32_t b0 = bhf[nf >> 1][(nf & 1) * 2 + 0];
                uint32_t b1 = bhf[nf >> 1][(nf & 1) * 2 + 1];
                uint32_t c0 = blf[nf >> 1][(nf & 1) * 2 + 0];
                uint32_t c1 = blf[nf >> 1][(nf & 1) * 2 + 1];
                MMA_BF16(acc[nf], ah, b0, b1);
                MMA_BF16(acc[nf], ah, c0, c1);
                MMA_BF16(acc[nf], al, b0, b1);
            }
        }
        MBAR_ARRIVE(emptyb[buf]);
    }

    int gid = lane >> 2, tig = lane & 3;
    #pragma unroll
    for (int nf = 0; nf < 8; nf++) {
        int d = nBase + nf * 8 + tig * 2;
        #pragma unroll
        for (int rr = 0; rr < 2; rr++) {
            int i = rowBase + wm * 16 + gid + rr * 8;
            size_t off = ((size_t)b * QN + i) * C_ + h * HD + d;
            float2 qv = *(const float2*)(g_q + off);
            float v0 = acc[nf][rr * 2 + 0] + qv.x;
            float v1 = acc[nf][rr * 2 + 1] + qv.y;
            __nv_bfloat162 th, tl;
            split2(v0, th.x, tl.x);
            split2(v1, th.y, tl.y);
            *(__nv_bfloat162*)(g_aoh + off) = th;
            *(__nv_bfloat162*)(g_aol + off) = tl;
        }
    }
}

// ---------------- host: tensormap builder ----------------
typedef CUresult (*EncodeTiledFn)(CUtensorMap*, CUtensorMapDataType, cuuint32_t, void*,
                                  const cuuint64_t*, const cuuint64_t*, const cuuint32_t*,
                                  const cuuint32_t*, CUtensorMapInterleave, CUtensorMapSwizzle,
                                  CUtensorMapL2promotion, CUtensorMapFloatOOBfill);

static void make_map_t(EncodeTiledFn enc, CUtensorMap* m, void* ptr,
                       uint64_t dim0, uint64_t rows, uint32_t box0, uint32_t box1,
                       CUtensorMapDataType dt) {
    cuuint64_t dims[2]    = {(cuuint64_t)dim0, (cuuint64_t)rows};
    cuuint64_t strides[1] = {(cuuint64_t)dim0 * 2};
    cuuint32_t box[2]     = {box0, box1};
    cuuint32_t es[2]      = {1, 1};
    enc(m, dt, 2, ptr, dims, strides, box, es,
        CU_TENSOR_MAP_INTERLEAVE_NONE, CU_TENSOR_MAP_SWIZZLE_128B,
        CU_TENSOR_MAP_L2_PROMOTION_L2_128B, CU_TENSOR_MAP_FLOAT_OOB_FILL_NONE);
}
static void make_map(EncodeTiledFn enc, CUtensorMap* m, void* ptr,
                     uint64_t dim0, uint64_t rows, uint32_t box0, uint32_t box1) {
    make_map_t(enc, m, ptr, dim0, rows, box0, box1, CU_TENSOR_MAP_DATA_TYPE_BFLOAT16);
}

// ---------------- launch ----------------
extern "C" void kernel_launch(void* const* d_in, const int* in_sizes, int n_in,
                              void* d_out, int out_size) {
    const float* x   = (const float*)d_in[0];
    const float* Wq  = (const float*)d_in[1];
    const float* Wk  = (const float*)d_in[2];
    const float* Wv  = (const float*)d_in[3];
    const float* Wp  = (const float*)d_in[4];
    const float* bp  = (const float*)d_in[5];
    const float* rph = (const float*)d_in[6];
    const float* rpw = (const float*)d_in[7];
    float* out = (float*)d_out;

    float *q;
    __nv_bfloat16 *axh, *axl, *aqh, *aql, *aoh, *aol;
    __nv_bfloat16 *wqh, *wql, *wkh, *wkl, *wph, *wpl;
    __nv_bfloat16 *qh, *ql, *kh, *kl, *vh, *vl, *ph, *pl;
    __half *axh2, *axl2, *wv2;
    cudaGetSymbolAddress((void**)&q,  g_q);
    cudaGetSymbolAddress((void**)&axh, g_axh);
    cudaGetSymbolAddress((void**)&axl, g_axl);
    cudaGetSymbolAddress((void**)&aqh, g_aqh);
    cudaGetSymbolAddress((void**)&aql, g_aql);
    cudaGetSymbolAddress((void**)&aoh, g_aoh);
    cudaGetSymbolAddress((void**)&aol, g_aol);
    cudaGetSymbolAddress((void**)&axh2, g_axh2);
    cudaGetSymbolAddress((void**)&axl2, g_axl2);
    cudaGetSymbolAddress((void**)&wv2, g_wv2);
    cudaGetSymbolAddress((void**)&wqh, g_wqh);
    cudaGetSymbolAddress((void**)&wql, g_wql);
    cudaGetSymbolAddress((void**)&wkh, g_wkh);
    cudaGetSymbolAddress((void**)&wkl, g_wkl);
    cudaGetSymbolAddress((void**)&wph, g_wph);
    cudaGetSymbolAddress((void**)&wpl, g_wpl);
    cudaGetSymbolAddress((void**)&qh, g_qh);
    cudaGetSymbolAddress((void**)&ql, g_ql);
    cudaGetSymbolAddress((void**)&kh, g_kh);
    cudaGetSymbolAddress((void**)&kl, g_kl);
    cudaGetSymbolAddress((void**)&vh, g_vh);
    cudaGetSymbolAddress((void**)&vl, g_vl);
    cudaGetSymbolAddress((void**)&ph, g_ph);
    cudaGetSymbolAddress((void**)&pl, g_pl);

    EncodeTiledFn enc = nullptr;
    {
        void* fn = nullptr;
        cudaDriverEntryPointQueryResult st;
        cudaGetDriverEntryPoint("cuTensorMapEncodeTiled", &fn, cudaEnableDefault, &st);
        enc = (EncodeTiledFn)fn;
    }
    CUtensorMap mAxh, mAxl, mAqh, mAql, mAoh, mAol;
    CUtensorMap mAxh2, mAxl2, mWv2;
    CUtensorMap mWqh, mWql, mWkh, mWkl, mWph, mWpl;
    CUtensorMap mQh, mQl, mKh, mKl, mVh, mVl, mPh, mPl;
    make_map(enc, &mAxh, axh, C_, (uint64_t)B_ * N_, 64, 128);
    make_map(enc, &mAxl, axl, C_, (uint64_t)B_ * N_, 64, 128);
    make_map(enc, &mAqh, aqh, C_, (uint64_t)B_ * QN, 64, 128);
    make_map(enc, &mAql, aql, C_, (uint64_t)B_ * QN, 64, 128);
    make_map(enc, &mAoh, aoh, C_, (uint64_t)B_ * QN, 64, 128);
    make_map(enc, &mAol, aol, C_, (uint64_t)B_ * QN, 64, 128);
    make_map_t(enc, &mAxh2, axh2, C_, (uint64_t)B_ * N_, 64, 128, CU_TENSOR_MAP_DATA_TYPE_FLOAT16);
    make_map_t(enc, &mAxl2, axl2, C_, (uint64_t)B_ * N_, 64, 128, CU_TENSOR_MAP_DATA_TYPE_FLOAT16);
    make_map_t(enc, &mWv2,  wv2,  C_, C_, 64, 128, CU_TENSOR_MAP_DATA_TYPE_FLOAT16);
    make_map(enc, &mWqh, wqh, C_, C_, 64, 128);
    make_map(enc, &mWql, wql, C_, C_, 64, 128);
    make_map(enc, &mWkh, wkh, C_, C_, 64, 128);
    make_map(enc, &mWkl, wkl, C_, C_, 64, 128);
    make_map(enc, &mWph, wph, C_, C_, 64, 128);
    make_map(enc, &mWpl, wpl, C_, C_, 64, 128);
    make_map(enc, &mQh, qh, HD, (uint64_t)BH * QN, 64, 48);
    make_map(enc, &mQl, ql, HD, (uint64_t)BH * QN, 64, 48);
    make_map(enc, &mKh, kh, HD, (uint64_t)BH * N_, 64, 96);
    make_map(enc, &mKl, kl, HD, (uint64_t)BH * N_, 64, 96);
    make_map(enc, &mVh, vh, HD, (uint64_t)BH * N_, 64, 64);
    make_map(enc, &mVl, vl, HD, (uint64_t)BH * N_, 64, 64);
    make_map(enc, &mPh, ph, N_, (uint64_t)BH * QN, 64, 48);
    make_map(enc, &mPl, pl, N_, (uint64_t)BH * QN, 64, 48);

    cudaFuncSetAttribute(gemm_tma, cudaFuncAttributeMaxDynamicSharedMemorySize, GT_SMEM);
    cudaFuncSetAttribute(gemm_f16, cudaFuncAttributeMaxDynamicSharedMemorySize, G2_SMEM);
    cudaFuncSetAttribute(qk_fused, cudaFuncAttributeMaxDynamicSharedMemorySize, QKF_SMEM);
    cudaFuncSetAttribute(av_mma, cudaFuncAttributeMaxDynamicSharedMemorySize, AV_SMEM);

    // launches interleaved so an ncu capture in positions 3-5 hits a GEMM
    split_x2_kernel<<<dim3(18, 32, B_), dim3(32, 8)>>>(x);
    split_wT_kernel<<<dim3(32, 32), dim3(32, 8)>>>(Wk, wkh, wkl);
    gemm_tma<<<dim3(8, (B_ * N_) / 128), 512, GT_SMEM>>>(mAxh, mAxl, mWkh, mWkl, nullptr, nullptr, kh, kl, N_, 2);
    split_wT_f16_kernel<<<dim3(32, 32), dim3(32, 8)>>>(Wv, wv2);
    gemm_f16<<<dim3(8, (B_ * N_) / 128), 512, G2_SMEM>>>(mAxh2, mAxl2, mWv2, vh, vl, N_);

    split_wT_kernel<<<dim3(32, 32), dim3(32, 8)>>>(Wq, wqh, wql);
    pool_kernel<<<dim3(C_ / 16, B_), 256>>>(x);
    gemm_tma<<<dim3(8, (B_ * QN) / 128), 512, GT_SMEM>>>(mAqh, mAql, mWqh, mWql, nullptr, q, qh, ql, QN, 3);

    relpos_kernel<<<BH * QN, 64>>>(rph, rpw);
    qk_fused<<<dim3(1, 3, BH), 576, QKF_SMEM>>>(mQh, mQl, mKh, mKl);
    av_mma<<<dim3(1, 3, BH), 192, AV_SMEM>>>(mPh, mPl, mVh, mVl);

    split_wT_kernel<<<dim3(32, 32), dim3(32, 8)>>>(Wp, wph, wpl);
    gemm_tma<<<dim3(8, (B_ * QN) / 128), 512, GT_SMEM>>>(mAoh, mAol, mWph, mWpl, bp, out, nullptr, nullptr, QN, 1);
}

// round 12
// speedup vs baseline: 2.9837x; 1.1140x over previous
#include <cuda.h>
#include <cuda_runtime.h>
#include <cuda_bf16.h>
#include <cuda_fp16.h>
#include <math.h>
#include <stdint.h>

#define B_  128
#define C_  1024
#define H_  24
#define W_  24
#define N_  576
#define NH  8
#define HD  128
#define QH  12
#define QW  12
#define QN  144
#define BH  (B_*NH)

// ---------------- fp32 scratch ----------------
__device__ float g_q   [(size_t)B_*QN*C_];
__device__ float g_relh[(size_t)BH*QN*H_];
__device__ float g_relw[(size_t)BH*QN*W_];
// fp16 hi/lo A operands
__device__ __half g_axh2[(size_t)B_*N_*C_];
__device__ __half g_axl2[(size_t)B_*N_*C_];
__device__ __half g_aqh2[(size_t)B_*QN*C_];
__device__ __half g_aql2[(size_t)B_*QN*C_];
__device__ __half g_aoh2[(size_t)B_*QN*C_];
__device__ __half g_aol2[(size_t)B_*QN*C_];
// TRANSPOSED weights [N,K], single fp16
__device__ __half g_wq2[(size_t)C_*C_];
__device__ __half g_wk2[(size_t)C_*C_];
__device__ __half g_wv2[(size_t)C_*C_];
__device__ __half g_wp2[(size_t)C_*C_];
// head-major fp16 tensors
__device__ __half g_qh2[(size_t)BH*QN*HD];
__device__ __half g_ql2[(size_t)BH*QN*HD];
__device__ __half g_k2 [(size_t)BH*N_*HD];    // single
__device__ __half g_v2 [(size_t)BH*N_*HD];    // single
__device__ __half g_ph2[(size_t)BH*QN*N_];
__device__ __half g_pl2[(size_t)BH*QN*N_];

// ---------------- helpers ----------------
__device__ __forceinline__ void split2h(float v, __half& hi, __half& lo) {
    hi = __float2half(v);
    lo = __float2half(v - __half2float(hi));
}
__device__ __forceinline__ uint32_t smem_u32(const void* p) {
    return (uint32_t)__cvta_generic_to_shared(p);
}
__device__ __forceinline__ uint32_t swz(uint32_t o) {      // SW128, 128B rows
    return o ^ ((o >> 3) & 0x70);
}

#define MMA_F16(ACC, A, B0, B1)                                               \
    asm volatile(                                                             \
        "mma.sync.aligned.m16n8k16.row.col.f32.f16.f16.f32 "                  \
        "{%0,%1,%2,%3}, {%4,%5,%6,%7}, {%8,%9}, {%0,%1,%2,%3};"               \
        : "+f"((ACC)[0]), "+f"((ACC)[1]), "+f"((ACC)[2]), "+f"((ACC)[3])      \
        : "r"((A)[0]), "r"((A)[1]), "r"((A)[2]), "r"((A)[3]),                 \
          "r"(B0), "r"(B1))

#define LDSM_X4(R, ADDR)                                                      \
    asm volatile("ldmatrix.sync.aligned.m8n8.x4.shared.b16 {%0,%1,%2,%3}, [%4];" \
                 : "=r"((R)[0]), "=r"((R)[1]), "=r"((R)[2]), "=r"((R)[3]) : "r"(ADDR))
#define LDSM_X4T(R, ADDR)                                                     \
    asm volatile("ldmatrix.sync.aligned.m8n8.x4.trans.shared.b16 {%0,%1,%2,%3}, [%4];" \
                 : "=r"((R)[0]), "=r"((R)[1]), "=r"((R)[2]), "=r"((R)[3]) : "r"(ADDR))

#define MBAR_INIT(mb, cnt) \
    asm volatile("mbarrier.init.shared.b64 [%0], %1;" :: "r"(mb), "r"((uint32_t)(cnt)) : "memory")
#define MBAR_EXPECT_TX(mb, bytes) \
    asm volatile("mbarrier.arrive.expect_tx.shared.b64 _, [%0], %1;" :: "r"(mb), "r"((uint32_t)(bytes)) : "memory")
#define MBAR_ARRIVE(mb) \
    asm volatile("mbarrier.arrive.shared.b64 _, [%0];" :: "r"(mb) : "memory")
#define MBAR_WAIT(mb, ph) do {                                                    \
    asm volatile("{\n\t.reg .pred P1;\n\t"                                        \
        "WAIT_LOOP_%=:\n\t"                                                       \
        "mbarrier.try_wait.parity.acquire.cta.shared::cta.b64 P1, [%0], %1, 0x989680;\n\t" \
        "@P1 bra.uni WAIT_DONE_%=;\n\t"                                           \
        "bra.uni WAIT_LOOP_%=;\n\t"                                               \
        "WAIT_DONE_%=:\n\t}"                                                      \
        :: "r"(mb), "r"((uint32_t)(ph)) : "memory");                              \
} while(0)

#define TMA_LOAD_2D(sa, map, cx, cy, mb)                                          \
    asm volatile("cp.async.bulk.tensor.2d.shared::cta.global.tile.mbarrier::complete_tx::bytes " \
        "[%0], [%1, {%2, %3}], [%4];"                                             \
        :: "r"(sa), "l"(map), "r"((int32_t)(cx)), "r"((int32_t)(cy)), "r"(mb) : "memory")

// ---------------- conversions ----------------
// W -> single fp16, transposed [N,K]
__global__ __launch_bounds__(256) void split_wT_f16_kernel(const float* __restrict__ W,
                                                           __half* __restrict__ WT) {
    __shared__ float t[32][33];
    int k0 = blockIdx.x * 32, n0 = blockIdx.y * 32;
    int tx = threadIdx.x, ty = threadIdx.y;
    #pragma unroll
    for (int i = 0; i < 4; i++)
        t[ty + i * 8][tx] = W[(size_t)(k0 + ty + i * 8) * C_ + n0 + tx];
    __syncthreads();
    #pragma unroll
    for (int i = 0; i < 4; i++)
        WT[(size_t)(n0 + ty + i * 8) * C_ + k0 + tx] = __float2half(t[tx][ty + i * 8]);
}

// x[B,C,N] -> transposed fp16 hi/lo
__global__ __launch_bounds__(256) void split_x2_kernel(const float* __restrict__ x) {
    __shared__ float tile[32][33];
    int b  = blockIdx.z;
    int n0 = blockIdx.x * 32;
    int c0 = blockIdx.y * 32;
    int tx = threadIdx.x, ty = threadIdx.y;
    const float* xb = x + (size_t)b * C_ * N_;
    #pragma unroll
    for (int i = 0; i < 4; i++)
        tile[ty + i * 8][tx] = xb[(size_t)(c0 + ty + i * 8) * N_ + n0 + tx];
    __syncthreads();
    #pragma unroll
    for (int i = 0; i < 4; i++) {
        int n = n0 + ty + i * 8;
        size_t base = ((size_t)b * N_ + n) * C_ + c0 + tx;
        __half h2, l2; split2h(tile[tx][ty + i * 8], h2, l2);
        g_axh2[base] = h2; g_axl2[base] = l2;
    }
}

// ---------------- avg-pool 3x3 s2 pad1 -> aq fp16 hi/lo ----------------
__global__ __launch_bounds__(256) void pool_kernel(const float* __restrict__ x) {
    __shared__ float sp[16][577];
    int b  = blockIdx.y;
    int c0 = blockIdx.x * 16;
    int tid = threadIdx.x;
    const float* xb = x + (size_t)b * C_ * N_ + (size_t)c0 * N_;
    #pragma unroll
    for (int r = 0; r < 36; r++) {
        int idx = tid + r * 256;
        int p = idx / 576, n = idx - p * 576;
        sp[p][n] = xb[(size_t)p * N_ + n];
    }
    __syncthreads();
    #pragma unroll
    for (int r = 0; r < 9; r++) {
        int idx = tid + r * 256;
        int qn = idx >> 4, cl = idx & 15;
        int qy = qn / 12, qx = qn - qy * 12;
        float s = 0.f;
        #pragma unroll
        for (int dy = -1; dy <= 1; dy++) {
            int y = 2 * qy + dy;
            if ((unsigned)y < 24u) {
                #pragma unroll
                for (int dx = -1; dx <= 1; dx++) {
                    int xx = 2 * qx + dx;
                    if ((unsigned)xx < 24u) s += sp[cl][y * 24 + xx];
                }
            }
        }
        __half hi, lo; split2h(s * (1.0f / 9.0f), hi, lo);
        size_t o = ((size_t)b * QN + qn) * C_ + c0 + cl;
        g_aqh2[o] = hi; g_aql2[o] = lo;
    }
}

// ---------------- fp16 2-term GEMM: C = (Ah+Al)·B ----------------
// mode 1: fp32 NCHW scatter + bias.  mode 2: single fp16 head-major (Ds).
// mode 3: fp16 hi/lo head-major (Dh/Dl) + fp32 row-major (Cm).
#define G2_TILE  16384
#define G2_BUF   (3*G2_TILE)
#define G2_SMEM  (3*G2_BUF + 1024)
#define NSTAGE   16

__global__ __launch_bounds__(512) void gemm_f16(
    const __grid_constant__ CUtensorMap tmAh,
    const __grid_constant__ CUtensorMap tmAl,
    const __grid_constant__ CUtensorMap tmB,
    const float* __restrict__ bias,
    float* __restrict__ Cm,
    __half* __restrict__ Dh,
    __half* __restrict__ Dl,
    __half* __restrict__ Ds,
    int rpb, int mode)
{
    extern __shared__ char smem[];
    uint32_t sraw = smem_u32(smem);
    uint32_t fullb[3]  = {sraw, sraw + 8, sraw + 16};
    uint32_t emptyb[3] = {sraw + 24, sraw + 32, sraw + 40};
    uint32_t tiles = (sraw + 64 + 1023) & ~1023u;

    int tid = threadIdx.x, lane = tid & 31, warp = tid >> 5;
    int wm = warp >> 2, wn = warp & 3;
    int rowBase = blockIdx.y * 128;
    int colBase = blockIdx.x * 128;

    if (tid == 0) {
        MBAR_INIT(fullb[0], 1);  MBAR_INIT(fullb[1], 1);  MBAR_INIT(fullb[2], 1);
        MBAR_INIT(emptyb[0], 512); MBAR_INIT(emptyb[1], 512); MBAR_INIT(emptyb[2], 512);
    }
    __syncthreads();

    float acc[2][4][4];
    #pragma unroll
    for (int i = 0; i < 2; i++)
        #pragma unroll
        for (int j = 0; j < 4; j++)
            #pragma unroll
            for (int r = 0; r < 4; r++) acc[i][j][r] = 0.f;

    int phF[3] = {0, 0, 0};
    int phE[3] = {0, 0, 0};

    auto issue = [&](int s, int slot) {
        uint32_t base = tiles + slot * G2_BUF;
        MBAR_EXPECT_TX(fullb[slot], G2_BUF);
        int k0 = s * 64;
        TMA_LOAD_2D(base,               &tmAh, k0, rowBase, fullb[slot]);
        TMA_LOAD_2D(base + G2_TILE,     &tmAl, k0, rowBase, fullb[slot]);
        TMA_LOAD_2D(base + 2 * G2_TILE, &tmB,  k0, colBase, fullb[slot]);
    };

    if (tid == 0) { issue(0, 0); issue(1, 1); issue(2, 2); }

    uint32_t ah[2][2][4], al[2][2][4], bf[2][2][4];

    int arow0 = wm * 32 + (lane & 7) + ((lane >> 3) & 1) * 8;
    int acol8 = (lane >> 4) << 3;
    int brow0 = wn * 32 + (lane & 7) + ((lane >> 4) & 1) * 8;
    int bcol8 = (lane >> 3) & 1 ? 8 : 0;

    for (int s = 0; s < NSTAGE; s++) {
        int slot = s % 3;
        MBAR_WAIT(fullb[slot], phF[slot]); phF[slot] ^= 1;

        uint32_t aH = tiles + slot * G2_BUF;
        uint32_t aL = aH + G2_TILE;
        uint32_t bB = aH + 2 * G2_TILE;

        {
            #pragma unroll
            for (int mf = 0; mf < 2; mf++) {
                uint32_t off = swz((uint32_t)((arow0 + mf * 16) * 128 + acol8 * 2));
                LDSM_X4(ah[0][mf], aH + off);
                LDSM_X4(al[0][mf], aL + off);
            }
            #pragma unroll
            for (int g = 0; g < 2; g++) {
                uint32_t off = swz((uint32_t)((brow0 + g * 16) * 128 + bcol8 * 2));
                LDSM_X4(bf[0][g], bB + off);
            }
        }

        #pragma unroll
        for (int kki = 0; kki < 4; kki++) {
            int pb = kki & 1;
            if (kki < 3) {
                int nb = pb ^ 1;
                int kk = (kki + 1) * 16;
                #pragma unroll
                for (int mf = 0; mf < 2; mf++) {
                    uint32_t off = swz((uint32_t)((arow0 + mf * 16) * 128 + (kk + acol8) * 2));
                    LDSM_X4(ah[nb][mf], aH + off);
                    LDSM_X4(al[nb][mf], aL + off);
                }
                #pragma unroll
                for (int g = 0; g < 2; g++) {
                    uint32_t off = swz((uint32_t)((brow0 + g * 16) * 128 + (kk + bcol8) * 2));
                    LDSM_X4(bf[nb][g], bB + off);
                }
            }
            #pragma unroll
            for (int mf = 0; mf < 2; mf++)
                #pragma unroll
                for (int nf = 0; nf < 4; nf++) {
                    uint32_t b0 = bf[pb][nf >> 1][(nf & 1) * 2 + 0];
                    uint32_t b1 = bf[pb][nf >> 1][(nf & 1) * 2 + 1];
                    MMA_F16(acc[mf][nf], ah[pb][mf], b0, b1);
                    MMA_F16(acc[mf][nf], al[pb][mf], b0, b1);
                }
        }
        MBAR_ARRIVE(emptyb[slot]);
        if (tid == 0 && s + 3 < NSTAGE) {
            MBAR_WAIT(emptyb[slot], phE[slot]); phE[slot] ^= 1;
            issue(s + 3, slot);
        }
    }

    int gid = lane >> 2, tig = lane & 3;
    #pragma unroll
    for (int mf = 0; mf < 2; mf++)
        #pragma unroll
        for (int nf = 0; nf < 4; nf++) {
            int c0 = colBase + wn * 32 + nf * 8 + tig * 2;
            #pragma unroll
            for (int rr = 0; rr < 2; rr++) {
                int row = rowBase + wm * 32 + mf * 16 + gid + rr * 8;
                float v0 = acc[mf][nf][rr * 2 + 0];
                float v1 = acc[mf][nf][rr * 2 + 1];
                if (mode == 1) {
                    int bq = row / QN, qi = row - bq * QN;
                    Cm[((size_t)bq * C_ + c0) * QN + qi]     = v0 + bias[c0];
                    Cm[((size_t)bq * C_ + c0 + 1) * QN + qi] = v1 + bias[c0 + 1];
                } else {
                    int b = row / rpb, n = row - b * rpb;
                    int h = c0 >> 7, d = c0 & 127;
                    size_t di = (((size_t)b * NH + h) * rpb + n) * HD + d;
                    if (mode == 2) {
                        __half2 hv = __floats2half2_rn(v0, v1);
                        *(__half2*)(Ds + di) = hv;
                    } else {
                        __half2 th, tl;
                        split2h(v0, th.x, tl.x);
                        split2h(v1, th.y, tl.y);
                        *(__half2*)(Dh + di) = th;
                        *(__half2*)(Dl + di) = tl;
                        *(float2*)&Cm[(size_t)row * C_ + c0] = make_float2(v0, v1);
                    }
                }
            }
        }
}

// ---------------- relative position bias dots ----------------
__global__ __launch_bounds__(64) void relpos_kernel(const float* __restrict__ rel_h,
                                                    const float* __restrict__ rel_w) {
    int gid = blockIdx.x;
    int bh = gid / QN, i = gid - bh * QN;
    int b = bh >> 3, h = bh & 7;
    int qy = i / 12, qx = i - qy * 12;
    int t = threadIdx.x;
    const float* qrow = g_q + ((size_t)b * QN + i) * C_ + h * HD;
    if (t < 24) {
        const float* R = rel_h + (size_t)(2 * qy - t + 23) * HD;
        float a0 = 0, a1 = 0, a2 = 0, a3 = 0;
        #pragma unroll
        for (int d = 0; d < HD; d += 4) {
            a0 += qrow[d + 0] * R[d + 0];
            a1 += qrow[d + 1] * R[d + 1];
            a2 += qrow[d + 2] * R[d + 2];
            a3 += qrow[d + 3] * R[d + 3];
        }
        g_relh[(size_t)gid * 24 + t] = (a0 + a1) + (a2 + a3);
    } else if (t >= 32 && t < 56) {
        int kx = t - 32;
        const float* R = rel_w + (size_t)(2 * qx - kx + 23) * HD;
        float a0 = 0, a1 = 0, a2 = 0, a3 = 0;
        #pragma unroll
        for (int d = 0; d < HD; d += 4) {
            a0 += qrow[d + 0] * R[d + 0];
            a1 += qrow[d + 1] * R[d + 1];
            a2 += qrow[d + 2] * R[d + 2];
            a3 += qrow[d + 3] * R[d + 3];
        }
        g_relw[(size_t)gid * 24 + kx] = (a0 + a1) + (a2 + a3);
    }
}

// ---------------- FUSED QK^T + bias + softmax + P-split (fp16 2-term) ----------------
// Q fp16 hi/lo resident (48x128), K single fp16 staged in 6 chunks of 96.
#define QKF_QH   0
#define QKF_QL   12288
#define QKF_K0   24576
#define QKF_KBUF 24576
#define QKF_REL  (24576 + 2*24576)     // 73728
#define QKF_RED  (QKF_REL + 9216)
#define QKF_SMEM (QKF_RED + 2304 + 1088)

__global__ __launch_bounds__(576) void qk_fused(
    const __grid_constant__ CUtensorMap tmQh,
    const __grid_constant__ CUtensorMap tmQl,
    const __grid_constant__ CUtensorMap tmK)
{
    extern __shared__ char smem[];
    uint32_t sraw = smem_u32(smem);
    uint32_t fullb[2]  = {sraw, sraw + 8};
    uint32_t emptyb[2] = {sraw + 16, sraw + 24};
    uint32_t tiles = (sraw + 64 + 1023) & ~1023u;
    char* tilesp = smem + (tiles - sraw);
    float* srelh = (float*)(tilesp + QKF_REL);
    float* srelw = srelh + 48 * 24;
    float* smax  = (float*)(tilesp + QKF_RED);
    float* ssum  = smax + 48 * 6;

    int bh = blockIdx.z;
    int rowBase = blockIdx.y * 48;
    int tid = threadIdx.x, lane = tid & 31, warp = tid >> 5;
    int wm = warp / 6, wn = warp % 6;
    int gid = lane >> 2, tig = lane & 3;

    if (tid == 0) {
        MBAR_INIT(fullb[0], 1);  MBAR_INIT(fullb[1], 1);
        MBAR_INIT(emptyb[0], 576); MBAR_INIT(emptyb[1], 576);
    }
    __syncthreads();

    for (int idx = tid; idx < 48 * 24; idx += 576) {
        size_t gidx = ((size_t)bh * QN + rowBase + idx / 24) * 24 + (idx % 24);
        srelh[idx] = g_relh[gidx];
        srelw[idx] = g_relw[gidx];
    }

    int phF[2] = {0, 0}, phE[2] = {0, 0};
    auto issue = [&](int c, int buf) {
        uint32_t kb = tiles + QKF_K0 + buf * QKF_KBUF;
        MBAR_EXPECT_TX(fullb[buf], (c == 0) ? (24576u + QKF_KBUF) : (uint32_t)QKF_KBUF);
        int ky0 = bh * N_ + c * 96;
        if (c == 0) {
            int qy = bh * QN + rowBase;
            TMA_LOAD_2D(tiles + QKF_QH,        &tmQh, 0,  qy, fullb[0]);
            TMA_LOAD_2D(tiles + QKF_QH + 6144, &tmQh, 64, qy, fullb[0]);
            TMA_LOAD_2D(tiles + QKF_QL,        &tmQl, 0,  qy, fullb[0]);
            TMA_LOAD_2D(tiles + QKF_QL + 6144, &tmQl, 64, qy, fullb[0]);
        }
        TMA_LOAD_2D(kb,         &tmK, 0,  ky0, fullb[buf]);
        TMA_LOAD_2D(kb + 12288, &tmK, 64, ky0, fullb[buf]);
    };
    if (tid == 0) { issue(0, 0); issue(1, 1); }

    float acc[12][4];
    #pragma unroll
    for (int j = 0; j < 12; j++)
        #pragma unroll
        for (int r = 0; r < 4; r++) acc[j][r] = 0.f;

    int arow = wm * 16 + (lane & 7) + ((lane >> 3) & 1) * 8;
    int acol8 = (lane >> 4) << 3;
    int brow = wn * 16 + (lane & 7) + ((lane >> 4) & 1) * 8;
    int bcol8 = ((lane >> 3) & 1) * 8;

    for (int c = 0; c < 6; c++) {
        int buf = c & 1;
        MBAR_WAIT(fullb[buf], phF[buf]); phF[buf] ^= 1;
        uint32_t kB = tiles + QKF_K0 + buf * QKF_KBUF;

        #pragma unroll
        for (int kk = 0; kk < 128; kk += 16) {
            uint32_t a_h[4], a_l[4];
            {
                int ce = kk + acol8;
                uint32_t off = (uint32_t)((ce >> 6) * 6144) + swz((uint32_t)(arow * 128 + (ce & 63) * 2));
                LDSM_X4(a_h, tiles + QKF_QH + off);
                LDSM_X4(a_l, tiles + QKF_QL + off);
            }
            uint32_t b_[4];
            {
                int kc = kk + bcol8;
                uint32_t off = (uint32_t)((kc >> 6) * 12288) + swz((uint32_t)(brow * 128 + (kc & 63) * 2));
                LDSM_X4(b_, kB + off);
            }
            #pragma unroll
            for (int j = 0; j < 2; j++) {
                float* A = acc[c * 2 + j];
                MMA_F16(A, a_h, b_[j * 2], b_[j * 2 + 1]);
                MMA_F16(A, a_l, b_[j * 2], b_[j * 2 + 1]);
            }
        }
        MBAR_ARRIVE(emptyb[buf]);
        if (tid == 0 && c + 2 < 6) {
            MBAR_WAIT(emptyb[buf], phE[buf]); phE[buf] ^= 1;
            issue(c + 2, buf);
        }
    }
    __syncthreads();

    const float scale = 0.08838834764831845f;
    int il0 = wm * 16 + gid;
    float mrow[2] = {-1e30f, -1e30f};
    #pragma unroll
    for (int nf = 0; nf < 12; nf++) {
        int colb = (nf >> 1) * 96 + wn * 16 + (nf & 1) * 8 + tig * 2;
        #pragma unroll
        for (int rr = 0; rr < 2; rr++) {
            int il = il0 + rr * 8;
            #pragma unroll
            for (int cc = 0; cc < 2; cc++) {
                int col = colb + cc;
                int ky = col / 24, kx = col - ky * 24;
                float v = acc[nf][rr * 2 + cc] * scale + srelh[il * 24 + ky] + srelw[il * 24 + kx];
                acc[nf][rr * 2 + cc] = v;
                mrow[rr] = fmaxf(mrow[rr], v);
            }
        }
    }
    #pragma unroll
    for (int o = 1; o <= 2; o <<= 1) {
        mrow[0] = fmaxf(mrow[0], __shfl_xor_sync(0xffffffffu, mrow[0], o));
        mrow[1] = fmaxf(mrow[1], __shfl_xor_sync(0xffffffffu, mrow[1], o));
    }
    if (tig == 0) {
        smax[(il0) * 6 + wn] = mrow[0];
        smax[(il0 + 8) * 6 + wn] = mrow[1];
    }
    __syncthreads();
    float M[2];
    #pragma unroll
    for (int rr = 0; rr < 2; rr++) {
        const float* r = smax + (il0 + rr * 8) * 6;
        M[rr] = fmaxf(fmaxf(fmaxf(r[0], r[1]), fmaxf(r[2], r[3])), fmaxf(r[4], r[5]));
    }
    float srow[2] = {0.f, 0.f};
    #pragma unroll
    for (int nf = 0; nf < 12; nf++)
        #pragma unroll
        for (int rr = 0; rr < 2; rr++)
            #pragma unroll
            for (int cc = 0; cc < 2; cc++) {
                float e = __expf(acc[nf][rr * 2 + cc] - M[rr]);
                acc[nf][rr * 2 + cc] = e;
                srow[rr] += e;
            }
    #pragma unroll
    for (int o = 1; o <= 2; o <<= 1) {
        srow[0] += __shfl_xor_sync(0xffffffffu, srow[0], o);
        srow[1] += __shfl_xor_sync(0xffffffffu, srow[1], o);
    }
    if (tig == 0) {
        ssum[(il0) * 6 + wn] = srow[0];
        ssum[(il0 + 8) * 6 + wn] = srow[1];
    }
    __syncthreads();
    float inv[2];
    #pragma unroll
    for (int rr = 0; rr < 2; rr++) {
        const float* r = ssum + (il0 + rr * 8) * 6;
        inv[rr] = 1.0f / ((r[0] + r[1]) + (r[2] + r[3]) + (r[4] + r[5]));
    }
    #pragma unroll
    for (int nf = 0; nf < 12; nf++) {
        int colb = (nf >> 1) * 96 + wn * 16 + (nf & 1) * 8 + tig * 2;
        #pragma unroll
        for (int rr = 0; rr < 2; rr++) {
            size_t off = ((size_t)bh * QN + rowBase + il0 + rr * 8) * N_ + colb;
            __half2 th, tl;
            split2h(acc[nf][rr * 2 + 0] * inv[rr], th.x, tl.x);
            split2h(acc[nf][rr * 2 + 1] * inv[rr], th.y, tl.y);
            *(__half2*)(g_ph2 + off) = th;
            *(__half2*)(g_pl2 + off) = tl;
        }
    }
}

// ---------------- AV mma (fp16 2-term): P hi/lo, V single ----------------
#define AV_PH   0
#define AV_PL   6144
#define AV_V    12288
#define AV_BUF  28672
#define AV_SMEM (2*AV_BUF + 2048)

__global__ __launch_bounds__(192) void av_mma(
    const __grid_constant__ CUtensorMap tmPh,
    const __grid_constant__ CUtensorMap tmPl,
    const __grid_constant__ CUtensorMap tmV)
{
    extern __shared__ char smem[];
    uint32_t sraw = smem_u32(smem);
    uint32_t fullb[2]  = {sraw, sraw + 8};
    uint32_t emptyb[2] = {sraw + 16, sraw + 24};
    uint32_t tiles = (sraw + 64 + 1023) & ~1023u;

    int bh = blockIdx.z;
    int b = bh >> 3, h = bh & 7;
    int rowBase = blockIdx.y * 48;
    int tid = threadIdx.x, lane = tid & 31, warp = tid >> 5;
    int wm = warp >> 1, wn = warp & 1;
    int nBase = wn * 64;

    if (tid == 0) {
        MBAR_INIT(fullb[0], 1);  MBAR_INIT(fullb[1], 1);
        MBAR_INIT(emptyb[0], 192); MBAR_INIT(emptyb[1], 192);
    }
    __syncthreads();

    float acc[8][4];
    #pragma unroll
    for (int j = 0; j < 8; j++)
        #pragma unroll
        for (int r = 0; r < 4; r++) acc[j][r] = 0.f;

    int phF[2] = {0, 0};
    int phE[2] = {1, 1};

    auto issue = [&](int s, int buf) {
        uint32_t base = tiles + buf * AV_BUF;
        MBAR_EXPECT_TX(fullb[buf], AV_BUF);
        int k0 = s * 64;
        int py = bh * QN + rowBase;
        int vy = bh * N_ + k0;
        TMA_LOAD_2D(base + AV_PH, &tmPh, k0, py, fullb[buf]);
        TMA_LOAD_2D(base + AV_PL, &tmPl, k0, py, fullb[buf]);
        TMA_LOAD_2D(base + AV_V,        &tmV, 0,  vy, fullb[buf]);
        TMA_LOAD_2D(base + AV_V + 8192, &tmV, 64, vy, fullb[buf]);
    };

    if (tid == 0) {
        MBAR_WAIT(emptyb[0], phE[0]); phE[0] ^= 1;
        issue(0, 0);
    }

    for (int s = 0; s < 9; s++) {
        int buf = s & 1;
        if (tid == 0 && s + 1 < 9) {
            int nb = buf ^ 1;
            MBAR_WAIT(emptyb[nb], phE[nb]); phE[nb] ^= 1;
            issue(s + 1, nb);
        }
        MBAR_WAIT(fullb[buf], phF[buf]); phF[buf] ^= 1;
        uint32_t base = tiles + buf * AV_BUF;

        #pragma unroll
        for (int kk = 0; kk < 64; kk += 16) {
            uint32_t ah[4], al[4];
            {
                int row = wm * 16 + (lane & 7) + ((lane >> 3) & 1) * 8;
                int ce  = kk + ((lane >> 4) << 3);
                uint32_t off = swz((uint32_t)(row * 128 + ce * 2));
                LDSM_X4(ah, base + AV_PH + off);
                LDSM_X4(al, base + AV_PL + off);
            }
            uint32_t bvf[4][4];
            #pragma unroll
            for (int g = 0; g < 4; g++) {
                int vrow = kk + (lane & 15);
                int d    = nBase + g * 16 + ((lane >> 4) << 3);
                uint32_t off = (uint32_t)((d >> 6) * 8192) + swz((uint32_t)(vrow * 128 + (d & 63) * 2));
                LDSM_X4T(bvf[g], base + AV_V + off);
            }
            #pragma unroll
            for (int nf = 0; nf < 8; nf++) {
                uint32_t b0 = bvf[nf >> 1][(nf & 1) * 2 + 0];
                uint32_t b1 = bvf[nf >> 1][(nf & 1) * 2 + 1];
                MMA_F16(acc[nf], ah, b0, b1);
                MMA_F16(acc[nf], al, b0, b1);
            }
        }
        MBAR_ARRIVE(emptyb[buf]);
    }

    int gid = lane >> 2, tig = lane & 3;
    #pragma unroll
    for (int nf = 0; nf < 8; nf++) {
        int d = nBase + nf * 8 + tig * 2;
        #pragma unroll
        for (int rr = 0; rr < 2; rr++) {
            int i = rowBase + wm * 16 + gid + rr * 8;
            size_t off = ((size_t)b * QN + i) * C_ + h * HD + d;
            float2 qv = *(const float2*)(g_q + off);
            float v0 = acc[nf][rr * 2 + 0] + qv.x;
            float v1 = acc[nf][rr * 2 + 1] + qv.y;
            __half2 th, tl;
            split2h(v0, th.x, tl.x);
            split2h(v1, th.y, tl.y);
            *(__half2*)(g_aoh2 + off) = th;
            *(__half2*)(g_aol2 + off) = tl;
        }
    }
}

// ---------------- host: tensormap builder ----------------
typedef CUresult (*EncodeTiledFn)(CUtensorMap*, CUtensorMapDataType, cuuint32_t, void*,
                                  const cuuint64_t*, const cuuint64_t*, const cuuint32_t*,
                                  const cuuint32_t*, CUtensorMapInterleave, CUtensorMapSwizzle,
                                  CUtensorMapL2promotion, CUtensorMapFloatOOBfill);

static void make_map(EncodeTiledFn enc, CUtensorMap* m, void* ptr,
                     uint64_t dim0, uint64_t rows, uint32_t box0, uint32_t box1) {
    cuuint64_t dims[2]    = {(cuuint64_t)dim0, (cuuint64_t)rows};
    cuuint64_t strides[1] = {(cuuint64_t)dim0 * 2};
    cuuint32_t box[2]     = {box0, box1};
    cuuint32_t es[2]      = {1, 1};
    enc(m, CU_TENSOR_MAP_DATA_TYPE_FLOAT16, 2, ptr, dims, strides, box, es,
        CU_TENSOR_MAP_INTERLEAVE_NONE, CU_TENSOR_MAP_SWIZZLE_128B,
        CU_TENSOR_MAP_L2_PROMOTION_L2_128B, CU_TENSOR_MAP_FLOAT_OOB_FILL_NONE);
}

// ---------------- launch ----------------
extern "C" void kernel_launch(void* const* d_in, const int* in_sizes, int n_in,
                              void* d_out, int out_size) {
    const float* x   = (const float*)d_in[0];
    const float* Wq  = (const float*)d_in[1];
    const float* Wk  = (const float*)d_in[2];
    const float* Wv  = (const float*)d_in[3];
    const float* Wp  = (const float*)d_in[4];
    const float* bp  = (const float*)d_in[5];
    const float* rph = (const float*)d_in[6];
    const float* rpw = (const float*)d_in[7];
    float* out = (float*)d_out;

    float *q;
    __half *axh2, *axl2, *aqh2, *aql2, *aoh2, *aol2;
    __half *wq2, *wk2, *wv2, *wp2;
    __half *qh2, *ql2, *k2, *v2, *ph2, *pl2;
    cudaGetSymbolAddress((void**)&q,  g_q);
    cudaGetSymbolAddress((void**)&axh2, g_axh2);
    cudaGetSymbolAddress((void**)&axl2, g_axl2);
    cudaGetSymbolAddress((void**)&aqh2, g_aqh2);
    cudaGetSymbolAddress((void**)&aql2, g_aql2);
    cudaGetSymbolAddress((void**)&aoh2, g_aoh2);
    cudaGetSymbolAddress((void**)&aol2, g_aol2);
    cudaGetSymbolAddress((void**)&wq2, g_wq2);
    cudaGetSymbolAddress((void**)&wk2, g_wk2);
    cudaGetSymbolAddress((void**)&wv2, g_wv2);
    cudaGetSymbolAddress((void**)&wp2, g_wp2);
    cudaGetSymbolAddress((void**)&qh2, g_qh2);
    cudaGetSymbolAddress((void**)&ql2, g_ql2);
    cudaGetSymbolAddress((void**)&k2, g_k2);
    cudaGetSymbolAddress((void**)&v2, g_v2);
    cudaGetSymbolAddress((void**)&ph2, g_ph2);
    cudaGetSymbolAddress((void**)&pl2, g_pl2);

    EncodeTiledFn enc = nullptr;
    {
        void* fn = nullptr;
        cudaDriverEntryPointQueryResult st;
        cudaGetDriverEntryPoint("cuTensorMapEncodeTiled", &fn, cudaEnableDefault, &st);
        enc = (EncodeTiledFn)fn;
    }
    CUtensorMap mAxh, mAxl, mAqh, mAql, mAoh, mAol;
    CUtensorMap mWq, mWk, mWv, mWp;
    CUtensorMap mQh, mQl, mK, mV, mPh, mPl;
    make_map(enc, &mAxh, axh2, C_, (uint64_t)B_ * N_, 64, 128);
    make_map(enc, &mAxl, axl2, C_, (uint64_t)B_ * N_, 64, 128);
    make_map(enc, &mAqh, aqh2, C_, (uint64_t)B_ * QN, 64, 128);
    make_map(enc, &mAql, aql2, C_, (uint64_t)B_ * QN, 64, 128);
    make_map(enc, &mAoh, aoh2, C_, (uint64_t)B_ * QN, 64, 128);
    make_map(enc, &mAol, aol2, C_, (uint64_t)B_ * QN, 64, 128);
    make_map(enc, &mWq, wq2, C_, C_, 64, 128);
    make_map(enc, &mWk, wk2, C_, C_, 64, 128);
    make_map(enc, &mWv, wv2, C_, C_, 64, 128);
    make_map(enc, &mWp, wp2, C_, C_, 64, 128);
    make_map(enc, &mQh, qh2, HD, (uint64_t)BH * QN, 64, 48);
    make_map(enc, &mQl, ql2, HD, (uint64_t)BH * QN, 64, 48);
    make_map(enc, &mK,  k2,  HD, (uint64_t)BH * N_, 64, 96);
    make_map(enc, &mV,  v2,  HD, (uint64_t)BH * N_, 64, 64);
    make_map(enc, &mPh, ph2, N_, (uint64_t)BH * QN, 64, 48);
    make_map(enc, &mPl, pl2, N_, (uint64_t)BH * QN, 64, 48);

    cudaFuncSetAttribute(gemm_f16, cudaFuncAttributeMaxDynamicSharedMemorySize, G2_SMEM);
    cudaFuncSetAttribute(qk_fused, cudaFuncAttributeMaxDynamicSharedMemorySize, QKF_SMEM);
    cudaFuncSetAttribute(av_mma, cudaFuncAttributeMaxDynamicSharedMemorySize, AV_SMEM);

    // GEMMs at positions 3 and 5 for ncu (-s 5 -c 1) coverage
    split_x2_kernel<<<dim3(18, 32, B_), dim3(32, 8)>>>(x);
    split_wT_f16_kernel<<<dim3(32, 32), dim3(32, 8)>>>(Wk, wk2);
    gemm_f16<<<dim3(8, (B_ * N_) / 128), 512, G2_SMEM>>>(mAxh, mAxl, mWk, nullptr, nullptr, nullptr, nullptr, k2, N_, 2);
    split_wT_f16_kernel<<<dim3(32, 32), dim3(32, 8)>>>(Wv, wv2);
    gemm_f16<<<dim3(8, (B_ * N_) / 128), 512, G2_SMEM>>>(mAxh, mAxl, mWv, nullptr, nullptr, nullptr, nullptr, v2, N_, 2);

    split_wT_f16_kernel<<<dim3(32, 32), dim3(32, 8)>>>(Wq, wq2);
    pool_kernel<<<dim3(C_ / 16, B_), 256>>>(x);
    gemm_f16<<<dim3(8, (B_ * QN) / 128), 512, G2_SMEM>>>(mAqh, mAql, mWq, nullptr, q, qh2, ql2, nullptr, QN, 3);

    relpos_kernel<<<BH * QN, 64>>>(rph, rpw);
    qk_fused<<<dim3(1, 3, BH), 576, QKF_SMEM>>>(mQh, mQl, mK);
    av_mma<<<dim3(1, 3, BH), 192, AV_SMEM>>>(mPh, mPl, mV);

    split_wT_f16_kernel<<<dim3(32, 32), dim3(32, 8)>>>(Wp, wp2);
    gemm_f16<<<dim3(8, (B_ * QN) / 128), 512, G2_SMEM>>>(mAoh, mAol, mWp, bp, out, nullptr, nullptr, nullptr, QN, 1);
}

// round 13
// speedup vs baseline: 2.9923x; 1.0029x over previous
#include <cuda.h>
#include <cuda_runtime.h>
#include <cuda_bf16.h>
#include <cuda_fp16.h>
#include <math.h>
#include <stdint.h>

#define B_  128
#define C_  1024
#define H_  24
#define W_  24
#define N_  576
#define NH  8
#define HD  128
#define QH  12
#define QW  12
#define QN  144
#define BH  (B_*NH)

// ---------------- fp32 scratch ----------------
__device__ float g_q   [(size_t)B_*QN*C_];
__device__ float g_relh[(size_t)BH*QN*H_];
__device__ float g_relw[(size_t)BH*QN*W_];
// fp16 hi/lo A operands
__device__ __half g_axh2[(size_t)B_*N_*C_];
__device__ __half g_axl2[(size_t)B_*N_*C_];
__device__ __half g_aqh2[(size_t)B_*QN*C_];
__device__ __half g_aql2[(size_t)B_*QN*C_];
__device__ __half g_aoh2[(size_t)B_*QN*C_];
__device__ __half g_aol2[(size_t)B_*QN*C_];
// TRANSPOSED weights [N,K], single fp16
__device__ __half g_wq2[(size_t)C_*C_];
__device__ __half g_wk2[(size_t)C_*C_];
__device__ __half g_wv2[(size_t)C_*C_];
__device__ __half g_wp2[(size_t)C_*C_];
// head-major fp16 tensors
__device__ __half g_qh2[(size_t)BH*QN*HD];
__device__ __half g_ql2[(size_t)BH*QN*HD];
__device__ __half g_k2 [(size_t)BH*N_*HD];
__device__ __half g_v2 [(size_t)BH*N_*HD];
__device__ __half g_ph2[(size_t)BH*QN*N_];
__device__ __half g_pl2[(size_t)BH*QN*N_];

// ---------------- helpers ----------------
__device__ __forceinline__ void split2h(float v, __half& hi, __half& lo) {
    hi = __float2half(v);
    lo = __float2half(v - __half2float(hi));
}
__device__ __forceinline__ uint32_t smem_u32(const void* p) {
    return (uint32_t)__cvta_generic_to_shared(p);
}
__device__ __forceinline__ uint32_t swz(uint32_t o) {
    return o ^ ((o >> 3) & 0x70);
}

#define MMA_F16(ACC, A, B0, B1)                                               \
    asm volatile(                                                             \
        "mma.sync.aligned.m16n8k16.row.col.f32.f16.f16.f32 "                  \
        "{%0,%1,%2,%3}, {%4,%5,%6,%7}, {%8,%9}, {%0,%1,%2,%3};"               \
        : "+f"((ACC)[0]), "+f"((ACC)[1]), "+f"((ACC)[2]), "+f"((ACC)[3])      \
        : "r"((A)[0]), "r"((A)[1]), "r"((A)[2]), "r"((A)[3]),                 \
          "r"(B0), "r"(B1))

#define LDSM_X4(R, ADDR)                                                      \
    asm volatile("ldmatrix.sync.aligned.m8n8.x4.shared.b16 {%0,%1,%2,%3}, [%4];" \
                 : "=r"((R)[0]), "=r"((R)[1]), "=r"((R)[2]), "=r"((R)[3]) : "r"(ADDR))
#define LDSM_X4T(R, ADDR)                                                     \
    asm volatile("ldmatrix.sync.aligned.m8n8.x4.trans.shared.b16 {%0,%1,%2,%3}, [%4];" \
                 : "=r"((R)[0]), "=r"((R)[1]), "=r"((R)[2]), "=r"((R)[3]) : "r"(ADDR))

#define MBAR_INIT(mb, cnt) \
    asm volatile("mbarrier.init.shared.b64 [%0], %1;" :: "r"(mb), "r"((uint32_t)(cnt)) : "memory")
#define MBAR_EXPECT_TX(mb, bytes) \
    asm volatile("mbarrier.arrive.expect_tx.shared.b64 _, [%0], %1;" :: "r"(mb), "r"((uint32_t)(bytes)) : "memory")
#define MBAR_ARRIVE(mb) \
    asm volatile("mbarrier.arrive.shared.b64 _, [%0];" :: "r"(mb) : "memory")
#define MBAR_WAIT(mb, ph) do {                                                    \
    asm volatile("{\n\t.reg .pred P1;\n\t"                                        \
        "WAIT_LOOP_%=:\n\t"                                                       \
        "mbarrier.try_wait.parity.acquire.cta.shared::cta.b64 P1, [%0], %1, 0x989680;\n\t" \
        "@P1 bra.uni WAIT_DONE_%=;\n\t"                                           \
        "bra.uni WAIT_LOOP_%=;\n\t"                                               \
        "WAIT_DONE_%=:\n\t}"                                                      \
        :: "r"(mb), "r"((uint32_t)(ph)) : "memory");                              \
} while(0)

#define TMA_LOAD_2D(sa, map, cx, cy, mb)                                          \
    asm volatile("cp.async.bulk.tensor.2d.shared::cta.global.tile.mbarrier::complete_tx::bytes " \
        "[%0], [%1, {%2, %3}], [%4];"                                             \
        :: "r"(sa), "l"(map), "r"((int32_t)(cx)), "r"((int32_t)(cy)), "r"(mb) : "memory")

// ---------------- conversions ----------------
__global__ __launch_bounds__(256) void split_wT_f16_kernel(const float* __restrict__ W,
                                                           __half* __restrict__ WT) {
    __shared__ float t[32][33];
    int k0 = blockIdx.x * 32, n0 = blockIdx.y * 32;
    int tx = threadIdx.x, ty = threadIdx.y;
    #pragma unroll
    for (int i = 0; i < 4; i++)
        t[ty + i * 8][tx] = W[(size_t)(k0 + ty + i * 8) * C_ + n0 + tx];
    __syncthreads();
    #pragma unroll
    for (int i = 0; i < 4; i++)
        WT[(size_t)(n0 + ty + i * 8) * C_ + k0 + tx] = __float2half(t[tx][ty + i * 8]);
}

__global__ __launch_bounds__(256) void split_x2_kernel(const float* __restrict__ x) {
    __shared__ float tile[32][33];
    int b  = blockIdx.z;
    int n0 = blockIdx.x * 32;
    int c0 = blockIdx.y * 32;
    int tx = threadIdx.x, ty = threadIdx.y;
    const float* xb = x + (size_t)b * C_ * N_;
    #pragma unroll
    for (int i = 0; i < 4; i++)
        tile[ty + i * 8][tx] = xb[(size_t)(c0 + ty + i * 8) * N_ + n0 + tx];
    __syncthreads();
    #pragma unroll
    for (int i = 0; i < 4; i++) {
        int n = n0 + ty + i * 8;
        size_t base = ((size_t)b * N_ + n) * C_ + c0 + tx;
        __half h2, l2; split2h(tile[tx][ty + i * 8], h2, l2);
        g_axh2[base] = h2; g_axl2[base] = l2;
    }
}

// ---------------- avg-pool -> aq fp16 hi/lo ----------------
__global__ __launch_bounds__(256) void pool_kernel(const float* __restrict__ x) {
    __shared__ float sp[16][577];
    int b  = blockIdx.y;
    int c0 = blockIdx.x * 16;
    int tid = threadIdx.x;
    const float* xb = x + (size_t)b * C_ * N_ + (size_t)c0 * N_;
    #pragma unroll
    for (int r = 0; r < 36; r++) {
        int idx = tid + r * 256;
        int p = idx / 576, n = idx - p * 576;
        sp[p][n] = xb[(size_t)p * N_ + n];
    }
    __syncthreads();
    #pragma unroll
    for (int r = 0; r < 9; r++) {
        int idx = tid + r * 256;
        int qn = idx >> 4, cl = idx & 15;
        int qy = qn / 12, qx = qn - qy * 12;
        float s = 0.f;
        #pragma unroll
        for (int dy = -1; dy <= 1; dy++) {
            int y = 2 * qy + dy;
            if ((unsigned)y < 24u) {
                #pragma unroll
                for (int dx = -1; dx <= 1; dx++) {
                    int xx = 2 * qx + dx;
                    if ((unsigned)xx < 24u) s += sp[cl][y * 24 + xx];
                }
            }
        }
        __half hi, lo; split2h(s * (1.0f / 9.0f), hi, lo);
        size_t o = ((size_t)b * QN + qn) * C_ + c0 + cl;
        g_aqh2[o] = hi; g_aql2[o] = lo;
    }
}

// ---------------- fp16 2-term GEMM core (macro-shared body) ----------------
#define G2_TILE  16384
#define G2_BUF   (3*G2_TILE)
#define G2_SMEM  (3*G2_BUF + 1024)
#define NSTAGE   16

// Mainloop shared by gemm_f16 and gemm_kv. Produces acc[2][4][4].
#define GEMM_MAINLOOP(PTR_AH, PTR_AL, PTR_B)                                       \
    if (tid == 0) { issue(0, 0); issue(1, 1); issue(2, 2); }                       \
    uint32_t ah[2][2][4], al[2][2][4], bf[2][2][4];                                \
    int arow0 = wm * 32 + (lane & 7) + ((lane >> 3) & 1) * 8;                      \
    int acol8 = (lane >> 4) << 3;                                                  \
    int brow0 = wn * 32 + (lane & 7) + ((lane >> 4) & 1) * 8;                      \
    int bcol8 = (lane >> 3) & 1 ? 8 : 0;                                           \
    for (int s = 0; s < NSTAGE; s++) {                                             \
        int slot = s % 3;                                                          \
        MBAR_WAIT(fullb[slot], phF[slot]); phF[slot] ^= 1;                         \
        uint32_t aH = tiles + slot * G2_BUF;                                       \
        uint32_t aL = aH + G2_TILE;                                                \
        uint32_t bB = aH + 2 * G2_TILE;                                            \
        {                                                                          \
            _Pragma("unroll")                                                      \
            for (int mf = 0; mf < 2; mf++) {                                       \
                uint32_t off = swz((uint32_t)((arow0 + mf * 16) * 128 + acol8 * 2)); \
                LDSM_X4(ah[0][mf], aH + off);                                      \
                LDSM_X4(al[0][mf], aL + off);                                      \
            }                                                                      \
            _Pragma("unroll")                                                      \
            for (int g = 0; g < 2; g++) {                                          \
                uint32_t off = swz((uint32_t)((brow0 + g * 16) * 128 + bcol8 * 2)); \
                LDSM_X4(bf[0][g], bB + off);                                       \
            }                                                                      \
        }                                                                          \
        _Pragma("unroll")                                                          \
        for (int kki = 0; kki < 4; kki++) {                                        \
            int pb = kki & 1;                                                      \
            if (kki < 3) {                                                         \
                int nb = pb ^ 1;                                                   \
                int kk = (kki + 1) * 16;                                           \
                _Pragma("unroll")                                                  \
                for (int mf = 0; mf < 2; mf++) {                                   \
                    uint32_t off = swz((uint32_t)((arow0 + mf * 16) * 128 + (kk + acol8) * 2)); \
                    LDSM_X4(ah[nb][mf], aH + off);                                 \
                    LDSM_X4(al[nb][mf], aL + off);                                 \
                }                                                                  \
                _Pragma("unroll")                                                  \
                for (int g = 0; g < 2; g++) {                                      \
                    uint32_t off = swz((uint32_t)((brow0 + g * 16) * 128 + (kk + bcol8) * 2)); \
                    LDSM_X4(bf[nb][g], bB + off);                                  \
                }                                                                  \
            }                                                                      \
            _Pragma("unroll")                                                      \
            for (int mf = 0; mf < 2; mf++)                                         \
                _Pragma("unroll")                                                  \
                for (int nf = 0; nf < 4; nf++) {                                   \
                    uint32_t b0 = bf[pb][nf >> 1][(nf & 1) * 2 + 0];               \
                    uint32_t b1 = bf[pb][nf >> 1][(nf & 1) * 2 + 1];               \
                    MMA_F16(acc[mf][nf], ah[pb][mf], b0, b1);                      \
                    MMA_F16(acc[mf][nf], al[pb][mf], b0, b1);                      \
                }                                                                  \
        }                                                                          \
        MBAR_ARRIVE(emptyb[slot]);                                                 \
        if (tid == 0 && s + 3 < NSTAGE) {                                          \
            MBAR_WAIT(emptyb[slot], phE[slot]); phE[slot] ^= 1;                    \
            issue(s + 3, slot);                                                    \
        }                                                                          \
    }

// merged K/V projection: blockIdx.z selects B matrix and destination
__global__ __launch_bounds__(512) void gemm_kv(
    const __grid_constant__ CUtensorMap tmAh,
    const __grid_constant__ CUtensorMap tmAl,
    const __grid_constant__ CUtensorMap tmBk,
    const __grid_constant__ CUtensorMap tmBv,
    __half* __restrict__ Dk,
    __half* __restrict__ Dv)
{
    extern __shared__ char smem[];
    uint32_t sraw = smem_u32(smem);
    uint32_t fullb[3]  = {sraw, sraw + 8, sraw + 16};
    uint32_t emptyb[3] = {sraw + 24, sraw + 32, sraw + 40};
    uint32_t tiles = (sraw + 64 + 1023) & ~1023u;

    int tid = threadIdx.x, lane = tid & 31, warp = tid >> 5;
    int wm = warp >> 2, wn = warp & 3;
    int rowBase = blockIdx.y * 128;
    int colBase = blockIdx.x * 128;
    const CUtensorMap* pB = blockIdx.z ? &tmBv : &tmBk;
    __half* Ds = blockIdx.z ? Dv : Dk;

    if (tid == 0) {
        MBAR_INIT(fullb[0], 1);  MBAR_INIT(fullb[1], 1);  MBAR_INIT(fullb[2], 1);
        MBAR_INIT(emptyb[0], 512); MBAR_INIT(emptyb[1], 512); MBAR_INIT(emptyb[2], 512);
    }
    __syncthreads();

    float acc[2][4][4];
    #pragma unroll
    for (int i = 0; i < 2; i++)
        #pragma unroll
        for (int j = 0; j < 4; j++)
            #pragma unroll
            for (int r = 0; r < 4; r++) acc[i][j][r] = 0.f;

    int phF[3] = {0, 0, 0};
    int phE[3] = {0, 0, 0};
    auto issue = [&](int s, int slot) {
        uint32_t base = tiles + slot * G2_BUF;
        MBAR_EXPECT_TX(fullb[slot], G2_BUF);
        int k0 = s * 64;
        TMA_LOAD_2D(base,               &tmAh, k0, rowBase, fullb[slot]);
        TMA_LOAD_2D(base + G2_TILE,     &tmAl, k0, rowBase, fullb[slot]);
        TMA_LOAD_2D(base + 2 * G2_TILE, pB,    k0, colBase, fullb[slot]);
    };

    GEMM_MAINLOOP(tmAh, tmAl, pB)

    int gid = lane >> 2, tig = lane & 3;
    #pragma unroll
    for (int mf = 0; mf < 2; mf++)
        #pragma unroll
        for (int nf = 0; nf < 4; nf++) {
            int c0 = colBase + wn * 32 + nf * 8 + tig * 2;
            #pragma unroll
            for (int rr = 0; rr < 2; rr++) {
                int row = rowBase + wm * 32 + mf * 16 + gid + rr * 8;
                int b = row / N_, n = row - b * N_;
                int h = c0 >> 7, d = c0 & 127;
                size_t di = (((size_t)b * NH + h) * N_ + n) * HD + d;
                __half2 hv = __floats2half2_rn(acc[mf][nf][rr * 2 + 0], acc[mf][nf][rr * 2 + 1]);
                *(__half2*)(Ds + di) = hv;
            }
        }
}

// generic projection (Q: mode 3, P: mode 1)
__global__ __launch_bounds__(512) void gemm_f16(
    const __grid_constant__ CUtensorMap tmAh,
    const __grid_constant__ CUtensorMap tmAl,
    const __grid_constant__ CUtensorMap tmB,
    const float* __restrict__ bias,
    float* __restrict__ Cm,
    __half* __restrict__ Dh,
    __half* __restrict__ Dl,
    int rpb, int mode)
{
    extern __shared__ char smem[];
    uint32_t sraw = smem_u32(smem);
    uint32_t fullb[3]  = {sraw, sraw + 8, sraw + 16};
    uint32_t emptyb[3] = {sraw + 24, sraw + 32, sraw + 40};
    uint32_t tiles = (sraw + 64 + 1023) & ~1023u;

    int tid = threadIdx.x, lane = tid & 31, warp = tid >> 5;
    int wm = warp >> 2, wn = warp & 3;
    int rowBase = blockIdx.y * 128;
    int colBase = blockIdx.x * 128;

    if (tid == 0) {
        MBAR_INIT(fullb[0], 1);  MBAR_INIT(fullb[1], 1);  MBAR_INIT(fullb[2], 1);
        MBAR_INIT(emptyb[0], 512); MBAR_INIT(emptyb[1], 512); MBAR_INIT(emptyb[2], 512);
    }
    __syncthreads();

    float acc[2][4][4];
    #pragma unroll
    for (int i = 0; i < 2; i++)
        #pragma unroll
        for (int j = 0; j < 4; j++)
            #pragma unroll
            for (int r = 0; r < 4; r++) acc[i][j][r] = 0.f;

    int phF[3] = {0, 0, 0};
    int phE[3] = {0, 0, 0};
    auto issue = [&](int s, int slot) {
        uint32_t base = tiles + slot * G2_BUF;
        MBAR_EXPECT_TX(fullb[slot], G2_BUF);
        int k0 = s * 64;
        TMA_LOAD_2D(base,               &tmAh, k0, rowBase, fullb[slot]);
        TMA_LOAD_2D(base + G2_TILE,     &tmAl, k0, rowBase, fullb[slot]);
        TMA_LOAD_2D(base + 2 * G2_TILE, &tmB,  k0, colBase, fullb[slot]);
    };

    GEMM_MAINLOOP(tmAh, tmAl, &tmB)

    int gid = lane >> 2, tig = lane & 3;
    #pragma unroll
    for (int mf = 0; mf < 2; mf++)
        #pragma unroll
        for (int nf = 0; nf < 4; nf++) {
            int c0 = colBase + wn * 32 + nf * 8 + tig * 2;
            #pragma unroll
            for (int rr = 0; rr < 2; rr++) {
                int row = rowBase + wm * 32 + mf * 16 + gid + rr * 8;
                float v0 = acc[mf][nf][rr * 2 + 0];
                float v1 = acc[mf][nf][rr * 2 + 1];
                if (mode == 1) {
                    int bq = row / QN, qi = row - bq * QN;
                    Cm[((size_t)bq * C_ + c0) * QN + qi]     = v0 + bias[c0];
                    Cm[((size_t)bq * C_ + c0 + 1) * QN + qi] = v1 + bias[c0 + 1];
                } else {
                    int b = row / rpb, n = row - b * rpb;
                    int h = c0 >> 7, d = c0 & 127;
                    size_t di = (((size_t)b * NH + h) * rpb + n) * HD + d;
                    __half2 th, tl;
                    split2h(v0, th.x, tl.x);
                    split2h(v1, th.y, tl.y);
                    *(__half2*)(Dh + di) = th;
                    *(__half2*)(Dl + di) = tl;
                    *(float2*)&Cm[(size_t)row * C_ + c0] = make_float2(v0, v1);
                }
            }
        }
}

// ---------------- relative position bias dots ----------------
__global__ __launch_bounds__(64) void relpos_kernel(const float* __restrict__ rel_h,
                                                    const float* __restrict__ rel_w) {
    int gid = blockIdx.x;
    int bh = gid / QN, i = gid - bh * QN;
    int b = bh >> 3, h = bh & 7;
    int qy = i / 12, qx = i - qy * 12;
    int t = threadIdx.x;
    const float* qrow = g_q + ((size_t)b * QN + i) * C_ + h * HD;
    if (t < 24) {
        const float* R = rel_h + (size_t)(2 * qy - t + 23) * HD;
        float a0 = 0, a1 = 0, a2 = 0, a3 = 0;
        #pragma unroll
        for (int d = 0; d < HD; d += 4) {
            a0 += qrow[d + 0] * R[d + 0];
            a1 += qrow[d + 1] * R[d + 1];
            a2 += qrow[d + 2] * R[d + 2];
            a3 += qrow[d + 3] * R[d + 3];
        }
        g_relh[(size_t)gid * 24 + t] = (a0 + a1) + (a2 + a3);
    } else if (t >= 32 && t < 56) {
        int kx = t - 32;
        const float* R = rel_w + (size_t)(2 * qx - kx + 23) * HD;
        float a0 = 0, a1 = 0, a2 = 0, a3 = 0;
        #pragma unroll
        for (int d = 0; d < HD; d += 4) {
            a0 += qrow[d + 0] * R[d + 0];
            a1 += qrow[d + 1] * R[d + 1];
            a2 += qrow[d + 2] * R[d + 2];
            a3 += qrow[d + 3] * R[d + 3];
        }
        g_relw[(size_t)gid * 24 + kx] = (a0 + a1) + (a2 + a3);
    }
}

// ---------------- FUSED QK^T + bias + softmax + P-split ----------------
#define QKF_QH   0
#define QKF_QL   12288
#define QKF_K0   24576
#define QKF_KBUF 24576
#define QKF_REL  (24576 + 2*24576)
#define QKF_RED  (QKF_REL + 9216)
#define QKF_SMEM (QKF_RED + 2304 + 1088)

__global__ __launch_bounds__(576) void qk_fused(
    const __grid_constant__ CUtensorMap tmQh,
    const __grid_constant__ CUtensorMap tmQl,
    const __grid_constant__ CUtensorMap tmK)
{
    extern __shared__ char smem[];
    uint32_t sraw = smem_u32(smem);
    uint32_t fullb[2]  = {sraw, sraw + 8};
    uint32_t emptyb[2] = {sraw + 16, sraw + 24};
    uint32_t tiles = (sraw + 64 + 1023) & ~1023u;
    char* tilesp = smem + (tiles - sraw);
    float* srelh = (float*)(tilesp + QKF_REL);
    float* srelw = srelh + 48 * 24;
    float* smax  = (float*)(tilesp + QKF_RED);
    float* ssum  = smax + 48 * 6;

    int bh = blockIdx.z;
    int rowBase = blockIdx.y * 48;
    int tid = threadIdx.x, lane = tid & 31, warp = tid >> 5;
    int wm = warp / 6, wn = warp % 6;
    int gid = lane >> 2, tig = lane & 3;

    if (tid == 0) {
        MBAR_INIT(fullb[0], 1);  MBAR_INIT(fullb[1], 1);
        MBAR_INIT(emptyb[0], 576); MBAR_INIT(emptyb[1], 576);
    }
    __syncthreads();

    for (int idx = tid; idx < 48 * 24; idx += 576) {
        size_t gidx = ((size_t)bh * QN + rowBase + idx / 24) * 24 + (idx % 24);
        srelh[idx] = g_relh[gidx];
        srelw[idx] = g_relw[gidx];
    }

    int phF[2] = {0, 0}, phE[2] = {0, 0};
    auto issue = [&](int c, int buf) {
        uint32_t kb = tiles + QKF_K0 + buf * QKF_KBUF;
        MBAR_EXPECT_TX(fullb[buf], (c == 0) ? (24576u + QKF_KBUF) : (uint32_t)QKF_KBUF);
        int ky0 = bh * N_ + c * 96;
        if (c == 0) {
            int qy = bh * QN + rowBase;
            TMA_LOAD_2D(tiles + QKF_QH,        &tmQh, 0,  qy, fullb[0]);
            TMA_LOAD_2D(tiles + QKF_QH + 6144, &tmQh, 64, qy, fullb[0]);
            TMA_LOAD_2D(tiles + QKF_QL,        &tmQl, 0,  qy, fullb[0]);
            TMA_LOAD_2D(tiles + QKF_QL + 6144, &tmQl, 64, qy, fullb[0]);
        }
        TMA_LOAD_2D(kb,         &tmK, 0,  ky0, fullb[buf]);
        TMA_LOAD_2D(kb + 12288, &tmK, 64, ky0, fullb[buf]);
    };
    if (tid == 0) { issue(0, 0); issue(1, 1); }

    float acc[12][4];
    #pragma unroll
    for (int j = 0; j < 12; j++)
        #pragma unroll
        for (int r = 0; r < 4; r++) acc[j][r] = 0.f;

    int arow = wm * 16 + (lane & 7) + ((lane >> 3) & 1) * 8;
    int acol8 = (lane >> 4) << 3;
    int brow = wn * 16 + (lane & 7) + ((lane >> 4) & 1) * 8;
    int bcol8 = ((lane >> 3) & 1) * 8;

    for (int c = 0; c < 6; c++) {
        int buf = c & 1;
        MBAR_WAIT(fullb[buf], phF[buf]); phF[buf] ^= 1;
        uint32_t kB = tiles + QKF_K0 + buf * QKF_KBUF;

        #pragma unroll
        for (int kk = 0; kk < 128; kk += 16) {
            uint32_t a_h[4], a_l[4];
            {
                int ce = kk + acol8;
                uint32_t off = (uint32_t)((ce >> 6) * 6144) + swz((uint32_t)(arow * 128 + (ce & 63) * 2));
                LDSM_X4(a_h, tiles + QKF_QH + off);
                LDSM_X4(a_l, tiles + QKF_QL + off);
            }
            uint32_t b_[4];
            {
                int kc = kk + bcol8;
                uint32_t off = (uint32_t)((kc >> 6) * 12288) + swz((uint32_t)(brow * 128 + (kc & 63) * 2));
                LDSM_X4(b_, kB + off);
            }
            #pragma unroll
            for (int j = 0; j < 2; j++) {
                float* A = acc[c * 2 + j];
                MMA_F16(A, a_h, b_[j * 2], b_[j * 2 + 1]);
                MMA_F16(A, a_l, b_[j * 2], b_[j * 2 + 1]);
            }
        }
        MBAR_ARRIVE(emptyb[buf]);
        if (tid == 0 && c + 2 < 6) {
            MBAR_WAIT(emptyb[buf], phE[buf]); phE[buf] ^= 1;
            issue(c + 2, buf);
        }
    }
    __syncthreads();

    const float scale = 0.08838834764831845f;
    int il0 = wm * 16 + gid;
    float mrow[2] = {-1e30f, -1e30f};
    #pragma unroll
    for (int nf = 0; nf < 12; nf++) {
        int colb = (nf >> 1) * 96 + wn * 16 + (nf & 1) * 8 + tig * 2;
        #pragma unroll
        for (int rr = 0; rr < 2; rr++) {
            int il = il0 + rr * 8;
            #pragma unroll
            for (int cc = 0; cc < 2; cc++) {
                int col = colb + cc;
                int ky = col / 24, kx = col - ky * 24;
                float v = acc[nf][rr * 2 + cc] * scale + srelh[il * 24 + ky] + srelw[il * 24 + kx];
                acc[nf][rr * 2 + cc] = v;
                mrow[rr] = fmaxf(mrow[rr], v);
            }
        }
    }
    #pragma unroll
    for (int o = 1; o <= 2; o <<= 1) {
        mrow[0] = fmaxf(mrow[0], __shfl_xor_sync(0xffffffffu, mrow[0], o));
        mrow[1] = fmaxf(mrow[1], __shfl_xor_sync(0xffffffffu, mrow[1], o));
    }
    if (tig == 0) {
        smax[(il0) * 6 + wn] = mrow[0];
        smax[(il0 + 8) * 6 + wn] = mrow[1];
    }
    __syncthreads();
    float M[2];
    #pragma unroll
    for (int rr = 0; rr < 2; rr++) {
        const float* r = smax + (il0 + rr * 8) * 6;
        M[rr] = fmaxf(fmaxf(fmaxf(r[0], r[1]), fmaxf(r[2], r[3])), fmaxf(r[4], r[5]));
    }
    float srow[2] = {0.f, 0.f};
    #pragma unroll
    for (int nf = 0; nf < 12; nf++)
        #pragma unroll
        for (int rr = 0; rr < 2; rr++)
            #pragma unroll
            for (int cc = 0; cc < 2; cc++) {
                float e = __expf(acc[nf][rr * 2 + cc] - M[rr]);
                acc[nf][rr * 2 + cc] = e;
                srow[rr] += e;
            }
    #pragma unroll
    for (int o = 1; o <= 2; o <<= 1) {
        srow[0] += __shfl_xor_sync(0xffffffffu, srow[0], o);
        srow[1] += __shfl_xor_sync(0xffffffffu, srow[1], o);
    }
    if (tig == 0) {
        ssum[(il0) * 6 + wn] = srow[0];
        ssum[(il0 + 8) * 6 + wn] = srow[1];
    }
    __syncthreads();
    float inv[2];
    #pragma unroll
    for (int rr = 0; rr < 2; rr++) {
        const float* r = ssum + (il0 + rr * 8) * 6;
        inv[rr] = 1.0f / ((r[0] + r[1]) + (r[2] + r[3]) + (r[4] + r[5]));
    }
    #pragma unroll
    for (int nf = 0; nf < 12; nf++) {
        int colb = (nf >> 1) * 96 + wn * 16 + (nf & 1) * 8 + tig * 2;
        #pragma unroll
        for (int rr = 0; rr < 2; rr++) {
            size_t off = ((size_t)bh * QN + rowBase + il0 + rr * 8) * N_ + colb;
            __half2 th, tl;
            split2h(acc[nf][rr * 2 + 0] * inv[rr], th.x, tl.x);
            split2h(acc[nf][rr * 2 + 1] * inv[rr], th.y, tl.y);
            *(__half2*)(g_ph2 + off) = th;
            *(__half2*)(g_pl2 + off) = tl;
        }
    }
}

// ---------------- AV mma (384 thr / 12 warps, 3m x 4n) ----------------
#define AV_PH   0
#define AV_PL   6144
#define AV_V    12288
#define AV_BUF  28672
#define AV_SMEM (2*AV_BUF + 2048)

__global__ __launch_bounds__(384) void av_mma(
    const __grid_constant__ CUtensorMap tmPh,
    const __grid_constant__ CUtensorMap tmPl,
    const __grid_constant__ CUtensorMap tmV)
{
    extern __shared__ char smem[];
    uint32_t sraw = smem_u32(smem);
    uint32_t fullb[2]  = {sraw, sraw + 8};
    uint32_t emptyb[2] = {sraw + 16, sraw + 24};
    uint32_t tiles = (sraw + 64 + 1023) & ~1023u;

    int bh = blockIdx.z;
    int b = bh >> 3, h = bh & 7;
    int rowBase = blockIdx.y * 48;
    int tid = threadIdx.x, lane = tid & 31, warp = tid >> 5;
    int wm = warp >> 2, wn = warp & 3;
    int nBase = wn * 32;

    if (tid == 0) {
        MBAR_INIT(fullb[0], 1);  MBAR_INIT(fullb[1], 1);
        MBAR_INIT(emptyb[0], 384); MBAR_INIT(emptyb[1], 384);
    }
    __syncthreads();

    float acc[4][4];
    #pragma unroll
    for (int j = 0; j < 4; j++)
        #pragma unroll
        for (int r = 0; r < 4; r++) acc[j][r] = 0.f;

    int phF[2] = {0, 0};
    int phE[2] = {1, 1};

    auto issue = [&](int s, int buf) {
        uint32_t base = tiles + buf * AV_BUF;
        MBAR_EXPECT_TX(fullb[buf], AV_BUF);
        int k0 = s * 64;
        int py = bh * QN + rowBase;
        int vy = bh * N_ + k0;
        TMA_LOAD_2D(base + AV_PH, &tmPh, k0, py, fullb[buf]);
        TMA_LOAD_2D(base + AV_PL, &tmPl, k0, py, fullb[buf]);
        TMA_LOAD_2D(base + AV_V,        &tmV, 0,  vy, fullb[buf]);
        TMA_LOAD_2D(base + AV_V + 8192, &tmV, 64, vy, fullb[buf]);
    };

    if (tid == 0) {
        MBAR_WAIT(emptyb[0], phE[0]); phE[0] ^= 1;
        issue(0, 0);
    }

    for (int s = 0; s < 9; s++) {
        int buf = s & 1;
        if (tid == 0 && s + 1 < 9) {
            int nb = buf ^ 1;
            MBAR_WAIT(emptyb[nb], phE[nb]); phE[nb] ^= 1;
            issue(s + 1, nb);
        }
        MBAR_WAIT(fullb[buf], phF[buf]); phF[buf] ^= 1;
        uint32_t base = tiles + buf * AV_BUF;

        #pragma unroll
        for (int kk = 0; kk < 64; kk += 16) {
            uint32_t ah[4], al[4];
            {
                int row = wm * 16 + (lane & 7) + ((lane >> 3) & 1) * 8;
                int ce  = kk + ((lane >> 4) << 3);
                uint32_t off = swz((uint32_t)(row * 128 + ce * 2));
                LDSM_X4(ah, base + AV_PH + off);
                LDSM_X4(al, base + AV_PL + off);
            }
            uint32_t bvf[2][4];
            #pragma unroll
            for (int g = 0; g < 2; g++) {
                int vrow = kk + (lane & 15);
                int d    = nBase + g * 16 + ((lane >> 4) << 3);
                uint32_t off = (uint32_t)((d >> 6) * 8192) + swz((uint32_t)(vrow * 128 + (d & 63) * 2));
                LDSM_X4T(bvf[g], base + AV_V + off);
            }
            #pragma unroll
            for (int nf = 0; nf < 4; nf++) {
                uint32_t b0 = bvf[nf >> 1][(nf & 1) * 2 + 0];
                uint32_t b1 = bvf[nf >> 1][(nf & 1) * 2 + 1];
                MMA_F16(acc[nf], ah, b0, b1);
                MMA_F16(acc[nf], al, b0, b1);
            }
        }
        MBAR_ARRIVE(emptyb[buf]);
    }

    int gid = lane >> 2, tig = lane & 3;
    #pragma unroll
    for (int nf = 0; nf < 4; nf++) {
        int d = nBase + nf * 8 + tig * 2;
        #pragma unroll
        for (int rr = 0; rr < 2; rr++) {
            int i = rowBase + wm * 16 + gid + rr * 8;
            size_t off = ((size_t)b * QN + i) * C_ + h * HD + d;
            float2 qv = *(const float2*)(g_q + off);
            float v0 = acc[nf][rr * 2 + 0] + qv.x;
            float v1 = acc[nf][rr * 2 + 1] + qv.y;
            __half2 th, tl;
            split2h(v0, th.x, tl.x);
            split2h(v1, th.y, tl.y);
            *(__half2*)(g_aoh2 + off) = th;
            *(__half2*)(g_aol2 + off) = tl;
        }
    }
}

// ---------------- host: tensormap builder ----------------
typedef CUresult (*EncodeTiledFn)(CUtensorMap*, CUtensorMapDataType, cuuint32_t, void*,
                                  const cuuint64_t*, const cuuint64_t*, const cuuint32_t*,
                                  const cuuint32_t*, CUtensorMapInterleave, CUtensorMapSwizzle,
                                  CUtensorMapL2promotion, CUtensorMapFloatOOBfill);

static void make_map(EncodeTiledFn enc, CUtensorMap* m, void* ptr,
                     uint64_t dim0, uint64_t rows, uint32_t box0, uint32_t box1) {
    cuuint64_t dims[2]    = {(cuuint64_t)dim0, (cuuint64_t)rows};
    cuuint64_t strides[1] = {(cuuint64_t)dim0 * 2};
    cuuint32_t box[2]     = {box0, box1};
    cuuint32_t es[2]      = {1, 1};
    enc(m, CU_TENSOR_MAP_DATA_TYPE_FLOAT16, 2, ptr, dims, strides, box, es,
        CU_TENSOR_MAP_INTERLEAVE_NONE, CU_TENSOR_MAP_SWIZZLE_128B,
        CU_TENSOR_MAP_L2_PROMOTION_L2_128B, CU_TENSOR_MAP_FLOAT_OOB_FILL_NONE);
}

// ---------------- launch ----------------
extern "C" void kernel_launch(void* const* d_in, const int* in_sizes, int n_in,
                              void* d_out, int out_size) {
    const float* x   = (const float*)d_in[0];
    const float* Wq  = (const float*)d_in[1];
    const float* Wk  = (const float*)d_in[2];
    const float* Wv  = (const float*)d_in[3];
    const float* Wp  = (const float*)d_in[4];
    const float* bp  = (const float*)d_in[5];
    const float* rph = (const float*)d_in[6];
    const float* rpw = (const float*)d_in[7];
    float* out = (float*)d_out;

    float *q;
    __half *axh2, *axl2, *aqh2, *aql2, *aoh2, *aol2;
    __half *wq2, *wk2, *wv2, *wp2;
    __half *qh2, *ql2, *k2, *v2, *ph2, *pl2;
    cudaGetSymbolAddress((void**)&q,  g_q);
    cudaGetSymbolAddress((void**)&axh2, g_axh2);
    cudaGetSymbolAddress((void**)&axl2, g_axl2);
    cudaGetSymbolAddress((void**)&aqh2, g_aqh2);
    cudaGetSymbolAddress((void**)&aql2, g_aql2);
    cudaGetSymbolAddress((void**)&aoh2, g_aoh2);
    cudaGetSymbolAddress((void**)&aol2, g_aol2);
    cudaGetSymbolAddress((void**)&wq2, g_wq2);
    cudaGetSymbolAddress((void**)&wk2, g_wk2);
    cudaGetSymbolAddress((void**)&wv2, g_wv2);
    cudaGetSymbolAddress((void**)&wp2, g_wp2);
    cudaGetSymbolAddress((void**)&qh2, g_qh2);
    cudaGetSymbolAddress((void**)&ql2, g_ql2);
    cudaGetSymbolAddress((void**)&k2, g_k2);
    cudaGetSymbolAddress((void**)&v2, g_v2);
    cudaGetSymbolAddress((void**)&ph2, g_ph2);
    cudaGetSymbolAddress((void**)&pl2, g_pl2);

    EncodeTiledFn enc = nullptr;
    {
        void* fn = nullptr;
        cudaDriverEntryPointQueryResult st;
        cudaGetDriverEntryPoint("cuTensorMapEncodeTiled", &fn, cudaEnableDefault, &st);
        enc = (EncodeTiledFn)fn;
    }
    CUtensorMap mAxh, mAxl, mAqh, mAql, mAoh, mAol;
    CUtensorMap mWq, mWk, mWv, mWp;
    CUtensorMap mQh, mQl, mK, mV, mPh, mPl;
    make_map(enc, &mAxh, axh2, C_, (uint64_t)B_ * N_, 64, 128);
    make_map(enc, &mAxl, axl2, C_, (uint64_t)B_ * N_, 64, 128);
    make_map(enc, &mAqh, aqh2, C_, (uint64_t)B_ * QN, 64, 128);
    make_map(enc, &mAql, aql2, C_, (uint64_t)B_ * QN, 64, 128);
    make_map(enc, &mAoh, aoh2, C_, (uint64_t)B_ * QN, 64, 128);
    make_map(enc, &mAol, aol2, C_, (uint64_t)B_ * QN, 64, 128);
    make_map(enc, &mWq, wq2, C_, C_, 64, 128);
    make_map(enc, &mWk, wk2, C_, C_, 64, 128);
    make_map(enc, &mWv, wv2, C_, C_, 64, 128);
    make_map(enc, &mWp, wp2, C_, C_, 64, 128);
    make_map(enc, &mQh, qh2, HD, (uint64_t)BH * QN, 64, 48);
    make_map(enc, &mQl, ql2, HD, (uint64_t)BH * QN, 64, 48);
    make_map(enc, &mK,  k2,  HD, (uint64_t)BH * N_, 64, 96);
    make_map(enc, &mV,  v2,  HD, (uint64_t)BH * N_, 64, 64);
    make_map(enc, &mPh, ph2, N_, (uint64_t)BH * QN, 64, 48);
    make_map(enc, &mPl, pl2, N_, (uint64_t)BH * QN, 64, 48);

    cudaFuncSetAttribute(gemm_kv,  cudaFuncAttributeMaxDynamicSharedMemorySize, G2_SMEM);
    cudaFuncSetAttribute(gemm_f16, cudaFuncAttributeMaxDynamicSharedMemorySize, G2_SMEM);
    cudaFuncSetAttribute(qk_fused, cudaFuncAttributeMaxDynamicSharedMemorySize, QKF_SMEM);
    cudaFuncSetAttribute(av_mma, cudaFuncAttributeMaxDynamicSharedMemorySize, AV_SMEM);

    // ncu (-s 5 -c 1) captures launch #6 = gemm_kv (the dominant kernel)
    split_x2_kernel<<<dim3(18, 32, B_), dim3(32, 8)>>>(x);          // 1
    split_wT_f16_kernel<<<dim3(32, 32), dim3(32, 8)>>>(Wk, wk2);    // 2
    split_wT_f16_kernel<<<dim3(32, 32), dim3(32, 8)>>>(Wv, wv2);    // 3
    split_wT_f16_kernel<<<dim3(32, 32), dim3(32, 8)>>>(Wq, wq2);    // 4
    split_wT_f16_kernel<<<dim3(32, 32), dim3(32, 8)>>>(Wp, wp2);    // 5
    gemm_kv<<<dim3(8, (B_ * N_) / 128, 2), 512, G2_SMEM>>>(mAxh, mAxl, mWk, mWv, k2, v2);  // 6

    pool_kernel<<<dim3(C_ / 16, B_), 256>>>(x);                     // 7
    gemm_f16<<<dim3(8, (B_ * QN) / 128), 512, G2_SMEM>>>(mAqh, mAql, mWq, nullptr, q, qh2, ql2, QN, 3);  // 8

    relpos_kernel<<<BH * QN, 64>>>(rph, rpw);                       // 9
    qk_fused<<<dim3(1, 3, BH), 576, QKF_SMEM>>>(mQh, mQl, mK);      // 10
    av_mma<<<dim3(1, 3, BH), 384, AV_SMEM>>>(mPh, mPl, mV);         // 11

    gemm_f16<<<dim3(8, (B_ * QN) / 128), 512, G2_SMEM>>>(mAoh, mAol, mWp, bp, out, nullptr, nullptr, QN, 1);  // 12
}

// round 14
// speedup vs baseline: 3.3648x; 1.1245x over previous
#include <cuda.h>
#include <cuda_runtime.h>
#include <cuda_bf16.h>
#include <cuda_fp16.h>
#include <math.h>
#include <stdint.h>

#define B_  128
#define C_  1024
#define H_  24
#define W_  24
#define N_  576
#define NH  8
#define HD  128
#define QH  12
#define QW  12
#define QN  144
#define BH  (B_*NH)

// ---------------- fp32 scratch ----------------
__device__ float g_q   [(size_t)B_*QN*C_];
__device__ float g_relh[(size_t)BH*QN*H_];
__device__ float g_relw[(size_t)BH*QN*W_];
// fp16 operands
__device__ __half g_axs [(size_t)B_*N_*C_];     // single fp16(x), transposed
__device__ __half g_aqh2[(size_t)B_*QN*C_];     // pooled x hi/lo (Q proj stays 2-term)
__device__ __half g_aql2[(size_t)B_*QN*C_];
__device__ __half g_aoh2[(size_t)B_*QN*C_];     // o hi/lo (P proj stays 2-term)
__device__ __half g_aol2[(size_t)B_*QN*C_];
// TRANSPOSED weights [N,K], single fp16
__device__ __half g_wq2[(size_t)C_*C_];
__device__ __half g_wk2[(size_t)C_*C_];
__device__ __half g_wv2[(size_t)C_*C_];
__device__ __half g_wp2[(size_t)C_*C_];
// head-major fp16 tensors
__device__ __half g_qs [(size_t)BH*QN*HD];      // single fp16(q) for QK^T
__device__ __half g_k2 [(size_t)BH*N_*HD];
__device__ __half g_v2 [(size_t)BH*N_*HD];
__device__ __half g_ph2[(size_t)BH*QN*N_];
__device__ __half g_pl2[(size_t)BH*QN*N_];

// ---------------- helpers ----------------
__device__ __forceinline__ void split2h(float v, __half& hi, __half& lo) {
    hi = __float2half(v);
    lo = __float2half(v - __half2float(hi));
}
__device__ __forceinline__ uint32_t smem_u32(const void* p) {
    return (uint32_t)__cvta_generic_to_shared(p);
}
__device__ __forceinline__ uint32_t swz(uint32_t o) {
    return o ^ ((o >> 3) & 0x70);
}

#define MMA_F16(ACC, A, B0, B1)                                               \
    asm volatile(                                                             \
        "mma.sync.aligned.m16n8k16.row.col.f32.f16.f16.f32 "                  \
        "{%0,%1,%2,%3}, {%4,%5,%6,%7}, {%8,%9}, {%0,%1,%2,%3};"               \
        : "+f"((ACC)[0]), "+f"((ACC)[1]), "+f"((ACC)[2]), "+f"((ACC)[3])      \
        : "r"((A)[0]), "r"((A)[1]), "r"((A)[2]), "r"((A)[3]),                 \
          "r"(B0), "r"(B1))

#define LDSM_X4(R, ADDR)                                                      \
    asm volatile("ldmatrix.sync.aligned.m8n8.x4.shared.b16 {%0,%1,%2,%3}, [%4];" \
                 : "=r"((R)[0]), "=r"((R)[1]), "=r"((R)[2]), "=r"((R)[3]) : "r"(ADDR))
#define LDSM_X4T(R, ADDR)                                                     \
    asm volatile("ldmatrix.sync.aligned.m8n8.x4.trans.shared.b16 {%0,%1,%2,%3}, [%4];" \
                 : "=r"((R)[0]), "=r"((R)[1]), "=r"((R)[2]), "=r"((R)[3]) : "r"(ADDR))

#define MBAR_INIT(mb, cnt) \
    asm volatile("mbarrier.init.shared.b64 [%0], %1;" :: "r"(mb), "r"((uint32_t)(cnt)) : "memory")
#define MBAR_EXPECT_TX(mb, bytes) \
    asm volatile("mbarrier.arrive.expect_tx.shared.b64 _, [%0], %1;" :: "r"(mb), "r"((uint32_t)(bytes)) : "memory")
#define MBAR_ARRIVE(mb) \
    asm volatile("mbarrier.arrive.shared.b64 _, [%0];" :: "r"(mb) : "memory")
#define MBAR_WAIT(mb, ph) do {                                                    \
    asm volatile("{\n\t.reg .pred P1;\n\t"                                        \
        "WAIT_LOOP_%=:\n\t"                                                       \
        "mbarrier.try_wait.parity.acquire.cta.shared::cta.b64 P1, [%0], %1, 0x989680;\n\t" \
        "@P1 bra.uni WAIT_DONE_%=;\n\t"                                           \
        "bra.uni WAIT_LOOP_%=;\n\t"                                               \
        "WAIT_DONE_%=:\n\t}"                                                      \
        :: "r"(mb), "r"((uint32_t)(ph)) : "memory");                              \
} while(0)

#define TMA_LOAD_2D(sa, map, cx, cy, mb)                                          \
    asm volatile("cp.async.bulk.tensor.2d.shared::cta.global.tile.mbarrier::complete_tx::bytes " \
        "[%0], [%1, {%2, %3}], [%4];"                                             \
        :: "r"(sa), "l"(map), "r"((int32_t)(cx)), "r"((int32_t)(cy)), "r"(mb) : "memory")

// ---------------- conversions ----------------
__global__ __launch_bounds__(256) void split_wT_f16_kernel(const float* __restrict__ W,
                                                           __half* __restrict__ WT) {
    __shared__ float t[32][33];
    int k0 = blockIdx.x * 32, n0 = blockIdx.y * 32;
    int tx = threadIdx.x, ty = threadIdx.y;
    #pragma unroll
    for (int i = 0; i < 4; i++)
        t[ty + i * 8][tx] = W[(size_t)(k0 + ty + i * 8) * C_ + n0 + tx];
    __syncthreads();
    #pragma unroll
    for (int i = 0; i < 4; i++)
        WT[(size_t)(n0 + ty + i * 8) * C_ + k0 + tx] = __float2half(t[tx][ty + i * 8]);
}

// x[B,C,N] -> transposed single fp16
__global__ __launch_bounds__(256) void conv_x_kernel(const float* __restrict__ x) {
    __shared__ float tile[32][33];
    int b  = blockIdx.z;
    int n0 = blockIdx.x * 32;
    int c0 = blockIdx.y * 32;
    int tx = threadIdx.x, ty = threadIdx.y;
    const float* xb = x + (size_t)b * C_ * N_;
    #pragma unroll
    for (int i = 0; i < 4; i++)
        tile[ty + i * 8][tx] = xb[(size_t)(c0 + ty + i * 8) * N_ + n0 + tx];
    __syncthreads();
    #pragma unroll
    for (int i = 0; i < 4; i++) {
        int n = n0 + ty + i * 8;
        g_axs[((size_t)b * N_ + n) * C_ + c0 + tx] = __float2half(tile[tx][ty + i * 8]);
    }
}

// ---------------- avg-pool -> aq fp16 hi/lo ----------------
__global__ __launch_bounds__(256) void pool_kernel(const float* __restrict__ x) {
    __shared__ float sp[16][577];
    int b  = blockIdx.y;
    int c0 = blockIdx.x * 16;
    int tid = threadIdx.x;
    const float* xb = x + (size_t)b * C_ * N_ + (size_t)c0 * N_;
    #pragma unroll
    for (int r = 0; r < 36; r++) {
        int idx = tid + r * 256;
        int p = idx / 576, n = idx - p * 576;
        sp[p][n] = xb[(size_t)p * N_ + n];
    }
    __syncthreads();
    #pragma unroll
    for (int r = 0; r < 9; r++) {
        int idx = tid + r * 256;
        int qn = idx >> 4, cl = idx & 15;
        int qy = qn / 12, qx = qn - qy * 12;
        float s = 0.f;
        #pragma unroll
        for (int dy = -1; dy <= 1; dy++) {
            int y = 2 * qy + dy;
            if ((unsigned)y < 24u) {
                #pragma unroll
                for (int dx = -1; dx <= 1; dx++) {
                    int xx = 2 * qx + dx;
                    if ((unsigned)xx < 24u) s += sp[cl][y * 24 + xx];
                }
            }
        }
        __half hi, lo; split2h(s * (1.0f / 9.0f), hi, lo);
        size_t o = ((size_t)b * QN + qn) * C_ + c0 + cl;
        g_aqh2[o] = hi; g_aql2[o] = lo;
    }
}

// ---------------- single-term K/V GEMM: C = A·B, A fp16(x), B fp16(W^T) ----------------
#define G1_TILE  16384
#define G1_BUF   (2*G1_TILE)
#define G1_SMEM  (3*G1_BUF + 1024)
#define NSTAGE   16

__global__ __launch_bounds__(512) void gemm_kv(
    const __grid_constant__ CUtensorMap tmA,
    const __grid_constant__ CUtensorMap tmBk,
    const __grid_constant__ CUtensorMap tmBv,
    __half* __restrict__ Dk,
    __half* __restrict__ Dv)
{
    extern __shared__ char smem[];
    uint32_t sraw = smem_u32(smem);
    uint32_t fullb[3]  = {sraw, sraw + 8, sraw + 16};
    uint32_t emptyb[3] = {sraw + 24, sraw + 32, sraw + 40};
    uint32_t tiles = (sraw + 64 + 1023) & ~1023u;

    int tid = threadIdx.x, lane = tid & 31, warp = tid >> 5;
    int wm = warp >> 2, wn = warp & 3;
    int rowBase = blockIdx.y * 128;
    int colBase = blockIdx.x * 128;
    const CUtensorMap* pB = blockIdx.z ? &tmBv : &tmBk;
    __half* Ds = blockIdx.z ? Dv : Dk;

    if (tid == 0) {
        MBAR_INIT(fullb[0], 1);  MBAR_INIT(fullb[1], 1);  MBAR_INIT(fullb[2], 1);
        MBAR_INIT(emptyb[0], 512); MBAR_INIT(emptyb[1], 512); MBAR_INIT(emptyb[2], 512);
    }
    __syncthreads();

    float acc[2][4][4];
    #pragma unroll
    for (int i = 0; i < 2; i++)
        #pragma unroll
        for (int j = 0; j < 4; j++)
            #pragma unroll
            for (int r = 0; r < 4; r++) acc[i][j][r] = 0.f;

    int phF[3] = {0, 0, 0};
    int phE[3] = {0, 0, 0};
    auto issue = [&](int s, int slot) {
        uint32_t base = tiles + slot * G1_BUF;
        MBAR_EXPECT_TX(fullb[slot], G1_BUF);
        int k0 = s * 64;
        TMA_LOAD_2D(base,           &tmA, k0, rowBase, fullb[slot]);
        TMA_LOAD_2D(base + G1_TILE, pB,   k0, colBase, fullb[slot]);
    };
    if (tid == 0) { issue(0, 0); issue(1, 1); issue(2, 2); }

    uint32_t ah[2][2][4], bf[2][2][4];
    int arow0 = wm * 32 + (lane & 7) + ((lane >> 3) & 1) * 8;
    int acol8 = (lane >> 4) << 3;
    int brow0 = wn * 32 + (lane & 7) + ((lane >> 4) & 1) * 8;
    int bcol8 = (lane >> 3) & 1 ? 8 : 0;

    for (int s = 0; s < NSTAGE; s++) {
        int slot = s % 3;
        MBAR_WAIT(fullb[slot], phF[slot]); phF[slot] ^= 1;
        uint32_t aA = tiles + slot * G1_BUF;
        uint32_t bB = aA + G1_TILE;
        {
            #pragma unroll
            for (int mf = 0; mf < 2; mf++) {
                uint32_t off = swz((uint32_t)((arow0 + mf * 16) * 128 + acol8 * 2));
                LDSM_X4(ah[0][mf], aA + off);
            }
            #pragma unroll
            for (int g = 0; g < 2; g++) {
                uint32_t off = swz((uint32_t)((brow0 + g * 16) * 128 + bcol8 * 2));
                LDSM_X4(bf[0][g], bB + off);
            }
        }
        #pragma unroll
        for (int kki = 0; kki < 4; kki++) {
            int pb = kki & 1;
            if (kki < 3) {
                int nb = pb ^ 1;
                int kk = (kki + 1) * 16;
                #pragma unroll
                for (int mf = 0; mf < 2; mf++) {
                    uint32_t off = swz((uint32_t)((arow0 + mf * 16) * 128 + (kk + acol8) * 2));
                    LDSM_X4(ah[nb][mf], aA + off);
                }
                #pragma unroll
                for (int g = 0; g < 2; g++) {
                    uint32_t off = swz((uint32_t)((brow0 + g * 16) * 128 + (kk + bcol8) * 2));
                    LDSM_X4(bf[nb][g], bB + off);
                }
            }
            #pragma unroll
            for (int mf = 0; mf < 2; mf++)
                #pragma unroll
                for (int nf = 0; nf < 4; nf++) {
                    uint32_t b0 = bf[pb][nf >> 1][(nf & 1) * 2 + 0];
                    uint32_t b1 = bf[pb][nf >> 1][(nf & 1) * 2 + 1];
                    MMA_F16(acc[mf][nf], ah[pb][mf], b0, b1);
                }
        }
        MBAR_ARRIVE(emptyb[slot]);
        if (tid == 0 && s + 3 < NSTAGE) {
            MBAR_WAIT(emptyb[slot], phE[slot]); phE[slot] ^= 1;
            issue(s + 3, slot);
        }
    }

    int gid = lane >> 2, tig = lane & 3;
    #pragma unroll
    for (int mf = 0; mf < 2; mf++)
        #pragma unroll
        for (int nf = 0; nf < 4; nf++) {
            int c0 = colBase + wn * 32 + nf * 8 + tig * 2;
            #pragma unroll
            for (int rr = 0; rr < 2; rr++) {
                int row = rowBase + wm * 32 + mf * 16 + gid + rr * 8;
                int b = row / N_, n = row - b * N_;
                int h = c0 >> 7, d = c0 & 127;
                size_t di = (((size_t)b * NH + h) * N_ + n) * HD + d;
                __half2 hv = __floats2half2_rn(acc[mf][nf][rr * 2 + 0], acc[mf][nf][rr * 2 + 1]);
                *(__half2*)(Ds + di) = hv;
            }
        }
}

// ---------------- 2-term GEMM (Q: mode 3, P: mode 1) ----------------
#define G2_TILE  16384
#define G2_BUF   (3*G2_TILE)
#define G2_SMEM  (3*G2_BUF + 1024)

__global__ __launch_bounds__(512) void gemm_f16(
    const __grid_constant__ CUtensorMap tmAh,
    const __grid_constant__ CUtensorMap tmAl,
    const __grid_constant__ CUtensorMap tmB,
    const float* __restrict__ bias,
    float* __restrict__ Cm,
    __half* __restrict__ Ds,
    int rpb, int mode)
{
    extern __shared__ char smem[];
    uint32_t sraw = smem_u32(smem);
    uint32_t fullb[3]  = {sraw, sraw + 8, sraw + 16};
    uint32_t emptyb[3] = {sraw + 24, sraw + 32, sraw + 40};
    uint32_t tiles = (sraw + 64 + 1023) & ~1023u;

    int tid = threadIdx.x, lane = tid & 31, warp = tid >> 5;
    int wm = warp >> 2, wn = warp & 3;
    int rowBase = blockIdx.y * 128;
    int colBase = blockIdx.x * 128;

    if (tid == 0) {
        MBAR_INIT(fullb[0], 1);  MBAR_INIT(fullb[1], 1);  MBAR_INIT(fullb[2], 1);
        MBAR_INIT(emptyb[0], 512); MBAR_INIT(emptyb[1], 512); MBAR_INIT(emptyb[2], 512);
    }
    __syncthreads();

    float acc[2][4][4];
    #pragma unroll
    for (int i = 0; i < 2; i++)
        #pragma unroll
        for (int j = 0; j < 4; j++)
            #pragma unroll
            for (int r = 0; r < 4; r++) acc[i][j][r] = 0.f;

    int phF[3] = {0, 0, 0};
    int phE[3] = {0, 0, 0};
    auto issue = [&](int s, int slot) {
        uint32_t base = tiles + slot * G2_BUF;
        MBAR_EXPECT_TX(fullb[slot], G2_BUF);
        int k0 = s * 64;
        TMA_LOAD_2D(base,               &tmAh, k0, rowBase, fullb[slot]);
        TMA_LOAD_2D(base + G2_TILE,     &tmAl, k0, rowBase, fullb[slot]);
        TMA_LOAD_2D(base + 2 * G2_TILE, &tmB,  k0, colBase, fullb[slot]);
    };
    if (tid == 0) { issue(0, 0); issue(1, 1); issue(2, 2); }

    uint32_t ah[2][2][4], al[2][2][4], bf[2][2][4];
    int arow0 = wm * 32 + (lane & 7) + ((lane >> 3) & 1) * 8;
    int acol8 = (lane >> 4) << 3;
    int brow0 = wn * 32 + (lane & 7) + ((lane >> 4) & 1) * 8;
    int bcol8 = (lane >> 3) & 1 ? 8 : 0;

    for (int s = 0; s < NSTAGE; s++) {
        int slot = s % 3;
        MBAR_WAIT(fullb[slot], phF[slot]); phF[slot] ^= 1;
        uint32_t aH = tiles + slot * G2_BUF;
        uint32_t aL = aH + G2_TILE;
        uint32_t bB = aH + 2 * G2_TILE;
        {
            #pragma unroll
            for (int mf = 0; mf < 2; mf++) {
                uint32_t off = swz((uint32_t)((arow0 + mf * 16) * 128 + acol8 * 2));
                LDSM_X4(ah[0][mf], aH + off);
                LDSM_X4(al[0][mf], aL + off);
            }
            #pragma unroll
            for (int g = 0; g < 2; g++) {
                uint32_t off = swz((uint32_t)((brow0 + g * 16) * 128 + bcol8 * 2));
                LDSM_X4(bf[0][g], bB + off);
            }
        }
        #pragma unroll
        for (int kki = 0; kki < 4; kki++) {
            int pb = kki & 1;
            if (kki < 3) {
                int nb = pb ^ 1;
                int kk = (kki + 1) * 16;
                #pragma unroll
                for (int mf = 0; mf < 2; mf++) {
                    uint32_t off = swz((uint32_t)((arow0 + mf * 16) * 128 + (kk + acol8) * 2));
                    LDSM_X4(ah[nb][mf], aH + off);
                    LDSM_X4(al[nb][mf], aL + off);
                }
                #pragma unroll
                for (int g = 0; g < 2; g++) {
                    uint32_t off = swz((uint32_t)((brow0 + g * 16) * 128 + (kk + bcol8) * 2));
                    LDSM_X4(bf[nb][g], bB + off);
                }
            }
            #pragma unroll
            for (int mf = 0; mf < 2; mf++)
                #pragma unroll
                for (int nf = 0; nf < 4; nf++) {
                    uint32_t b0 = bf[pb][nf >> 1][(nf & 1) * 2 + 0];
                    uint32_t b1 = bf[pb][nf >> 1][(nf & 1) * 2 + 1];
                    MMA_F16(acc[mf][nf], ah[pb][mf], b0, b1);
                    MMA_F16(acc[mf][nf], al[pb][mf], b0, b1);
                }
        }
        MBAR_ARRIVE(emptyb[slot]);
        if (tid == 0 && s + 3 < NSTAGE) {
            MBAR_WAIT(emptyb[slot], phE[slot]); phE[slot] ^= 1;
            issue(s + 3, slot);
        }
    }

    int gid = lane >> 2, tig = lane & 3;
    #pragma unroll
    for (int mf = 0; mf < 2; mf++)
        #pragma unroll
        for (int nf = 0; nf < 4; nf++) {
            int c0 = colBase + wn * 32 + nf * 8 + tig * 2;
            #pragma unroll
            for (int rr = 0; rr < 2; rr++) {
                int row = rowBase + wm * 32 + mf * 16 + gid + rr * 8;
                float v0 = acc[mf][nf][rr * 2 + 0];
                float v1 = acc[mf][nf][rr * 2 + 1];
                if (mode == 1) {
                    int bq = row / QN, qi = row - bq * QN;
                    Cm[((size_t)bq * C_ + c0) * QN + qi]     = v0 + bias[c0];
                    Cm[((size_t)bq * C_ + c0 + 1) * QN + qi] = v1 + bias[c0 + 1];
                } else {
                    // mode 3: q -> fp32 row-major + single fp16 head-major
                    int b = row / rpb, n = row - b * rpb;
                    int h = c0 >> 7, d = c0 & 127;
                    size_t di = (((size_t)b * NH + h) * rpb + n) * HD + d;
                    *(__half2*)(Ds + di) = __floats2half2_rn(v0, v1);
                    *(float2*)&Cm[(size_t)row * C_ + c0] = make_float2(v0, v1);
                }
            }
        }
}

// ---------------- relative position bias dots ----------------
__global__ __launch_bounds__(64) void relpos_kernel(const float* __restrict__ rel_h,
                                                    const float* __restrict__ rel_w) {
    int gid = blockIdx.x;
    int bh = gid / QN, i = gid - bh * QN;
    int b = bh >> 3, h = bh & 7;
    int qy = i / 12, qx = i - qy * 12;
    int t = threadIdx.x;
    const float* qrow = g_q + ((size_t)b * QN + i) * C_ + h * HD;
    if (t < 24) {
        const float* R = rel_h + (size_t)(2 * qy - t + 23) * HD;
        float a0 = 0, a1 = 0, a2 = 0, a3 = 0;
        #pragma unroll
        for (int d = 0; d < HD; d += 4) {
            a0 += qrow[d + 0] * R[d + 0];
            a1 += qrow[d + 1] * R[d + 1];
            a2 += qrow[d + 2] * R[d + 2];
            a3 += qrow[d + 3] * R[d + 3];
        }
        g_relh[(size_t)gid * 24 + t] = (a0 + a1) + (a2 + a3);
    } else if (t >= 32 && t < 56) {
        int kx = t - 32;
        const float* R = rel_w + (size_t)(2 * qx - kx + 23) * HD;
        float a0 = 0, a1 = 0, a2 = 0, a3 = 0;
        #pragma unroll
        for (int d = 0; d < HD; d += 4) {
            a0 += qrow[d + 0] * R[d + 0];
            a1 += qrow[d + 1] * R[d + 1];
            a2 += qrow[d + 2] * R[d + 2];
            a3 += qrow[d + 3] * R[d + 3];
        }
        g_relw[(size_t)gid * 24 + kx] = (a0 + a1) + (a2 + a3);
    }
}

// ---------------- FUSED QK^T + bias + softmax + P-split (single-term Q) ----------------
#define QKF_Q    0
#define QKF_K0   12288
#define QKF_KBUF 24576
#define QKF_REL  (12288 + 2*24576)     // 61440
#define QKF_RED  (QKF_REL + 9216)
#define QKF_SMEM (QKF_RED + 2304 + 1088)

__global__ __launch_bounds__(576) void qk_fused(
    const __grid_constant__ CUtensorMap tmQ,
    const __grid_constant__ CUtensorMap tmK)
{
    extern __shared__ char smem[];
    uint32_t sraw = smem_u32(smem);
    uint32_t fullb[2]  = {sraw, sraw + 8};
    uint32_t emptyb[2] = {sraw + 16, sraw + 24};
    uint32_t tiles = (sraw + 64 + 1023) & ~1023u;
    char* tilesp = smem + (tiles - sraw);
    float* srelh = (float*)(tilesp + QKF_REL);
    float* srelw = srelh + 48 * 24;
    float* smax  = (float*)(tilesp + QKF_RED);
    float* ssum  = smax + 48 * 6;

    int bh = blockIdx.z;
    int rowBase = blockIdx.y * 48;
    int tid = threadIdx.x, lane = tid & 31, warp = tid >> 5;
    int wm = warp / 6, wn = warp % 6;
    int gid = lane >> 2, tig = lane & 3;

    if (tid == 0) {
        MBAR_INIT(fullb[0], 1);  MBAR_INIT(fullb[1], 1);
        MBAR_INIT(emptyb[0], 576); MBAR_INIT(emptyb[1], 576);
    }
    __syncthreads();

    for (int idx = tid; idx < 48 * 24; idx += 576) {
        size_t gidx = ((size_t)bh * QN + rowBase + idx / 24) * 24 + (idx % 24);
        srelh[idx] = g_relh[gidx];
        srelw[idx] = g_relw[gidx];
    }

    int phF[2] = {0, 0}, phE[2] = {0, 0};
    auto issue = [&](int c, int buf) {
        uint32_t kb = tiles + QKF_K0 + buf * QKF_KBUF;
        MBAR_EXPECT_TX(fullb[buf], (c == 0) ? (12288u + QKF_KBUF) : (uint32_t)QKF_KBUF);
        int ky0 = bh * N_ + c * 96;
        if (c == 0) {
            int qy = bh * QN + rowBase;
            TMA_LOAD_2D(tiles + QKF_Q,        &tmQ, 0,  qy, fullb[0]);
            TMA_LOAD_2D(tiles + QKF_Q + 6144, &tmQ, 64, qy, fullb[0]);
        }
        TMA_LOAD_2D(kb,         &tmK, 0,  ky0, fullb[buf]);
        TMA_LOAD_2D(kb + 12288, &tmK, 64, ky0, fullb[buf]);
    };
    if (tid == 0) { issue(0, 0); issue(1, 1); }

    float acc[12][4];
    #pragma unroll
    for (int j = 0; j < 12; j++)
        #pragma unroll
        for (int r = 0; r < 4; r++) acc[j][r] = 0.f;

    int arow = wm * 16 + (lane & 7) + ((lane >> 3) & 1) * 8;
    int acol8 = (lane >> 4) << 3;
    int brow = wn * 16 + (lane & 7) + ((lane >> 4) & 1) * 8;
    int bcol8 = ((lane >> 3) & 1) * 8;

    for (int c = 0; c < 6; c++) {
        int buf = c & 1;
        MBAR_WAIT(fullb[buf], phF[buf]); phF[buf] ^= 1;
        uint32_t kB = tiles + QKF_K0 + buf * QKF_KBUF;

        #pragma unroll
        for (int kk = 0; kk < 128; kk += 16) {
            uint32_t a_[4];
            {
                int ce = kk + acol8;
                uint32_t off = (uint32_t)((ce >> 6) * 6144) + swz((uint32_t)(arow * 128 + (ce & 63) * 2));
                LDSM_X4(a_, tiles + QKF_Q + off);
            }
            uint32_t b_[4];
            {
                int kc = kk + bcol8;
                uint32_t off = (uint32_t)((kc >> 6) * 12288) + swz((uint32_t)(brow * 128 + (kc & 63) * 2));
                LDSM_X4(b_, kB + off);
            }
            #pragma unroll
            for (int j = 0; j < 2; j++) {
                float* A = acc[c * 2 + j];
                MMA_F16(A, a_, b_[j * 2], b_[j * 2 + 1]);
            }
        }
        MBAR_ARRIVE(emptyb[buf]);
        if (tid == 0 && c + 2 < 6) {
            MBAR_WAIT(emptyb[buf], phE[buf]); phE[buf] ^= 1;
            issue(c + 2, buf);
        }
    }
    __syncthreads();

    const float scale = 0.08838834764831845f;
    int il0 = wm * 16 + gid;
    float mrow[2] = {-1e30f, -1e30f};
    #pragma unroll
    for (int nf = 0; nf < 12; nf++) {
        int colb = (nf >> 1) * 96 + wn * 16 + (nf & 1) * 8 + tig * 2;
        #pragma unroll
        for (int rr = 0; rr < 2; rr++) {
            int il = il0 + rr * 8;
            #pragma unroll
            for (int cc = 0; cc < 2; cc++) {
                int col = colb + cc;
                int ky = col / 24, kx = col - ky * 24;
                float v = acc[nf][rr * 2 + cc] * scale + srelh[il * 24 + ky] + srelw[il * 24 + kx];
                acc[nf][rr * 2 + cc] = v;
                mrow[rr] = fmaxf(mrow[rr], v);
            }
        }
    }
    #pragma unroll
    for (int o = 1; o <= 2; o <<= 1) {
        mrow[0] = fmaxf(mrow[0], __shfl_xor_sync(0xffffffffu, mrow[0], o));
        mrow[1] = fmaxf(mrow[1], __shfl_xor_sync(0xffffffffu, mrow[1], o));
    }
    if (tig == 0) {
        smax[(il0) * 6 + wn] = mrow[0];
        smax[(il0 + 8) * 6 + wn] = mrow[1];
    }
    __syncthreads();
    float M[2];
    #pragma unroll
    for (int rr = 0; rr < 2; rr++) {
        const float* r = smax + (il0 + rr * 8) * 6;
        M[rr] = fmaxf(fmaxf(fmaxf(r[0], r[1]), fmaxf(r[2], r[3])), fmaxf(r[4], r[5]));
    }
    float srow[2] = {0.f, 0.f};
    #pragma unroll
    for (int nf = 0; nf < 12; nf++)
        #pragma unroll
        for (int rr = 0; rr < 2; rr++)
            #pragma unroll
            for (int cc = 0; cc < 2; cc++) {
                float e = __expf(acc[nf][rr * 2 + cc] - M[rr]);
                acc[nf][rr * 2 + cc] = e;
                srow[rr] += e;
            }
    #pragma unroll
    for (int o = 1; o <= 2; o <<= 1) {
        srow[0] += __shfl_xor_sync(0xffffffffu, srow[0], o);
        srow[1] += __shfl_xor_sync(0xffffffffu, srow[1], o);
    }
    if (tig == 0) {
        ssum[(il0) * 6 + wn] = srow[0];
        ssum[(il0 + 8) * 6 + wn] = srow[1];
    }
    __syncthreads();
    float inv[2];
    #pragma unroll
    for (int rr = 0; rr < 2; rr++) {
        const float* r = ssum + (il0 + rr * 8) * 6;
        inv[rr] = 1.0f / ((r[0] + r[1]) + (r[2] + r[3]) + (r[4] + r[5]));
    }
    #pragma unroll
    for (int nf = 0; nf < 12; nf++) {
        int colb = (nf >> 1) * 96 + wn * 16 + (nf & 1) * 8 + tig * 2;
        #pragma unroll
        for (int rr = 0; rr < 2; rr++) {
            size_t off = ((size_t)bh * QN + rowBase + il0 + rr * 8) * N_ + colb;
            __half2 th, tl;
            split2h(acc[nf][rr * 2 + 0] * inv[rr], th.x, tl.x);
            split2h(acc[nf][rr * 2 + 1] * inv[rr], th.y, tl.y);
            *(__half2*)(g_ph2 + off) = th;
            *(__half2*)(g_pl2 + off) = tl;
        }
    }
}

// ---------------- AV mma (2-term P, single V) ----------------
#define AV_PH   0
#define AV_PL   6144
#define AV_V    12288
#define AV_BUF  28672
#define AV_SMEM (2*AV_BUF + 2048)

__global__ __launch_bounds__(384) void av_mma(
    const __grid_constant__ CUtensorMap tmPh,
    const __grid_constant__ CUtensorMap tmPl,
    const __grid_constant__ CUtensorMap tmV)
{
    extern __shared__ char smem[];
    uint32_t sraw = smem_u32(smem);
    uint32_t fullb[2]  = {sraw, sraw + 8};
    uint32_t emptyb[2] = {sraw + 16, sraw + 24};
    uint32_t tiles = (sraw + 64 + 1023) & ~1023u;

    int bh = blockIdx.z;
    int b = bh >> 3, h = bh & 7;
    int rowBase = blockIdx.y * 48;
    int tid = threadIdx.x, lane = tid & 31, warp = tid >> 5;
    int wm = warp >> 2, wn = warp & 3;
    int nBase = wn * 32;

    if (tid == 0) {
        MBAR_INIT(fullb[0], 1);  MBAR_INIT(fullb[1], 1);
        MBAR_INIT(emptyb[0], 384); MBAR_INIT(emptyb[1], 384);
    }
    __syncthreads();

    float acc[4][4];
    #pragma unroll
    for (int j = 0; j < 4; j++)
        #pragma unroll
        for (int r = 0; r < 4; r++) acc[j][r] = 0.f;

    int phF[2] = {0, 0};
    int phE[2] = {1, 1};

    auto issue = [&](int s, int buf) {
        uint32_t base = tiles + buf * AV_BUF;
        MBAR_EXPECT_TX(fullb[buf], AV_BUF);
        int k0 = s * 64;
        int py = bh * QN + rowBase;
        int vy = bh * N_ + k0;
        TMA_LOAD_2D(base + AV_PH, &tmPh, k0, py, fullb[buf]);
        TMA_LOAD_2D(base + AV_PL, &tmPl, k0, py, fullb[buf]);
        TMA_LOAD_2D(base + AV_V,        &tmV, 0,  vy, fullb[buf]);
        TMA_LOAD_2D(base + AV_V + 8192, &tmV, 64, vy, fullb[buf]);
    };

    if (tid == 0) {
        MBAR_WAIT(emptyb[0], phE[0]); phE[0] ^= 1;
        issue(0, 0);
    }

    for (int s = 0; s < 9; s++) {
        int buf = s & 1;
        if (tid == 0 && s + 1 < 9) {
            int nb = buf ^ 1;
            MBAR_WAIT(emptyb[nb], phE[nb]); phE[nb] ^= 1;
            issue(s + 1, nb);
        }
        MBAR_WAIT(fullb[buf], phF[buf]); phF[buf] ^= 1;
        uint32_t base = tiles + buf * AV_BUF;

        #pragma unroll
        for (int kk = 0; kk < 64; kk += 16) {
            uint32_t ah[4], al[4];
            {
                int row = wm * 16 + (lane & 7) + ((lane >> 3) & 1) * 8;
                int ce  = kk + ((lane >> 4) << 3);
                uint32_t off = swz((uint32_t)(row * 128 + ce * 2));
                LDSM_X4(ah, base + AV_PH + off);
                LDSM_X4(al, base + AV_PL + off);
            }
            uint32_t bvf[2][4];
            #pragma unroll
            for (int g = 0; g < 2; g++) {
                int vrow = kk + (lane & 15);
                int d    = nBase + g * 16 + ((lane >> 4) << 3);
                uint32_t off = (uint32_t)((d >> 6) * 8192) + swz((uint32_t)(vrow * 128 + (d & 63) * 2));
                LDSM_X4T(bvf[g], base + AV_V + off);
            }
            #pragma unroll
            for (int nf = 0; nf < 4; nf++) {
                uint32_t b0 = bvf[nf >> 1][(nf & 1) * 2 + 0];
                uint32_t b1 = bvf[nf >> 1][(nf & 1) * 2 + 1];
                MMA_F16(acc[nf], ah, b0, b1);
                MMA_F16(acc[nf], al, b0, b1);
            }
        }
        MBAR_ARRIVE(emptyb[buf]);
    }

    int gid = lane >> 2, tig = lane & 3;
    #pragma unroll
    for (int nf = 0; nf < 4; nf++) {
        int d = nBase + nf * 8 + tig * 2;
        #pragma unroll
        for (int rr = 0; rr < 2; rr++) {
            int i = rowBase + wm * 16 + gid + rr * 8;
            size_t off = ((size_t)b * QN + i) * C_ + h * HD + d;
            float2 qv = *(const float2*)(g_q + off);
            float v0 = acc[nf][rr * 2 + 0] + qv.x;
            float v1 = acc[nf][rr * 2 + 1] + qv.y;
            __half2 th, tl;
            split2h(v0, th.x, tl.x);
            split2h(v1, th.y, tl.y);
            *(__half2*)(g_aoh2 + off) = th;
            *(__half2*)(g_aol2 + off) = tl;
        }
    }
}

// ---------------- host: tensormap builder ----------------
typedef CUresult (*EncodeTiledFn)(CUtensorMap*, CUtensorMapDataType, cuuint32_t, void*,
                                  const cuuint64_t*, const cuuint64_t*, const cuuint32_t*,
                                  const cuuint32_t*, CUtensorMapInterleave, CUtensorMapSwizzle,
                                  CUtensorMapL2promotion, CUtensorMapFloatOOBfill);

static void make_map(EncodeTiledFn enc, CUtensorMap* m, void* ptr,
                     uint64_t dim0, uint64_t rows, uint32_t box0, uint32_t box1) {
    cuuint64_t dims[2]    = {(cuuint64_t)dim0, (cuuint64_t)rows};
    cuuint64_t strides[1] = {(cuuint64_t)dim0 * 2};
    cuuint32_t box[2]     = {box0, box1};
    cuuint32_t es[2]      = {1, 1};
    enc(m, CU_TENSOR_MAP_DATA_TYPE_FLOAT16, 2, ptr, dims, strides, box, es,
        CU_TENSOR_MAP_INTERLEAVE_NONE, CU_TENSOR_MAP_SWIZZLE_128B,
        CU_TENSOR_MAP_L2_PROMOTION_L2_128B, CU_TENSOR_MAP_FLOAT_OOB_FILL_NONE);
}

// ---------------- launch ----------------
extern "C" void kernel_launch(void* const* d_in, const int* in_sizes, int n_in,
                              void* d_out, int out_size) {
    const float* x   = (const float*)d_in[0];
    const float* Wq  = (const float*)d_in[1];
    const float* Wk  = (const float*)d_in[2];
    const float* Wv  = (const float*)d_in[3];
    const float* Wp  = (const float*)d_in[4];
    const float* bp  = (const float*)d_in[5];
    const float* rph = (const float*)d_in[6];
    const float* rpw = (const float*)d_in[7];
    float* out = (float*)d_out;

    float *q;
    __half *axs, *aqh2, *aql2, *aoh2, *aol2;
    __half *wq2, *wk2, *wv2, *wp2;
    __half *qs, *k2, *v2, *ph2, *pl2;
    cudaGetSymbolAddress((void**)&q,  g_q);
    cudaGetSymbolAddress((void**)&axs, g_axs);
    cudaGetSymbolAddress((void**)&aqh2, g_aqh2);
    cudaGetSymbolAddress((void**)&aql2, g_aql2);
    cudaGetSymbolAddress((void**)&aoh2, g_aoh2);
    cudaGetSymbolAddress((void**)&aol2, g_aol2);
    cudaGetSymbolAddress((void**)&wq2, g_wq2);
    cudaGetSymbolAddress((void**)&wk2, g_wk2);
    cudaGetSymbolAddress((void**)&wv2, g_wv2);
    cudaGetSymbolAddress((void**)&wp2, g_wp2);
    cudaGetSymbolAddress((void**)&qs, g_qs);
    cudaGetSymbolAddress((void**)&k2, g_k2);
    cudaGetSymbolAddress((void**)&v2, g_v2);
    cudaGetSymbolAddress((void**)&ph2, g_ph2);
    cudaGetSymbolAddress((void**)&pl2, g_pl2);

    EncodeTiledFn enc = nullptr;
    {
        void* fn = nullptr;
        cudaDriverEntryPointQueryResult st;
        cudaGetDriverEntryPoint("cuTensorMapEncodeTiled", &fn, cudaEnableDefault, &st);
        enc = (EncodeTiledFn)fn;
    }
    CUtensorMap mAx, mAqh, mAql, mAoh, mAol;
    CUtensorMap mWq, mWk, mWv, mWp;
    CUtensorMap mQ, mK, mV, mPh, mPl;
    make_map(enc, &mAx, axs, C_, (uint64_t)B_ * N_, 64, 128);
    make_map(enc, &mAqh, aqh2, C_, (uint64_t)B_ * QN, 64, 128);
    make_map(enc, &mAql, aql2, C_, (uint64_t)B_ * QN, 64, 128);
    make_map(enc, &mAoh, aoh2, C_, (uint64_t)B_ * QN, 64, 128);
    make_map(enc, &mAol, aol2, C_, (uint64_t)B_ * QN, 64, 128);
    make_map(enc, &mWq, wq2, C_, C_, 64, 128);
    make_map(enc, &mWk, wk2, C_, C_, 64, 128);
    make_map(enc, &mWv, wv2, C_, C_, 64, 128);
    make_map(enc, &mWp, wp2, C_, C_, 64, 128);
    make_map(enc, &mQ,  qs,  HD, (uint64_t)BH * QN, 64, 48);
    make_map(enc, &mK,  k2,  HD, (uint64_t)BH * N_, 64, 96);
    make_map(enc, &mV,  v2,  HD, (uint64_t)BH * N_, 64, 64);
    make_map(enc, &mPh, ph2, N_, (uint64_t)BH * QN, 64, 48);
    make_map(enc, &mPl, pl2, N_, (uint64_t)BH * QN, 64, 48);

    cudaFuncSetAttribute(gemm_kv,  cudaFuncAttributeMaxDynamicSharedMemorySize, G1_SMEM);
    cudaFuncSetAttribute(gemm_f16, cudaFuncAttributeMaxDynamicSharedMemorySize, G2_SMEM);
    cudaFuncSetAttribute(qk_fused, cudaFuncAttributeMaxDynamicSharedMemorySize, QKF_SMEM);
    cudaFuncSetAttribute(av_mma, cudaFuncAttributeMaxDynamicSharedMemorySize, AV_SMEM);

    conv_x_kernel<<<dim3(18, 32, B_), dim3(32, 8)>>>(x);
    split_wT_f16_kernel<<<dim3(32, 32), dim3(32, 8)>>>(Wk, wk2);
    split_wT_f16_kernel<<<dim3(32, 32), dim3(32, 8)>>>(Wv, wv2);
    split_wT_f16_kernel<<<dim3(32, 32), dim3(32, 8)>>>(Wq, wq2);
    split_wT_f16_kernel<<<dim3(32, 32), dim3(32, 8)>>>(Wp, wp2);
    gemm_kv<<<dim3(8, (B_ * N_) / 128, 2), 512, G1_SMEM>>>(mAx, mWk, mWv, k2, v2);

    pool_kernel<<<dim3(C_ / 16, B_), 256>>>(x);
    gemm_f16<<<dim3(8, (B_ * QN) / 128), 512, G2_SMEM>>>(mAqh, mAql, mWq, nullptr, q, qs, QN, 3);

    relpos_kernel<<<BH * QN, 64>>>(rph, rpw);
    qk_fused<<<dim3(1, 3, BH), 576, QKF_SMEM>>>(mQ, mK);
    av_mma<<<dim3(1, 3, BH), 384, AV_SMEM>>>(mPh, mPl, mV);

    gemm_f16<<<dim3(8, (B_ * QN) / 128), 512, G2_SMEM>>>(mAoh, mAol, mWp, bp, out, nullptr, QN, 1);
}

// round 15
// speedup vs baseline: 3.4748x; 1.0327x over previous
#include <cuda.h>
#include <cuda_runtime.h>
#include <cuda_bf16.h>
#include <cuda_fp16.h>
#include <math.h>
#include <stdint.h>

#define B_  128
#define C_  1024
#define H_  24
#define W_  24
#define N_  576
#define NH  8
#define HD  128
#define QH  12
#define QW  12
#define QN  144
#define BH  (B_*NH)

// ---------------- fp32 scratch ----------------
__device__ float g_q   [(size_t)B_*QN*C_];
__device__ float g_relh[(size_t)BH*QN*H_];
__device__ float g_relw[(size_t)BH*QN*W_];
// fp16 operands
__device__ __half g_axs [(size_t)B_*N_*C_];     // single fp16(x), transposed
__device__ __half g_aqs [(size_t)B_*QN*C_];     // single fp16(pooled x)
__device__ __half g_aoh2[(size_t)B_*QN*C_];     // o hi/lo (P proj stays 2-term)
__device__ __half g_aol2[(size_t)B_*QN*C_];
// TRANSPOSED weights [N,K], single fp16
__device__ __half g_wq2[(size_t)C_*C_];
__device__ __half g_wk2[(size_t)C_*C_];
__device__ __half g_wv2[(size_t)C_*C_];
__device__ __half g_wp2[(size_t)C_*C_];
// head-major fp16 tensors
__device__ __half g_qs [(size_t)BH*QN*HD];      // single fp16(q)
__device__ __half g_k2 [(size_t)BH*N_*HD];
__device__ __half g_v2 [(size_t)BH*N_*HD];
__device__ __half g_ps [(size_t)BH*QN*N_];      // single fp16(P)

// ---------------- helpers ----------------
__device__ __forceinline__ void split2h(float v, __half& hi, __half& lo) {
    hi = __float2half(v);
    lo = __float2half(v - __half2float(hi));
}
__device__ __forceinline__ uint32_t smem_u32(const void* p) {
    return (uint32_t)__cvta_generic_to_shared(p);
}
__device__ __forceinline__ uint32_t swz(uint32_t o) {
    return o ^ ((o >> 3) & 0x70);
}

#define MMA_F16(ACC, A, B0, B1)                                               \
    asm volatile(                                                             \
        "mma.sync.aligned.m16n8k16.row.col.f32.f16.f16.f32 "                  \
        "{%0,%1,%2,%3}, {%4,%5,%6,%7}, {%8,%9}, {%0,%1,%2,%3};"               \
        : "+f"((ACC)[0]), "+f"((ACC)[1]), "+f"((ACC)[2]), "+f"((ACC)[3])      \
        : "r"((A)[0]), "r"((A)[1]), "r"((A)[2]), "r"((A)[3]),                 \
          "r"(B0), "r"(B1))

#define LDSM_X4(R, ADDR)                                                      \
    asm volatile("ldmatrix.sync.aligned.m8n8.x4.shared.b16 {%0,%1,%2,%3}, [%4];" \
                 : "=r"((R)[0]), "=r"((R)[1]), "=r"((R)[2]), "=r"((R)[3]) : "r"(ADDR))
#define LDSM_X4T(R, ADDR)                                                     \
    asm volatile("ldmatrix.sync.aligned.m8n8.x4.trans.shared.b16 {%0,%1,%2,%3}, [%4];" \
                 : "=r"((R)[0]), "=r"((R)[1]), "=r"((R)[2]), "=r"((R)[3]) : "r"(ADDR))

#define MBAR_INIT(mb, cnt) \
    asm volatile("mbarrier.init.shared.b64 [%0], %1;" :: "r"(mb), "r"((uint32_t)(cnt)) : "memory")
#define MBAR_EXPECT_TX(mb, bytes) \
    asm volatile("mbarrier.arrive.expect_tx.shared.b64 _, [%0], %1;" :: "r"(mb), "r"((uint32_t)(bytes)) : "memory")
#define MBAR_ARRIVE(mb) \
    asm volatile("mbarrier.arrive.shared.b64 _, [%0];" :: "r"(mb) : "memory")
#define MBAR_WAIT(mb, ph) do {                                                    \
    asm volatile("{\n\t.reg .pred P1;\n\t"                                        \
        "WAIT_LOOP_%=:\n\t"                                                       \
        "mbarrier.try_wait.parity.acquire.cta.shared::cta.b64 P1, [%0], %1, 0x989680;\n\t" \
        "@P1 bra.uni WAIT_DONE_%=;\n\t"                                           \
        "bra.uni WAIT_LOOP_%=;\n\t"                                               \
        "WAIT_DONE_%=:\n\t}"                                                      \
        :: "r"(mb), "r"((uint32_t)(ph)) : "memory");                              \
} while(0)

#define TMA_LOAD_2D(sa, map, cx, cy, mb)                                          \
    asm volatile("cp.async.bulk.tensor.2d.shared::cta.global.tile.mbarrier::complete_tx::bytes " \
        "[%0], [%1, {%2, %3}], [%4];"                                             \
        :: "r"(sa), "l"(map), "r"((int32_t)(cx)), "r"((int32_t)(cy)), "r"(mb) : "memory")

// ---------------- conversions ----------------
__global__ __launch_bounds__(256) void split_wT_f16_kernel(const float* __restrict__ W,
                                                           __half* __restrict__ WT) {
    __shared__ float t[32][33];
    int k0 = blockIdx.x * 32, n0 = blockIdx.y * 32;
    int tx = threadIdx.x, ty = threadIdx.y;
    #pragma unroll
    for (int i = 0; i < 4; i++)
        t[ty + i * 8][tx] = W[(size_t)(k0 + ty + i * 8) * C_ + n0 + tx];
    __syncthreads();
    #pragma unroll
    for (int i = 0; i < 4; i++)
        WT[(size_t)(n0 + ty + i * 8) * C_ + k0 + tx] = __float2half(t[tx][ty + i * 8]);
}

__global__ __launch_bounds__(256) void conv_x_kernel(const float* __restrict__ x) {
    __shared__ float tile[32][33];
    int b  = blockIdx.z;
    int n0 = blockIdx.x * 32;
    int c0 = blockIdx.y * 32;
    int tx = threadIdx.x, ty = threadIdx.y;
    const float* xb = x + (size_t)b * C_ * N_;
    #pragma unroll
    for (int i = 0; i < 4; i++)
        tile[ty + i * 8][tx] = xb[(size_t)(c0 + ty + i * 8) * N_ + n0 + tx];
    __syncthreads();
    #pragma unroll
    for (int i = 0; i < 4; i++) {
        int n = n0 + ty + i * 8;
        g_axs[((size_t)b * N_ + n) * C_ + c0 + tx] = __float2half(tile[tx][ty + i * 8]);
    }
}

// ---------------- avg-pool -> single fp16 ----------------
__global__ __launch_bounds__(256) void pool_kernel(const float* __restrict__ x) {
    __shared__ float sp[16][577];
    int b  = blockIdx.y;
    int c0 = blockIdx.x * 16;
    int tid = threadIdx.x;
    const float* xb = x + (size_t)b * C_ * N_ + (size_t)c0 * N_;
    #pragma unroll
    for (int r = 0; r < 36; r++) {
        int idx = tid + r * 256;
        int p = idx / 576, n = idx - p * 576;
        sp[p][n] = xb[(size_t)p * N_ + n];
    }
    __syncthreads();
    #pragma unroll
    for (int r = 0; r < 9; r++) {
        int idx = tid + r * 256;
        int qn = idx >> 4, cl = idx & 15;
        int qy = qn / 12, qx = qn - qy * 12;
        float s = 0.f;
        #pragma unroll
        for (int dy = -1; dy <= 1; dy++) {
            int y = 2 * qy + dy;
            if ((unsigned)y < 24u) {
                #pragma unroll
                for (int dx = -1; dx <= 1; dx++) {
                    int xx = 2 * qx + dx;
                    if ((unsigned)xx < 24u) s += sp[cl][y * 24 + xx];
                }
            }
        }
        g_aqs[((size_t)b * QN + qn) * C_ + c0 + cl] = __float2half(s * (1.0f / 9.0f));
    }
}

// ---------------- single-term GEMM: C = A·B ----------------
// blockIdx.z selects (B,D) pair. mode 2: single fp16 head-major. mode 3: + fp32 row-major.
#define G1_TILE  16384
#define G1_BUF   (2*G1_TILE)
#define G1_SMEM  (3*G1_BUF + 1024)
#define NSTAGE   16

__global__ __launch_bounds__(512) void gemm_1t(
    const __grid_constant__ CUtensorMap tmA,
    const __grid_constant__ CUtensorMap tmBa,
    const __grid_constant__ CUtensorMap tmBb,
    __half* __restrict__ Da,
    __half* __restrict__ Db,
    float* __restrict__ Cm,
    int rpb, int mode)
{
    extern __shared__ char smem[];
    uint32_t sraw = smem_u32(smem);
    uint32_t fullb[3]  = {sraw, sraw + 8, sraw + 16};
    uint32_t emptyb[3] = {sraw + 24, sraw + 32, sraw + 40};
    uint32_t tiles = (sraw + 64 + 1023) & ~1023u;

    int tid = threadIdx.x, lane = tid & 31, warp = tid >> 5;
    int wm = warp >> 2, wn = warp & 3;
    int rowBase = blockIdx.y * 128;
    int colBase = blockIdx.x * 128;
    const CUtensorMap* pB = blockIdx.z ? &tmBb : &tmBa;
    __half* Ds = blockIdx.z ? Db : Da;

    if (tid == 0) {
        MBAR_INIT(fullb[0], 1);  MBAR_INIT(fullb[1], 1);  MBAR_INIT(fullb[2], 1);
        MBAR_INIT(emptyb[0], 512); MBAR_INIT(emptyb[1], 512); MBAR_INIT(emptyb[2], 512);
    }
    __syncthreads();

    float acc[2][4][4];
    #pragma unroll
    for (int i = 0; i < 2; i++)
        #pragma unroll
        for (int j = 0; j < 4; j++)
            #pragma unroll
            for (int r = 0; r < 4; r++) acc[i][j][r] = 0.f;

    int phF[3] = {0, 0, 0};
    int phE[3] = {0, 0, 0};
    auto issue = [&](int s, int slot) {
        uint32_t base = tiles + slot * G1_BUF;
        MBAR_EXPECT_TX(fullb[slot], G1_BUF);
        int k0 = s * 64;
        TMA_LOAD_2D(base,           &tmA, k0, rowBase, fullb[slot]);
        TMA_LOAD_2D(base + G1_TILE, pB,   k0, colBase, fullb[slot]);
    };
    if (tid == 0) { issue(0, 0); issue(1, 1); issue(2, 2); }

    uint32_t ah[2][2][4], bf[2][2][4];
    int arow0 = wm * 32 + (lane & 7) + ((lane >> 3) & 1) * 8;
    int acol8 = (lane >> 4) << 3;
    int brow0 = wn * 32 + (lane & 7) + ((lane >> 4) & 1) * 8;
    int bcol8 = (lane >> 3) & 1 ? 8 : 0;

    for (int s = 0; s < NSTAGE; s++) {
        int slot = s % 3;
        MBAR_WAIT(fullb[slot], phF[slot]); phF[slot] ^= 1;
        uint32_t aA = tiles + slot * G1_BUF;
        uint32_t bB = aA + G1_TILE;
        {
            #pragma unroll
            for (int mf = 0; mf < 2; mf++) {
                uint32_t off = swz((uint32_t)((arow0 + mf * 16) * 128 + acol8 * 2));
                LDSM_X4(ah[0][mf], aA + off);
            }
            #pragma unroll
            for (int g = 0; g < 2; g++) {
                uint32_t off = swz((uint32_t)((brow0 + g * 16) * 128 + bcol8 * 2));
                LDSM_X4(bf[0][g], bB + off);
            }
        }
        #pragma unroll
        for (int kki = 0; kki < 4; kki++) {
            int pb = kki & 1;
            if (kki < 3) {
                int nb = pb ^ 1;
                int kk = (kki + 1) * 16;
                #pragma unroll
                for (int mf = 0; mf < 2; mf++) {
                    uint32_t off = swz((uint32_t)((arow0 + mf * 16) * 128 + (kk + acol8) * 2));
                    LDSM_X4(ah[nb][mf], aA + off);
                }
                #pragma unroll
                for (int g = 0; g < 2; g++) {
                    uint32_t off = swz((uint32_t)((brow0 + g * 16) * 128 + (kk + bcol8) * 2));
                    LDSM_X4(bf[nb][g], bB + off);
                }
            }
            #pragma unroll
            for (int mf = 0; mf < 2; mf++)
                #pragma unroll
                for (int nf = 0; nf < 4; nf++) {
                    uint32_t b0 = bf[pb][nf >> 1][(nf & 1) * 2 + 0];
                    uint32_t b1 = bf[pb][nf >> 1][(nf & 1) * 2 + 1];
                    MMA_F16(acc[mf][nf], ah[pb][mf], b0, b1);
                }
        }
        MBAR_ARRIVE(emptyb[slot]);
        if (tid == 0 && s + 3 < NSTAGE) {
            MBAR_WAIT(emptyb[slot], phE[slot]); phE[slot] ^= 1;
            issue(s + 3, slot);
        }
    }

    int gid = lane >> 2, tig = lane & 3;
    #pragma unroll
    for (int mf = 0; mf < 2; mf++)
        #pragma unroll
        for (int nf = 0; nf < 4; nf++) {
            int c0 = colBase + wn * 32 + nf * 8 + tig * 2;
            #pragma unroll
            for (int rr = 0; rr < 2; rr++) {
                int row = rowBase + wm * 32 + mf * 16 + gid + rr * 8;
                float v0 = acc[mf][nf][rr * 2 + 0];
                float v1 = acc[mf][nf][rr * 2 + 1];
                int b = row / rpb, n = row - b * rpb;
                int h = c0 >> 7, d = c0 & 127;
                size_t di = (((size_t)b * NH + h) * rpb + n) * HD + d;
                *(__half2*)(Ds + di) = __floats2half2_rn(v0, v1);
                if (mode == 3)
                    *(float2*)&Cm[(size_t)row * C_ + c0] = make_float2(v0, v1);
            }
        }
}

// ---------------- 2-term GEMM (P projection only, mode 1) ----------------
#define G2_TILE  16384
#define G2_BUF   (3*G2_TILE)
#define G2_SMEM  (3*G2_BUF + 1024)

__global__ __launch_bounds__(512) void gemm_f16(
    const __grid_constant__ CUtensorMap tmAh,
    const __grid_constant__ CUtensorMap tmAl,
    const __grid_constant__ CUtensorMap tmB,
    const float* __restrict__ bias,
    float* __restrict__ Cm)
{
    extern __shared__ char smem[];
    uint32_t sraw = smem_u32(smem);
    uint32_t fullb[3]  = {sraw, sraw + 8, sraw + 16};
    uint32_t emptyb[3] = {sraw + 24, sraw + 32, sraw + 40};
    uint32_t tiles = (sraw + 64 + 1023) & ~1023u;

    int tid = threadIdx.x, lane = tid & 31, warp = tid >> 5;
    int wm = warp >> 2, wn = warp & 3;
    int rowBase = blockIdx.y * 128;
    int colBase = blockIdx.x * 128;

    if (tid == 0) {
        MBAR_INIT(fullb[0], 1);  MBAR_INIT(fullb[1], 1);  MBAR_INIT(fullb[2], 1);
        MBAR_INIT(emptyb[0], 512); MBAR_INIT(emptyb[1], 512); MBAR_INIT(emptyb[2], 512);
    }
    __syncthreads();

    float acc[2][4][4];
    #pragma unroll
    for (int i = 0; i < 2; i++)
        #pragma unroll
        for (int j = 0; j < 4; j++)
            #pragma unroll
            for (int r = 0; r < 4; r++) acc[i][j][r] = 0.f;

    int phF[3] = {0, 0, 0};
    int phE[3] = {0, 0, 0};
    auto issue = [&](int s, int slot) {
        uint32_t base = tiles + slot * G2_BUF;
        MBAR_EXPECT_TX(fullb[slot], G2_BUF);
        int k0 = s * 64;
        TMA_LOAD_2D(base,               &tmAh, k0, rowBase, fullb[slot]);
        TMA_LOAD_2D(base + G2_TILE,     &tmAl, k0, rowBase, fullb[slot]);
        TMA_LOAD_2D(base + 2 * G2_TILE, &tmB,  k0, colBase, fullb[slot]);
    };
    if (tid == 0) { issue(0, 0); issue(1, 1); issue(2, 2); }

    uint32_t ah[2][2][4], al[2][2][4], bf[2][2][4];
    int arow0 = wm * 32 + (lane & 7) + ((lane >> 3) & 1) * 8;
    int acol8 = (lane >> 4) << 3;
    int brow0 = wn * 32 + (lane & 7) + ((lane >> 4) & 1) * 8;
    int bcol8 = (lane >> 3) & 1 ? 8 : 0;

    for (int s = 0; s < NSTAGE; s++) {
        int slot = s % 3;
        MBAR_WAIT(fullb[slot], phF[slot]); phF[slot] ^= 1;
        uint32_t aH = tiles + slot * G2_BUF;
        uint32_t aL = aH + G2_TILE;
        uint32_t bB = aH + 2 * G2_TILE;
        {
            #pragma unroll
            for (int mf = 0; mf < 2; mf++) {
                uint32_t off = swz((uint32_t)((arow0 + mf * 16) * 128 + acol8 * 2));
                LDSM_X4(ah[0][mf], aH + off);
                LDSM_X4(al[0][mf], aL + off);
            }
            #pragma unroll
            for (int g = 0; g < 2; g++) {
                uint32_t off = swz((uint32_t)((brow0 + g * 16) * 128 + bcol8 * 2));
                LDSM_X4(bf[0][g], bB + off);
            }
        }
        #pragma unroll
        for (int kki = 0; kki < 4; kki++) {
            int pb = kki & 1;
            if (kki < 3) {
                int nb = pb ^ 1;
                int kk = (kki + 1) * 16;
                #pragma unroll
                for (int mf = 0; mf < 2; mf++) {
                    uint32_t off = swz((uint32_t)((arow0 + mf * 16) * 128 + (kk + acol8) * 2));
                    LDSM_X4(ah[nb][mf], aH + off);
                    LDSM_X4(al[nb][mf], aL + off);
                }
                #pragma unroll
                for (int g = 0; g < 2; g++) {
                    uint32_t off = swz((uint32_t)((brow0 + g * 16) * 128 + (kk + bcol8) * 2));
                    LDSM_X4(bf[nb][g], bB + off);
                }
            }
            #pragma unroll
            for (int mf = 0; mf < 2; mf++)
                #pragma unroll
                for (int nf = 0; nf < 4; nf++) {
                    uint32_t b0 = bf[pb][nf >> 1][(nf & 1) * 2 + 0];
                    uint32_t b1 = bf[pb][nf >> 1][(nf & 1) * 2 + 1];
                    MMA_F16(acc[mf][nf], ah[pb][mf], b0, b1);
                    MMA_F16(acc[mf][nf], al[pb][mf], b0, b1);
                }
        }
        MBAR_ARRIVE(emptyb[slot]);
        if (tid == 0 && s + 3 < NSTAGE) {
            MBAR_WAIT(emptyb[slot], phE[slot]); phE[slot] ^= 1;
            issue(s + 3, slot);
        }
    }

    int gid = lane >> 2, tig = lane & 3;
    #pragma unroll
    for (int mf = 0; mf < 2; mf++)
        #pragma unroll
        for (int nf = 0; nf < 4; nf++) {
            int c0 = colBase + wn * 32 + nf * 8 + tig * 2;
            #pragma unroll
            for (int rr = 0; rr < 2; rr++) {
                int row = rowBase + wm * 32 + mf * 16 + gid + rr * 8;
                int bq = row / QN, qi = row - bq * QN;
                Cm[((size_t)bq * C_ + c0) * QN + qi]     = acc[mf][nf][rr * 2 + 0] + bias[c0];
                Cm[((size_t)bq * C_ + c0 + 1) * QN + qi] = acc[mf][nf][rr * 2 + 1] + bias[c0 + 1];
            }
        }
}

// ---------------- relative position bias dots ----------------
__global__ __launch_bounds__(64) void relpos_kernel(const float* __restrict__ rel_h,
                                                    const float* __restrict__ rel_w) {
    int gid = blockIdx.x;
    int bh = gid / QN, i = gid - bh * QN;
    int b = bh >> 3, h = bh & 7;
    int qy = i / 12, qx = i - qy * 12;
    int t = threadIdx.x;
    const float* qrow = g_q + ((size_t)b * QN + i) * C_ + h * HD;
    if (t < 24) {
        const float* R = rel_h + (size_t)(2 * qy - t + 23) * HD;
        float a0 = 0, a1 = 0, a2 = 0, a3 = 0;
        #pragma unroll
        for (int d = 0; d < HD; d += 4) {
            a0 += qrow[d + 0] * R[d + 0];
            a1 += qrow[d + 1] * R[d + 1];
            a2 += qrow[d + 2] * R[d + 2];
            a3 += qrow[d + 3] * R[d + 3];
        }
        g_relh[(size_t)gid * 24 + t] = (a0 + a1) + (a2 + a3);
    } else if (t >= 32 && t < 56) {
        int kx = t - 32;
        const float* R = rel_w + (size_t)(2 * qx - kx + 23) * HD;
        float a0 = 0, a1 = 0, a2 = 0, a3 = 0;
        #pragma unroll
        for (int d = 0; d < HD; d += 4) {
            a0 += qrow[d + 0] * R[d + 0];
            a1 += qrow[d + 1] * R[d + 1];
            a2 += qrow[d + 2] * R[d + 2];
            a3 += qrow[d + 3] * R[d + 3];
        }
        g_relw[(size_t)gid * 24 + kx] = (a0 + a1) + (a2 + a3);
    }
}

// ---------------- FUSED QK^T + bias + softmax -> single fp16 P ----------------
#define QKF_Q    0
#define QKF_K0   12288
#define QKF_KBUF 24576
#define QKF_REL  (12288 + 2*24576)
#define QKF_RED  (QKF_REL + 9216)
#define QKF_SMEM (QKF_RED + 2304 + 1088)

__global__ __launch_bounds__(576) void qk_fused(
    const __grid_constant__ CUtensorMap tmQ,
    const __grid_constant__ CUtensorMap tmK)
{
    extern __shared__ char smem[];
    uint32_t sraw = smem_u32(smem);
    uint32_t fullb[2]  = {sraw, sraw + 8};
    uint32_t emptyb[2] = {sraw + 16, sraw + 24};
    uint32_t tiles = (sraw + 64 + 1023) & ~1023u;
    char* tilesp = smem + (tiles - sraw);
    float* srelh = (float*)(tilesp + QKF_REL);
    float* srelw = srelh + 48 * 24;
    float* smax  = (float*)(tilesp + QKF_RED);
    float* ssum  = smax + 48 * 6;

    int bh = blockIdx.z;
    int rowBase = blockIdx.y * 48;
    int tid = threadIdx.x, lane = tid & 31, warp = tid >> 5;
    int wm = warp / 6, wn = warp % 6;
    int gid = lane >> 2, tig = lane & 3;

    if (tid == 0) {
        MBAR_INIT(fullb[0], 1);  MBAR_INIT(fullb[1], 1);
        MBAR_INIT(emptyb[0], 576); MBAR_INIT(emptyb[1], 576);
    }
    __syncthreads();

    for (int idx = tid; idx < 48 * 24; idx += 576) {
        size_t gidx = ((size_t)bh * QN + rowBase + idx / 24) * 24 + (idx % 24);
        srelh[idx] = g_relh[gidx];
        srelw[idx] = g_relw[gidx];
    }

    int phF[2] = {0, 0}, phE[2] = {0, 0};
    auto issue = [&](int c, int buf) {
        uint32_t kb = tiles + QKF_K0 + buf * QKF_KBUF;
        MBAR_EXPECT_TX(fullb[buf], (c == 0) ? (12288u + QKF_KBUF) : (uint32_t)QKF_KBUF);
        int ky0 = bh * N_ + c * 96;
        if (c == 0) {
            int qy = bh * QN + rowBase;
            TMA_LOAD_2D(tiles + QKF_Q,        &tmQ, 0,  qy, fullb[0]);
            TMA_LOAD_2D(tiles + QKF_Q + 6144, &tmQ, 64, qy, fullb[0]);
        }
        TMA_LOAD_2D(kb,         &tmK, 0,  ky0, fullb[buf]);
        TMA_LOAD_2D(kb + 12288, &tmK, 64, ky0, fullb[buf]);
    };
    if (tid == 0) { issue(0, 0); issue(1, 1); }

    float acc[12][4];
    #pragma unroll
    for (int j = 0; j < 12; j++)
        #pragma unroll
        for (int r = 0; r < 4; r++) acc[j][r] = 0.f;

    int arow = wm * 16 + (lane & 7) + ((lane >> 3) & 1) * 8;
    int acol8 = (lane >> 4) << 3;
    int brow = wn * 16 + (lane & 7) + ((lane >> 4) & 1) * 8;
    int bcol8 = ((lane >> 3) & 1) * 8;

    for (int c = 0; c < 6; c++) {
        int buf = c & 1;
        MBAR_WAIT(fullb[buf], phF[buf]); phF[buf] ^= 1;
        uint32_t kB = tiles + QKF_K0 + buf * QKF_KBUF;

        #pragma unroll
        for (int kk = 0; kk < 128; kk += 16) {
            uint32_t a_[4];
            {
                int ce = kk + acol8;
                uint32_t off = (uint32_t)((ce >> 6) * 6144) + swz((uint32_t)(arow * 128 + (ce & 63) * 2));
                LDSM_X4(a_, tiles + QKF_Q + off);
            }
            uint32_t b_[4];
            {
                int kc = kk + bcol8;
                uint32_t off = (uint32_t)((kc >> 6) * 12288) + swz((uint32_t)(brow * 128 + (kc & 63) * 2));
                LDSM_X4(b_, kB + off);
            }
            #pragma unroll
            for (int j = 0; j < 2; j++) {
                float* A = acc[c * 2 + j];
                MMA_F16(A, a_, b_[j * 2], b_[j * 2 + 1]);
            }
        }
        MBAR_ARRIVE(emptyb[buf]);
        if (tid == 0 && c + 2 < 6) {
            MBAR_WAIT(emptyb[buf], phE[buf]); phE[buf] ^= 1;
            issue(c + 2, buf);
        }
    }
    __syncthreads();

    const float scale = 0.08838834764831845f;
    int il0 = wm * 16 + gid;
    float mrow[2] = {-1e30f, -1e30f};
    #pragma unroll
    for (int nf = 0; nf < 12; nf++) {
        int colb = (nf >> 1) * 96 + wn * 16 + (nf & 1) * 8 + tig * 2;
        #pragma unroll
        for (int rr = 0; rr < 2; rr++) {
            int il = il0 + rr * 8;
            #pragma unroll
            for (int cc = 0; cc < 2; cc++) {
                int col = colb + cc;
                int ky = col / 24, kx = col - ky * 24;
                float v = acc[nf][rr * 2 + cc] * scale + srelh[il * 24 + ky] + srelw[il * 24 + kx];
                acc[nf][rr * 2 + cc] = v;
                mrow[rr] = fmaxf(mrow[rr], v);
            }
        }
    }
    #pragma unroll
    for (int o = 1; o <= 2; o <<= 1) {
        mrow[0] = fmaxf(mrow[0], __shfl_xor_sync(0xffffffffu, mrow[0], o));
        mrow[1] = fmaxf(mrow[1], __shfl_xor_sync(0xffffffffu, mrow[1], o));
    }
    if (tig == 0) {
        smax[(il0) * 6 + wn] = mrow[0];
        smax[(il0 + 8) * 6 + wn] = mrow[1];
    }
    __syncthreads();
    float M[2];
    #pragma unroll
    for (int rr = 0; rr < 2; rr++) {
        const float* r = smax + (il0 + rr * 8) * 6;
        M[rr] = fmaxf(fmaxf(fmaxf(r[0], r[1]), fmaxf(r[2], r[3])), fmaxf(r[4], r[5]));
    }
    float srow[2] = {0.f, 0.f};
    #pragma unroll
    for (int nf = 0; nf < 12; nf++)
        #pragma unroll
        for (int rr = 0; rr < 2; rr++)
            #pragma unroll
            for (int cc = 0; cc < 2; cc++) {
                float e = __expf(acc[nf][rr * 2 + cc] - M[rr]);
                acc[nf][rr * 2 + cc] = e;
                srow[rr] += e;
            }
    #pragma unroll
    for (int o = 1; o <= 2; o <<= 1) {
        srow[0] += __shfl_xor_sync(0xffffffffu, srow[0], o);
        srow[1] += __shfl_xor_sync(0xffffffffu, srow[1], o);
    }
    if (tig == 0) {
        ssum[(il0) * 6 + wn] = srow[0];
        ssum[(il0 + 8) * 6 + wn] = srow[1];
    }
    __syncthreads();
    float inv[2];
    #pragma unroll
    for (int rr = 0; rr < 2; rr++) {
        const float* r = ssum + (il0 + rr * 8) * 6;
        inv[rr] = 1.0f / ((r[0] + r[1]) + (r[2] + r[3]) + (r[4] + r[5]));
    }
    #pragma unroll
    for (int nf = 0; nf < 12; nf++) {
        int colb = (nf >> 1) * 96 + wn * 16 + (nf & 1) * 8 + tig * 2;
        #pragma unroll
        for (int rr = 0; rr < 2; rr++) {
            size_t off = ((size_t)bh * QN + rowBase + il0 + rr * 8) * N_ + colb;
            *(__half2*)(g_ps + off) = __floats2half2_rn(acc[nf][rr * 2 + 0] * inv[rr],
                                                        acc[nf][rr * 2 + 1] * inv[rr]);
        }
    }
}

// ---------------- AV mma (single-term P, single V) ----------------
#define AV_P    0
#define AV_V    6144
#define AV_BUF  22528
#define AV_SMEM (2*AV_BUF + 2048)

__global__ __launch_bounds__(384) void av_mma(
    const __grid_constant__ CUtensorMap tmP,
    const __grid_constant__ CUtensorMap tmV)
{
    extern __shared__ char smem[];
    uint32_t sraw = smem_u32(smem);
    uint32_t fullb[2]  = {sraw, sraw + 8};
    uint32_t emptyb[2] = {sraw + 16, sraw + 24};
    uint32_t tiles = (sraw + 64 + 1023) & ~1023u;

    int bh = blockIdx.z;
    int b = bh >> 3, h = bh & 7;
    int rowBase = blockIdx.y * 48;
    int tid = threadIdx.x, lane = tid & 31, warp = tid >> 5;
    int wm = warp >> 2, wn = warp & 3;
    int nBase = wn * 32;

    if (tid == 0) {
        MBAR_INIT(fullb[0], 1);  MBAR_INIT(fullb[1], 1);
        MBAR_INIT(emptyb[0], 384); MBAR_INIT(emptyb[1], 384);
    }
    __syncthreads();

    float acc[4][4];
    #pragma unroll
    for (int j = 0; j < 4; j++)
        #pragma unroll
        for (int r = 0; r < 4; r++) acc[j][r] = 0.f;

    int phF[2] = {0, 0};
    int phE[2] = {1, 1};

    auto issue = [&](int s, int buf) {
        uint32_t base = tiles + buf * AV_BUF;
        MBAR_EXPECT_TX(fullb[buf], AV_BUF);
        int k0 = s * 64;
        int py = bh * QN + rowBase;
        int vy = bh * N_ + k0;
        TMA_LOAD_2D(base + AV_P, &tmP, k0, py, fullb[buf]);
        TMA_LOAD_2D(base + AV_V,        &tmV, 0,  vy, fullb[buf]);
        TMA_LOAD_2D(base + AV_V + 8192, &tmV, 64, vy, fullb[buf]);
    };

    if (tid == 0) {
        MBAR_WAIT(emptyb[0], phE[0]); phE[0] ^= 1;
        issue(0, 0);
    }

    for (int s = 0; s < 9; s++) {
        int buf = s & 1;
        if (tid == 0 && s + 1 < 9) {
            int nb = buf ^ 1;
            MBAR_WAIT(emptyb[nb], phE[nb]); phE[nb] ^= 1;
            issue(s + 1, nb);
        }
        MBAR_WAIT(fullb[buf], phF[buf]); phF[buf] ^= 1;
        uint32_t base = tiles + buf * AV_BUF;

        #pragma unroll
        for (int kk = 0; kk < 64; kk += 16) {
            uint32_t ap[4];
            {
                int row = wm * 16 + (lane & 7) + ((lane >> 3) & 1) * 8;
                int ce  = kk + ((lane >> 4) << 3);
                uint32_t off = swz((uint32_t)(row * 128 + ce * 2));
                LDSM_X4(ap, base + AV_P + off);
            }
            uint32_t bvf[2][4];
            #pragma unroll
            for (int g = 0; g < 2; g++) {
                int vrow = kk + (lane & 15);
                int d    = nBase + g * 16 + ((lane >> 4) << 3);
                uint32_t off = (uint32_t)((d >> 6) * 8192) + swz((uint32_t)(vrow * 128 + (d & 63) * 2));
                LDSM_X4T(bvf[g], base + AV_V + off);
            }
            #pragma unroll
            for (int nf = 0; nf < 4; nf++) {
                uint32_t b0 = bvf[nf >> 1][(nf & 1) * 2 + 0];
                uint32_t b1 = bvf[nf >> 1][(nf & 1) * 2 + 1];
                MMA_F16(acc[nf], ap, b0, b1);
            }
        }
        MBAR_ARRIVE(emptyb[buf]);
    }

    int gid = lane >> 2, tig = lane & 3;
    #pragma unroll
    for (int nf = 0; nf < 4; nf++) {
        int d = nBase + nf * 8 + tig * 2;
        #pragma unroll
        for (int rr = 0; rr < 2; rr++) {
            int i = rowBase + wm * 16 + gid + rr * 8;
            size_t off = ((size_t)b * QN + i) * C_ + h * HD + d;
            float2 qv = *(const float2*)(g_q + off);
            float v0 = acc[nf][rr * 2 + 0] + qv.x;
            float v1 = acc[nf][rr * 2 + 1] + qv.y;
            __half2 th, tl;
            split2h(v0, th.x, tl.x);
            split2h(v1, th.y, tl.y);
            *(__half2*)(g_aoh2 + off) = th;
            *(__half2*)(g_aol2 + off) = tl;
        }
    }
}

// ---------------- host: tensormap builder ----------------
typedef CUresult (*EncodeTiledFn)(CUtensorMap*, CUtensorMapDataType, cuuint32_t, void*,
                                  const cuuint64_t*, const cuuint64_t*, const cuuint32_t*,
                                  const cuuint32_t*, CUtensorMapInterleave, CUtensorMapSwizzle,
                                  CUtensorMapL2promotion, CUtensorMapFloatOOBfill);

static void make_map(EncodeTiledFn enc, CUtensorMap* m, void* ptr,
                     uint64_t dim0, uint64_t rows, uint32_t box0, uint32_t box1) {
    cuuint64_t dims[2]    = {(cuuint64_t)dim0, (cuuint64_t)rows};
    cuuint64_t strides[1] = {(cuuint64_t)dim0 * 2};
    cuuint32_t box[2]     = {box0, box1};
    cuuint32_t es[2]      = {1, 1};
    enc(m, CU_TENSOR_MAP_DATA_TYPE_FLOAT16, 2, ptr, dims, strides, box, es,
        CU_TENSOR_MAP_INTERLEAVE_NONE, CU_TENSOR_MAP_SWIZZLE_128B,
        CU_TENSOR_MAP_L2_PROMOTION_L2_128B, CU_TENSOR_MAP_FLOAT_OOB_FILL_NONE);
}

// ---------------- launch ----------------
extern "C" void kernel_launch(void* const* d_in, const int* in_sizes, int n_in,
                              void* d_out, int out_size) {
    const float* x   = (const float*)d_in[0];
    const float* Wq  = (const float*)d_in[1];
    const float* Wk  = (const float*)d_in[2];
    const float* Wv  = (const float*)d_in[3];
    const float* Wp  = (const float*)d_in[4];
    const float* bp  = (const float*)d_in[5];
    const float* rph = (const float*)d_in[6];
    const float* rpw = (const float*)d_in[7];
    float* out = (float*)d_out;

    float *q;
    __half *axs, *aqs, *aoh2, *aol2;
    __half *wq2, *wk2, *wv2, *wp2;
    __half *qs, *k2, *v2, *ps;
    cudaGetSymbolAddress((void**)&q,  g_q);
    cudaGetSymbolAddress((void**)&axs, g_axs);
    cudaGetSymbolAddress((void**)&aqs, g_aqs);
    cudaGetSymbolAddress((void**)&aoh2, g_aoh2);
    cudaGetSymbolAddress((void**)&aol2, g_aol2);
    cudaGetSymbolAddress((void**)&wq2, g_wq2);
    cudaGetSymbolAddress((void**)&wk2, g_wk2);
    cudaGetSymbolAddress((void**)&wv2, g_wv2);
    cudaGetSymbolAddress((void**)&wp2, g_wp2);
    cudaGetSymbolAddress((void**)&qs, g_qs);
    cudaGetSymbolAddress((void**)&k2, g_k2);
    cudaGetSymbolAddress((void**)&v2, g_v2);
    cudaGetSymbolAddress((void**)&ps, g_ps);

    EncodeTiledFn enc = nullptr;
    {
        void* fn = nullptr;
        cudaDriverEntryPointQueryResult st;
        cudaGetDriverEntryPoint("cuTensorMapEncodeTiled", &fn, cudaEnableDefault, &st);
        enc = (EncodeTiledFn)fn;
    }
    CUtensorMap mAx, mAq, mAoh, mAol;
    CUtensorMap mWq, mWk, mWv, mWp;
    CUtensorMap mQ, mK, mV, mP;
    make_map(enc, &mAx, axs, C_, (uint64_t)B_ * N_, 64, 128);
    make_map(enc, &mAq, aqs, C_, (uint64_t)B_ * QN, 64, 128);
    make_map(enc, &mAoh, aoh2, C_, (uint64_t)B_ * QN, 64, 128);
    make_map(enc, &mAol, aol2, C_, (uint64_t)B_ * QN, 64, 128);
    make_map(enc, &mWq, wq2, C_, C_, 64, 128);
    make_map(enc, &mWk, wk2, C_, C_, 64, 128);
    make_map(enc, &mWv, wv2, C_, C_, 64, 128);
    make_map(enc, &mWp, wp2, C_, C_, 64, 128);
    make_map(enc, &mQ,  qs,  HD, (uint64_t)BH * QN, 64, 48);
    make_map(enc, &mK,  k2,  HD, (uint64_t)BH * N_, 64, 96);
    make_map(enc, &mV,  v2,  HD, (uint64_t)BH * N_, 64, 64);
    make_map(enc, &mP,  ps,  N_, (uint64_t)BH * QN, 64, 48);

    cudaFuncSetAttribute(gemm_1t,  cudaFuncAttributeMaxDynamicSharedMemorySize, G1_SMEM);
    cudaFuncSetAttribute(gemm_f16, cudaFuncAttributeMaxDynamicSharedMemorySize, G2_SMEM);
    cudaFuncSetAttribute(qk_fused, cudaFuncAttributeMaxDynamicSharedMemorySize, QKF_SMEM);
    cudaFuncSetAttribute(av_mma, cudaFuncAttributeMaxDynamicSharedMemorySize, AV_SMEM);

    conv_x_kernel<<<dim3(18, 32, B_), dim3(32, 8)>>>(x);
    split_wT_f16_kernel<<<dim3(32, 32), dim3(32, 8)>>>(Wk, wk2);
    split_wT_f16_kernel<<<dim3(32, 32), dim3(32, 8)>>>(Wv, wv2);
    split_wT_f16_kernel<<<dim3(32, 32), dim3(32, 8)>>>(Wq, wq2);
    split_wT_f16_kernel<<<dim3(32, 32), dim3(32, 8)>>>(Wp, wp2);
    gemm_1t<<<dim3(8, (B_ * N_) / 128, 2), 512, G1_SMEM>>>(mAx, mWk, mWv, k2, v2, nullptr, N_, 2);

    pool_kernel<<<dim3(C_ / 16, B_), 256>>>(x);
    gemm_1t<<<dim3(8, (B_ * QN) / 128, 1), 512, G1_SMEM>>>(mAq, mWq, mWq, qs, qs, q, QN, 3);

    relpos_kernel<<<BH * QN, 64>>>(rph, rpw);
    qk_fused<<<dim3(1, 3, BH), 576, QKF_SMEM>>>(mQ, mK);
    av_mma<<<dim3(1, 3, BH), 384, AV_SMEM>>>(mP, mV);

    gemm_f16<<<dim3(8, (B_ * QN) / 128), 512, G2_SMEM>>>(mAoh, mAol, mWp, bp, out);
}